// round 6
// baseline (speedup 1.0000x reference)
#include <cuda_runtime.h>
#include <cuda_bf16.h>
#include <math.h>
#include <stdint.h>

#define NSEQ   1024
#define NBATCH 8
#define NDIM   512
#define NHEADS 8
#define NDH    64
#define NHD    512
#define NFF    2048
#define MROWS  (NBATCH*NSEQ)
#define ATT_ELEMS ((size_t)NBATCH*NHEADS*NSEQ*NSEQ)
#define X_ELEMS   ((size_t)MROWS*NDIM)

// transposed weight offsets (elements)
#define WQKVT 0
#define WKRT  786432
#define WOUTT 1048576
#define W1T   1310720
#define W2T   2359296
#define WT_TOTAL 3407872

// ---------------- scratch --------------------------------------------------
static __device__ float g_x [MROWS*NDIM];
static __device__ float g_ac[NBATCH*NHEADS*NSEQ*NSEQ];
static __device__ float g_bd[NBATCH*NHEADS*NSEQ*NSEQ];
static __device__ float g_bk[NBATCH*NHEADS*NSEQ];
static __device__ float g_br[NBATCH*NHEADS*NSEQ];
static __device__ __nv_bfloat16 g_xnh [MROWS*NDIM],  g_xnl [MROWS*NDIM];
static __device__ __nv_bfloat16 g_rth [MROWS*NDIM],  g_rtl [MROWS*NDIM];
static __device__ __nv_bfloat16 g_qkvh[MROWS*3*NHD], g_qkvl[MROWS*3*NHD];
static __device__ __nv_bfloat16 g_krh [MROWS*NHD],   g_krl [MROWS*NHD];
static __device__ __nv_bfloat16 g_avh [MROWS*NHD],   g_avl [MROWS*NHD];
static __device__ __nv_bfloat16 g_ffh [MROWS*NFF],   g_ffl [MROWS*NFF];
static __device__ __nv_bfloat16 g_wth [WT_TOTAL],    g_wtl [WT_TOTAL];
static __device__ __nv_bfloat16 g_vth [NBATCH*NHEADS*NDH*NSEQ];
static __device__ __nv_bfloat16 g_vtl [NBATCH*NHEADS*NDH*NSEQ];
static __device__ __nv_bfloat16 g_atth[NBATCH*NHEADS*NSEQ*NSEQ];
static __device__ __nv_bfloat16 g_attl[NBATCH*NHEADS*NSEQ*NSEQ];

// ---------------- primitives ------------------------------------------------
__device__ __forceinline__ uint32_t smem_u32(const void* p) {
    uint32_t a;
    asm("{ .reg .u64 t; cvta.to.shared.u64 t, %1; cvt.u32.u64 %0, t; }"
        : "=r"(a) : "l"(p));
    return a;
}
__device__ __forceinline__ void cp16(uint32_t dst, const void* src) {
    asm volatile("cp.async.cg.shared.global [%0], [%1], 16;" :: "r"(dst), "l"(src));
}
#define CP_COMMIT() asm volatile("cp.async.commit_group;")
#define CP_WAIT(n)  asm volatile("cp.async.wait_group %0;" :: "n"(n))

__device__ __forceinline__ void mma_bf16(float* d, const uint32_t* a, const uint32_t* b) {
    asm volatile(
        "mma.sync.aligned.m16n8k16.row.col.f32.bf16.bf16.f32 "
        "{%0,%1,%2,%3}, {%4,%5,%6,%7}, {%8,%9}, {%0,%1,%2,%3};"
        : "+f"(d[0]), "+f"(d[1]), "+f"(d[2]), "+f"(d[3])
        : "r"(a[0]), "r"(a[1]), "r"(a[2]), "r"(a[3]), "r"(b[0]), "r"(b[1]));
}
__device__ __forceinline__ void ldm_x4(uint32_t* r, uint32_t addr) {
    asm volatile("ldmatrix.sync.aligned.m8n8.x4.shared.b16 {%0,%1,%2,%3}, [%4];"
        : "=r"(r[0]), "=r"(r[1]), "=r"(r[2]), "=r"(r[3]) : "r"(addr));
}
__device__ __forceinline__ void ldm_x2(uint32_t* r, uint32_t addr) {
    asm volatile("ldmatrix.sync.aligned.m8n8.x2.shared.b16 {%0,%1}, [%2];"
        : "=r"(r[0]), "=r"(r[1]) : "r"(addr));
}
__device__ __forceinline__ float gelu_exact(float v) {
    return 0.5f * v * (1.0f + erff(v * 0.70710678118654752f));
}
__device__ __forceinline__ void split1(float v, __nv_bfloat16& h, __nv_bfloat16& l) {
    h = __float2bfloat16_rn(v);
    l = __float2bfloat16_rn(v - __bfloat162float(h));
}

// ---------------- weight transpose+split: W[K][N] -> Wt_h/l[N][K] -----------
__global__ __launch_bounds__(256) void transpose_split_kernel(
    const float* __restrict__ W, __nv_bfloat16* __restrict__ Wth,
    __nv_bfloat16* __restrict__ Wtl, int K, int N)
{
    __shared__ float t[32][33];
    const int k0 = blockIdx.y * 32, n0 = blockIdx.x * 32;
    const int x = threadIdx.x, y = threadIdx.y;
#pragma unroll
    for (int i = 0; i < 32; i += 8)
        t[y + i][x] = W[(size_t)(k0 + y + i) * N + n0 + x];
    __syncthreads();
#pragma unroll
    for (int i = 0; i < 32; i += 8) {
        float v = t[x][y + i];
        __nv_bfloat16 h, l; split1(v, h, l);
        Wth[(size_t)(n0 + y + i) * K + k0 + x] = h;
        Wtl[(size_t)(n0 + y + i) * K + k0 + x] = l;
    }
}

// ---------------- r_t split -------------------------------------------------
__global__ __launch_bounds__(256) void split_rt_kernel(
    const float* __restrict__ src, __nv_bfloat16* __restrict__ dh,
    __nv_bfloat16* __restrict__ dl)
{
    const size_t i = ((size_t)blockIdx.x * 256 + threadIdx.x) * 4;
    float4 v = *(const float4*)(src + i);
    __nv_bfloat16 h, l;
    split1(v.x, h, l); dh[i]   = h; dl[i]   = l;
    split1(v.y, h, l); dh[i+1] = h; dl[i+1] = l;
    split1(v.z, h, l); dh[i+2] = h; dl[i+2] = l;
    split1(v.w, h, l); dh[i+3] = h; dl[i+3] = l;
}

// ---------------- LayerNorm + split ------------------------------------------
__global__ __launch_bounds__(128) void ln_split_kernel(
    const float* __restrict__ x, const float* __restrict__ g,
    const float* __restrict__ b, __nv_bfloat16* __restrict__ yh,
    __nv_bfloat16* __restrict__ yl)
{
    const int row = blockIdx.x;
    const int tid = threadIdx.x;
    const float* xr = x + (size_t)row * NDIM;

    float4 v = ((const float4*)xr)[tid];
    float s  = v.x + v.y + v.z + v.w;
    float sq = v.x*v.x + v.y*v.y + v.z*v.z + v.w*v.w;
#pragma unroll
    for (int o = 16; o > 0; o >>= 1) {
        s  += __shfl_xor_sync(0xffffffffu, s,  o);
        sq += __shfl_xor_sync(0xffffffffu, sq, o);
    }
    __shared__ float red[8];
    const int w = tid >> 5;
    if ((tid & 31) == 0) { red[w] = s; red[4 + w] = sq; }
    __syncthreads();
    const float st  = red[0] + red[1] + red[2] + red[3];
    const float sqt = red[4] + red[5] + red[6] + red[7];
    const float mu  = st * (1.0f / NDIM);
    const float var = sqt * (1.0f / NDIM) - mu * mu;
    const float inv = rsqrtf(var + 1e-5f);

    float4 gg = ((const float4*)g)[tid];
    float4 bb = ((const float4*)b)[tid];
    float o0 = (v.x - mu) * inv * gg.x + bb.x;
    float o1 = (v.y - mu) * inv * gg.y + bb.y;
    float o2 = (v.z - mu) * inv * gg.z + bb.z;
    float o3 = (v.w - mu) * inv * gg.w + bb.w;
    const size_t base = (size_t)row * NDIM + tid * 4;
    __nv_bfloat16 h, l;
    split1(o0, h, l); yh[base]   = h; yl[base]   = l;
    split1(o1, h, l); yh[base+1] = h; yl[base+1] = l;
    split1(o2, h, l); yh[base+2] = h; yl[base+2] = l;
    split1(o3, h, l); yh[base+3] = h; yl[base+3] = l;
}

// =============== dense bf16x3 mma GEMM, cp.async double-buffered =============
#define LDS 40
#define ARR   (128*LDS)
#define STAGE (4*ARR)
#define MMA2_SMEM (2*STAGE*2)

template<int SPLIT, int ACT>
__global__ __launch_bounds__(256, 2) void mma2_kernel(
    const __nv_bfloat16* __restrict__ Ah, const __nv_bfloat16* __restrict__ Al,
    const __nv_bfloat16* __restrict__ Bh, const __nv_bfloat16* __restrict__ Bl,
    float* __restrict__ Cf, __nv_bfloat16* __restrict__ Ch,
    __nv_bfloat16* __restrict__ Cl,
    const float* __restrict__ bias, const float* __restrict__ res,
    int M, int N, int K)
{
    extern __shared__ char dsm[];
    const uint32_t sbase = smem_u32(dsm);
    const int tid = threadIdx.x, wid = tid >> 5, lane = tid & 31;
    const int wm = wid >> 2, wn = wid & 3;
    const int bm = blockIdx.y * 128, bn = blockIdx.x * 128;

    const int lrow = tid >> 2, lcc = (tid & 3) * 8;
    const int lrow2 = (tid + 256) >> 2, lcc2 = ((tid + 256) & 3) * 8;

#define MMA2_ISSUE(kt, s) do {                                                   \
        const uint32_t st_ = sbase + (uint32_t)(s) * (STAGE * 2);                \
        const int k0_ = (kt) * 32;                                               \
        cp16(st_ + (uint32_t)((lrow * LDS + lcc) * 2),                           \
             Ah + (size_t)(bm + lrow) * K + k0_ + lcc);                          \
        cp16(st_ + (uint32_t)((lrow2 * LDS + lcc2) * 2),                         \
             Ah + (size_t)(bm + lrow2) * K + k0_ + lcc2);                        \
        cp16(st_ + (uint32_t)(ARR * 2) + (uint32_t)((lrow * LDS + lcc) * 2),     \
             Al + (size_t)(bm + lrow) * K + k0_ + lcc);                          \
        cp16(st_ + (uint32_t)(ARR * 2) + (uint32_t)((lrow2 * LDS + lcc2) * 2),   \
             Al + (size_t)(bm + lrow2) * K + k0_ + lcc2);                        \
        cp16(st_ + (uint32_t)(2 * ARR * 2) + (uint32_t)((lrow * LDS + lcc) * 2), \
             Bh + (size_t)(bn + lrow) * K + k0_ + lcc);                          \
        cp16(st_ + (uint32_t)(2 * ARR * 2) + (uint32_t)((lrow2 * LDS + lcc2) * 2),\
             Bh + (size_t)(bn + lrow2) * K + k0_ + lcc2);                        \
        cp16(st_ + (uint32_t)(3 * ARR * 2) + (uint32_t)((lrow * LDS + lcc) * 2), \
             Bl + (size_t)(bn + lrow) * K + k0_ + lcc);                          \
        cp16(st_ + (uint32_t)(3 * ARR * 2) + (uint32_t)((lrow2 * LDS + lcc2) * 2),\
             Bl + (size_t)(bn + lrow2) * K + k0_ + lcc2);                        \
    } while (0)

    const int l15 = lane & 15;
    const uint32_t aoff = (uint32_t)(((wm * 64 + l15) * LDS + ((lane >> 4) << 3)) * 2);
    const uint32_t boff = (uint32_t)(((wn * 32 + (l15 & 7)) * LDS + (((l15 >> 3) & 1) << 3)) * 2);

    float acc[4][4][4];
#pragma unroll
    for (int i = 0; i < 4; ++i)
#pragma unroll
        for (int j = 0; j < 4; ++j)
#pragma unroll
            for (int q = 0; q < 4; ++q) acc[i][j][q] = 0.0f;

    const int NKT = K >> 5;
    MMA2_ISSUE(0, 0);
    CP_COMMIT();

    for (int kt = 0; kt < NKT; ++kt) {
        if (kt + 1 < NKT) {
            MMA2_ISSUE(kt + 1, (kt + 1) & 1);
            CP_COMMIT();
            CP_WAIT(1);
        } else {
            CP_WAIT(0);
        }
        __syncthreads();

        const uint32_t st = sbase + (uint32_t)(kt & 1) * (STAGE * 2);
        const uint32_t aAh = st, aAl = st + ARR * 2;
        const uint32_t aBh = st + 2 * ARR * 2, aBl = st + 3 * ARR * 2;
#pragma unroll
        for (int kk = 0; kk < 32; kk += 16) {
            uint32_t bh[4][2], bl[4][2], a[4][4];
#pragma unroll
            for (int nt = 0; nt < 4; ++nt) {
                const uint32_t bo = boff + (uint32_t)((nt * 8 * LDS + kk) * 2);
                ldm_x2(bh[nt], aBh + bo);
                ldm_x2(bl[nt], aBl + bo);
            }
#pragma unroll
            for (int mt = 0; mt < 4; ++mt)
                ldm_x4(a[mt], aAh + aoff + (uint32_t)((mt * 16 * LDS + kk) * 2));
#pragma unroll
            for (int mt = 0; mt < 4; ++mt)
#pragma unroll
                for (int nt = 0; nt < 4; ++nt) {
                    mma_bf16(acc[mt][nt], a[mt], bh[nt]);
                    mma_bf16(acc[mt][nt], a[mt], bl[nt]);
                }
#pragma unroll
            for (int mt = 0; mt < 4; ++mt)
                ldm_x4(a[mt], aAl + aoff + (uint32_t)((mt * 16 * LDS + kk) * 2));
#pragma unroll
            for (int mt = 0; mt < 4; ++mt)
#pragma unroll
                for (int nt = 0; nt < 4; ++nt)
                    mma_bf16(acc[mt][nt], a[mt], bh[nt]);
        }
        __syncthreads();
    }
#undef MMA2_ISSUE

    const int g = lane >> 2, t2 = (lane & 3) * 2;
#pragma unroll
    for (int mt = 0; mt < 4; ++mt) {
#pragma unroll
        for (int nt = 0; nt < 4; ++nt) {
            const int r0 = bm + wm * 64 + mt * 16 + g;
            const int r1 = r0 + 8;
            const int c  = bn + wn * 32 + nt * 8 + t2;
            float v0 = acc[mt][nt][0], v1 = acc[mt][nt][1];
            float v2 = acc[mt][nt][2], v3 = acc[mt][nt][3];
            if (bias) {
                const float b0 = bias[c], b1 = bias[c + 1];
                v0 += b0; v1 += b1; v2 += b0; v3 += b1;
            }
            if (ACT) {
                v0 = gelu_exact(v0); v1 = gelu_exact(v1);
                v2 = gelu_exact(v2); v3 = gelu_exact(v3);
            }
            if (SPLIT) {
                __nv_bfloat16 h0, l0, h1, l1;
                split1(v0, h0, l0); split1(v1, h1, l1);
                __nv_bfloat162 hp; hp.x = h0; hp.y = h1;
                __nv_bfloat162 lp; lp.x = l0; lp.y = l1;
                *(__nv_bfloat162*)(Ch + (size_t)r0 * N + c) = hp;
                *(__nv_bfloat162*)(Cl + (size_t)r0 * N + c) = lp;
                split1(v2, h0, l0); split1(v3, h1, l1);
                hp.x = h0; hp.y = h1; lp.x = l0; lp.y = l1;
                *(__nv_bfloat162*)(Ch + (size_t)r1 * N + c) = hp;
                *(__nv_bfloat162*)(Cl + (size_t)r1 * N + c) = lp;
            } else {
                if (res) {
                    const float2 q0 = *(const float2*)(res + (size_t)r0 * N + c);
                    const float2 q1 = *(const float2*)(res + (size_t)r1 * N + c);
                    v0 += q0.x; v1 += q0.y; v2 += q1.x; v3 += q1.y;
                }
                *(float2*)(Cf + (size_t)r0 * N + c) = make_float2(v0, v1);
                *(float2*)(Cf + (size_t)r1 * N + c) = make_float2(v2, v3);
            }
        }
    }
}

// ---------------- bias rank-1 terms: bk = bias_pf . K, br = bias_pf . KR ----
__global__ __launch_bounds__(256) void bias_terms_kernel(
    const __nv_bfloat16* __restrict__ qkvh, const __nv_bfloat16* __restrict__ qkvl,
    const __nv_bfloat16* __restrict__ krh, const __nv_bfloat16* __restrict__ krl,
    const float* __restrict__ bias_pf,
    float* __restrict__ bk, float* __restrict__ br)
{
    const int idx = blockIdx.x * 256 + threadIdx.x;
    const int bh = idx >> 10, j = idx & 1023;
    const int b = bh >> 3, h = bh & 7;
    const size_t kb = ((size_t)b * NSEQ + j) * 1536 + 512 + h * 64;
    const size_t rb = ((size_t)b * NSEQ + j) * 512 + h * 64;
    float sk = 0.0f, sr = 0.0f;
#pragma unroll 16
    for (int d = 0; d < 64; ++d) {
        const float bp = bias_pf[h * 64 + d];
        sk += bp * (__bfloat162float(qkvh[kb + d]) + __bfloat162float(qkvl[kb + d]));
        sr += bp * (__bfloat162float(krh[rb + d]) + __bfloat162float(krl[rb + d]));
    }
    bk[idx] = sk;
    br[idx] = sr;
}

// =========== acbd bf16x3 mma ================================================
__global__ __launch_bounds__(256, 2) void acbd2_kernel(
    const __nv_bfloat16* __restrict__ qkvh, const __nv_bfloat16* __restrict__ qkvl,
    const __nv_bfloat16* __restrict__ krh, const __nv_bfloat16* __restrict__ krl,
    const float* __restrict__ bk, const float* __restrict__ br,
    float* __restrict__ AC, float* __restrict__ BD)
{
    extern __shared__ char dsm[];
    const uint32_t sbase = smem_u32(dsm);
    const int tid = threadIdx.x, wid = tid >> 5, lane = tid & 31;
    const int wm = wid >> 2, wn = wid & 3;
    const int z = blockIdx.z, bh_idx = z & 63, isBD = z >> 6;
    const int b = bh_idx >> 3, h = bh_idx & 7;
    const int i0 = blockIdx.y * 128, j0 = blockIdx.x * 128;

    const __nv_bfloat16* Ah = qkvh + ((size_t)b * NSEQ + i0) * 1536 + h * 64;
    const __nv_bfloat16* Al = qkvl + ((size_t)b * NSEQ + i0) * 1536 + h * 64;
    const __nv_bfloat16* Bh = isBD ? (krh + ((size_t)b * NSEQ + j0) * 512 + h * 64)
                                   : (qkvh + ((size_t)b * NSEQ + j0) * 1536 + 512 + h * 64);
    const __nv_bfloat16* Bl = isBD ? (krl + ((size_t)b * NSEQ + j0) * 512 + h * 64)
                                   : (qkvl + ((size_t)b * NSEQ + j0) * 1536 + 512 + h * 64);
    const int ldb = isBD ? 512 : 1536;
    float* Cbase = (isBD ? BD : AC) + (size_t)bh_idx * NSEQ * NSEQ;
    const float* bvec = (isBD ? br : bk) + (size_t)bh_idx * NSEQ;

    const int lrow = tid >> 2, lcc = (tid & 3) * 8;
    const int lrow2 = (tid + 256) >> 2, lcc2 = ((tid + 256) & 3) * 8;

#define ACBD_ISSUE(kt, s) do {                                                   \
        const uint32_t st_ = sbase + (uint32_t)(s) * (STAGE * 2);                \
        const int k0_ = (kt) * 32;                                               \
        cp16(st_ + (uint32_t)((lrow * LDS + lcc) * 2),                           \
             Ah + (size_t)lrow * 1536 + k0_ + lcc);                              \
        cp16(st_ + (uint32_t)((lrow2 * LDS + lcc2) * 2),                         \
             Ah + (size_t)lrow2 * 1536 + k0_ + lcc2);                            \
        cp16(st_ + (uint32_t)(ARR * 2) + (uint32_t)((lrow * LDS + lcc) * 2),     \
             Al + (size_t)lrow * 1536 + k0_ + lcc);                              \
        cp16(st_ + (uint32_t)(ARR * 2) + (uint32_t)((lrow2 * LDS + lcc2) * 2),   \
             Al + (size_t)lrow2 * 1536 + k0_ + lcc2);                            \
        cp16(st_ + (uint32_t)(2 * ARR * 2) + (uint32_t)((lrow * LDS + lcc) * 2), \
             Bh + (size_t)lrow * ldb + k0_ + lcc);                               \
        cp16(st_ + (uint32_t)(2 * ARR * 2) + (uint32_t)((lrow2 * LDS + lcc2) * 2),\
             Bh + (size_t)lrow2 * ldb + k0_ + lcc2);                             \
        cp16(st_ + (uint32_t)(3 * ARR * 2) + (uint32_t)((lrow * LDS + lcc) * 2), \
             Bl + (size_t)lrow * ldb + k0_ + lcc);                               \
        cp16(st_ + (uint32_t)(3 * ARR * 2) + (uint32_t)((lrow2 * LDS + lcc2) * 2),\
             Bl + (size_t)lrow2 * ldb + k0_ + lcc2);                             \
    } while (0)

    const int l15 = lane & 15;
    const uint32_t aoff = (uint32_t)(((wm * 64 + l15) * LDS + ((lane >> 4) << 3)) * 2);
    const uint32_t boff = (uint32_t)(((wn * 32 + (l15 & 7)) * LDS + (((l15 >> 3) & 1) << 3)) * 2);

    float acc[4][4][4];
#pragma unroll
    for (int i = 0; i < 4; ++i)
#pragma unroll
        for (int j = 0; j < 4; ++j)
#pragma unroll
            for (int q = 0; q < 4; ++q) acc[i][j][q] = 0.0f;

    ACBD_ISSUE(0, 0);
    CP_COMMIT();
#pragma unroll
    for (int kt = 0; kt < 2; ++kt) {
        if (kt == 0) {
            ACBD_ISSUE(1, 1);
            CP_COMMIT();
            CP_WAIT(1);
        } else {
            CP_WAIT(0);
        }
        __syncthreads();
        const uint32_t st = sbase + (uint32_t)(kt & 1) * (STAGE * 2);
        const uint32_t aAh = st, aAl = st + ARR * 2;
        const uint32_t aBh = st + 2 * ARR * 2, aBl = st + 3 * ARR * 2;
#pragma unroll
        for (int kk = 0; kk < 32; kk += 16) {
            uint32_t bh[4][2], bl[4][2], a[4][4];
#pragma unroll
            for (int nt = 0; nt < 4; ++nt) {
                const uint32_t bo = boff + (uint32_t)((nt * 8 * LDS + kk) * 2);
                ldm_x2(bh[nt], aBh + bo);
                ldm_x2(bl[nt], aBl + bo);
            }
#pragma unroll
            for (int mt = 0; mt < 4; ++mt)
                ldm_x4(a[mt], aAh + aoff + (uint32_t)((mt * 16 * LDS + kk) * 2));
#pragma unroll
            for (int mt = 0; mt < 4; ++mt)
#pragma unroll
                for (int nt = 0; nt < 4; ++nt) {
                    mma_bf16(acc[mt][nt], a[mt], bh[nt]);
                    mma_bf16(acc[mt][nt], a[mt], bl[nt]);
                }
#pragma unroll
            for (int mt = 0; mt < 4; ++mt)
                ldm_x4(a[mt], aAl + aoff + (uint32_t)((mt * 16 * LDS + kk) * 2));
#pragma unroll
            for (int mt = 0; mt < 4; ++mt)
#pragma unroll
                for (int nt = 0; nt < 4; ++nt)
                    mma_bf16(acc[mt][nt], a[mt], bh[nt]);
        }
        __syncthreads();
    }
#undef ACBD_ISSUE

    const int g = lane >> 2, t2 = (lane & 3) * 2;
#pragma unroll
    for (int mt = 0; mt < 4; ++mt) {
#pragma unroll
        for (int nt = 0; nt < 4; ++nt) {
            const int r0 = i0 + wm * 64 + mt * 16 + g;
            const int c  = j0 + wn * 32 + nt * 8 + t2;
            const float b0 = bvec[c], b1 = bvec[c + 1];
            *(float2*)(Cbase + (size_t)r0 * NSEQ + c) =
                make_float2(acc[mt][nt][0] + b0, acc[mt][nt][1] + b1);
            *(float2*)(Cbase + (size_t)(r0 + 8) * NSEQ + c) =
                make_float2(acc[mt][nt][2] + b0, acc[mt][nt][3] + b1);
        }
    }
}

// ---------------- V transpose hi+lo: qkv -> vth/vtl[bh][d][j] ---------------
__global__ __launch_bounds__(256) void vt_kernel(
    const __nv_bfloat16* __restrict__ qkvh, const __nv_bfloat16* __restrict__ qkvl,
    __nv_bfloat16* __restrict__ vth, __nv_bfloat16* __restrict__ vtl)
{
    __shared__ __nv_bfloat16 th[32][33], tl[32][33];
    const int bh = blockIdx.z, b = bh >> 3, h = bh & 7;
    const int j0 = blockIdx.x * 32, d0 = blockIdx.y * 32;
    const int x = threadIdx.x, y = threadIdx.y;
#pragma unroll
    for (int i = 0; i < 32; i += 8) {
        const size_t src = ((size_t)b * NSEQ + j0 + y + i) * 1536 + 1024 + h * 64 + d0 + x;
        th[y + i][x] = qkvh[src];
        tl[y + i][x] = qkvl[src];
    }
    __syncthreads();
#pragma unroll
    for (int i = 0; i < 32; i += 8) {
        const size_t dst = ((size_t)bh * 64 + d0 + y + i) * NSEQ + j0 + x;
        vth[dst] = th[x][y + i];
        vtl[dst] = tl[x][y + i];
    }
}

// ---------------- rel_shift + scale + softmax over heads --------------------
__global__ __launch_bounds__(256) void softmax2_kernel(
    const float* AC, const float* __restrict__ BDp,
    __nv_bfloat16* __restrict__ atth, __nv_bfloat16* __restrict__ attl,
    float* attnf)
{
    const int j = blockIdx.x * blockDim.x + threadIdx.x;
    const int i = blockIdx.y;
    const int b = blockIdx.z;
    const int g  = (i + 1) * NSEQ + j;
    const int si = g / (NSEQ + 1);
    const int sj = g % (NSEQ + 1) - 1;

    float v[NHEADS];
    float mx = -1e30f;
#pragma unroll
    for (int h = 0; h < NHEADS; ++h) {
        const size_t idx = (((size_t)(b * NHEADS + h)) * NSEQ + i) * NSEQ + j;
        float acv = AC[idx];
        float bdv = 0.0f;
        if (sj >= 0)
            bdv = BDp[(((size_t)(b * NHEADS + h)) * NSEQ + si) * NSEQ + sj];
        const float d = (acv + bdv) * 0.125f;
        v[h] = d;
        mx = fmaxf(mx, d);
    }
    float s = 0.0f;
#pragma unroll
    for (int h = 0; h < NHEADS; ++h) { v[h] = __expf(v[h] - mx); s += v[h]; }
    const float inv = 1.0f / s;
#pragma unroll
    for (int h = 0; h < NHEADS; ++h) {
        const size_t idx = (((size_t)(b * NHEADS + h)) * NSEQ + i) * NSEQ + j;
        const float p = v[h] * inv;
        __nv_bfloat16 ph, pl; split1(p, ph, pl);
        atth[idx] = ph;
        attl[idx] = pl;
        if (attnf) attnf[idx] = p;
    }
}

// ========= av 3-term bf16x3 mma: out = attn[bh] @ Vt[bh]^T ===================
#define ARRA (128*LDS)
#define ARRB (64*LDS)
#define STAGEAV (2*ARRA + 2*ARRB)
#define AV_SMEM (2*STAGEAV*2)   // 61440 bytes

__global__ __launch_bounds__(256, 2) void av2_kernel(
    const __nv_bfloat16* __restrict__ atth, const __nv_bfloat16* __restrict__ attl,
    const __nv_bfloat16* __restrict__ vth, const __nv_bfloat16* __restrict__ vtl,
    __nv_bfloat16* __restrict__ outh, __nv_bfloat16* __restrict__ outl)
{
    extern __shared__ char dsm[];
    const uint32_t sbase = smem_u32(dsm);
    const int tid = threadIdx.x, wid = tid >> 5, lane = tid & 31;
    const int wm = wid >> 1, wn = wid & 1;
    const int bh_idx = blockIdx.y, b = bh_idx >> 3, h = bh_idx & 7;
    const int i0 = blockIdx.x * 128;

    const __nv_bfloat16* AHb = atth + ((size_t)bh_idx * NSEQ + i0) * NSEQ;
    const __nv_bfloat16* ALb = attl + ((size_t)bh_idx * NSEQ + i0) * NSEQ;
    const __nv_bfloat16* BHb = vth + (size_t)bh_idx * 64 * NSEQ;
    const __nv_bfloat16* BLb = vtl + (size_t)bh_idx * 64 * NSEQ;

#define AV_ISSUE(kt, s) do {                                                      \
        const uint32_t st_ = sbase + (uint32_t)(s) * (STAGEAV * 2);               \
        const int k0_ = (kt) * 32;                                                \
        _Pragma("unroll")                                                         \
        for (int i_ = 0; i_ < 6; ++i_) {                                          \
            const int c_ = tid + i_ * 256;                                        \
            if (c_ < 512) {                                                       \
                const int row_ = c_ >> 2, cc_ = (c_ & 3) * 8;                     \
                cp16(st_ + (uint32_t)((row_ * LDS + cc_) * 2),                    \
                     AHb + (size_t)row_ * NSEQ + k0_ + cc_);                      \
            } else if (c_ < 1024) {                                               \
                const int cb_ = c_ - 512;                                         \
                const int row_ = cb_ >> 2, cc_ = (cb_ & 3) * 8;                   \
                cp16(st_ + (uint32_t)(ARRA * 2) + (uint32_t)((row_ * LDS + cc_) * 2), \
                     ALb + (size_t)row_ * NSEQ + k0_ + cc_);                      \
            } else if (c_ < 1280) {                                               \
                const int cb_ = c_ - 1024;                                        \
                const int row_ = cb_ >> 2, cc_ = (cb_ & 3) * 8;                   \
                cp16(st_ + (uint32_t)(2 * ARRA * 2) + (uint32_t)((row_ * LDS + cc_) * 2), \
                     BHb + (size_t)row_ * NSEQ + k0_ + cc_);                      \
            } else {                                                              \
                const int cb_ = c_ - 1280;                                        \
                const int row_ = cb_ >> 2, cc_ = (cb_ & 3) * 8;                   \
                cp16(st_ + (uint32_t)((2 * ARRA + ARRB) * 2) + (uint32_t)((row_ * LDS + cc_) * 2), \
                     BLb + (size_t)row_ * NSEQ + k0_ + cc_);                      \
            }                                                                     \
        }                                                                         \
    } while (0)

    const int l15 = lane & 15;
    const uint32_t aoff = (uint32_t)(((wm * 32 + l15) * LDS + ((lane >> 4) << 3)) * 2);
    const uint32_t boff = (uint32_t)(((wn * 32 + (l15 & 7)) * LDS + (((l15 >> 3) & 1) << 3)) * 2);

    float acc[2][4][4];
#pragma unroll
    for (int i = 0; i < 2; ++i)
#pragma unroll
        for (int j = 0; j < 4; ++j)
#pragma unroll
            for (int q = 0; q < 4; ++q) acc[i][j][q] = 0.0f;

    AV_ISSUE(0, 0);
    CP_COMMIT();
    for (int kt = 0; kt < 32; ++kt) {
        if (kt + 1 < 32) {
            AV_ISSUE(kt + 1, (kt + 1) & 1);
            CP_COMMIT();
            CP_WAIT(1);
        } else {
            CP_WAIT(0);
        }
        __syncthreads();
        const uint32_t st = sbase + (uint32_t)(kt & 1) * (STAGEAV * 2);
        const uint32_t aAh = st, aAl = st + ARRA * 2;
        const uint32_t aBh = st + 2 * ARRA * 2, aBl = st + (2 * ARRA + ARRB) * 2;
#pragma unroll
        for (int kk = 0; kk < 32; kk += 16) {
            uint32_t bh[4][2], bl[4][2], a[2][4];
#pragma unroll
            for (int nt = 0; nt < 4; ++nt) {
                const uint32_t bo = boff + (uint32_t)((nt * 8 * LDS + kk) * 2);
                ldm_x2(bh[nt], aBh + bo);
                ldm_x2(bl[nt], aBl + bo);
            }
#pragma unroll
            for (int mt = 0; mt < 2; ++mt)
                ldm_x4(a[mt], aAh + aoff + (uint32_t)((mt * 16 * LDS + kk) * 2));
#pragma unroll
            for (int mt = 0; mt < 2; ++mt)
#pragma unroll
                for (int nt = 0; nt < 4; ++nt) {
                    mma_bf16(acc[mt][nt], a[mt], bh[nt]);
                    mma_bf16(acc[mt][nt], a[mt], bl[nt]);
                }
#pragma unroll
            for (int mt = 0; mt < 2; ++mt)
                ldm_x4(a[mt], aAl + aoff + (uint32_t)((mt * 16 * LDS + kk) * 2));
#pragma unroll
            for (int mt = 0; mt < 2; ++mt)
#pragma unroll
                for (int nt = 0; nt < 4; ++nt)
                    mma_bf16(acc[mt][nt], a[mt], bh[nt]);
        }
        __syncthreads();
    }
#undef AV_ISSUE

    const int g = lane >> 2, t2 = (lane & 3) * 2;
#pragma unroll
    for (int mt = 0; mt < 2; ++mt) {
#pragma unroll
        for (int nt = 0; nt < 4; ++nt) {
            const int r0 = i0 + wm * 32 + mt * 16 + g;
            const int c  = h * 64 + wn * 32 + nt * 8 + t2;
            __nv_bfloat16 h0, l0, h1, l1;
            split1(acc[mt][nt][0], h0, l0); split1(acc[mt][nt][1], h1, l1);
            __nv_bfloat162 hp; hp.x = h0; hp.y = h1;
            __nv_bfloat162 lp; lp.x = l0; lp.y = l1;
            *(__nv_bfloat162*)(outh + ((size_t)b * NSEQ + r0) * NHD + c) = hp;
            *(__nv_bfloat162*)(outl + ((size_t)b * NSEQ + r0) * NHD + c) = lp;
            split1(acc[mt][nt][2], h0, l0); split1(acc[mt][nt][3], h1, l1);
            hp.x = h0; hp.y = h1; lp.x = l0; lp.y = l1;
            *(__nv_bfloat162*)(outh + ((size_t)b * NSEQ + r0 + 8) * NHD + c) = hp;
            *(__nv_bfloat162*)(outl + ((size_t)b * NSEQ + r0 + 8) * NHD + c) = lp;
        }
    }
}

// ---------------- host orchestration ----------------------------------------
extern "C" void kernel_launch(void* const* d_in, const int* in_sizes, int n_in,
                              void* d_out, int out_size)
{
    (void)in_sizes; (void)n_in;
    const float* x_in    = (const float*)d_in[0];
    const float* r_t     = (const float*)d_in[1];
    const float* bias_pf = (const float*)d_in[3];
    const float* ln1_g   = (const float*)d_in[4];
    const float* ln1_b   = (const float*)d_in[5];
    const float* Wqkv    = (const float*)d_in[6];
    const float* Wkr_t   = (const float*)d_in[7];
    const float* Wout    = (const float*)d_in[9];
    const float* bout    = (const float*)d_in[10];
    const float* ln2_g   = (const float*)d_in[11];
    const float* ln2_b   = (const float*)d_in[12];
    const float* W1      = (const float*)d_in[13];
    const float* b1      = (const float*)d_in[14];
    const float* W2      = (const float*)d_in[15];
    const float* b2      = (const float*)d_in[16];
    float* outp = (float*)d_out;

    static int attr_done = 0;
    if (!attr_done) {
        cudaFuncSetAttribute(mma2_kernel<0,0>, cudaFuncAttributeMaxDynamicSharedMemorySize, MMA2_SMEM);
        cudaFuncSetAttribute(mma2_kernel<1,0>, cudaFuncAttributeMaxDynamicSharedMemorySize, MMA2_SMEM);
        cudaFuncSetAttribute(mma2_kernel<1,1>, cudaFuncAttributeMaxDynamicSharedMemorySize, MMA2_SMEM);
        cudaFuncSetAttribute(acbd2_kernel,     cudaFuncAttributeMaxDynamicSharedMemorySize, MMA2_SMEM);
        cudaFuncSetAttribute(av2_kernel,       cudaFuncAttributeMaxDynamicSharedMemorySize, AV_SMEM);
        attr_done = 1;
    }

    float *gx, *gac, *gbd, *gbk, *gbr;
    __nv_bfloat16 *gxnh, *gxnl, *grth, *grtl, *gqkvh, *gqkvl, *gkrh, *gkrl;
    __nv_bfloat16 *gavh, *gavl, *gffh, *gffl, *gwth, *gwtl;
    __nv_bfloat16 *gvth, *gvtl, *gatth, *gattl;
    cudaGetSymbolAddress((void**)&gx,    g_x);
    cudaGetSymbolAddress((void**)&gac,   g_ac);
    cudaGetSymbolAddress((void**)&gbd,   g_bd);
    cudaGetSymbolAddress((void**)&gbk,   g_bk);
    cudaGetSymbolAddress((void**)&gbr,   g_br);
    cudaGetSymbolAddress((void**)&gxnh,  g_xnh);
    cudaGetSymbolAddress((void**)&gxnl,  g_xnl);
    cudaGetSymbolAddress((void**)&grth,  g_rth);
    cudaGetSymbolAddress((void**)&grtl,  g_rtl);
    cudaGetSymbolAddress((void**)&gqkvh, g_qkvh);
    cudaGetSymbolAddress((void**)&gqkvl, g_qkvl);
    cudaGetSymbolAddress((void**)&gkrh,  g_krh);
    cudaGetSymbolAddress((void**)&gkrl,  g_krl);
    cudaGetSymbolAddress((void**)&gavh,  g_avh);
    cudaGetSymbolAddress((void**)&gavl,  g_avl);
    cudaGetSymbolAddress((void**)&gffh,  g_ffh);
    cudaGetSymbolAddress((void**)&gffl,  g_ffl);
    cudaGetSymbolAddress((void**)&gwth,  g_wth);
    cudaGetSymbolAddress((void**)&gwtl,  g_wtl);
    cudaGetSymbolAddress((void**)&gvth,  g_vth);
    cudaGetSymbolAddress((void**)&gvtl,  g_vtl);
    cudaGetSymbolAddress((void**)&gatth, g_atth);
    cudaGetSymbolAddress((void**)&gattl, g_attl);

    float* attn_out = outp + ((size_t)out_size - ATT_ELEMS);

    cudaMemcpyAsync(gx, x_in, X_ELEMS * sizeof(float), cudaMemcpyDeviceToDevice, 0);
    split_rt_kernel<<<X_ELEMS / 1024, 256>>>(r_t, grth, grtl);

    const dim3 tb(32, 8);
    for (int l = 0; l < 4; ++l) {
        transpose_split_kernel<<<dim3(48, 16), tb>>>(Wqkv  + (size_t)l*512*1536, gwth + WQKVT, gwtl + WQKVT, 512, 1536);
        transpose_split_kernel<<<dim3(16, 16), tb>>>(Wkr_t + (size_t)l*512*512,  gwth + WKRT,  gwtl + WKRT,  512, 512);
        transpose_split_kernel<<<dim3(16, 16), tb>>>(Wout  + (size_t)l*512*512,  gwth + WOUTT, gwtl + WOUTT, 512, 512);
        transpose_split_kernel<<<dim3(64, 16), tb>>>(W1    + (size_t)l*512*2048, gwth + W1T,   gwtl + W1T,   512, 2048);
        transpose_split_kernel<<<dim3(16, 64), tb>>>(W2    + (size_t)l*2048*512, gwth + W2T,   gwtl + W2T,  2048, 512);

        ln_split_kernel<<<MROWS, 128>>>(gx, ln1_g + l * NDIM, ln1_b + l * NDIM, gxnh, gxnl);
        mma2_kernel<1,0><<<dim3(12, 64), 256, MMA2_SMEM>>>(
            gxnh, gxnl, gwth + WQKVT, gwtl + WQKVT,
            nullptr, gqkvh, gqkvl, nullptr, nullptr, MROWS, 1536, 512);
        mma2_kernel<1,0><<<dim3(4, 64), 256, MMA2_SMEM>>>(
            grth, grtl, gwth + WKRT, gwtl + WKRT,
            nullptr, gkrh, gkrl, nullptr, nullptr, MROWS, 512, 512);

        bias_terms_kernel<<<256, 256>>>(gqkvh, gqkvl, gkrh, gkrl, bias_pf, gbk, gbr);

        acbd2_kernel<<<dim3(8, 8, 128), 256, MMA2_SMEM>>>(
            gqkvh, gqkvl, gkrh, gkrl, gbk, gbr, gac, gbd);

        vt_kernel<<<dim3(32, 2, 64), tb>>>(gqkvh, gqkvl, gvth, gvtl);

        softmax2_kernel<<<dim3(4, NSEQ, NBATCH), 256>>>(
            gac, gbd, gatth, gattl, (l == 3) ? attn_out : nullptr);

        av2_kernel<<<dim3(8, 64), 256, AV_SMEM>>>(gatth, gattl, gvth, gvtl, gavh, gavl);

        mma2_kernel<0,0><<<dim3(4, 64), 256, MMA2_SMEM>>>(
            gavh, gavl, gwth + WOUTT, gwtl + WOUTT,
            gx, nullptr, nullptr, bout + l * NDIM, gx, MROWS, 512, 512);

        ln_split_kernel<<<MROWS, 128>>>(gx, ln2_g + l * NDIM, ln2_b + l * NDIM, gxnh, gxnl);
        mma2_kernel<1,1><<<dim3(16, 64), 256, MMA2_SMEM>>>(
            gxnh, gxnl, gwth + W1T, gwtl + W1T,
            nullptr, gffh, gffl, b1 + l * NFF, nullptr, MROWS, 2048, 512);
        float* xdst = (l == 3) ? outp : gx;
        mma2_kernel<0,0><<<dim3(4, 64), 256, MMA2_SMEM>>>(
            gffh, gffl, gwth + W2T, gwtl + W2T,
            xdst, nullptr, nullptr, b2 + l * NDIM, gx, MROWS, 512, 2048);
    }
}

// round 7
// speedup vs baseline: 1.0031x; 1.0031x over previous
#include <cuda_runtime.h>
#include <cuda_bf16.h>
#include <math.h>
#include <stdint.h>

#define NSEQ   1024
#define NBATCH 8
#define NDIM   512
#define NHEADS 8
#define NDH    64
#define NHD    512
#define NFF    2048
#define MROWS  (NBATCH*NSEQ)
#define ATT_ELEMS ((size_t)NBATCH*NHEADS*NSEQ*NSEQ)
#define X_ELEMS   ((size_t)MROWS*NDIM)

// transposed weight offsets (elements)
#define WQKVT 0
#define WKRT  786432
#define WOUTT 1048576
#define W1T   1310720
#define W2T   2359296
#define WT_TOTAL 3407872

// ---------------- scratch --------------------------------------------------
static __device__ float g_x [MROWS*NDIM];
static __device__ float g_ac[NBATCH*NHEADS*NSEQ*NSEQ];
static __device__ float g_bd[NBATCH*NHEADS*NSEQ*NSEQ];
static __device__ float g_bk[NBATCH*NHEADS*NSEQ];
static __device__ float g_br[NBATCH*NHEADS*NSEQ];
static __device__ __nv_bfloat16 g_xnh [MROWS*NDIM],  g_xnl [MROWS*NDIM];
static __device__ __nv_bfloat16 g_rth [MROWS*NDIM],  g_rtl [MROWS*NDIM];
static __device__ __nv_bfloat16 g_qkvh[MROWS*3*NHD], g_qkvl[MROWS*3*NHD];
static __device__ __nv_bfloat16 g_krh [MROWS*NHD],   g_krl [MROWS*NHD];
static __device__ __nv_bfloat16 g_avh [MROWS*NHD],   g_avl [MROWS*NHD];
static __device__ __nv_bfloat16 g_ffh [MROWS*NFF],   g_ffl [MROWS*NFF];
static __device__ __nv_bfloat16 g_wth [WT_TOTAL],    g_wtl [WT_TOTAL];
static __device__ __nv_bfloat16 g_vth [NBATCH*NHEADS*NDH*NSEQ];
static __device__ __nv_bfloat16 g_vtl [NBATCH*NHEADS*NDH*NSEQ];

// ---------------- primitives ------------------------------------------------
__device__ __forceinline__ uint32_t smem_u32(const void* p) {
    uint32_t a;
    asm("{ .reg .u64 t; cvta.to.shared.u64 t, %1; cvt.u32.u64 %0, t; }"
        : "=r"(a) : "l"(p));
    return a;
}
__device__ __forceinline__ void cp16(uint32_t dst, const void* src) {
    asm volatile("cp.async.cg.shared.global [%0], [%1], 16;" :: "r"(dst), "l"(src));
}
#define CP_COMMIT() asm volatile("cp.async.commit_group;")
#define CP_WAIT(n)  asm volatile("cp.async.wait_group %0;" :: "n"(n))

__device__ __forceinline__ void mma_bf16(float* d, const uint32_t* a, const uint32_t* b) {
    asm volatile(
        "mma.sync.aligned.m16n8k16.row.col.f32.bf16.bf16.f32 "
        "{%0,%1,%2,%3}, {%4,%5,%6,%7}, {%8,%9}, {%0,%1,%2,%3};"
        : "+f"(d[0]), "+f"(d[1]), "+f"(d[2]), "+f"(d[3])
        : "r"(a[0]), "r"(a[1]), "r"(a[2]), "r"(a[3]), "r"(b[0]), "r"(b[1]));
}
__device__ __forceinline__ void ldm_x4(uint32_t* r, uint32_t addr) {
    asm volatile("ldmatrix.sync.aligned.m8n8.x4.shared.b16 {%0,%1,%2,%3}, [%4];"
        : "=r"(r[0]), "=r"(r[1]), "=r"(r[2]), "=r"(r[3]) : "r"(addr));
}
__device__ __forceinline__ void ldm_x2(uint32_t* r, uint32_t addr) {
    asm volatile("ldmatrix.sync.aligned.m8n8.x2.shared.b16 {%0,%1}, [%2];"
        : "=r"(r[0]), "=r"(r[1]) : "r"(addr));
}
__device__ __forceinline__ float gelu_exact(float v) {
    return 0.5f * v * (1.0f + erff(v * 0.70710678118654752f));
}
__device__ __forceinline__ void split1(float v, __nv_bfloat16& h, __nv_bfloat16& l) {
    h = __float2bfloat16_rn(v);
    l = __float2bfloat16_rn(v - __bfloat162float(h));
}

// ---------------- weight transpose+split: W[K][N] -> Wt_h/l[N][K] -----------
__global__ __launch_bounds__(256) void transpose_split_kernel(
    const float* __restrict__ W, __nv_bfloat16* __restrict__ Wth,
    __nv_bfloat16* __restrict__ Wtl, int K, int N)
{
    __shared__ float t[32][33];
    const int k0 = blockIdx.y * 32, n0 = blockIdx.x * 32;
    const int x = threadIdx.x, y = threadIdx.y;
#pragma unroll
    for (int i = 0; i < 32; i += 8)
        t[y + i][x] = W[(size_t)(k0 + y + i) * N + n0 + x];
    __syncthreads();
#pragma unroll
    for (int i = 0; i < 32; i += 8) {
        float v = t[x][y + i];
        __nv_bfloat16 h, l; split1(v, h, l);
        Wth[(size_t)(n0 + y + i) * K + k0 + x] = h;
        Wtl[(size_t)(n0 + y + i) * K + k0 + x] = l;
    }
}

// ---------------- r_t split -------------------------------------------------
__global__ __launch_bounds__(256) void split_rt_kernel(
    const float* __restrict__ src, __nv_bfloat16* __restrict__ dh,
    __nv_bfloat16* __restrict__ dl)
{
    const size_t i = ((size_t)blockIdx.x * 256 + threadIdx.x) * 4;
    float4 v = *(const float4*)(src + i);
    __nv_bfloat16 h, l;
    split1(v.x, h, l); dh[i]   = h; dl[i]   = l;
    split1(v.y, h, l); dh[i+1] = h; dl[i+1] = l;
    split1(v.z, h, l); dh[i+2] = h; dl[i+2] = l;
    split1(v.w, h, l); dh[i+3] = h; dl[i+3] = l;
}

// ---------------- LayerNorm + split ------------------------------------------
__global__ __launch_bounds__(128) void ln_split_kernel(
    const float* __restrict__ x, const float* __restrict__ g,
    const float* __restrict__ b, __nv_bfloat16* __restrict__ yh,
    __nv_bfloat16* __restrict__ yl)
{
    const int row = blockIdx.x;
    const int tid = threadIdx.x;
    const float* xr = x + (size_t)row * NDIM;

    float4 v = ((const float4*)xr)[tid];
    float s  = v.x + v.y + v.z + v.w;
    float sq = v.x*v.x + v.y*v.y + v.z*v.z + v.w*v.w;
#pragma unroll
    for (int o = 16; o > 0; o >>= 1) {
        s  += __shfl_xor_sync(0xffffffffu, s,  o);
        sq += __shfl_xor_sync(0xffffffffu, sq, o);
    }
    __shared__ float red[8];
    const int w = tid >> 5;
    if ((tid & 31) == 0) { red[w] = s; red[4 + w] = sq; }
    __syncthreads();
    const float st  = red[0] + red[1] + red[2] + red[3];
    const float sqt = red[4] + red[5] + red[6] + red[7];
    const float mu  = st * (1.0f / NDIM);
    const float var = sqt * (1.0f / NDIM) - mu * mu;
    const float inv = rsqrtf(var + 1e-5f);

    float4 gg = ((const float4*)g)[tid];
    float4 bb = ((const float4*)b)[tid];
    float o0 = (v.x - mu) * inv * gg.x + bb.x;
    float o1 = (v.y - mu) * inv * gg.y + bb.y;
    float o2 = (v.z - mu) * inv * gg.z + bb.z;
    float o3 = (v.w - mu) * inv * gg.w + bb.w;
    const size_t base = (size_t)row * NDIM + tid * 4;
    __nv_bfloat16 h, l;
    split1(o0, h, l); yh[base]   = h; yl[base]   = l;
    split1(o1, h, l); yh[base+1] = h; yl[base+1] = l;
    split1(o2, h, l); yh[base+2] = h; yl[base+2] = l;
    split1(o3, h, l); yh[base+3] = h; yl[base+3] = l;
}

// =============== dense bf16x3 mma GEMM, cp.async double-buffered =============
#define LDS 40
#define ARR   (128*LDS)
#define STAGE (4*ARR)
#define MMA2_SMEM (2*STAGE*2)

template<int SPLIT, int ACT>
__global__ __launch_bounds__(256, 2) void mma2_kernel(
    const __nv_bfloat16* __restrict__ Ah, const __nv_bfloat16* __restrict__ Al,
    const __nv_bfloat16* __restrict__ Bh, const __nv_bfloat16* __restrict__ Bl,
    float* __restrict__ Cf, __nv_bfloat16* __restrict__ Ch,
    __nv_bfloat16* __restrict__ Cl,
    const float* __restrict__ bias, const float* __restrict__ res,
    int M, int N, int K)
{
    extern __shared__ char dsm[];
    const uint32_t sbase = smem_u32(dsm);
    const int tid = threadIdx.x, wid = tid >> 5, lane = tid & 31;
    const int wm = wid >> 2, wn = wid & 3;
    const int bm = blockIdx.y * 128, bn = blockIdx.x * 128;

    const int lrow = tid >> 2, lcc = (tid & 3) * 8;
    const int lrow2 = (tid + 256) >> 2, lcc2 = ((tid + 256) & 3) * 8;

#define MMA2_ISSUE(kt, s) do {                                                   \
        const uint32_t st_ = sbase + (uint32_t)(s) * (STAGE * 2);                \
        const int k0_ = (kt) * 32;                                               \
        cp16(st_ + (uint32_t)((lrow * LDS + lcc) * 2),                           \
             Ah + (size_t)(bm + lrow) * K + k0_ + lcc);                          \
        cp16(st_ + (uint32_t)((lrow2 * LDS + lcc2) * 2),                         \
             Ah + (size_t)(bm + lrow2) * K + k0_ + lcc2);                        \
        cp16(st_ + (uint32_t)(ARR * 2) + (uint32_t)((lrow * LDS + lcc) * 2),     \
             Al + (size_t)(bm + lrow) * K + k0_ + lcc);                          \
        cp16(st_ + (uint32_t)(ARR * 2) + (uint32_t)((lrow2 * LDS + lcc2) * 2),   \
             Al + (size_t)(bm + lrow2) * K + k0_ + lcc2);                        \
        cp16(st_ + (uint32_t)(2 * ARR * 2) + (uint32_t)((lrow * LDS + lcc) * 2), \
             Bh + (size_t)(bn + lrow) * K + k0_ + lcc);                          \
        cp16(st_ + (uint32_t)(2 * ARR * 2) + (uint32_t)((lrow2 * LDS + lcc2) * 2),\
             Bh + (size_t)(bn + lrow2) * K + k0_ + lcc2);                        \
        cp16(st_ + (uint32_t)(3 * ARR * 2) + (uint32_t)((lrow * LDS + lcc) * 2), \
             Bl + (size_t)(bn + lrow) * K + k0_ + lcc);                          \
        cp16(st_ + (uint32_t)(3 * ARR * 2) + (uint32_t)((lrow2 * LDS + lcc2) * 2),\
             Bl + (size_t)(bn + lrow2) * K + k0_ + lcc2);                        \
    } while (0)

    const int l15 = lane & 15;
    const uint32_t aoff = (uint32_t)(((wm * 64 + l15) * LDS + ((lane >> 4) << 3)) * 2);
    const uint32_t boff = (uint32_t)(((wn * 32 + (l15 & 7)) * LDS + (((l15 >> 3) & 1) << 3)) * 2);

    float acc[4][4][4];
#pragma unroll
    for (int i = 0; i < 4; ++i)
#pragma unroll
        for (int j = 0; j < 4; ++j)
#pragma unroll
            for (int q = 0; q < 4; ++q) acc[i][j][q] = 0.0f;

    const int NKT = K >> 5;
    MMA2_ISSUE(0, 0);
    CP_COMMIT();

    for (int kt = 0; kt < NKT; ++kt) {
        if (kt + 1 < NKT) {
            MMA2_ISSUE(kt + 1, (kt + 1) & 1);
            CP_COMMIT();
            CP_WAIT(1);
        } else {
            CP_WAIT(0);
        }
        __syncthreads();

        const uint32_t st = sbase + (uint32_t)(kt & 1) * (STAGE * 2);
        const uint32_t aAh = st, aAl = st + ARR * 2;
        const uint32_t aBh = st + 2 * ARR * 2, aBl = st + 3 * ARR * 2;
#pragma unroll
        for (int kk = 0; kk < 32; kk += 16) {
            uint32_t bh[4][2], bl[4][2], a[4][4];
#pragma unroll
            for (int nt = 0; nt < 4; ++nt) {
                const uint32_t bo = boff + (uint32_t)((nt * 8 * LDS + kk) * 2);
                ldm_x2(bh[nt], aBh + bo);
                ldm_x2(bl[nt], aBl + bo);
            }
#pragma unroll
            for (int mt = 0; mt < 4; ++mt)
                ldm_x4(a[mt], aAh + aoff + (uint32_t)((mt * 16 * LDS + kk) * 2));
#pragma unroll
            for (int mt = 0; mt < 4; ++mt)
#pragma unroll
                for (int nt = 0; nt < 4; ++nt) {
                    mma_bf16(acc[mt][nt], a[mt], bh[nt]);
                    mma_bf16(acc[mt][nt], a[mt], bl[nt]);
                }
#pragma unroll
            for (int mt = 0; mt < 4; ++mt)
                ldm_x4(a[mt], aAl + aoff + (uint32_t)((mt * 16 * LDS + kk) * 2));
#pragma unroll
            for (int mt = 0; mt < 4; ++mt)
#pragma unroll
                for (int nt = 0; nt < 4; ++nt)
                    mma_bf16(acc[mt][nt], a[mt], bh[nt]);
        }
        __syncthreads();
    }
#undef MMA2_ISSUE

    const int g = lane >> 2, t2 = (lane & 3) * 2;
#pragma unroll
    for (int mt = 0; mt < 4; ++mt) {
#pragma unroll
        for (int nt = 0; nt < 4; ++nt) {
            const int r0 = bm + wm * 64 + mt * 16 + g;
            const int r1 = r0 + 8;
            const int c  = bn + wn * 32 + nt * 8 + t2;
            float v0 = acc[mt][nt][0], v1 = acc[mt][nt][1];
            float v2 = acc[mt][nt][2], v3 = acc[mt][nt][3];
            if (bias) {
                const float b0 = bias[c], b1 = bias[c + 1];
                v0 += b0; v1 += b1; v2 += b0; v3 += b1;
            }
            if (ACT) {
                v0 = gelu_exact(v0); v1 = gelu_exact(v1);
                v2 = gelu_exact(v2); v3 = gelu_exact(v3);
            }
            if (SPLIT) {
                __nv_bfloat16 h0, l0, h1, l1;
                split1(v0, h0, l0); split1(v1, h1, l1);
                __nv_bfloat162 hp; hp.x = h0; hp.y = h1;
                __nv_bfloat162 lp; lp.x = l0; lp.y = l1;
                *(__nv_bfloat162*)(Ch + (size_t)r0 * N + c) = hp;
                *(__nv_bfloat162*)(Cl + (size_t)r0 * N + c) = lp;
                split1(v2, h0, l0); split1(v3, h1, l1);
                hp.x = h0; hp.y = h1; lp.x = l0; lp.y = l1;
                *(__nv_bfloat162*)(Ch + (size_t)r1 * N + c) = hp;
                *(__nv_bfloat162*)(Cl + (size_t)r1 * N + c) = lp;
            } else {
                if (res) {
                    const float2 q0 = *(const float2*)(res + (size_t)r0 * N + c);
                    const float2 q1 = *(const float2*)(res + (size_t)r1 * N + c);
                    v0 += q0.x; v1 += q0.y; v2 += q1.x; v3 += q1.y;
                }
                *(float2*)(Cf + (size_t)r0 * N + c) = make_float2(v0, v1);
                *(float2*)(Cf + (size_t)r1 * N + c) = make_float2(v2, v3);
            }
        }
    }
}

// ---------------- bias rank-1 terms: bk = bias_pf . K, br = bias_pf . KR ----
__global__ __launch_bounds__(256) void bias_terms_kernel(
    const __nv_bfloat16* __restrict__ qkvh, const __nv_bfloat16* __restrict__ qkvl,
    const __nv_bfloat16* __restrict__ krh, const __nv_bfloat16* __restrict__ krl,
    const float* __restrict__ bias_pf,
    float* __restrict__ bk, float* __restrict__ br)
{
    const int idx = blockIdx.x * 256 + threadIdx.x;
    const int bh = idx >> 10, j = idx & 1023;
    const int b = bh >> 3, h = bh & 7;
    const size_t kb = ((size_t)b * NSEQ + j) * 1536 + 512 + h * 64;
    const size_t rb = ((size_t)b * NSEQ + j) * 512 + h * 64;
    float sk = 0.0f, sr = 0.0f;
#pragma unroll 16
    for (int d = 0; d < 64; ++d) {
        const float bp = bias_pf[h * 64 + d];
        sk += bp * (__bfloat162float(qkvh[kb + d]) + __bfloat162float(qkvl[kb + d]));
        sr += bp * (__bfloat162float(krh[rb + d]) + __bfloat162float(krl[rb + d]));
    }
    bk[idx] = sk;
    br[idx] = sr;
}

// =========== acbd bf16x3 mma ================================================
__global__ __launch_bounds__(256, 2) void acbd2_kernel(
    const __nv_bfloat16* __restrict__ qkvh, const __nv_bfloat16* __restrict__ qkvl,
    const __nv_bfloat16* __restrict__ krh, const __nv_bfloat16* __restrict__ krl,
    const float* __restrict__ bk, const float* __restrict__ br,
    float* __restrict__ AC, float* __restrict__ BD)
{
    extern __shared__ char dsm[];
    const uint32_t sbase = smem_u32(dsm);
    const int tid = threadIdx.x, wid = tid >> 5, lane = tid & 31;
    const int wm = wid >> 2, wn = wid & 3;
    const int z = blockIdx.z, bh_idx = z & 63, isBD = z >> 6;
    const int b = bh_idx >> 3, h = bh_idx & 7;
    const int i0 = blockIdx.y * 128, j0 = blockIdx.x * 128;

    const __nv_bfloat16* Ah = qkvh + ((size_t)b * NSEQ + i0) * 1536 + h * 64;
    const __nv_bfloat16* Al = qkvl + ((size_t)b * NSEQ + i0) * 1536 + h * 64;
    const __nv_bfloat16* Bh = isBD ? (krh + ((size_t)b * NSEQ + j0) * 512 + h * 64)
                                   : (qkvh + ((size_t)b * NSEQ + j0) * 1536 + 512 + h * 64);
    const __nv_bfloat16* Bl = isBD ? (krl + ((size_t)b * NSEQ + j0) * 512 + h * 64)
                                   : (qkvl + ((size_t)b * NSEQ + j0) * 1536 + 512 + h * 64);
    const int ldb = isBD ? 512 : 1536;
    float* Cbase = (isBD ? BD : AC) + (size_t)bh_idx * NSEQ * NSEQ;
    const float* bvec = (isBD ? br : bk) + (size_t)bh_idx * NSEQ;

    const int lrow = tid >> 2, lcc = (tid & 3) * 8;
    const int lrow2 = (tid + 256) >> 2, lcc2 = ((tid + 256) & 3) * 8;

#define ACBD_ISSUE(kt, s) do {                                                   \
        const uint32_t st_ = sbase + (uint32_t)(s) * (STAGE * 2);                \
        const int k0_ = (kt) * 32;                                               \
        cp16(st_ + (uint32_t)((lrow * LDS + lcc) * 2),                           \
             Ah + (size_t)lrow * 1536 + k0_ + lcc);                              \
        cp16(st_ + (uint32_t)((lrow2 * LDS + lcc2) * 2),                         \
             Ah + (size_t)lrow2 * 1536 + k0_ + lcc2);                            \
        cp16(st_ + (uint32_t)(ARR * 2) + (uint32_t)((lrow * LDS + lcc) * 2),     \
             Al + (size_t)lrow * 1536 + k0_ + lcc);                              \
        cp16(st_ + (uint32_t)(ARR * 2) + (uint32_t)((lrow2 * LDS + lcc2) * 2),   \
             Al + (size_t)lrow2 * 1536 + k0_ + lcc2);                            \
        cp16(st_ + (uint32_t)(2 * ARR * 2) + (uint32_t)((lrow * LDS + lcc) * 2), \
             Bh + (size_t)lrow * ldb + k0_ + lcc);                               \
        cp16(st_ + (uint32_t)(2 * ARR * 2) + (uint32_t)((lrow2 * LDS + lcc2) * 2),\
             Bh + (size_t)lrow2 * ldb + k0_ + lcc2);                             \
        cp16(st_ + (uint32_t)(3 * ARR * 2) + (uint32_t)((lrow * LDS + lcc) * 2), \
             Bl + (size_t)lrow * ldb + k0_ + lcc);                               \
        cp16(st_ + (uint32_t)(3 * ARR * 2) + (uint32_t)((lrow2 * LDS + lcc2) * 2),\
             Bl + (size_t)lrow2 * ldb + k0_ + lcc2);                             \
    } while (0)

    const int l15 = lane & 15;
    const uint32_t aoff = (uint32_t)(((wm * 64 + l15) * LDS + ((lane >> 4) << 3)) * 2);
    const uint32_t boff = (uint32_t)(((wn * 32 + (l15 & 7)) * LDS + (((l15 >> 3) & 1) << 3)) * 2);

    float acc[4][4][4];
#pragma unroll
    for (int i = 0; i < 4; ++i)
#pragma unroll
        for (int j = 0; j < 4; ++j)
#pragma unroll
            for (int q = 0; q < 4; ++q) acc[i][j][q] = 0.0f;

    ACBD_ISSUE(0, 0);
    CP_COMMIT();
#pragma unroll
    for (int kt = 0; kt < 2; ++kt) {
        if (kt == 0) {
            ACBD_ISSUE(1, 1);
            CP_COMMIT();
            CP_WAIT(1);
        } else {
            CP_WAIT(0);
        }
        __syncthreads();
        const uint32_t st = sbase + (uint32_t)(kt & 1) * (STAGE * 2);
        const uint32_t aAh = st, aAl = st + ARR * 2;
        const uint32_t aBh = st + 2 * ARR * 2, aBl = st + 3 * ARR * 2;
#pragma unroll
        for (int kk = 0; kk < 32; kk += 16) {
            uint32_t bh[4][2], bl[4][2], a[4][4];
#pragma unroll
            for (int nt = 0; nt < 4; ++nt) {
                const uint32_t bo = boff + (uint32_t)((nt * 8 * LDS + kk) * 2);
                ldm_x2(bh[nt], aBh + bo);
                ldm_x2(bl[nt], aBl + bo);
            }
#pragma unroll
            for (int mt = 0; mt < 4; ++mt)
                ldm_x4(a[mt], aAh + aoff + (uint32_t)((mt * 16 * LDS + kk) * 2));
#pragma unroll
            for (int mt = 0; mt < 4; ++mt)
#pragma unroll
                for (int nt = 0; nt < 4; ++nt) {
                    mma_bf16(acc[mt][nt], a[mt], bh[nt]);
                    mma_bf16(acc[mt][nt], a[mt], bl[nt]);
                }
#pragma unroll
            for (int mt = 0; mt < 4; ++mt)
                ldm_x4(a[mt], aAl + aoff + (uint32_t)((mt * 16 * LDS + kk) * 2));
#pragma unroll
            for (int mt = 0; mt < 4; ++mt)
#pragma unroll
                for (int nt = 0; nt < 4; ++nt)
                    mma_bf16(acc[mt][nt], a[mt], bh[nt]);
        }
        __syncthreads();
    }
#undef ACBD_ISSUE

    const int g = lane >> 2, t2 = (lane & 3) * 2;
#pragma unroll
    for (int mt = 0; mt < 4; ++mt) {
#pragma unroll
        for (int nt = 0; nt < 4; ++nt) {
            const int r0 = i0 + wm * 64 + mt * 16 + g;
            const int c  = j0 + wn * 32 + nt * 8 + t2;
            const float b0 = bvec[c], b1 = bvec[c + 1];
            *(float2*)(Cbase + (size_t)r0 * NSEQ + c) =
                make_float2(acc[mt][nt][0] + b0, acc[mt][nt][1] + b1);
            *(float2*)(Cbase + (size_t)(r0 + 8) * NSEQ + c) =
                make_float2(acc[mt][nt][2] + b0, acc[mt][nt][3] + b1);
        }
    }
}

// ---------------- V transpose hi+lo: qkv -> vth/vtl[bh][d][j] ---------------
__global__ __launch_bounds__(256) void vt_kernel(
    const __nv_bfloat16* __restrict__ qkvh, const __nv_bfloat16* __restrict__ qkvl,
    __nv_bfloat16* __restrict__ vth, __nv_bfloat16* __restrict__ vtl)
{
    __shared__ __nv_bfloat16 th[32][33], tl[32][33];
    const int bh = blockIdx.z, b = bh >> 3, h = bh & 7;
    const int j0 = blockIdx.x * 32, d0 = blockIdx.y * 32;
    const int x = threadIdx.x, y = threadIdx.y;
#pragma unroll
    for (int i = 0; i < 32; i += 8) {
        const size_t src = ((size_t)b * NSEQ + j0 + y + i) * 1536 + 1024 + h * 64 + d0 + x;
        th[y + i][x] = qkvh[src];
        tl[y + i][x] = qkvl[src];
    }
    __syncthreads();
#pragma unroll
    for (int i = 0; i < 32; i += 8) {
        const size_t dst = ((size_t)bh * 64 + d0 + y + i) * NSEQ + j0 + x;
        vth[dst] = th[x][y + i];
        vtl[dst] = tl[x][y + i];
    }
}

// ======= FUSED shift+scale+softmax(heads) + attn@V (bf16x3) ==================
// Grid (16, 8): i-tile 64 rows x batch b, all 8 heads. 512 threads (16 warps).
// Warp w: head = w&7, ihalf = w>>3, out tile 32 x 64.
// Per j-tile of 32: phase A computes attn (fp32 softmax over heads) into smem
// as bf16 hi/lo; phase B runs the 3-term mma against cp.async'd V hi/lo tiles.
#define SAV_ATT_H 0
#define SAV_ATT_L 40960
#define SAV_V_H   81920
#define SAV_V_L   122880
#define SAV_SMEM  163840

__global__ __launch_bounds__(512, 1) void fused_sav_kernel(
    const float* __restrict__ AC, const float* __restrict__ BDp,
    const __nv_bfloat16* __restrict__ vth, const __nv_bfloat16* __restrict__ vtl,
    __nv_bfloat16* __restrict__ outh, __nv_bfloat16* __restrict__ outl,
    float* __restrict__ attnf)
{
    extern __shared__ char dsm[];
    const uint32_t sb = smem_u32(dsm);
    const int tid = threadIdx.x, wid = tid >> 5, lane = tid & 31;
    const int b = blockIdx.y;
    const int i0 = blockIdx.x * 64;
    const int bq = b * NHEADS;

    // phase A mapping: thread -> (i_base, jj pair)
    const int ibA = tid >> 4;            // 0..31
    const int jjA = (tid & 15) * 2;      // 0,2,..,30

    // phase B mapping
    const int h = wid & 7, ihalf = wid >> 3;
    const int l15 = lane & 15;
    const uint32_t headOff = (uint32_t)(h * 64 * 40 * 2);
    const uint32_t aAH = sb + SAV_ATT_H + headOff;
    const uint32_t aAL = sb + SAV_ATT_L + headOff;
    const uint32_t aVH = sb + SAV_V_H + headOff;
    const uint32_t aVL = sb + SAV_V_L + headOff;
    const uint32_t aoff = (uint32_t)(((ihalf * 32 + l15) * 40 + ((lane >> 4) << 3)) * 2);
    const uint32_t boff = (uint32_t)(((l15 & 7) * 40 + (((l15 >> 3) & 1) << 3)) * 2);

    float acc[2][8][4];
#pragma unroll
    for (int i = 0; i < 2; ++i)
#pragma unroll
        for (int j = 0; j < 8; ++j)
#pragma unroll
            for (int q = 0; q < 4; ++q) acc[i][j][q] = 0.0f;

    for (int kt = 0; kt < 32; ++kt) {
        const int j0 = kt * 32;

        // ---- issue V tile loads (hi+lo): 8 cp16 per thread ----
#pragma unroll
        for (int k = 0; k < 4; ++k) {
            const int idx = tid + k * 512;           // 0..2047
            const int hv = idx >> 8;                 // head
            const int r = idx & 255;
            const int d = r >> 2, seg = r & 3;
            const uint32_t so = (uint32_t)((hv * 64 + d) * 80 + seg * 16);
            const size_t gsrc = (((size_t)(bq + hv) * 64 + d) << 10) + j0 + seg * 8;
            cp16(sb + SAV_V_H + so, vth + gsrc);
            cp16(sb + SAV_V_L + so, vtl + gsrc);
        }
        CP_COMMIT();

        // ---- phase A: softmax over heads for (i, j0+jj), (i, j0+jj+1) ----
#pragma unroll
        for (int it = 0; it < 2; ++it) {
            const int i = ibA + it * 32;
            const int gi = i0 + i;
            float p0[8], p1[8];
#pragma unroll
            for (int e = 0; e < 2; ++e) {
                const int gj = j0 + jjA + e;
                const int g = (gi + 1) * NSEQ + gj;
                const int si = g / (NSEQ + 1);
                const int sj = g % (NSEQ + 1) - 1;
                float v[8];
                float mx = -1e30f;
#pragma unroll
                for (int hh = 0; hh < 8; ++hh) {
                    const size_t base = (size_t)(bq + hh) * NSEQ;
                    float d = AC[(base + gi) * NSEQ + gj];
                    if (sj >= 0) d += BDp[(base + si) * NSEQ + sj];
                    d *= 0.125f;
                    v[hh] = d;
                    mx = fmaxf(mx, d);
                }
                float s = 0.0f;
#pragma unroll
                for (int hh = 0; hh < 8; ++hh) { v[hh] = __expf(v[hh] - mx); s += v[hh]; }
                const float inv = 1.0f / s;
                float* pp = e ? p1 : p0;
#pragma unroll
                for (int hh = 0; hh < 8; ++hh) pp[hh] = v[hh] * inv;
            }
            // store smem attn (hi/lo) + optional fp32 attention output
#pragma unroll
            for (int hh = 0; hh < 8; ++hh) {
                __nv_bfloat16 h0, l0, h1, l1;
                split1(p0[hh], h0, l0);
                split1(p1[hh], h1, l1);
                __nv_bfloat162 hp; hp.x = h0; hp.y = h1;
                __nv_bfloat162 lp; lp.x = l0; lp.y = l1;
                const uint32_t so = (uint32_t)(((hh * 64 + i) * 40 + jjA) * 2);
                *(__nv_bfloat162*)(dsm + SAV_ATT_H + so) = hp;
                *(__nv_bfloat162*)(dsm + SAV_ATT_L + so) = lp;
                if (attnf) {
                    *(float2*)(attnf + ((size_t)(bq + hh) * NSEQ + gi) * NSEQ + j0 + jjA) =
                        make_float2(p0[hh], p1[hh]);
                }
            }
        }
        CP_WAIT(0);
        __syncthreads();

        // ---- phase B: 3-term mma, k = 32 ----
#pragma unroll
        for (int kk = 0; kk < 32; kk += 16) {
            uint32_t bhf[8][2], blf[8][2], ah[2][4], al[2][4];
#pragma unroll
            for (int nt = 0; nt < 8; ++nt) {
                const uint32_t bo = boff + (uint32_t)((nt * 8 * 40 + kk) * 2);
                ldm_x2(bhf[nt], aVH + bo);
                ldm_x2(blf[nt], aVL + bo);
            }
#pragma unroll
            for (int mt = 0; mt < 2; ++mt) {
                const uint32_t ao = aoff + (uint32_t)((mt * 16 * 40 + kk) * 2);
                ldm_x4(ah[mt], aAH + ao);
                ldm_x4(al[mt], aAL + ao);
            }
#pragma unroll
            for (int mt = 0; mt < 2; ++mt)
#pragma unroll
                for (int nt = 0; nt < 8; ++nt) {
                    mma_bf16(acc[mt][nt], ah[mt], bhf[nt]);
                    mma_bf16(acc[mt][nt], ah[mt], blf[nt]);
                    mma_bf16(acc[mt][nt], al[mt], bhf[nt]);
                }
        }
        __syncthreads();
    }

    // ---- epilogue: split out to bf16 hi/lo ----
    const int g = lane >> 2, t2 = (lane & 3) * 2;
#pragma unroll
    for (int mt = 0; mt < 2; ++mt) {
#pragma unroll
        for (int nt = 0; nt < 8; ++nt) {
            const int r0 = i0 + ihalf * 32 + mt * 16 + g;
            const int c  = h * 64 + nt * 8 + t2;
            __nv_bfloat16 h0, l0, h1, l1;
            split1(acc[mt][nt][0], h0, l0); split1(acc[mt][nt][1], h1, l1);
            __nv_bfloat162 hp; hp.x = h0; hp.y = h1;
            __nv_bfloat162 lp; lp.x = l0; lp.y = l1;
            *(__nv_bfloat162*)(outh + ((size_t)b * NSEQ + r0) * NHD + c) = hp;
            *(__nv_bfloat162*)(outl + ((size_t)b * NSEQ + r0) * NHD + c) = lp;
            split1(acc[mt][nt][2], h0, l0); split1(acc[mt][nt][3], h1, l1);
            hp.x = h0; hp.y = h1; lp.x = l0; lp.y = l1;
            *(__nv_bfloat162*)(outh + ((size_t)b * NSEQ + r0 + 8) * NHD + c) = hp;
            *(__nv_bfloat162*)(outl + ((size_t)b * NSEQ + r0 + 8) * NHD + c) = lp;
        }
    }
}

// ---------------- host orchestration ----------------------------------------
extern "C" void kernel_launch(void* const* d_in, const int* in_sizes, int n_in,
                              void* d_out, int out_size)
{
    (void)in_sizes; (void)n_in;
    const float* x_in    = (const float*)d_in[0];
    const float* r_t     = (const float*)d_in[1];
    const float* bias_pf = (const float*)d_in[3];
    const float* ln1_g   = (const float*)d_in[4];
    const float* ln1_b   = (const float*)d_in[5];
    const float* Wqkv    = (const float*)d_in[6];
    const float* Wkr_t   = (const float*)d_in[7];
    const float* Wout    = (const float*)d_in[9];
    const float* bout    = (const float*)d_in[10];
    const float* ln2_g   = (const float*)d_in[11];
    const float* ln2_b   = (const float*)d_in[12];
    const float* W1      = (const float*)d_in[13];
    const float* b1      = (const float*)d_in[14];
    const float* W2      = (const float*)d_in[15];
    const float* b2      = (const float*)d_in[16];
    float* outp = (float*)d_out;

    static int attr_done = 0;
    if (!attr_done) {
        cudaFuncSetAttribute(mma2_kernel<0,0>, cudaFuncAttributeMaxDynamicSharedMemorySize, MMA2_SMEM);
        cudaFuncSetAttribute(mma2_kernel<1,0>, cudaFuncAttributeMaxDynamicSharedMemorySize, MMA2_SMEM);
        cudaFuncSetAttribute(mma2_kernel<1,1>, cudaFuncAttributeMaxDynamicSharedMemorySize, MMA2_SMEM);
        cudaFuncSetAttribute(acbd2_kernel,     cudaFuncAttributeMaxDynamicSharedMemorySize, MMA2_SMEM);
        cudaFuncSetAttribute(fused_sav_kernel, cudaFuncAttributeMaxDynamicSharedMemorySize, SAV_SMEM);
        attr_done = 1;
    }

    float *gx, *gac, *gbd, *gbk, *gbr;
    __nv_bfloat16 *gxnh, *gxnl, *grth, *grtl, *gqkvh, *gqkvl, *gkrh, *gkrl;
    __nv_bfloat16 *gavh, *gavl, *gffh, *gffl, *gwth, *gwtl, *gvth, *gvtl;
    cudaGetSymbolAddress((void**)&gx,    g_x);
    cudaGetSymbolAddress((void**)&gac,   g_ac);
    cudaGetSymbolAddress((void**)&gbd,   g_bd);
    cudaGetSymbolAddress((void**)&gbk,   g_bk);
    cudaGetSymbolAddress((void**)&gbr,   g_br);
    cudaGetSymbolAddress((void**)&gxnh,  g_xnh);
    cudaGetSymbolAddress((void**)&gxnl,  g_xnl);
    cudaGetSymbolAddress((void**)&grth,  g_rth);
    cudaGetSymbolAddress((void**)&grtl,  g_rtl);
    cudaGetSymbolAddress((void**)&gqkvh, g_qkvh);
    cudaGetSymbolAddress((void**)&gqkvl, g_qkvl);
    cudaGetSymbolAddress((void**)&gkrh,  g_krh);
    cudaGetSymbolAddress((void**)&gkrl,  g_krl);
    cudaGetSymbolAddress((void**)&gavh,  g_avh);
    cudaGetSymbolAddress((void**)&gavl,  g_avl);
    cudaGetSymbolAddress((void**)&gffh,  g_ffh);
    cudaGetSymbolAddress((void**)&gffl,  g_ffl);
    cudaGetSymbolAddress((void**)&gwth,  g_wth);
    cudaGetSymbolAddress((void**)&gwtl,  g_wtl);
    cudaGetSymbolAddress((void**)&gvth,  g_vth);
    cudaGetSymbolAddress((void**)&gvtl,  g_vtl);

    float* attn_out = outp + ((size_t)out_size - ATT_ELEMS);

    cudaMemcpyAsync(gx, x_in, X_ELEMS * sizeof(float), cudaMemcpyDeviceToDevice, 0);
    split_rt_kernel<<<X_ELEMS / 1024, 256>>>(r_t, grth, grtl);

    const dim3 tb(32, 8);
    for (int l = 0; l < 4; ++l) {
        transpose_split_kernel<<<dim3(48, 16), tb>>>(Wqkv  + (size_t)l*512*1536, gwth + WQKVT, gwtl + WQKVT, 512, 1536);
        transpose_split_kernel<<<dim3(16, 16), tb>>>(Wkr_t + (size_t)l*512*512,  gwth + WKRT,  gwtl + WKRT,  512, 512);
        transpose_split_kernel<<<dim3(16, 16), tb>>>(Wout  + (size_t)l*512*512,  gwth + WOUTT, gwtl + WOUTT, 512, 512);
        transpose_split_kernel<<<dim3(64, 16), tb>>>(W1    + (size_t)l*512*2048, gwth + W1T,   gwtl + W1T,   512, 2048);
        transpose_split_kernel<<<dim3(16, 64), tb>>>(W2    + (size_t)l*2048*512, gwth + W2T,   gwtl + W2T,  2048, 512);

        ln_split_kernel<<<MROWS, 128>>>(gx, ln1_g + l * NDIM, ln1_b + l * NDIM, gxnh, gxnl);
        mma2_kernel<1,0><<<dim3(12, 64), 256, MMA2_SMEM>>>(
            gxnh, gxnl, gwth + WQKVT, gwtl + WQKVT,
            nullptr, gqkvh, gqkvl, nullptr, nullptr, MROWS, 1536, 512);
        mma2_kernel<1,0><<<dim3(4, 64), 256, MMA2_SMEM>>>(
            grth, grtl, gwth + WKRT, gwtl + WKRT,
            nullptr, gkrh, gkrl, nullptr, nullptr, MROWS, 512, 512);

        bias_terms_kernel<<<256, 256>>>(gqkvh, gqkvl, gkrh, gkrl, bias_pf, gbk, gbr);

        acbd2_kernel<<<dim3(8, 8, 128), 256, MMA2_SMEM>>>(
            gqkvh, gqkvl, gkrh, gkrl, gbk, gbr, gac, gbd);

        vt_kernel<<<dim3(32, 2, 64), tb>>>(gqkvh, gqkvl, gvth, gvtl);

        // fused shift+softmax(heads)+attn@V (writes attn fp32 only on last layer)
        fused_sav_kernel<<<dim3(16, 8), 512, SAV_SMEM>>>(
            gac, gbd, gvth, gvtl, gavh, gavl,
            (l == 3) ? attn_out : nullptr);

        mma2_kernel<0,0><<<dim3(4, 64), 256, MMA2_SMEM>>>(
            gavh, gavl, gwth + WOUTT, gwtl + WOUTT,
            gx, nullptr, nullptr, bout + l * NDIM, gx, MROWS, 512, 512);

        ln_split_kernel<<<MROWS, 128>>>(gx, ln2_g + l * NDIM, ln2_b + l * NDIM, gxnh, gxnl);
        mma2_kernel<1,1><<<dim3(16, 64), 256, MMA2_SMEM>>>(
            gxnh, gxnl, gwth + W1T, gwtl + W1T,
            nullptr, gffh, gffl, b1 + l * NFF, nullptr, MROWS, 2048, 512);
        float* xdst = (l == 3) ? outp : gx;
        mma2_kernel<0,0><<<dim3(4, 64), 256, MMA2_SMEM>>>(
            gffh, gffl, gwth + W2T, gwtl + W2T,
            xdst, nullptr, nullptr, b2 + l * NDIM, gx, MROWS, 512, 2048);
    }
}

// round 8
// speedup vs baseline: 1.1362x; 1.1328x over previous
#include <cuda_runtime.h>
#include <cuda_fp16.h>
#include <math.h>
#include <stdint.h>

#define NSEQ   1024
#define NBATCH 8
#define NDIM   512
#define NHEADS 8
#define NDH    64
#define NHD    512
#define NFF    2048
#define MROWS  (NBATCH*NSEQ)
#define ATT_ELEMS ((size_t)NBATCH*NHEADS*NSEQ*NSEQ)
#define X_ELEMS   ((size_t)MROWS*NDIM)

// transposed weight offsets (elements, within one layer's block)
#define WQKVT 0
#define WKRT  786432
#define WOUTT 1048576
#define W1T   1310720
#define W2T   2359296
#define WT_TOTAL 3407872

// ---------------- scratch --------------------------------------------------
static __device__ float g_x [MROWS*NDIM];
static __device__ float g_ac[NBATCH*NHEADS*NSEQ*NSEQ];
static __device__ float g_bd[NBATCH*NHEADS*NSEQ*NSEQ];
static __device__ float g_bk[NBATCH*NHEADS*NSEQ];
static __device__ float g_br[NBATCH*NHEADS*NSEQ];
static __device__ __half g_xnh [MROWS*NDIM],  g_xnl [MROWS*NDIM];
static __device__ __half g_rth [MROWS*NDIM],  g_rtl [MROWS*NDIM];
static __device__ __half g_qkvh[MROWS*3*NHD], g_qkvl[MROWS*3*NHD];
static __device__ __half g_krh [MROWS*NHD],   g_krl [MROWS*NHD];
static __device__ __half g_avh [MROWS*NHD];
static __device__ __half g_ffh [MROWS*NFF];
static __device__ __half g_wth [4*WT_TOTAL],  g_wtl [4*WT_TOTAL];
static __device__ __half g_vth [NBATCH*NHEADS*NDH*NSEQ];
static __device__ __half g_vtl [NBATCH*NHEADS*NDH*NSEQ];

// ---------------- primitives ------------------------------------------------
__device__ __forceinline__ uint32_t smem_u32(const void* p) {
    uint32_t a;
    asm("{ .reg .u64 t; cvta.to.shared.u64 t, %1; cvt.u32.u64 %0, t; }"
        : "=r"(a) : "l"(p));
    return a;
}
__device__ __forceinline__ void cp16(uint32_t dst, const void* src) {
    asm volatile("cp.async.cg.shared.global [%0], [%1], 16;" :: "r"(dst), "l"(src));
}
#define CP_COMMIT() asm volatile("cp.async.commit_group;")
#define CP_WAIT(n)  asm volatile("cp.async.wait_group %0;" :: "n"(n))

__device__ __forceinline__ void mma_f16(float* d, const uint32_t* a, const uint32_t* b) {
    asm volatile(
        "mma.sync.aligned.m16n8k16.row.col.f32.f16.f16.f32 "
        "{%0,%1,%2,%3}, {%4,%5,%6,%7}, {%8,%9}, {%0,%1,%2,%3};"
        : "+f"(d[0]), "+f"(d[1]), "+f"(d[2]), "+f"(d[3])
        : "r"(a[0]), "r"(a[1]), "r"(a[2]), "r"(a[3]), "r"(b[0]), "r"(b[1]));
}
__device__ __forceinline__ void ldm_x4(uint32_t* r, uint32_t addr) {
    asm volatile("ldmatrix.sync.aligned.m8n8.x4.shared.b16 {%0,%1,%2,%3}, [%4];"
        : "=r"(r[0]), "=r"(r[1]), "=r"(r[2]), "=r"(r[3]) : "r"(addr));
}
__device__ __forceinline__ void ldm_x2(uint32_t* r, uint32_t addr) {
    asm volatile("ldmatrix.sync.aligned.m8n8.x2.shared.b16 {%0,%1}, [%2];"
        : "=r"(r[0]), "=r"(r[1]) : "r"(addr));
}
__device__ __forceinline__ float gelu_exact(float v) {
    return 0.5f * v * (1.0f + erff(v * 0.70710678118654752f));
}
__device__ __forceinline__ void split1(float v, __half& h, __half& l) {
    h = __float2half_rn(v);
    l = __float2half_rn(v - __half2float(h));
}

// ---------- merged weight transpose+split for ALL layers: one launch --------
__global__ __launch_bounds__(256) void transpose_all_kernel(
    const float* __restrict__ Wqkv, const float* __restrict__ Wkr,
    const float* __restrict__ Wout, const float* __restrict__ W1,
    const float* __restrict__ W2,
    __half* __restrict__ Wth, __half* __restrict__ Wtl)
{
    __shared__ float t[32][33];
    const int l = blockIdx.y;
    const int tt = blockIdx.x;
    const float* W; int K, N, off, tloc;
    if (tt < 768)       { W = Wqkv + (size_t)l * 786432;  K = 512;  N = 1536; off = WQKVT; tloc = tt; }
    else if (tt < 1024) { W = Wkr  + (size_t)l * 262144;  K = 512;  N = 512;  off = WKRT;  tloc = tt - 768; }
    else if (tt < 1280) { W = Wout + (size_t)l * 262144;  K = 512;  N = 512;  off = WOUTT; tloc = tt - 1024; }
    else if (tt < 2304) { W = W1   + (size_t)l * 1048576; K = 512;  N = 2048; off = W1T;   tloc = tt - 1280; }
    else                { W = W2   + (size_t)l * 1048576; K = 2048; N = 512;  off = W2T;   tloc = tt - 2304; }
    const int ntn = N >> 5;
    const int kt = tloc / ntn, nt = tloc % ntn;
    const int k0 = kt * 32, n0 = nt * 32;
    const int x = threadIdx.x, y = threadIdx.y;
    const size_t dst = (size_t)l * WT_TOTAL + off;
#pragma unroll
    for (int i = 0; i < 32; i += 8)
        t[y + i][x] = W[(size_t)(k0 + y + i) * N + n0 + x];
    __syncthreads();
#pragma unroll
    for (int i = 0; i < 32; i += 8) {
        float v = t[x][y + i];
        __half h, lo; split1(v, h, lo);
        Wth[dst + (size_t)(n0 + y + i) * K + k0 + x] = h;
        Wtl[dst + (size_t)(n0 + y + i) * K + k0 + x] = lo;
    }
}

// ---------------- r_t split -------------------------------------------------
__global__ __launch_bounds__(256) void split_rt_kernel(
    const float* __restrict__ src, __half* __restrict__ dh,
    __half* __restrict__ dl)
{
    const size_t i = ((size_t)blockIdx.x * 256 + threadIdx.x) * 4;
    float4 v = *(const float4*)(src + i);
    __half h, l;
    split1(v.x, h, l); dh[i]   = h; dl[i]   = l;
    split1(v.y, h, l); dh[i+1] = h; dl[i+1] = l;
    split1(v.z, h, l); dh[i+2] = h; dl[i+2] = l;
    split1(v.w, h, l); dh[i+3] = h; dl[i+3] = l;
}

// ---------------- LayerNorm + split ------------------------------------------
__global__ __launch_bounds__(128) void ln_split_kernel(
    const float* __restrict__ x, const float* __restrict__ g,
    const float* __restrict__ b, __half* __restrict__ yh,
    __half* __restrict__ yl)
{
    const int row = blockIdx.x;
    const int tid = threadIdx.x;
    const float* xr = x + (size_t)row * NDIM;

    float4 v = ((const float4*)xr)[tid];
    float s  = v.x + v.y + v.z + v.w;
    float sq = v.x*v.x + v.y*v.y + v.z*v.z + v.w*v.w;
#pragma unroll
    for (int o = 16; o > 0; o >>= 1) {
        s  += __shfl_xor_sync(0xffffffffu, s,  o);
        sq += __shfl_xor_sync(0xffffffffu, sq, o);
    }
    __shared__ float red[8];
    const int w = tid >> 5;
    if ((tid & 31) == 0) { red[w] = s; red[4 + w] = sq; }
    __syncthreads();
    const float st  = red[0] + red[1] + red[2] + red[3];
    const float sqt = red[4] + red[5] + red[6] + red[7];
    const float mu  = st * (1.0f / NDIM);
    const float var = sqt * (1.0f / NDIM) - mu * mu;
    const float inv = rsqrtf(var + 1e-5f);

    float4 gg = ((const float4*)g)[tid];
    float4 bb = ((const float4*)b)[tid];
    float o0 = (v.x - mu) * inv * gg.x + bb.x;
    float o1 = (v.y - mu) * inv * gg.y + bb.y;
    float o2 = (v.z - mu) * inv * gg.z + bb.z;
    float o3 = (v.w - mu) * inv * gg.w + bb.w;
    const size_t base = (size_t)row * NDIM + tid * 4;
    __half h, l;
    split1(o0, h, l); yh[base]   = h; yl[base]   = l;
    split1(o1, h, l); yh[base+1] = h; yl[base+1] = l;
    split1(o2, h, l); yh[base+2] = h; yl[base+2] = l;
    split1(o3, h, l); yh[base+3] = h; yl[base+3] = l;
}

// ====== dense fp16 mma GEMM, cp.async double-buffered ========================
// NTERM=3: A hi/lo + B hi/lo, terms hh+hl+lh (err ~2^-22)
// NTERM=2: A hi only + B hi/lo, terms hh+hl (err ~2^-12 rms)
// SPLIT: 0 = fp32 out (+bias,+res); 1 = half hi/lo out; 2 = half hi-only out.
#define LDS 40
#define ARR   (128*LDS)
#define STAGE (4*ARR)
#define MMA2_SMEM (2*STAGE*2)

template<int SPLIT, int ACT, int NTERM>
__global__ __launch_bounds__(256, 2) void mma2_kernel(
    const __half* __restrict__ Ah, const __half* __restrict__ Al,
    const __half* __restrict__ Bh, const __half* __restrict__ Bl,
    float* __restrict__ Cf, __half* __restrict__ Ch,
    __half* __restrict__ Cl,
    const float* __restrict__ bias, const float* __restrict__ res,
    int M, int N, int K)
{
    extern __shared__ char dsm[];
    const uint32_t sbase = smem_u32(dsm);
    const int tid = threadIdx.x, wid = tid >> 5, lane = tid & 31;
    const int wm = wid >> 2, wn = wid & 3;
    const int bm = blockIdx.y * 128, bn = blockIdx.x * 128;

    const int lrow = tid >> 2, lcc = (tid & 3) * 8;
    const int lrow2 = (tid + 256) >> 2, lcc2 = ((tid + 256) & 3) * 8;

#define MMA2_ISSUE(kt, s) do {                                                   \
        const uint32_t st_ = sbase + (uint32_t)(s) * (STAGE * 2);                \
        const int k0_ = (kt) * 32;                                               \
        cp16(st_ + (uint32_t)((lrow * LDS + lcc) * 2),                           \
             Ah + (size_t)(bm + lrow) * K + k0_ + lcc);                          \
        cp16(st_ + (uint32_t)((lrow2 * LDS + lcc2) * 2),                         \
             Ah + (size_t)(bm + lrow2) * K + k0_ + lcc2);                        \
        if (NTERM == 3) {                                                        \
            cp16(st_ + (uint32_t)(ARR * 2) + (uint32_t)((lrow * LDS + lcc) * 2), \
                 Al + (size_t)(bm + lrow) * K + k0_ + lcc);                      \
            cp16(st_ + (uint32_t)(ARR * 2) + (uint32_t)((lrow2 * LDS + lcc2) * 2),\
                 Al + (size_t)(bm + lrow2) * K + k0_ + lcc2);                    \
        }                                                                        \
        cp16(st_ + (uint32_t)(2 * ARR * 2) + (uint32_t)((lrow * LDS + lcc) * 2), \
             Bh + (size_t)(bn + lrow) * K + k0_ + lcc);                          \
        cp16(st_ + (uint32_t)(2 * ARR * 2) + (uint32_t)((lrow2 * LDS + lcc2) * 2),\
             Bh + (size_t)(bn + lrow2) * K + k0_ + lcc2);                        \
        cp16(st_ + (uint32_t)(3 * ARR * 2) + (uint32_t)((lrow * LDS + lcc) * 2), \
             Bl + (size_t)(bn + lrow) * K + k0_ + lcc);                          \
        cp16(st_ + (uint32_t)(3 * ARR * 2) + (uint32_t)((lrow2 * LDS + lcc2) * 2),\
             Bl + (size_t)(bn + lrow2) * K + k0_ + lcc2);                        \
    } while (0)

    const int l15 = lane & 15;
    const uint32_t aoff = (uint32_t)(((wm * 64 + l15) * LDS + ((lane >> 4) << 3)) * 2);
    const uint32_t boff = (uint32_t)(((wn * 32 + (l15 & 7)) * LDS + (((l15 >> 3) & 1) << 3)) * 2);

    float acc[4][4][4];
#pragma unroll
    for (int i = 0; i < 4; ++i)
#pragma unroll
        for (int j = 0; j < 4; ++j)
#pragma unroll
            for (int q = 0; q < 4; ++q) acc[i][j][q] = 0.0f;

    const int NKT = K >> 5;
    MMA2_ISSUE(0, 0);
    CP_COMMIT();

    for (int kt = 0; kt < NKT; ++kt) {
        if (kt + 1 < NKT) {
            MMA2_ISSUE(kt + 1, (kt + 1) & 1);
            CP_COMMIT();
            CP_WAIT(1);
        } else {
            CP_WAIT(0);
        }
        __syncthreads();

        const uint32_t st = sbase + (uint32_t)(kt & 1) * (STAGE * 2);
        const uint32_t aAh = st, aAl = st + ARR * 2;
        const uint32_t aBh = st + 2 * ARR * 2, aBl = st + 3 * ARR * 2;
#pragma unroll
        for (int kk = 0; kk < 32; kk += 16) {
            uint32_t bh[4][2], bl[4][2], a[4][4];
#pragma unroll
            for (int nt = 0; nt < 4; ++nt) {
                const uint32_t bo = boff + (uint32_t)((nt * 8 * LDS + kk) * 2);
                ldm_x2(bh[nt], aBh + bo);
                ldm_x2(bl[nt], aBl + bo);
            }
#pragma unroll
            for (int mt = 0; mt < 4; ++mt)
                ldm_x4(a[mt], aAh + aoff + (uint32_t)((mt * 16 * LDS + kk) * 2));
#pragma unroll
            for (int mt = 0; mt < 4; ++mt)
#pragma unroll
                for (int nt = 0; nt < 4; ++nt) {
                    mma_f16(acc[mt][nt], a[mt], bh[nt]);
                    mma_f16(acc[mt][nt], a[mt], bl[nt]);
                }
            if (NTERM == 3) {
#pragma unroll
                for (int mt = 0; mt < 4; ++mt)
                    ldm_x4(a[mt], aAl + aoff + (uint32_t)((mt * 16 * LDS + kk) * 2));
#pragma unroll
                for (int mt = 0; mt < 4; ++mt)
#pragma unroll
                    for (int nt = 0; nt < 4; ++nt)
                        mma_f16(acc[mt][nt], a[mt], bh[nt]);
            }
        }
        __syncthreads();
    }
#undef MMA2_ISSUE

    const int g = lane >> 2, t2 = (lane & 3) * 2;
#pragma unroll
    for (int mt = 0; mt < 4; ++mt) {
#pragma unroll
        for (int nt = 0; nt < 4; ++nt) {
            const int r0 = bm + wm * 64 + mt * 16 + g;
            const int r1 = r0 + 8;
            const int c  = bn + wn * 32 + nt * 8 + t2;
            float v0 = acc[mt][nt][0], v1 = acc[mt][nt][1];
            float v2 = acc[mt][nt][2], v3 = acc[mt][nt][3];
            if (bias) {
                const float b0 = bias[c], b1 = bias[c + 1];
                v0 += b0; v1 += b1; v2 += b0; v3 += b1;
            }
            if (ACT) {
                v0 = gelu_exact(v0); v1 = gelu_exact(v1);
                v2 = gelu_exact(v2); v3 = gelu_exact(v3);
            }
            if (SPLIT == 1) {
                __half h0, l0, h1, l1;
                split1(v0, h0, l0); split1(v1, h1, l1);
                __half2 hp; hp.x = h0; hp.y = h1;
                __half2 lp; lp.x = l0; lp.y = l1;
                *(__half2*)(Ch + (size_t)r0 * N + c) = hp;
                *(__half2*)(Cl + (size_t)r0 * N + c) = lp;
                split1(v2, h0, l0); split1(v3, h1, l1);
                hp.x = h0; hp.y = h1; lp.x = l0; lp.y = l1;
                *(__half2*)(Ch + (size_t)r1 * N + c) = hp;
                *(__half2*)(Cl + (size_t)r1 * N + c) = lp;
            } else if (SPLIT == 2) {
                __half2 hp;
                hp.x = __float2half_rn(v0); hp.y = __float2half_rn(v1);
                *(__half2*)(Ch + (size_t)r0 * N + c) = hp;
                hp.x = __float2half_rn(v2); hp.y = __float2half_rn(v3);
                *(__half2*)(Ch + (size_t)r1 * N + c) = hp;
            } else {
                if (res) {
                    const float2 q0 = *(const float2*)(res + (size_t)r0 * N + c);
                    const float2 q1 = *(const float2*)(res + (size_t)r1 * N + c);
                    v0 += q0.x; v1 += q0.y; v2 += q1.x; v3 += q1.y;
                }
                *(float2*)(Cf + (size_t)r0 * N + c) = make_float2(v0, v1);
                *(float2*)(Cf + (size_t)r1 * N + c) = make_float2(v2, v3);
            }
        }
    }
}

// ---------------- bias rank-1 terms ------------------------------------------
__global__ __launch_bounds__(256) void bias_terms_kernel(
    const __half* __restrict__ qkvh, const __half* __restrict__ qkvl,
    const __half* __restrict__ krh, const __half* __restrict__ krl,
    const float* __restrict__ bias_pf,
    float* __restrict__ bk, float* __restrict__ br)
{
    const int idx = blockIdx.x * 256 + threadIdx.x;
    const int bh = idx >> 10, j = idx & 1023;
    const int b = bh >> 3, h = bh & 7;
    const size_t kb = ((size_t)b * NSEQ + j) * 1536 + 512 + h * 64;
    const size_t rb = ((size_t)b * NSEQ + j) * 512 + h * 64;
    float sk = 0.0f, sr = 0.0f;
#pragma unroll 16
    for (int d = 0; d < 64; ++d) {
        const float bp = bias_pf[h * 64 + d];
        sk += bp * (__half2float(qkvh[kb + d]) + __half2float(qkvl[kb + d]));
        sr += bp * (__half2float(krh[rb + d]) + __half2float(krl[rb + d]));
    }
    bk[idx] = sk;
    br[idx] = sr;
}

// =========== acbd fp16x3 mma (gate-critical: 3 terms) ========================
__global__ __launch_bounds__(256, 2) void acbd2_kernel(
    const __half* __restrict__ qkvh, const __half* __restrict__ qkvl,
    const __half* __restrict__ krh, const __half* __restrict__ krl,
    const float* __restrict__ bk, const float* __restrict__ br,
    float* __restrict__ AC, float* __restrict__ BD)
{
    extern __shared__ char dsm[];
    const uint32_t sbase = smem_u32(dsm);
    const int tid = threadIdx.x, wid = tid >> 5, lane = tid & 31;
    const int wm = wid >> 2, wn = wid & 3;
    const int z = blockIdx.z, bh_idx = z & 63, isBD = z >> 6;
    const int b = bh_idx >> 3, h = bh_idx & 7;
    const int i0 = blockIdx.y * 128, j0 = blockIdx.x * 128;

    const __half* Ah = qkvh + ((size_t)b * NSEQ + i0) * 1536 + h * 64;
    const __half* Al = qkvl + ((size_t)b * NSEQ + i0) * 1536 + h * 64;
    const __half* Bh = isBD ? (krh + ((size_t)b * NSEQ + j0) * 512 + h * 64)
                            : (qkvh + ((size_t)b * NSEQ + j0) * 1536 + 512 + h * 64);
    const __half* Bl = isBD ? (krl + ((size_t)b * NSEQ + j0) * 512 + h * 64)
                            : (qkvl + ((size_t)b * NSEQ + j0) * 1536 + 512 + h * 64);
    const int ldb = isBD ? 512 : 1536;
    float* Cbase = (isBD ? BD : AC) + (size_t)bh_idx * NSEQ * NSEQ;
    const float* bvec = (isBD ? br : bk) + (size_t)bh_idx * NSEQ;

    const int lrow = tid >> 2, lcc = (tid & 3) * 8;
    const int lrow2 = (tid + 256) >> 2, lcc2 = ((tid + 256) & 3) * 8;

#define ACBD_ISSUE(kt, s) do {                                                   \
        const uint32_t st_ = sbase + (uint32_t)(s) * (STAGE * 2);                \
        const int k0_ = (kt) * 32;                                               \
        cp16(st_ + (uint32_t)((lrow * LDS + lcc) * 2),                           \
             Ah + (size_t)lrow * 1536 + k0_ + lcc);                              \
        cp16(st_ + (uint32_t)((lrow2 * LDS + lcc2) * 2),                         \
             Ah + (size_t)lrow2 * 1536 + k0_ + lcc2);                            \
        cp16(st_ + (uint32_t)(ARR * 2) + (uint32_t)((lrow * LDS + lcc) * 2),     \
             Al + (size_t)lrow * 1536 + k0_ + lcc);                              \
        cp16(st_ + (uint32_t)(ARR * 2) + (uint32_t)((lrow2 * LDS + lcc2) * 2),   \
             Al + (size_t)lrow2 * 1536 + k0_ + lcc2);                            \
        cp16(st_ + (uint32_t)(2 * ARR * 2) + (uint32_t)((lrow * LDS + lcc) * 2), \
             Bh + (size_t)lrow * ldb + k0_ + lcc);                               \
        cp16(st_ + (uint32_t)(2 * ARR * 2) + (uint32_t)((lrow2 * LDS + lcc2) * 2),\
             Bh + (size_t)lrow2 * ldb + k0_ + lcc2);                             \
        cp16(st_ + (uint32_t)(3 * ARR * 2) + (uint32_t)((lrow * LDS + lcc) * 2), \
             Bl + (size_t)lrow * ldb + k0_ + lcc);                               \
        cp16(st_ + (uint32_t)(3 * ARR * 2) + (uint32_t)((lrow2 * LDS + lcc2) * 2),\
             Bl + (size_t)lrow2 * ldb + k0_ + lcc2);                             \
    } while (0)

    const int l15 = lane & 15;
    const uint32_t aoff = (uint32_t)(((wm * 64 + l15) * LDS + ((lane >> 4) << 3)) * 2);
    const uint32_t boff = (uint32_t)(((wn * 32 + (l15 & 7)) * LDS + (((l15 >> 3) & 1) << 3)) * 2);

    float acc[4][4][4];
#pragma unroll
    for (int i = 0; i < 4; ++i)
#pragma unroll
        for (int j = 0; j < 4; ++j)
#pragma unroll
            for (int q = 0; q < 4; ++q) acc[i][j][q] = 0.0f;

    ACBD_ISSUE(0, 0);
    CP_COMMIT();
#pragma unroll
    for (int kt = 0; kt < 2; ++kt) {
        if (kt == 0) {
            ACBD_ISSUE(1, 1);
            CP_COMMIT();
            CP_WAIT(1);
        } else {
            CP_WAIT(0);
        }
        __syncthreads();
        const uint32_t st = sbase + (uint32_t)(kt & 1) * (STAGE * 2);
        const uint32_t aAh = st, aAl = st + ARR * 2;
        const uint32_t aBh = st + 2 * ARR * 2, aBl = st + 3 * ARR * 2;
#pragma unroll
        for (int kk = 0; kk < 32; kk += 16) {
            uint32_t bh[4][2], bl[4][2], a[4][4];
#pragma unroll
            for (int nt = 0; nt < 4; ++nt) {
                const uint32_t bo = boff + (uint32_t)((nt * 8 * LDS + kk) * 2);
                ldm_x2(bh[nt], aBh + bo);
                ldm_x2(bl[nt], aBl + bo);
            }
#pragma unroll
            for (int mt = 0; mt < 4; ++mt)
                ldm_x4(a[mt], aAh + aoff + (uint32_t)((mt * 16 * LDS + kk) * 2));
#pragma unroll
            for (int mt = 0; mt < 4; ++mt)
#pragma unroll
                for (int nt = 0; nt < 4; ++nt) {
                    mma_f16(acc[mt][nt], a[mt], bh[nt]);
                    mma_f16(acc[mt][nt], a[mt], bl[nt]);
                }
#pragma unroll
            for (int mt = 0; mt < 4; ++mt)
                ldm_x4(a[mt], aAl + aoff + (uint32_t)((mt * 16 * LDS + kk) * 2));
#pragma unroll
            for (int mt = 0; mt < 4; ++mt)
#pragma unroll
                for (int nt = 0; nt < 4; ++nt)
                    mma_f16(acc[mt][nt], a[mt], bh[nt]);
        }
        __syncthreads();
    }
#undef ACBD_ISSUE

    const int g = lane >> 2, t2 = (lane & 3) * 2;
#pragma unroll
    for (int mt = 0; mt < 4; ++mt) {
#pragma unroll
        for (int nt = 0; nt < 4; ++nt) {
            const int r0 = i0 + wm * 64 + mt * 16 + g;
            const int c  = j0 + wn * 32 + nt * 8 + t2;
            const float b0 = bvec[c], b1 = bvec[c + 1];
            *(float2*)(Cbase + (size_t)r0 * NSEQ + c) =
                make_float2(acc[mt][nt][0] + b0, acc[mt][nt][1] + b1);
            *(float2*)(Cbase + (size_t)(r0 + 8) * NSEQ + c) =
                make_float2(acc[mt][nt][2] + b0, acc[mt][nt][3] + b1);
        }
    }
}

// ---------------- V transpose hi+lo ------------------------------------------
__global__ __launch_bounds__(256) void vt_kernel(
    const __half* __restrict__ qkvh, const __half* __restrict__ qkvl,
    __half* __restrict__ vth, __half* __restrict__ vtl)
{
    __shared__ __half th[32][33], tl[32][33];
    const int bh = blockIdx.z, b = bh >> 3, h = bh & 7;
    const int j0 = blockIdx.x * 32, d0 = blockIdx.y * 32;
    const int x = threadIdx.x, y = threadIdx.y;
#pragma unroll
    for (int i = 0; i < 32; i += 8) {
        const size_t src = ((size_t)b * NSEQ + j0 + y + i) * 1536 + 1024 + h * 64 + d0 + x;
        th[y + i][x] = qkvh[src];
        tl[y + i][x] = qkvl[src];
    }
    __syncthreads();
#pragma unroll
    for (int i = 0; i < 32; i += 8) {
        const size_t dst = ((size_t)bh * 64 + d0 + y + i) * NSEQ + j0 + x;
        vth[dst] = th[x][y + i];
        vtl[dst] = tl[x][y + i];
    }
}

// ======= FUSED shift+scale+softmax(heads) + attn@V (fp16 2-term) =============
#define SAV_ATT_H 0
#define SAV_V_H   40960
#define SAV_V_L   81920
#define SAV_SMEM  122880

__global__ __launch_bounds__(512, 1) void fused_sav_kernel(
    const float* __restrict__ AC, const float* __restrict__ BDp,
    const __half* __restrict__ vth, const __half* __restrict__ vtl,
    __half* __restrict__ outh, float* __restrict__ attnf)
{
    extern __shared__ char dsm[];
    const uint32_t sb = smem_u32(dsm);
    const int tid = threadIdx.x, wid = tid >> 5, lane = tid & 31;
    const int b = blockIdx.y;
    const int i0 = blockIdx.x * 64;
    const int bq = b * NHEADS;

    const int ibA = tid >> 4;
    const int jjA = (tid & 15) * 2;

    const int h = wid & 7, ihalf = wid >> 3;
    const int l15 = lane & 15;
    const uint32_t headOff = (uint32_t)(h * 64 * 40 * 2);
    const uint32_t aAH = sb + SAV_ATT_H + headOff;
    const uint32_t aVH = sb + SAV_V_H + headOff;
    const uint32_t aVL = sb + SAV_V_L + headOff;
    const uint32_t aoff = (uint32_t)(((ihalf * 32 + l15) * 40 + ((lane >> 4) << 3)) * 2);
    const uint32_t boff = (uint32_t)(((l15 & 7) * 40 + (((l15 >> 3) & 1) << 3)) * 2);

    float acc[2][8][4];
#pragma unroll
    for (int i = 0; i < 2; ++i)
#pragma unroll
        for (int j = 0; j < 8; ++j)
#pragma unroll
            for (int q = 0; q < 4; ++q) acc[i][j][q] = 0.0f;

    for (int kt = 0; kt < 32; ++kt) {
        const int j0 = kt * 32;
#pragma unroll
        for (int k = 0; k < 4; ++k) {
            const int idx = tid + k * 512;
            const int hv = idx >> 8;
            const int r = idx & 255;
            const int d = r >> 2, seg = r & 3;
            const uint32_t so = (uint32_t)((hv * 64 + d) * 80 + seg * 16);
            const size_t gsrc = (((size_t)(bq + hv) * 64 + d) << 10) + j0 + seg * 8;
            cp16(sb + SAV_V_H + so, vth + gsrc);
            cp16(sb + SAV_V_L + so, vtl + gsrc);
        }
        CP_COMMIT();

#pragma unroll
        for (int it = 0; it < 2; ++it) {
            const int i = ibA + it * 32;
            const int gi = i0 + i;
            float p0[8], p1[8];
#pragma unroll
            for (int e = 0; e < 2; ++e) {
                const int gj = j0 + jjA + e;
                const int g = (gi + 1) * NSEQ + gj;
                const int si = g / (NSEQ + 1);
                const int sj = g % (NSEQ + 1) - 1;
                float v[8];
                float mx = -1e30f;
#pragma unroll
                for (int hh = 0; hh < 8; ++hh) {
                    const size_t base = (size_t)(bq + hh) * NSEQ;
                    float d = AC[(base + gi) * NSEQ + gj];
                    if (sj >= 0) d += BDp[(base + si) * NSEQ + sj];
                    d *= 0.125f;
                    v[hh] = d;
                    mx = fmaxf(mx, d);
                }
                float s = 0.0f;
#pragma unroll
                for (int hh = 0; hh < 8; ++hh) { v[hh] = __expf(v[hh] - mx); s += v[hh]; }
                const float inv = 1.0f / s;
                float* pp = e ? p1 : p0;
#pragma unroll
                for (int hh = 0; hh < 8; ++hh) pp[hh] = v[hh] * inv;
            }
#pragma unroll
            for (int hh = 0; hh < 8; ++hh) {
                __half2 hp;
                hp.x = __float2half_rn(p0[hh]);
                hp.y = __float2half_rn(p1[hh]);
                const uint32_t so = (uint32_t)(((hh * 64 + i) * 40 + jjA) * 2);
                *(__half2*)(dsm + SAV_ATT_H + so) = hp;
                if (attnf) {
                    *(float2*)(attnf + ((size_t)(bq + hh) * NSEQ + gi) * NSEQ + j0 + jjA) =
                        make_float2(p0[hh], p1[hh]);
                }
            }
        }
        CP_WAIT(0);
        __syncthreads();

#pragma unroll
        for (int kk = 0; kk < 32; kk += 16) {
            uint32_t bhf[8][2], blf[8][2], ah[2][4];
#pragma unroll
            for (int nt = 0; nt < 8; ++nt) {
                const uint32_t bo = boff + (uint32_t)((nt * 8 * 40 + kk) * 2);
                ldm_x2(bhf[nt], aVH + bo);
                ldm_x2(blf[nt], aVL + bo);
            }
#pragma unroll
            for (int mt = 0; mt < 2; ++mt)
                ldm_x4(ah[mt], aAH + aoff + (uint32_t)((mt * 16 * 40 + kk) * 2));
#pragma unroll
            for (int mt = 0; mt < 2; ++mt)
#pragma unroll
                for (int nt = 0; nt < 8; ++nt) {
                    mma_f16(acc[mt][nt], ah[mt], bhf[nt]);
                    mma_f16(acc[mt][nt], ah[mt], blf[nt]);
                }
        }
        __syncthreads();
    }

    const int g = lane >> 2, t2 = (lane & 3) * 2;
#pragma unroll
    for (int mt = 0; mt < 2; ++mt) {
#pragma unroll
        for (int nt = 0; nt < 8; ++nt) {
            const int r0 = i0 + ihalf * 32 + mt * 16 + g;
            const int c  = h * 64 + nt * 8 + t2;
            __half2 hp;
            hp.x = __float2half_rn(acc[mt][nt][0]);
            hp.y = __float2half_rn(acc[mt][nt][1]);
            *(__half2*)(outh + ((size_t)b * NSEQ + r0) * NHD + c) = hp;
            hp.x = __float2half_rn(acc[mt][nt][2]);
            hp.y = __float2half_rn(acc[mt][nt][3]);
            *(__half2*)(outh + ((size_t)b * NSEQ + r0 + 8) * NHD + c) = hp;
        }
    }
}

// ---------------- host orchestration ----------------------------------------
extern "C" void kernel_launch(void* const* d_in, const int* in_sizes, int n_in,
                              void* d_out, int out_size)
{
    (void)in_sizes; (void)n_in;
    const float* x_in    = (const float*)d_in[0];
    const float* r_t     = (const float*)d_in[1];
    const float* bias_pf = (const float*)d_in[3];
    const float* ln1_g   = (const float*)d_in[4];
    const float* ln1_b   = (const float*)d_in[5];
    const float* Wqkv    = (const float*)d_in[6];
    const float* Wkr_t   = (const float*)d_in[7];
    const float* Wout    = (const float*)d_in[9];
    const float* bout    = (const float*)d_in[10];
    const float* ln2_g   = (const float*)d_in[11];
    const float* ln2_b   = (const float*)d_in[12];
    const float* W1      = (const float*)d_in[13];
    const float* b1      = (const float*)d_in[14];
    const float* W2      = (const float*)d_in[15];
    const float* b2      = (const float*)d_in[16];
    float* outp = (float*)d_out;

    static int attr_done = 0;
    if (!attr_done) {
        cudaFuncSetAttribute(mma2_kernel<1,0,3>, cudaFuncAttributeMaxDynamicSharedMemorySize, MMA2_SMEM);
        cudaFuncSetAttribute(mma2_kernel<0,0,2>, cudaFuncAttributeMaxDynamicSharedMemorySize, MMA2_SMEM);
        cudaFuncSetAttribute(mma2_kernel<2,1,2>, cudaFuncAttributeMaxDynamicSharedMemorySize, MMA2_SMEM);
        cudaFuncSetAttribute(acbd2_kernel,       cudaFuncAttributeMaxDynamicSharedMemorySize, MMA2_SMEM);
        cudaFuncSetAttribute(fused_sav_kernel,   cudaFuncAttributeMaxDynamicSharedMemorySize, SAV_SMEM);
        attr_done = 1;
    }

    float *gx, *gac, *gbd, *gbk, *gbr;
    __half *gxnh, *gxnl, *grth, *grtl, *gqkvh, *gqkvl, *gkrh, *gkrl;
    __half *gavh, *gffh, *gwth, *gwtl, *gvth, *gvtl;
    cudaGetSymbolAddress((void**)&gx,    g_x);
    cudaGetSymbolAddress((void**)&gac,   g_ac);
    cudaGetSymbolAddress((void**)&gbd,   g_bd);
    cudaGetSymbolAddress((void**)&gbk,   g_bk);
    cudaGetSymbolAddress((void**)&gbr,   g_br);
    cudaGetSymbolAddress((void**)&gxnh,  g_xnh);
    cudaGetSymbolAddress((void**)&gxnl,  g_xnl);
    cudaGetSymbolAddress((void**)&grth,  g_rth);
    cudaGetSymbolAddress((void**)&grtl,  g_rtl);
    cudaGetSymbolAddress((void**)&gqkvh, g_qkvh);
    cudaGetSymbolAddress((void**)&gqkvl, g_qkvl);
    cudaGetSymbolAddress((void**)&gkrh,  g_krh);
    cudaGetSymbolAddress((void**)&gkrl,  g_krl);
    cudaGetSymbolAddress((void**)&gavh,  g_avh);
    cudaGetSymbolAddress((void**)&gffh,  g_ffh);
    cudaGetSymbolAddress((void**)&gwth,  g_wth);
    cudaGetSymbolAddress((void**)&gwtl,  g_wtl);
    cudaGetSymbolAddress((void**)&gvth,  g_vth);
    cudaGetSymbolAddress((void**)&gvtl,  g_vtl);

    float* attn_out = outp + ((size_t)out_size - ATT_ELEMS);

    cudaMemcpyAsync(gx, x_in, X_ELEMS * sizeof(float), cudaMemcpyDeviceToDevice, 0);
    split_rt_kernel<<<X_ELEMS / 1024, 256>>>(r_t, grth, grtl);

    // one launch: transpose+split ALL weights for ALL 4 layers
    transpose_all_kernel<<<dim3(3328, 4), dim3(32, 8)>>>(
        Wqkv, Wkr_t, Wout, W1, W2, gwth, gwtl);

    const dim3 tb(32, 8);
    for (int l = 0; l < 4; ++l) {
        const size_t wb = (size_t)l * WT_TOTAL;

        ln_split_kernel<<<MROWS, 128>>>(gx, ln1_g + l * NDIM, ln1_b + l * NDIM, gxnh, gxnl);
        mma2_kernel<1,0,3><<<dim3(12, 64), 256, MMA2_SMEM>>>(
            gxnh, gxnl, gwth + wb + WQKVT, gwtl + wb + WQKVT,
            nullptr, gqkvh, gqkvl, nullptr, nullptr, MROWS, 1536, 512);
        mma2_kernel<1,0,3><<<dim3(4, 64), 256, MMA2_SMEM>>>(
            grth, grtl, gwth + wb + WKRT, gwtl + wb + WKRT,
            nullptr, gkrh, gkrl, nullptr, nullptr, MROWS, 512, 512);

        bias_terms_kernel<<<256, 256>>>(gqkvh, gqkvl, gkrh, gkrl, bias_pf, gbk, gbr);

        acbd2_kernel<<<dim3(8, 8, 128), 256, MMA2_SMEM>>>(
            gqkvh, gqkvl, gkrh, gkrl, gbk, gbr, gac, gbd);

        vt_kernel<<<dim3(32, 2, 64), tb>>>(gqkvh, gqkvl, gvth, gvtl);

        fused_sav_kernel<<<dim3(16, 8), 512, SAV_SMEM>>>(
            gac, gbd, gvth, gvtl, gavh, (l == 3) ? attn_out : nullptr);

        // x = av @ Wout + bout + x   (2-term: A = avh)
        mma2_kernel<0,0,2><<<dim3(4, 64), 256, MMA2_SMEM>>>(
            gavh, gavh, gwth + wb + WOUTT, gwtl + wb + WOUTT,
            gx, nullptr, nullptr, bout + l * NDIM, gx, MROWS, 512, 512);

        ln_split_kernel<<<MROWS, 128>>>(gx, ln2_g + l * NDIM, ln2_b + l * NDIM, gxnh, gxnl);
        // h = gelu(xn @ W1 + b1)    (2-term: A = xnh; output hi only)
        mma2_kernel<2,1,2><<<dim3(16, 64), 256, MMA2_SMEM>>>(
            gxnh, gxnh, gwth + wb + W1T, gwtl + wb + W1T,
            nullptr, gffh, nullptr, b1 + l * NFF, nullptr, MROWS, 2048, 512);
        float* xdst = (l == 3) ? outp : gx;
        // x = h @ W2 + b2 + x       (2-term: A = ffh)
        mma2_kernel<0,0,2><<<dim3(4, 64), 256, MMA2_SMEM>>>(
            gffh, gffh, gwth + wb + W2T, gwtl + wb + W2T,
            xdst, nullptr, nullptr, b2 + l * NDIM, gx, MROWS, 512, 2048);
    }
}

// round 9
// speedup vs baseline: 1.1942x; 1.0510x over previous
#include <cuda_runtime.h>
#include <cuda_fp16.h>
#include <math.h>
#include <stdint.h>

#define NSEQ   1024
#define NBATCH 8
#define NDIM   512
#define NHEADS 8
#define NDH    64
#define NHD    512
#define NFF    2048
#define MROWS  (NBATCH*NSEQ)
#define ATT_ELEMS ((size_t)NBATCH*NHEADS*NSEQ*NSEQ)
#define X_ELEMS   ((size_t)MROWS*NDIM)

// transposed weight offsets (elements, within one layer's block)
#define WQKVT 0
#define WKRT  786432
#define WOUTT 1048576
#define W1T   1310720
#define W2T   2359296
#define WT_TOTAL 3407872

// ---------------- scratch --------------------------------------------------
static __device__ float g_x [MROWS*NDIM];
static __device__ float g_ac[NBATCH*NHEADS*NSEQ*NSEQ];
static __device__ float g_bd[NBATCH*NHEADS*NSEQ*NSEQ];
static __device__ float g_bk[NBATCH*NHEADS*NSEQ];
static __device__ float g_br[NBATCH*NHEADS*NSEQ];
static __device__ __half g_xnh [MROWS*NDIM],  g_xnl [MROWS*NDIM];
static __device__ __half g_rth [MROWS*NDIM],  g_rtl [MROWS*NDIM];
static __device__ __half g_qkvh[MROWS*3*NHD], g_qkvl[MROWS*3*NHD];
static __device__ __half g_krh [MROWS*NHD],   g_krl [MROWS*NHD];
static __device__ __half g_avh [MROWS*NHD];
static __device__ __half g_ffh [MROWS*NFF];
static __device__ __half g_wth [4*WT_TOTAL],  g_wtl [4*WT_TOTAL];
static __device__ __half g_vth [NBATCH*NHEADS*NDH*NSEQ];
static __device__ __half g_vtl [NBATCH*NHEADS*NDH*NSEQ];

// ---------------- primitives ------------------------------------------------
__device__ __forceinline__ uint32_t smem_u32(const void* p) {
    uint32_t a;
    asm("{ .reg .u64 t; cvta.to.shared.u64 t, %1; cvt.u32.u64 %0, t; }"
        : "=r"(a) : "l"(p));
    return a;
}
__device__ __forceinline__ void cp16(uint32_t dst, const void* src) {
    asm volatile("cp.async.cg.shared.global [%0], [%1], 16;" :: "r"(dst), "l"(src));
}
#define CP_COMMIT() asm volatile("cp.async.commit_group;")
#define CP_WAIT(n)  asm volatile("cp.async.wait_group %0;" :: "n"(n))

__device__ __forceinline__ void mma_f16(float* d, const uint32_t* a, const uint32_t* b) {
    asm volatile(
        "mma.sync.aligned.m16n8k16.row.col.f32.f16.f16.f32 "
        "{%0,%1,%2,%3}, {%4,%5,%6,%7}, {%8,%9}, {%0,%1,%2,%3};"
        : "+f"(d[0]), "+f"(d[1]), "+f"(d[2]), "+f"(d[3])
        : "r"(a[0]), "r"(a[1]), "r"(a[2]), "r"(a[3]), "r"(b[0]), "r"(b[1]));
}
__device__ __forceinline__ void ldm_x4(uint32_t* r, uint32_t addr) {
    asm volatile("ldmatrix.sync.aligned.m8n8.x4.shared.b16 {%0,%1,%2,%3}, [%4];"
        : "=r"(r[0]), "=r"(r[1]), "=r"(r[2]), "=r"(r[3]) : "r"(addr));
}
__device__ __forceinline__ void ldm_x2(uint32_t* r, uint32_t addr) {
    asm volatile("ldmatrix.sync.aligned.m8n8.x2.shared.b16 {%0,%1}, [%2];"
        : "=r"(r[0]), "=r"(r[1]) : "r"(addr));
}
__device__ __forceinline__ float gelu_exact(float v) {
    return 0.5f * v * (1.0f + erff(v * 0.70710678118654752f));
}
__device__ __forceinline__ void split1(float v, __half& h, __half& l) {
    h = __float2half_rn(v);
    l = __float2half_rn(v - __half2float(h));
}

// ---------- merged weight transpose+split for ALL layers: one launch --------
__global__ __launch_bounds__(256) void transpose_all_kernel(
    const float* __restrict__ Wqkv, const float* __restrict__ Wkr,
    const float* __restrict__ Wout, const float* __restrict__ W1,
    const float* __restrict__ W2,
    __half* __restrict__ Wth, __half* __restrict__ Wtl)
{
    __shared__ float t[32][33];
    const int l = blockIdx.y;
    const int tt = blockIdx.x;
    const float* W; int K, N, off, tloc;
    if (tt < 768)       { W = Wqkv + (size_t)l * 786432;  K = 512;  N = 1536; off = WQKVT; tloc = tt; }
    else if (tt < 1024) { W = Wkr  + (size_t)l * 262144;  K = 512;  N = 512;  off = WKRT;  tloc = tt - 768; }
    else if (tt < 1280) { W = Wout + (size_t)l * 262144;  K = 512;  N = 512;  off = WOUTT; tloc = tt - 1024; }
    else if (tt < 2304) { W = W1   + (size_t)l * 1048576; K = 512;  N = 2048; off = W1T;   tloc = tt - 1280; }
    else                { W = W2   + (size_t)l * 1048576; K = 2048; N = 512;  off = W2T;   tloc = tt - 2304; }
    const int ntn = N >> 5;
    const int kt = tloc / ntn, nt = tloc % ntn;
    const int k0 = kt * 32, n0 = nt * 32;
    const int x = threadIdx.x, y = threadIdx.y;
    const size_t dst = (size_t)l * WT_TOTAL + off;
#pragma unroll
    for (int i = 0; i < 32; i += 8)
        t[y + i][x] = W[(size_t)(k0 + y + i) * N + n0 + x];
    __syncthreads();
#pragma unroll
    for (int i = 0; i < 32; i += 8) {
        float v = t[x][y + i];
        __half h, lo; split1(v, h, lo);
        Wth[dst + (size_t)(n0 + y + i) * K + k0 + x] = h;
        Wtl[dst + (size_t)(n0 + y + i) * K + k0 + x] = lo;
    }
}

// ---------------- r_t split -------------------------------------------------
__global__ __launch_bounds__(256) void split_rt_kernel(
    const float* __restrict__ src, __half* __restrict__ dh,
    __half* __restrict__ dl)
{
    const size_t i = ((size_t)blockIdx.x * 256 + threadIdx.x) * 4;
    float4 v = *(const float4*)(src + i);
    __half h, l;
    split1(v.x, h, l); dh[i]   = h; dl[i]   = l;
    split1(v.y, h, l); dh[i+1] = h; dl[i+1] = l;
    split1(v.z, h, l); dh[i+2] = h; dl[i+2] = l;
    split1(v.w, h, l); dh[i+3] = h; dl[i+3] = l;
}

// ---------------- LayerNorm + split ------------------------------------------
__global__ __launch_bounds__(128) void ln_split_kernel(
    const float* __restrict__ x, const float* __restrict__ g,
    const float* __restrict__ b, __half* __restrict__ yh,
    __half* __restrict__ yl)
{
    const int row = blockIdx.x;
    const int tid = threadIdx.x;
    const float* xr = x + (size_t)row * NDIM;

    float4 v = ((const float4*)xr)[tid];
    float s  = v.x + v.y + v.z + v.w;
    float sq = v.x*v.x + v.y*v.y + v.z*v.z + v.w*v.w;
#pragma unroll
    for (int o = 16; o > 0; o >>= 1) {
        s  += __shfl_xor_sync(0xffffffffu, s,  o);
        sq += __shfl_xor_sync(0xffffffffu, sq, o);
    }
    __shared__ float red[8];
    const int w = tid >> 5;
    if ((tid & 31) == 0) { red[w] = s; red[4 + w] = sq; }
    __syncthreads();
    const float st  = red[0] + red[1] + red[2] + red[3];
    const float sqt = red[4] + red[5] + red[6] + red[7];
    const float mu  = st * (1.0f / NDIM);
    const float var = sqt * (1.0f / NDIM) - mu * mu;
    const float inv = rsqrtf(var + 1e-5f);

    float4 gg = ((const float4*)g)[tid];
    float4 bb = ((const float4*)b)[tid];
    float o0 = (v.x - mu) * inv * gg.x + bb.x;
    float o1 = (v.y - mu) * inv * gg.y + bb.y;
    float o2 = (v.z - mu) * inv * gg.z + bb.z;
    float o3 = (v.w - mu) * inv * gg.w + bb.w;
    const size_t base = (size_t)row * NDIM + tid * 4;
    __half h, l;
    split1(o0, h, l); yh[base]   = h; yl[base]   = l;
    split1(o1, h, l); yh[base+1] = h; yl[base+1] = l;
    split1(o2, h, l); yh[base+2] = h; yl[base+2] = l;
    split1(o3, h, l); yh[base+3] = h; yl[base+3] = l;
}

// ====== dense fp16 mma GEMM, cp.async double-buffered ========================
// NTERM=3: A hi/lo + B hi/lo, terms hh+hl+lh (err ~2^-22)
// NTERM=2: A hi only + B hi/lo, terms hh+hl (err ~2^-12 rms)
// SPLIT: 0 = fp32 out (+bias,+res); 1 = half hi/lo out; 2 = half hi-only out.
#define LDS 40
#define ARR   (128*LDS)
#define STAGE (4*ARR)
#define MMA2_SMEM (2*STAGE*2)

template<int SPLIT, int ACT, int NTERM>
__global__ __launch_bounds__(256, 2) void mma2_kernel(
    const __half* __restrict__ Ah, const __half* __restrict__ Al,
    const __half* __restrict__ Bh, const __half* __restrict__ Bl,
    float* __restrict__ Cf, __half* __restrict__ Ch,
    __half* __restrict__ Cl,
    const float* __restrict__ bias, const float* __restrict__ res,
    int M, int N, int K)
{
    extern __shared__ char dsm[];
    const uint32_t sbase = smem_u32(dsm);
    const int tid = threadIdx.x, wid = tid >> 5, lane = tid & 31;
    const int wm = wid >> 2, wn = wid & 3;
    const int bm = blockIdx.y * 128, bn = blockIdx.x * 128;

    const int lrow = tid >> 2, lcc = (tid & 3) * 8;
    const int lrow2 = (tid + 256) >> 2, lcc2 = ((tid + 256) & 3) * 8;

#define MMA2_ISSUE(kt, s) do {                                                   \
        const uint32_t st_ = sbase + (uint32_t)(s) * (STAGE * 2);                \
        const int k0_ = (kt) * 32;                                               \
        cp16(st_ + (uint32_t)((lrow * LDS + lcc) * 2),                           \
             Ah + (size_t)(bm + lrow) * K + k0_ + lcc);                          \
        cp16(st_ + (uint32_t)((lrow2 * LDS + lcc2) * 2),                         \
             Ah + (size_t)(bm + lrow2) * K + k0_ + lcc2);                        \
        if (NTERM == 3) {                                                        \
            cp16(st_ + (uint32_t)(ARR * 2) + (uint32_t)((lrow * LDS + lcc) * 2), \
                 Al + (size_t)(bm + lrow) * K + k0_ + lcc);                      \
            cp16(st_ + (uint32_t)(ARR * 2) + (uint32_t)((lrow2 * LDS + lcc2) * 2),\
                 Al + (size_t)(bm + lrow2) * K + k0_ + lcc2);                    \
        }                                                                        \
        cp16(st_ + (uint32_t)(2 * ARR * 2) + (uint32_t)((lrow * LDS + lcc) * 2), \
             Bh + (size_t)(bn + lrow) * K + k0_ + lcc);                          \
        cp16(st_ + (uint32_t)(2 * ARR * 2) + (uint32_t)((lrow2 * LDS + lcc2) * 2),\
             Bh + (size_t)(bn + lrow2) * K + k0_ + lcc2);                        \
        cp16(st_ + (uint32_t)(3 * ARR * 2) + (uint32_t)((lrow * LDS + lcc) * 2), \
             Bl + (size_t)(bn + lrow) * K + k0_ + lcc);                          \
        cp16(st_ + (uint32_t)(3 * ARR * 2) + (uint32_t)((lrow2 * LDS + lcc2) * 2),\
             Bl + (size_t)(bn + lrow2) * K + k0_ + lcc2);                        \
    } while (0)

    const int l15 = lane & 15;
    const uint32_t aoff = (uint32_t)(((wm * 64 + l15) * LDS + ((lane >> 4) << 3)) * 2);
    const uint32_t boff = (uint32_t)(((wn * 32 + (l15 & 7)) * LDS + (((l15 >> 3) & 1) << 3)) * 2);

    float acc[4][4][4];
#pragma unroll
    for (int i = 0; i < 4; ++i)
#pragma unroll
        for (int j = 0; j < 4; ++j)
#pragma unroll
            for (int q = 0; q < 4; ++q) acc[i][j][q] = 0.0f;

    const int NKT = K >> 5;
    MMA2_ISSUE(0, 0);
    CP_COMMIT();

    for (int kt = 0; kt < NKT; ++kt) {
        if (kt + 1 < NKT) {
            MMA2_ISSUE(kt + 1, (kt + 1) & 1);
            CP_COMMIT();
            CP_WAIT(1);
        } else {
            CP_WAIT(0);
        }
        __syncthreads();

        const uint32_t st = sbase + (uint32_t)(kt & 1) * (STAGE * 2);
        const uint32_t aAh = st, aAl = st + ARR * 2;
        const uint32_t aBh = st + 2 * ARR * 2, aBl = st + 3 * ARR * 2;
#pragma unroll
        for (int kk = 0; kk < 32; kk += 16) {
            uint32_t bh[4][2], bl[4][2], a[4][4];
#pragma unroll
            for (int nt = 0; nt < 4; ++nt) {
                const uint32_t bo = boff + (uint32_t)((nt * 8 * LDS + kk) * 2);
                ldm_x2(bh[nt], aBh + bo);
                ldm_x2(bl[nt], aBl + bo);
            }
#pragma unroll
            for (int mt = 0; mt < 4; ++mt)
                ldm_x4(a[mt], aAh + aoff + (uint32_t)((mt * 16 * LDS + kk) * 2));
#pragma unroll
            for (int mt = 0; mt < 4; ++mt)
#pragma unroll
                for (int nt = 0; nt < 4; ++nt) {
                    mma_f16(acc[mt][nt], a[mt], bh[nt]);
                    mma_f16(acc[mt][nt], a[mt], bl[nt]);
                }
            if (NTERM == 3) {
#pragma unroll
                for (int mt = 0; mt < 4; ++mt)
                    ldm_x4(a[mt], aAl + aoff + (uint32_t)((mt * 16 * LDS + kk) * 2));
#pragma unroll
                for (int mt = 0; mt < 4; ++mt)
#pragma unroll
                    for (int nt = 0; nt < 4; ++nt)
                        mma_f16(acc[mt][nt], a[mt], bh[nt]);
            }
        }
        __syncthreads();
    }
#undef MMA2_ISSUE

    const int g = lane >> 2, t2 = (lane & 3) * 2;
#pragma unroll
    for (int mt = 0; mt < 4; ++mt) {
#pragma unroll
        for (int nt = 0; nt < 4; ++nt) {
            const int r0 = bm + wm * 64 + mt * 16 + g;
            const int r1 = r0 + 8;
            const int c  = bn + wn * 32 + nt * 8 + t2;
            float v0 = acc[mt][nt][0], v1 = acc[mt][nt][1];
            float v2 = acc[mt][nt][2], v3 = acc[mt][nt][3];
            if (bias) {
                const float b0 = bias[c], b1 = bias[c + 1];
                v0 += b0; v1 += b1; v2 += b0; v3 += b1;
            }
            if (ACT) {
                v0 = gelu_exact(v0); v1 = gelu_exact(v1);
                v2 = gelu_exact(v2); v3 = gelu_exact(v3);
            }
            if (SPLIT == 1) {
                __half h0, l0, h1, l1;
                split1(v0, h0, l0); split1(v1, h1, l1);
                __half2 hp; hp.x = h0; hp.y = h1;
                __half2 lp; lp.x = l0; lp.y = l1;
                *(__half2*)(Ch + (size_t)r0 * N + c) = hp;
                *(__half2*)(Cl + (size_t)r0 * N + c) = lp;
                split1(v2, h0, l0); split1(v3, h1, l1);
                hp.x = h0; hp.y = h1; lp.x = l0; lp.y = l1;
                *(__half2*)(Ch + (size_t)r1 * N + c) = hp;
                *(__half2*)(Cl + (size_t)r1 * N + c) = lp;
            } else if (SPLIT == 2) {
                __half2 hp;
                hp.x = __float2half_rn(v0); hp.y = __float2half_rn(v1);
                *(__half2*)(Ch + (size_t)r0 * N + c) = hp;
                hp.x = __float2half_rn(v2); hp.y = __float2half_rn(v3);
                *(__half2*)(Ch + (size_t)r1 * N + c) = hp;
            } else {
                if (res) {
                    const float2 q0 = *(const float2*)(res + (size_t)r0 * N + c);
                    const float2 q1 = *(const float2*)(res + (size_t)r1 * N + c);
                    v0 += q0.x; v1 += q0.y; v2 += q1.x; v3 += q1.y;
                }
                *(float2*)(Cf + (size_t)r0 * N + c) = make_float2(v0, v1);
                *(float2*)(Cf + (size_t)r1 * N + c) = make_float2(v2, v3);
            }
        }
    }
}

// ---------------- bias rank-1 terms ------------------------------------------
__global__ __launch_bounds__(256) void bias_terms_kernel(
    const __half* __restrict__ qkvh, const __half* __restrict__ qkvl,
    const __half* __restrict__ krh, const __half* __restrict__ krl,
    const float* __restrict__ bias_pf,
    float* __restrict__ bk, float* __restrict__ br)
{
    const int idx = blockIdx.x * 256 + threadIdx.x;
    const int bh = idx >> 10, j = idx & 1023;
    const int b = bh >> 3, h = bh & 7;
    const size_t kb = ((size_t)b * NSEQ + j) * 1536 + 512 + h * 64;
    const size_t rb = ((size_t)b * NSEQ + j) * 512 + h * 64;
    float sk = 0.0f, sr = 0.0f;
#pragma unroll 16
    for (int d = 0; d < 64; ++d) {
        const float bp = bias_pf[h * 64 + d];
        sk += bp * (__half2float(qkvh[kb + d]) + __half2float(qkvl[kb + d]));
        sr += bp * (__half2float(krh[rb + d]) + __half2float(krl[rb + d]));
    }
    bk[idx] = sk;
    br[idx] = sr;
}

// =========== acbd fp16 mma, 2-term (A=Q hi; B hi/lo) =========================
__global__ __launch_bounds__(256, 2) void acbd2_kernel(
    const __half* __restrict__ qkvh,
    const __half* __restrict__ krh, const __half* __restrict__ krl,
    const float* __restrict__ bk, const float* __restrict__ br,
    float* __restrict__ AC, float* __restrict__ BD)
{
    extern __shared__ char dsm[];
    const uint32_t sbase = smem_u32(dsm);
    const int tid = threadIdx.x, wid = tid >> 5, lane = tid & 31;
    const int wm = wid >> 2, wn = wid & 3;
    const int z = blockIdx.z, bh_idx = z & 63, isBD = z >> 6;
    const int b = bh_idx >> 3, h = bh_idx & 7;
    const int i0 = blockIdx.y * 128, j0 = blockIdx.x * 128;

    const __half* Ah = qkvh + ((size_t)b * NSEQ + i0) * 1536 + h * 64;
    const __half* Bh = isBD ? (krh + ((size_t)b * NSEQ + j0) * 512 + h * 64)
                            : (qkvh + ((size_t)b * NSEQ + j0) * 1536 + 512 + h * 64);
    const __half* Bl = isBD ? (krl + ((size_t)b * NSEQ + j0) * 512 + h * 64)
                            : nullptr;
    const int ldb = isBD ? 512 : 1536;
    // for AC (isBD=0), K-lo lives in qkvl at the same offset pattern; pass via Bl below
    float* Cbase = (isBD ? BD : AC) + (size_t)bh_idx * NSEQ * NSEQ;
    const float* bvec = (isBD ? br : bk) + (size_t)bh_idx * NSEQ;

    const int lrow = tid >> 2, lcc = (tid & 3) * 8;
    const int lrow2 = (tid + 256) >> 2, lcc2 = ((tid + 256) & 3) * 8;

#define ACBD_ISSUE(kt, s) do {                                                   \
        const uint32_t st_ = sbase + (uint32_t)(s) * (STAGE * 2);                \
        const int k0_ = (kt) * 32;                                               \
        cp16(st_ + (uint32_t)((lrow * LDS + lcc) * 2),                           \
             Ah + (size_t)lrow * 1536 + k0_ + lcc);                              \
        cp16(st_ + (uint32_t)((lrow2 * LDS + lcc2) * 2),                         \
             Ah + (size_t)lrow2 * 1536 + k0_ + lcc2);                            \
        cp16(st_ + (uint32_t)(2 * ARR * 2) + (uint32_t)((lrow * LDS + lcc) * 2), \
             Bh + (size_t)lrow * ldb + k0_ + lcc);                               \
        cp16(st_ + (uint32_t)(2 * ARR * 2) + (uint32_t)((lrow2 * LDS + lcc2) * 2),\
             Bh + (size_t)lrow2 * ldb + k0_ + lcc2);                             \
        cp16(st_ + (uint32_t)(3 * ARR * 2) + (uint32_t)((lrow * LDS + lcc) * 2), \
             Blp + (size_t)lrow * ldb + k0_ + lcc);                              \
        cp16(st_ + (uint32_t)(3 * ARR * 2) + (uint32_t)((lrow2 * LDS + lcc2) * 2),\
             Blp + (size_t)lrow2 * ldb + k0_ + lcc2);                            \
    } while (0)

    // Bl pointer: BD uses krl; AC uses qkvl's K slice (passed through bk arg trick is
    // ugly — compute directly here instead)
    const __half* Blp = Bl;
    // AC case: K-lo slice of qkvl
    extern __device__ __half g_qkvl[];
    if (!isBD)
        Blp = g_qkvl + ((size_t)b * NSEQ + j0) * 1536 + 512 + h * 64;

    const int l15 = lane & 15;
    const uint32_t aoff = (uint32_t)(((wm * 64 + l15) * LDS + ((lane >> 4) << 3)) * 2);
    const uint32_t boff = (uint32_t)(((wn * 32 + (l15 & 7)) * LDS + (((l15 >> 3) & 1) << 3)) * 2);

    float acc[4][4][4];
#pragma unroll
    for (int i = 0; i < 4; ++i)
#pragma unroll
        for (int j = 0; j < 4; ++j)
#pragma unroll
            for (int q = 0; q < 4; ++q) acc[i][j][q] = 0.0f;

    ACBD_ISSUE(0, 0);
    CP_COMMIT();
#pragma unroll
    for (int kt = 0; kt < 2; ++kt) {
        if (kt == 0) {
            ACBD_ISSUE(1, 1);
            CP_COMMIT();
            CP_WAIT(1);
        } else {
            CP_WAIT(0);
        }
        __syncthreads();
        const uint32_t st = sbase + (uint32_t)(kt & 1) * (STAGE * 2);
        const uint32_t aAh = st;
        const uint32_t aBh = st + 2 * ARR * 2, aBl = st + 3 * ARR * 2;
#pragma unroll
        for (int kk = 0; kk < 32; kk += 16) {
            uint32_t bh[4][2], bl[4][2], a[4][4];
#pragma unroll
            for (int nt = 0; nt < 4; ++nt) {
                const uint32_t bo = boff + (uint32_t)((nt * 8 * LDS + kk) * 2);
                ldm_x2(bh[nt], aBh + bo);
                ldm_x2(bl[nt], aBl + bo);
            }
#pragma unroll
            for (int mt = 0; mt < 4; ++mt)
                ldm_x4(a[mt], aAh + aoff + (uint32_t)((mt * 16 * LDS + kk) * 2));
#pragma unroll
            for (int mt = 0; mt < 4; ++mt)
#pragma unroll
                for (int nt = 0; nt < 4; ++nt) {
                    mma_f16(acc[mt][nt], a[mt], bh[nt]);
                    mma_f16(acc[mt][nt], a[mt], bl[nt]);
                }
        }
        __syncthreads();
    }
#undef ACBD_ISSUE

    const int g = lane >> 2, t2 = (lane & 3) * 2;
#pragma unroll
    for (int mt = 0; mt < 4; ++mt) {
#pragma unroll
        for (int nt = 0; nt < 4; ++nt) {
            const int r0 = i0 + wm * 64 + mt * 16 + g;
            const int c  = j0 + wn * 32 + nt * 8 + t2;
            const float b0 = bvec[c], b1 = bvec[c + 1];
            *(float2*)(Cbase + (size_t)r0 * NSEQ + c) =
                make_float2(acc[mt][nt][0] + b0, acc[mt][nt][1] + b1);
            *(float2*)(Cbase + (size_t)(r0 + 8) * NSEQ + c) =
                make_float2(acc[mt][nt][2] + b0, acc[mt][nt][3] + b1);
        }
    }
}

// ---------------- V transpose hi+lo ------------------------------------------
__global__ __launch_bounds__(256) void vt_kernel(
    const __half* __restrict__ qkvh, const __half* __restrict__ qkvl,
    __half* __restrict__ vth, __half* __restrict__ vtl)
{
    __shared__ __half th[32][33], tl[32][33];
    const int bh = blockIdx.z, b = bh >> 3, h = bh & 7;
    const int j0 = blockIdx.x * 32, d0 = blockIdx.y * 32;
    const int x = threadIdx.x, y = threadIdx.y;
#pragma unroll
    for (int i = 0; i < 32; i += 8) {
        const size_t src = ((size_t)b * NSEQ + j0 + y + i) * 1536 + 1024 + h * 64 + d0 + x;
        th[y + i][x] = qkvh[src];
        tl[y + i][x] = qkvl[src];
    }
    __syncthreads();
#pragma unroll
    for (int i = 0; i < 32; i += 8) {
        const size_t dst = ((size_t)bh * 64 + d0 + y + i) * NSEQ + j0 + x;
        vth[dst] = th[x][y + i];
        vtl[dst] = tl[x][y + i];
    }
}

// ======= FUSED shift+scale+softmax(heads) + attn@V (fp16 2-term) =============
#define SAV_ATT_H 0
#define SAV_V_H   40960
#define SAV_V_L   81920
#define SAV_SMEM  122880

__global__ __launch_bounds__(512, 1) void fused_sav_kernel(
    const float* __restrict__ AC, const float* __restrict__ BDp,
    const __half* __restrict__ vth, const __half* __restrict__ vtl,
    __half* __restrict__ outh, float* __restrict__ attnf)
{
    extern __shared__ char dsm[];
    const uint32_t sb = smem_u32(dsm);
    const int tid = threadIdx.x, wid = tid >> 5, lane = tid & 31;
    const int b = blockIdx.y;
    const int i0 = blockIdx.x * 64;
    const int bq = b * NHEADS;

    const int ibA = tid >> 4;
    const int jjA = (tid & 15) * 2;

    const int h = wid & 7, ihalf = wid >> 3;
    const int l15 = lane & 15;
    const uint32_t headOff = (uint32_t)(h * 64 * 40 * 2);
    const uint32_t aAH = sb + SAV_ATT_H + headOff;
    const uint32_t aVH = sb + SAV_V_H + headOff;
    const uint32_t aVL = sb + SAV_V_L + headOff;
    const uint32_t aoff = (uint32_t)(((ihalf * 32 + l15) * 40 + ((lane >> 4) << 3)) * 2);
    const uint32_t boff = (uint32_t)(((l15 & 7) * 40 + (((l15 >> 3) & 1) << 3)) * 2);

    float acc[2][8][4];
#pragma unroll
    for (int i = 0; i < 2; ++i)
#pragma unroll
        for (int j = 0; j < 8; ++j)
#pragma unroll
            for (int q = 0; q < 4; ++q) acc[i][j][q] = 0.0f;

    for (int kt = 0; kt < 32; ++kt) {
        const int j0 = kt * 32;
#pragma unroll
        for (int k = 0; k < 4; ++k) {
            const int idx = tid + k * 512;
            const int hv = idx >> 8;
            const int r = idx & 255;
            const int d = r >> 2, seg = r & 3;
            const uint32_t so = (uint32_t)((hv * 64 + d) * 80 + seg * 16);
            const size_t gsrc = (((size_t)(bq + hv) * 64 + d) << 10) + j0 + seg * 8;
            cp16(sb + SAV_V_H + so, vth + gsrc);
            cp16(sb + SAV_V_L + so, vtl + gsrc);
        }
        CP_COMMIT();

#pragma unroll
        for (int it = 0; it < 2; ++it) {
            const int i = ibA + it * 32;
            const int gi = i0 + i;
            float p0[8], p1[8];
#pragma unroll
            for (int e = 0; e < 2; ++e) {
                const int gj = j0 + jjA + e;
                const int g = (gi + 1) * NSEQ + gj;
                const int si = g / (NSEQ + 1);
                const int sj = g % (NSEQ + 1) - 1;
                float v[8];
                float mx = -1e30f;
#pragma unroll
                for (int hh = 0; hh < 8; ++hh) {
                    const size_t base = (size_t)(bq + hh) * NSEQ;
                    float d = AC[(base + gi) * NSEQ + gj];
                    if (sj >= 0) d += BDp[(base + si) * NSEQ + sj];
                    d *= 0.125f;
                    v[hh] = d;
                    mx = fmaxf(mx, d);
                }
                float s = 0.0f;
#pragma unroll
                for (int hh = 0; hh < 8; ++hh) { v[hh] = __expf(v[hh] - mx); s += v[hh]; }
                const float inv = 1.0f / s;
                float* pp = e ? p1 : p0;
#pragma unroll
                for (int hh = 0; hh < 8; ++hh) pp[hh] = v[hh] * inv;
            }
#pragma unroll
            for (int hh = 0; hh < 8; ++hh) {
                __half2 hp;
                hp.x = __float2half_rn(p0[hh]);
                hp.y = __float2half_rn(p1[hh]);
                const uint32_t so = (uint32_t)(((hh * 64 + i) * 40 + jjA) * 2);
                *(__half2*)(dsm + SAV_ATT_H + so) = hp;
                if (attnf) {
                    *(float2*)(attnf + ((size_t)(bq + hh) * NSEQ + gi) * NSEQ + j0 + jjA) =
                        make_float2(p0[hh], p1[hh]);
                }
            }
        }
        CP_WAIT(0);
        __syncthreads();

#pragma unroll
        for (int kk = 0; kk < 32; kk += 16) {
            uint32_t bhf[8][2], blf[8][2], ah[2][4];
#pragma unroll
            for (int nt = 0; nt < 8; ++nt) {
                const uint32_t bo = boff + (uint32_t)((nt * 8 * 40 + kk) * 2);
                ldm_x2(bhf[nt], aVH + bo);
                ldm_x2(blf[nt], aVL + bo);
            }
#pragma unroll
            for (int mt = 0; mt < 2; ++mt)
                ldm_x4(ah[mt], aAH + aoff + (uint32_t)((mt * 16 * 40 + kk) * 2));
#pragma unroll
            for (int mt = 0; mt < 2; ++mt)
#pragma unroll
                for (int nt = 0; nt < 8; ++nt) {
                    mma_f16(acc[mt][nt], ah[mt], bhf[nt]);
                    mma_f16(acc[mt][nt], ah[mt], blf[nt]);
                }
        }
        __syncthreads();
    }

    const int g = lane >> 2, t2 = (lane & 3) * 2;
#pragma unroll
    for (int mt = 0; mt < 2; ++mt) {
#pragma unroll
        for (int nt = 0; nt < 8; ++nt) {
            const int r0 = i0 + ihalf * 32 + mt * 16 + g;
            const int c  = h * 64 + nt * 8 + t2;
            __half2 hp;
            hp.x = __float2half_rn(acc[mt][nt][0]);
            hp.y = __float2half_rn(acc[mt][nt][1]);
            *(__half2*)(outh + ((size_t)b * NSEQ + r0) * NHD + c) = hp;
            hp.x = __float2half_rn(acc[mt][nt][2]);
            hp.y = __float2half_rn(acc[mt][nt][3]);
            *(__half2*)(outh + ((size_t)b * NSEQ + r0 + 8) * NHD + c) = hp;
        }
    }
}

// ---------------- host orchestration ----------------------------------------
extern "C" void kernel_launch(void* const* d_in, const int* in_sizes, int n_in,
                              void* d_out, int out_size)
{
    (void)in_sizes; (void)n_in;
    const float* x_in    = (const float*)d_in[0];
    const float* r_t     = (const float*)d_in[1];
    const float* bias_pf = (const float*)d_in[3];
    const float* ln1_g   = (const float*)d_in[4];
    const float* ln1_b   = (const float*)d_in[5];
    const float* Wqkv    = (const float*)d_in[6];
    const float* Wkr_t   = (const float*)d_in[7];
    const float* Wout    = (const float*)d_in[9];
    const float* bout    = (const float*)d_in[10];
    const float* ln2_g   = (const float*)d_in[11];
    const float* ln2_b   = (const float*)d_in[12];
    const float* W1      = (const float*)d_in[13];
    const float* b1      = (const float*)d_in[14];
    const float* W2      = (const float*)d_in[15];
    const float* b2      = (const float*)d_in[16];
    float* outp = (float*)d_out;

    static int attr_done = 0;
    if (!attr_done) {
        cudaFuncSetAttribute(mma2_kernel<1,0,3>, cudaFuncAttributeMaxDynamicSharedMemorySize, MMA2_SMEM);
        cudaFuncSetAttribute(mma2_kernel<1,0,2>, cudaFuncAttributeMaxDynamicSharedMemorySize, MMA2_SMEM);
        cudaFuncSetAttribute(mma2_kernel<0,0,2>, cudaFuncAttributeMaxDynamicSharedMemorySize, MMA2_SMEM);
        cudaFuncSetAttribute(mma2_kernel<2,1,2>, cudaFuncAttributeMaxDynamicSharedMemorySize, MMA2_SMEM);
        cudaFuncSetAttribute(acbd2_kernel,       cudaFuncAttributeMaxDynamicSharedMemorySize, MMA2_SMEM);
        cudaFuncSetAttribute(fused_sav_kernel,   cudaFuncAttributeMaxDynamicSharedMemorySize, SAV_SMEM);
        attr_done = 1;
    }

    float *gx, *gac, *gbd, *gbk, *gbr;
    __half *gxnh, *gxnl, *grth, *grtl, *gqkvh, *gqkvl, *gkrh, *gkrl;
    __half *gavh, *gffh, *gwth, *gwtl, *gvth, *gvtl;
    cudaGetSymbolAddress((void**)&gx,    g_x);
    cudaGetSymbolAddress((void**)&gac,   g_ac);
    cudaGetSymbolAddress((void**)&gbd,   g_bd);
    cudaGetSymbolAddress((void**)&gbk,   g_bk);
    cudaGetSymbolAddress((void**)&gbr,   g_br);
    cudaGetSymbolAddress((void**)&gxnh,  g_xnh);
    cudaGetSymbolAddress((void**)&gxnl,  g_xnl);
    cudaGetSymbolAddress((void**)&grth,  g_rth);
    cudaGetSymbolAddress((void**)&grtl,  g_rtl);
    cudaGetSymbolAddress((void**)&gqkvh, g_qkvh);
    cudaGetSymbolAddress((void**)&gqkvl, g_qkvl);
    cudaGetSymbolAddress((void**)&gkrh,  g_krh);
    cudaGetSymbolAddress((void**)&gkrl,  g_krl);
    cudaGetSymbolAddress((void**)&gavh,  g_avh);
    cudaGetSymbolAddress((void**)&gffh,  g_ffh);
    cudaGetSymbolAddress((void**)&gwth,  g_wth);
    cudaGetSymbolAddress((void**)&gwtl,  g_wtl);
    cudaGetSymbolAddress((void**)&gvth,  g_vth);
    cudaGetSymbolAddress((void**)&gvtl,  g_vtl);

    float* attn_out = outp + ((size_t)out_size - ATT_ELEMS);

    cudaMemcpyAsync(gx, x_in, X_ELEMS * sizeof(float), cudaMemcpyDeviceToDevice, 0);
    split_rt_kernel<<<X_ELEMS / 1024, 256>>>(r_t, grth, grtl);

    transpose_all_kernel<<<dim3(3328, 4), dim3(32, 8)>>>(
        Wqkv, Wkr_t, Wout, W1, W2, gwth, gwtl);

    const dim3 tb(32, 8);
    for (int l = 0; l < 4; ++l) {
        const size_t wb = (size_t)l * WT_TOTAL;

        ln_split_kernel<<<MROWS, 128>>>(gx, ln1_g + l * NDIM, ln1_b + l * NDIM, gxnh, gxnl);
        mma2_kernel<1,0,3><<<dim3(12, 64), 256, MMA2_SMEM>>>(
            gxnh, gxnl, gwth + wb + WQKVT, gwtl + wb + WQKVT,
            nullptr, gqkvh, gqkvl, nullptr, nullptr, MROWS, 1536, 512);
        // kr: 2-term (A = r_t hi only), hi/lo output
        mma2_kernel<1,0,2><<<dim3(4, 64), 256, MMA2_SMEM>>>(
            grth, grth, gwth + wb + WKRT, gwtl + wb + WKRT,
            nullptr, gkrh, gkrl, nullptr, nullptr, MROWS, 512, 512);

        bias_terms_kernel<<<256, 256>>>(gqkvh, gqkvl, gkrh, gkrl, bias_pf, gbk, gbr);

        // acbd: 2-term (A = Q hi; B hi/lo)
        acbd2_kernel<<<dim3(8, 8, 128), 256, MMA2_SMEM>>>(
            gqkvh, gkrh, gkrl, gbk, gbr, gac, gbd);

        vt_kernel<<<dim3(32, 2, 64), tb>>>(gqkvh, gqkvl, gvth, gvtl);

        fused_sav_kernel<<<dim3(16, 8), 512, SAV_SMEM>>>(
            gac, gbd, gvth, gvtl, gavh, (l == 3) ? attn_out : nullptr);

        mma2_kernel<0,0,2><<<dim3(4, 64), 256, MMA2_SMEM>>>(
            gavh, gavh, gwth + wb + WOUTT, gwtl + wb + WOUTT,
            gx, nullptr, nullptr, bout + l * NDIM, gx, MROWS, 512, 512);

        ln_split_kernel<<<MROWS, 128>>>(gx, ln2_g + l * NDIM, ln2_b + l * NDIM, gxnh, gxnl);
        mma2_kernel<2,1,2><<<dim3(16, 64), 256, MMA2_SMEM>>>(
            gxnh, gxnh, gwth + wb + W1T, gwtl + wb + W1T,
            nullptr, gffh, nullptr, b1 + l * NFF, nullptr, MROWS, 2048, 512);
        float* xdst = (l == 3) ? outp : gx;
        mma2_kernel<0,0,2><<<dim3(4, 64), 256, MMA2_SMEM>>>(
            gffh, gffh, gwth + wb + W2T, gwtl + wb + W2T,
            xdst, nullptr, nullptr, b2 + l * NDIM, gx, MROWS, 512, 2048);
    }
}

// round 10
// speedup vs baseline: 1.3018x; 1.0901x over previous
#include <cuda_runtime.h>
#include <cuda_fp16.h>
#include <math.h>
#include <stdint.h>

#define NSEQ   1024
#define NBATCH 8
#define NDIM   512
#define NHEADS 8
#define NDH    64
#define NHD    512
#define NFF    2048
#define MROWS  (NBATCH*NSEQ)
#define ATT_ELEMS ((size_t)NBATCH*NHEADS*NSEQ*NSEQ)
#define X_ELEMS   ((size_t)MROWS*NDIM)

// transposed weight offsets (elements, within one layer's block)
#define WQKVT 0
#define WKRT  786432
#define WOUTT 1048576
#define W1T   1310720
#define W2T   2359296
#define WT_TOTAL 3407872

// ---------------- scratch --------------------------------------------------
static __device__ float g_x [MROWS*NDIM];
static __device__ float g_ac[NBATCH*NHEADS*NSEQ*NSEQ];
static __device__ float g_bd[NBATCH*NHEADS*NSEQ*NSEQ];
static __device__ float g_bk[NBATCH*NHEADS*NSEQ];
static __device__ float g_br[NBATCH*NHEADS*NSEQ];
static __device__ __half g_xnh [MROWS*NDIM];
static __device__ __half g_rth [MROWS*NDIM];
static __device__ __half g_qkvh[MROWS*3*NHD], g_qkvl[MROWS*3*NHD];
static __device__ __half g_krh [MROWS*NHD],   g_krl [MROWS*NHD];
static __device__ __half g_avh [MROWS*NHD];
static __device__ __half g_ffh [MROWS*NFF];
static __device__ __half g_wth [4*WT_TOTAL],  g_wtl [4*WT_TOTAL];
static __device__ __half g_vth [NBATCH*NHEADS*NDH*NSEQ];

// ---------------- primitives ------------------------------------------------
__device__ __forceinline__ uint32_t smem_u32(const void* p) {
    uint32_t a;
    asm("{ .reg .u64 t; cvta.to.shared.u64 t, %1; cvt.u32.u64 %0, t; }"
        : "=r"(a) : "l"(p));
    return a;
}
__device__ __forceinline__ void cp16(uint32_t dst, const void* src) {
    asm volatile("cp.async.cg.shared.global [%0], [%1], 16;" :: "r"(dst), "l"(src));
}
#define CP_COMMIT() asm volatile("cp.async.commit_group;")
#define CP_WAIT(n)  asm volatile("cp.async.wait_group %0;" :: "n"(n))

__device__ __forceinline__ void mma_f16(float* d, const uint32_t* a, const uint32_t* b) {
    asm volatile(
        "mma.sync.aligned.m16n8k16.row.col.f32.f16.f16.f32 "
        "{%0,%1,%2,%3}, {%4,%5,%6,%7}, {%8,%9}, {%0,%1,%2,%3};"
        : "+f"(d[0]), "+f"(d[1]), "+f"(d[2]), "+f"(d[3])
        : "r"(a[0]), "r"(a[1]), "r"(a[2]), "r"(a[3]), "r"(b[0]), "r"(b[1]));
}
__device__ __forceinline__ void ldm_x4(uint32_t* r, uint32_t addr) {
    asm volatile("ldmatrix.sync.aligned.m8n8.x4.shared.b16 {%0,%1,%2,%3}, [%4];"
        : "=r"(r[0]), "=r"(r[1]), "=r"(r[2]), "=r"(r[3]) : "r"(addr));
}
__device__ __forceinline__ void ldm_x2(uint32_t* r, uint32_t addr) {
    asm volatile("ldmatrix.sync.aligned.m8n8.x2.shared.b16 {%0,%1}, [%2];"
        : "=r"(r[0]), "=r"(r[1]) : "r"(addr));
}
__device__ __forceinline__ float gelu_exact(float v) {
    return 0.5f * v * (1.0f + erff(v * 0.70710678118654752f));
}
__device__ __forceinline__ void split1(float v, __half& h, __half& l) {
    h = __float2half_rn(v);
    l = __float2half_rn(v - __half2float(h));
}

// ---------- merged weight transpose+split for ALL layers: one launch --------
__global__ __launch_bounds__(256) void transpose_all_kernel(
    const float* __restrict__ Wqkv, const float* __restrict__ Wkr,
    const float* __restrict__ Wout, const float* __restrict__ W1,
    const float* __restrict__ W2,
    __half* __restrict__ Wth, __half* __restrict__ Wtl)
{
    __shared__ float t[32][33];
    const int l = blockIdx.y;
    const int tt = blockIdx.x;
    const float* W; int K, N, off, tloc;
    if (tt < 768)       { W = Wqkv + (size_t)l * 786432;  K = 512;  N = 1536; off = WQKVT; tloc = tt; }
    else if (tt < 1024) { W = Wkr  + (size_t)l * 262144;  K = 512;  N = 512;  off = WKRT;  tloc = tt - 768; }
    else if (tt < 1280) { W = Wout + (size_t)l * 262144;  K = 512;  N = 512;  off = WOUTT; tloc = tt - 1024; }
    else if (tt < 2304) { W = W1   + (size_t)l * 1048576; K = 512;  N = 2048; off = W1T;   tloc = tt - 1280; }
    else                { W = W2   + (size_t)l * 1048576; K = 2048; N = 512;  off = W2T;   tloc = tt - 2304; }
    const int ntn = N >> 5;
    const int kt = tloc / ntn, nt = tloc % ntn;
    const int k0 = kt * 32, n0 = nt * 32;
    const int x = threadIdx.x, y = threadIdx.y;
    const size_t dst = (size_t)l * WT_TOTAL + off;
#pragma unroll
    for (int i = 0; i < 32; i += 8)
        t[y + i][x] = W[(size_t)(k0 + y + i) * N + n0 + x];
    __syncthreads();
#pragma unroll
    for (int i = 0; i < 32; i += 8) {
        float v = t[x][y + i];
        __half h, lo; split1(v, h, lo);
        Wth[dst + (size_t)(n0 + y + i) * K + k0 + x] = h;
        Wtl[dst + (size_t)(n0 + y + i) * K + k0 + x] = lo;
    }
}

// ---------------- r_t -> fp16 hi only ----------------------------------------
__global__ __launch_bounds__(256) void split_rt_kernel(
    const float* __restrict__ src, __half* __restrict__ dh)
{
    const size_t i = ((size_t)blockIdx.x * 256 + threadIdx.x) * 4;
    float4 v = *(const float4*)(src + i);
    __half2 a, b;
    a.x = __float2half_rn(v.x); a.y = __float2half_rn(v.y);
    b.x = __float2half_rn(v.z); b.y = __float2half_rn(v.w);
    *(__half2*)(dh + i) = a;
    *(__half2*)(dh + i + 2) = b;
}

// ---------------- LayerNorm -> fp16 hi only ----------------------------------
__global__ __launch_bounds__(128) void ln_half_kernel(
    const float* __restrict__ x, const float* __restrict__ g,
    const float* __restrict__ b, __half* __restrict__ yh)
{
    const int row = blockIdx.x;
    const int tid = threadIdx.x;
    const float* xr = x + (size_t)row * NDIM;

    float4 v = ((const float4*)xr)[tid];
    float s  = v.x + v.y + v.z + v.w;
    float sq = v.x*v.x + v.y*v.y + v.z*v.z + v.w*v.w;
#pragma unroll
    for (int o = 16; o > 0; o >>= 1) {
        s  += __shfl_xor_sync(0xffffffffu, s,  o);
        sq += __shfl_xor_sync(0xffffffffu, sq, o);
    }
    __shared__ float red[8];
    const int w = tid >> 5;
    if ((tid & 31) == 0) { red[w] = s; red[4 + w] = sq; }
    __syncthreads();
    const float st  = red[0] + red[1] + red[2] + red[3];
    const float sqt = red[4] + red[5] + red[6] + red[7];
    const float mu  = st * (1.0f / NDIM);
    const float var = sqt * (1.0f / NDIM) - mu * mu;
    const float inv = rsqrtf(var + 1e-5f);

    float4 gg = ((const float4*)g)[tid];
    float4 bb = ((const float4*)b)[tid];
    __half2 a, c;
    a.x = __float2half_rn((v.x - mu) * inv * gg.x + bb.x);
    a.y = __float2half_rn((v.y - mu) * inv * gg.y + bb.y);
    c.x = __float2half_rn((v.z - mu) * inv * gg.z + bb.z);
    c.y = __float2half_rn((v.w - mu) * inv * gg.w + bb.w);
    const size_t base = (size_t)row * NDIM + tid * 4;
    *(__half2*)(yh + base) = a;
    *(__half2*)(yh + base + 2) = c;
}

// ====== dense fp16 mma GEMM, cp.async double-buffered ========================
// NTERM=3: A hi/lo + B hi/lo (hh+hl+lh). NTERM=2: A hi + B hi/lo (hh+hl).
// SPLIT: 0 = fp32 out (+bias,+res); 1 = half hi/lo out; 2 = half hi-only out.
#define LDS 40
#define ARR   (128*LDS)
#define STAGE (4*ARR)
#define MMA2_SMEM (2*STAGE*2)

template<int SPLIT, int ACT, int NTERM>
__global__ __launch_bounds__(256, 2) void mma2_kernel(
    const __half* __restrict__ Ah, const __half* __restrict__ Al,
    const __half* __restrict__ Bh, const __half* __restrict__ Bl,
    float* __restrict__ Cf, __half* __restrict__ Ch,
    __half* __restrict__ Cl,
    const float* __restrict__ bias, const float* __restrict__ res,
    int M, int N, int K)
{
    extern __shared__ char dsm[];
    const uint32_t sbase = smem_u32(dsm);
    const int tid = threadIdx.x, wid = tid >> 5, lane = tid & 31;
    const int wm = wid >> 2, wn = wid & 3;
    const int bm = blockIdx.y * 128, bn = blockIdx.x * 128;

    const int lrow = tid >> 2, lcc = (tid & 3) * 8;
    const int lrow2 = (tid + 256) >> 2, lcc2 = ((tid + 256) & 3) * 8;

#define MMA2_ISSUE(kt, s) do {                                                   \
        const uint32_t st_ = sbase + (uint32_t)(s) * (STAGE * 2);                \
        const int k0_ = (kt) * 32;                                               \
        cp16(st_ + (uint32_t)((lrow * LDS + lcc) * 2),                           \
             Ah + (size_t)(bm + lrow) * K + k0_ + lcc);                          \
        cp16(st_ + (uint32_t)((lrow2 * LDS + lcc2) * 2),                         \
             Ah + (size_t)(bm + lrow2) * K + k0_ + lcc2);                        \
        if (NTERM == 3) {                                                        \
            cp16(st_ + (uint32_t)(ARR * 2) + (uint32_t)((lrow * LDS + lcc) * 2), \
                 Al + (size_t)(bm + lrow) * K + k0_ + lcc);                      \
            cp16(st_ + (uint32_t)(ARR * 2) + (uint32_t)((lrow2 * LDS + lcc2) * 2),\
                 Al + (size_t)(bm + lrow2) * K + k0_ + lcc2);                    \
        }                                                                        \
        cp16(st_ + (uint32_t)(2 * ARR * 2) + (uint32_t)((lrow * LDS + lcc) * 2), \
             Bh + (size_t)(bn + lrow) * K + k0_ + lcc);                          \
        cp16(st_ + (uint32_t)(2 * ARR * 2) + (uint32_t)((lrow2 * LDS + lcc2) * 2),\
             Bh + (size_t)(bn + lrow2) * K + k0_ + lcc2);                        \
        cp16(st_ + (uint32_t)(3 * ARR * 2) + (uint32_t)((lrow * LDS + lcc) * 2), \
             Bl + (size_t)(bn + lrow) * K + k0_ + lcc);                          \
        cp16(st_ + (uint32_t)(3 * ARR * 2) + (uint32_t)((lrow2 * LDS + lcc2) * 2),\
             Bl + (size_t)(bn + lrow2) * K + k0_ + lcc2);                        \
    } while (0)

    const int l15 = lane & 15;
    const uint32_t aoff = (uint32_t)(((wm * 64 + l15) * LDS + ((lane >> 4) << 3)) * 2);
    const uint32_t boff = (uint32_t)(((wn * 32 + (l15 & 7)) * LDS + (((l15 >> 3) & 1) << 3)) * 2);

    float acc[4][4][4];
#pragma unroll
    for (int i = 0; i < 4; ++i)
#pragma unroll
        for (int j = 0; j < 4; ++j)
#pragma unroll
            for (int q = 0; q < 4; ++q) acc[i][j][q] = 0.0f;

    const int NKT = K >> 5;
    MMA2_ISSUE(0, 0);
    CP_COMMIT();

    for (int kt = 0; kt < NKT; ++kt) {
        if (kt + 1 < NKT) {
            MMA2_ISSUE(kt + 1, (kt + 1) & 1);
            CP_COMMIT();
            CP_WAIT(1);
        } else {
            CP_WAIT(0);
        }
        __syncthreads();

        const uint32_t st = sbase + (uint32_t)(kt & 1) * (STAGE * 2);
        const uint32_t aAh = st, aAl = st + ARR * 2;
        const uint32_t aBh = st + 2 * ARR * 2, aBl = st + 3 * ARR * 2;
#pragma unroll
        for (int kk = 0; kk < 32; kk += 16) {
            uint32_t bh[4][2], bl[4][2], a[4][4];
#pragma unroll
            for (int nt = 0; nt < 4; ++nt) {
                const uint32_t bo = boff + (uint32_t)((nt * 8 * LDS + kk) * 2);
                ldm_x2(bh[nt], aBh + bo);
                ldm_x2(bl[nt], aBl + bo);
            }
#pragma unroll
            for (int mt = 0; mt < 4; ++mt)
                ldm_x4(a[mt], aAh + aoff + (uint32_t)((mt * 16 * LDS + kk) * 2));
#pragma unroll
            for (int mt = 0; mt < 4; ++mt)
#pragma unroll
                for (int nt = 0; nt < 4; ++nt) {
                    mma_f16(acc[mt][nt], a[mt], bh[nt]);
                    mma_f16(acc[mt][nt], a[mt], bl[nt]);
                }
            if (NTERM == 3) {
#pragma unroll
                for (int mt = 0; mt < 4; ++mt)
                    ldm_x4(a[mt], aAl + aoff + (uint32_t)((mt * 16 * LDS + kk) * 2));
#pragma unroll
                for (int mt = 0; mt < 4; ++mt)
#pragma unroll
                    for (int nt = 0; nt < 4; ++nt)
                        mma_f16(acc[mt][nt], a[mt], bh[nt]);
            }
        }
        __syncthreads();
    }
#undef MMA2_ISSUE

    const int g = lane >> 2, t2 = (lane & 3) * 2;
#pragma unroll
    for (int mt = 0; mt < 4; ++mt) {
#pragma unroll
        for (int nt = 0; nt < 4; ++nt) {
            const int r0 = bm + wm * 64 + mt * 16 + g;
            const int r1 = r0 + 8;
            const int c  = bn + wn * 32 + nt * 8 + t2;
            float v0 = acc[mt][nt][0], v1 = acc[mt][nt][1];
            float v2 = acc[mt][nt][2], v3 = acc[mt][nt][3];
            if (bias) {
                const float b0 = bias[c], b1 = bias[c + 1];
                v0 += b0; v1 += b1; v2 += b0; v3 += b1;
            }
            if (ACT) {
                v0 = gelu_exact(v0); v1 = gelu_exact(v1);
                v2 = gelu_exact(v2); v3 = gelu_exact(v3);
            }
            if (SPLIT == 1) {
                __half h0, l0, h1, l1;
                split1(v0, h0, l0); split1(v1, h1, l1);
                __half2 hp; hp.x = h0; hp.y = h1;
                __half2 lp; lp.x = l0; lp.y = l1;
                *(__half2*)(Ch + (size_t)r0 * N + c) = hp;
                *(__half2*)(Cl + (size_t)r0 * N + c) = lp;
                split1(v2, h0, l0); split1(v3, h1, l1);
                hp.x = h0; hp.y = h1; lp.x = l0; lp.y = l1;
                *(__half2*)(Ch + (size_t)r1 * N + c) = hp;
                *(__half2*)(Cl + (size_t)r1 * N + c) = lp;
            } else if (SPLIT == 2) {
                __half2 hp;
                hp.x = __float2half_rn(v0); hp.y = __float2half_rn(v1);
                *(__half2*)(Ch + (size_t)r0 * N + c) = hp;
                hp.x = __float2half_rn(v2); hp.y = __float2half_rn(v3);
                *(__half2*)(Ch + (size_t)r1 * N + c) = hp;
            } else {
                if (res) {
                    const float2 q0 = *(const float2*)(res + (size_t)r0 * N + c);
                    const float2 q1 = *(const float2*)(res + (size_t)r1 * N + c);
                    v0 += q0.x; v1 += q0.y; v2 += q1.x; v3 += q1.y;
                }
                *(float2*)(Cf + (size_t)r0 * N + c) = make_float2(v0, v1);
                *(float2*)(Cf + (size_t)r1 * N + c) = make_float2(v2, v3);
            }
        }
    }
}

// ---------------- bias rank-1 terms ------------------------------------------
__global__ __launch_bounds__(256) void bias_terms_kernel(
    const __half* __restrict__ qkvh, const __half* __restrict__ qkvl,
    const __half* __restrict__ krh, const __half* __restrict__ krl,
    const float* __restrict__ bias_pf,
    float* __restrict__ bk, float* __restrict__ br)
{
    const int idx = blockIdx.x * 256 + threadIdx.x;
    const int bh = idx >> 10, j = idx & 1023;
    const int b = bh >> 3, h = bh & 7;
    const size_t kb = ((size_t)b * NSEQ + j) * 1536 + 512 + h * 64;
    const size_t rb = ((size_t)b * NSEQ + j) * 512 + h * 64;
    float sk = 0.0f, sr = 0.0f;
#pragma unroll 16
    for (int d = 0; d < 64; ++d) {
        const float bp = bias_pf[h * 64 + d];
        sk += bp * (__half2float(qkvh[kb + d]) + __half2float(qkvl[kb + d]));
        sr += bp * (__half2float(krh[rb + d]) + __half2float(krl[rb + d]));
    }
    bk[idx] = sk;
    br[idx] = sr;
}

// =========== acbd fp16 mma, 2-term (A=Q hi; B hi/lo) =========================
__global__ __launch_bounds__(256, 2) void acbd2_kernel(
    const __half* __restrict__ qkvh, const __half* __restrict__ qkvl,
    const __half* __restrict__ krh, const __half* __restrict__ krl,
    const float* __restrict__ bk, const float* __restrict__ br,
    float* __restrict__ AC, float* __restrict__ BD)
{
    extern __shared__ char dsm[];
    const uint32_t sbase = smem_u32(dsm);
    const int tid = threadIdx.x, wid = tid >> 5, lane = tid & 31;
    const int wm = wid >> 2, wn = wid & 3;
    const int z = blockIdx.z, bh_idx = z & 63, isBD = z >> 6;
    const int b = bh_idx >> 3, h = bh_idx & 7;
    const int i0 = blockIdx.y * 128, j0 = blockIdx.x * 128;

    const __half* Ah = qkvh + ((size_t)b * NSEQ + i0) * 1536 + h * 64;
    const __half* Bh = isBD ? (krh + ((size_t)b * NSEQ + j0) * 512 + h * 64)
                            : (qkvh + ((size_t)b * NSEQ + j0) * 1536 + 512 + h * 64);
    const __half* Blp = isBD ? (krl + ((size_t)b * NSEQ + j0) * 512 + h * 64)
                             : (qkvl + ((size_t)b * NSEQ + j0) * 1536 + 512 + h * 64);
    const int ldb = isBD ? 512 : 1536;
    float* Cbase = (isBD ? BD : AC) + (size_t)bh_idx * NSEQ * NSEQ;
    const float* bvec = (isBD ? br : bk) + (size_t)bh_idx * NSEQ;

    const int lrow = tid >> 2, lcc = (tid & 3) * 8;
    const int lrow2 = (tid + 256) >> 2, lcc2 = ((tid + 256) & 3) * 8;

#define ACBD_ISSUE(kt, s) do {                                                   \
        const uint32_t st_ = sbase + (uint32_t)(s) * (STAGE * 2);                \
        const int k0_ = (kt) * 32;                                               \
        cp16(st_ + (uint32_t)((lrow * LDS + lcc) * 2),                           \
             Ah + (size_t)lrow * 1536 + k0_ + lcc);                              \
        cp16(st_ + (uint32_t)((lrow2 * LDS + lcc2) * 2),                         \
             Ah + (size_t)lrow2 * 1536 + k0_ + lcc2);                            \
        cp16(st_ + (uint32_t)(2 * ARR * 2) + (uint32_t)((lrow * LDS + lcc) * 2), \
             Bh + (size_t)lrow * ldb + k0_ + lcc);                               \
        cp16(st_ + (uint32_t)(2 * ARR * 2) + (uint32_t)((lrow2 * LDS + lcc2) * 2),\
             Bh + (size_t)lrow2 * ldb + k0_ + lcc2);                             \
        cp16(st_ + (uint32_t)(3 * ARR * 2) + (uint32_t)((lrow * LDS + lcc) * 2), \
             Blp + (size_t)lrow * ldb + k0_ + lcc);                              \
        cp16(st_ + (uint32_t)(3 * ARR * 2) + (uint32_t)((lrow2 * LDS + lcc2) * 2),\
             Blp + (size_t)lrow2 * ldb + k0_ + lcc2);                            \
    } while (0)

    const int l15 = lane & 15;
    const uint32_t aoff = (uint32_t)(((wm * 64 + l15) * LDS + ((lane >> 4) << 3)) * 2);
    const uint32_t boff = (uint32_t)(((wn * 32 + (l15 & 7)) * LDS + (((l15 >> 3) & 1) << 3)) * 2);

    float acc[4][4][4];
#pragma unroll
    for (int i = 0; i < 4; ++i)
#pragma unroll
        for (int j = 0; j < 4; ++j)
#pragma unroll
            for (int q = 0; q < 4; ++q) acc[i][j][q] = 0.0f;

    ACBD_ISSUE(0, 0);
    CP_COMMIT();
#pragma unroll
    for (int kt = 0; kt < 2; ++kt) {
        if (kt == 0) {
            ACBD_ISSUE(1, 1);
            CP_COMMIT();
            CP_WAIT(1);
        } else {
            CP_WAIT(0);
        }
        __syncthreads();
        const uint32_t st = sbase + (uint32_t)(kt & 1) * (STAGE * 2);
        const uint32_t aAh = st;
        const uint32_t aBh = st + 2 * ARR * 2, aBl = st + 3 * ARR * 2;
#pragma unroll
        for (int kk = 0; kk < 32; kk += 16) {
            uint32_t bh[4][2], bl[4][2], a[4][4];
#pragma unroll
            for (int nt = 0; nt < 4; ++nt) {
                const uint32_t bo = boff + (uint32_t)((nt * 8 * LDS + kk) * 2);
                ldm_x2(bh[nt], aBh + bo);
                ldm_x2(bl[nt], aBl + bo);
            }
#pragma unroll
            for (int mt = 0; mt < 4; ++mt)
                ldm_x4(a[mt], aAh + aoff + (uint32_t)((mt * 16 * LDS + kk) * 2));
#pragma unroll
            for (int mt = 0; mt < 4; ++mt)
#pragma unroll
                for (int nt = 0; nt < 4; ++nt) {
                    mma_f16(acc[mt][nt], a[mt], bh[nt]);
                    mma_f16(acc[mt][nt], a[mt], bl[nt]);
                }
        }
        __syncthreads();
    }
#undef ACBD_ISSUE

    const int g = lane >> 2, t2 = (lane & 3) * 2;
#pragma unroll
    for (int mt = 0; mt < 4; ++mt) {
#pragma unroll
        for (int nt = 0; nt < 4; ++nt) {
            const int r0 = i0 + wm * 64 + mt * 16 + g;
            const int c  = j0 + wn * 32 + nt * 8 + t2;
            const float b0 = bvec[c], b1 = bvec[c + 1];
            *(float2*)(Cbase + (size_t)r0 * NSEQ + c) =
                make_float2(acc[mt][nt][0] + b0, acc[mt][nt][1] + b1);
            *(float2*)(Cbase + (size_t)(r0 + 8) * NSEQ + c) =
                make_float2(acc[mt][nt][2] + b0, acc[mt][nt][3] + b1);
        }
    }
}

// ---------------- V transpose (hi only) --------------------------------------
__global__ __launch_bounds__(256) void vt_kernel(
    const __half* __restrict__ qkvh, __half* __restrict__ vth)
{
    __shared__ __half th[32][33];
    const int bh = blockIdx.z, b = bh >> 3, h = bh & 7;
    const int j0 = blockIdx.x * 32, d0 = blockIdx.y * 32;
    const int x = threadIdx.x, y = threadIdx.y;
#pragma unroll
    for (int i = 0; i < 32; i += 8)
        th[y + i][x] = qkvh[((size_t)b * NSEQ + j0 + y + i) * 1536 + 1024 + h * 64 + d0 + x];
    __syncthreads();
#pragma unroll
    for (int i = 0; i < 32; i += 8)
        vth[((size_t)bh * 64 + d0 + y + i) * NSEQ + j0 + x] = th[x][y + i];
}

// ======= FUSED shift+scale+softmax(heads) + attn@V (fp16 1-term) =============
#define SAV_ATT_H 0
#define SAV_V_H   40960
#define SAV_SMEM  81920

__global__ __launch_bounds__(512, 1) void fused_sav_kernel(
    const float* __restrict__ AC, const float* __restrict__ BDp,
    const __half* __restrict__ vth,
    __half* __restrict__ outh, float* __restrict__ attnf)
{
    extern __shared__ char dsm[];
    const uint32_t sb = smem_u32(dsm);
    const int tid = threadIdx.x, wid = tid >> 5, lane = tid & 31;
    const int b = blockIdx.y;
    const int i0 = blockIdx.x * 64;
    const int bq = b * NHEADS;

    const int ibA = tid >> 4;
    const int jjA = (tid & 15) * 2;

    const int h = wid & 7, ihalf = wid >> 3;
    const int l15 = lane & 15;
    const uint32_t headOff = (uint32_t)(h * 64 * 40 * 2);
    const uint32_t aAH = sb + SAV_ATT_H + headOff;
    const uint32_t aVH = sb + SAV_V_H + headOff;
    const uint32_t aoff = (uint32_t)(((ihalf * 32 + l15) * 40 + ((lane >> 4) << 3)) * 2);
    const uint32_t boff = (uint32_t)(((l15 & 7) * 40 + (((l15 >> 3) & 1) << 3)) * 2);

    float acc[2][8][4];
#pragma unroll
    for (int i = 0; i < 2; ++i)
#pragma unroll
        for (int j = 0; j < 8; ++j)
#pragma unroll
            for (int q = 0; q < 4; ++q) acc[i][j][q] = 0.0f;

    for (int kt = 0; kt < 32; ++kt) {
        const int j0 = kt * 32;
#pragma unroll
        for (int k = 0; k < 4; ++k) {
            const int idx = tid + k * 512;
            const int hv = idx >> 8;
            const int r = idx & 255;
            const int d = r >> 2, seg = r & 3;
            const uint32_t so = (uint32_t)((hv * 64 + d) * 80 + seg * 16);
            const size_t gsrc = (((size_t)(bq + hv) * 64 + d) << 10) + j0 + seg * 8;
            cp16(sb + SAV_V_H + so, vth + gsrc);
        }
        CP_COMMIT();

#pragma unroll
        for (int it = 0; it < 2; ++it) {
            const int i = ibA + it * 32;
            const int gi = i0 + i;
            float p0[8], p1[8];
#pragma unroll
            for (int e = 0; e < 2; ++e) {
                const int gj = j0 + jjA + e;
                const int g = (gi + 1) * NSEQ + gj;
                const int si = g / (NSEQ + 1);
                const int sj = g % (NSEQ + 1) - 1;
                float v[8];
                float mx = -1e30f;
#pragma unroll
                for (int hh = 0; hh < 8; ++hh) {
                    const size_t base = (size_t)(bq + hh) * NSEQ;
                    float d = AC[(base + gi) * NSEQ + gj];
                    if (sj >= 0) d += BDp[(base + si) * NSEQ + sj];
                    d *= 0.125f;
                    v[hh] = d;
                    mx = fmaxf(mx, d);
                }
                float s = 0.0f;
#pragma unroll
                for (int hh = 0; hh < 8; ++hh) { v[hh] = __expf(v[hh] - mx); s += v[hh]; }
                const float inv = 1.0f / s;
                float* pp = e ? p1 : p0;
#pragma unroll
                for (int hh = 0; hh < 8; ++hh) pp[hh] = v[hh] * inv;
            }
#pragma unroll
            for (int hh = 0; hh < 8; ++hh) {
                __half2 hp;
                hp.x = __float2half_rn(p0[hh]);
                hp.y = __float2half_rn(p1[hh]);
                const uint32_t so = (uint32_t)(((hh * 64 + i) * 40 + jjA) * 2);
                *(__half2*)(dsm + SAV_ATT_H + so) = hp;
                if (attnf) {
                    *(float2*)(attnf + ((size_t)(bq + hh) * NSEQ + gi) * NSEQ + j0 + jjA) =
                        make_float2(p0[hh], p1[hh]);
                }
            }
        }
        CP_WAIT(0);
        __syncthreads();

#pragma unroll
        for (int kk = 0; kk < 32; kk += 16) {
            uint32_t bhf[8][2], ah[2][4];
#pragma unroll
            for (int nt = 0; nt < 8; ++nt)
                ldm_x2(bhf[nt], aVH + boff + (uint32_t)((nt * 8 * 40 + kk) * 2));
#pragma unroll
            for (int mt = 0; mt < 2; ++mt)
                ldm_x4(ah[mt], aAH + aoff + (uint32_t)((mt * 16 * 40 + kk) * 2));
#pragma unroll
            for (int mt = 0; mt < 2; ++mt)
#pragma unroll
                for (int nt = 0; nt < 8; ++nt)
                    mma_f16(acc[mt][nt], ah[mt], bhf[nt]);
        }
        __syncthreads();
    }

    const int g = lane >> 2, t2 = (lane & 3) * 2;
#pragma unroll
    for (int mt = 0; mt < 2; ++mt) {
#pragma unroll
        for (int nt = 0; nt < 8; ++nt) {
            const int r0 = i0 + ihalf * 32 + mt * 16 + g;
            const int c  = h * 64 + nt * 8 + t2;
            __half2 hp;
            hp.x = __float2half_rn(acc[mt][nt][0]);
            hp.y = __float2half_rn(acc[mt][nt][1]);
            *(__half2*)(outh + ((size_t)b * NSEQ + r0) * NHD + c) = hp;
            hp.x = __float2half_rn(acc[mt][nt][2]);
            hp.y = __float2half_rn(acc[mt][nt][3]);
            *(__half2*)(outh + ((size_t)b * NSEQ + r0 + 8) * NHD + c) = hp;
        }
    }
}

// ---------------- host orchestration ----------------------------------------
extern "C" void kernel_launch(void* const* d_in, const int* in_sizes, int n_in,
                              void* d_out, int out_size)
{
    (void)in_sizes; (void)n_in;
    const float* x_in    = (const float*)d_in[0];
    const float* r_t     = (const float*)d_in[1];
    const float* bias_pf = (const float*)d_in[3];
    const float* ln1_g   = (const float*)d_in[4];
    const float* ln1_b   = (const float*)d_in[5];
    const float* Wqkv    = (const float*)d_in[6];
    const float* Wkr_t   = (const float*)d_in[7];
    const float* Wout    = (const float*)d_in[9];
    const float* bout    = (const float*)d_in[10];
    const float* ln2_g   = (const float*)d_in[11];
    const float* ln2_b   = (const float*)d_in[12];
    const float* W1      = (const float*)d_in[13];
    const float* b1      = (const float*)d_in[14];
    const float* W2      = (const float*)d_in[15];
    const float* b2      = (const float*)d_in[16];
    float* outp = (float*)d_out;

    static int attr_done = 0;
    if (!attr_done) {
        cudaFuncSetAttribute(mma2_kernel<1,0,2>, cudaFuncAttributeMaxDynamicSharedMemorySize, MMA2_SMEM);
        cudaFuncSetAttribute(mma2_kernel<0,0,2>, cudaFuncAttributeMaxDynamicSharedMemorySize, MMA2_SMEM);
        cudaFuncSetAttribute(mma2_kernel<2,1,2>, cudaFuncAttributeMaxDynamicSharedMemorySize, MMA2_SMEM);
        cudaFuncSetAttribute(acbd2_kernel,       cudaFuncAttributeMaxDynamicSharedMemorySize, MMA2_SMEM);
        cudaFuncSetAttribute(fused_sav_kernel,   cudaFuncAttributeMaxDynamicSharedMemorySize, SAV_SMEM);
        attr_done = 1;
    }

    float *gx, *gac, *gbd, *gbk, *gbr;
    __half *gxnh, *grth, *gqkvh, *gqkvl, *gkrh, *gkrl;
    __half *gavh, *gffh, *gwth, *gwtl, *gvth;
    cudaGetSymbolAddress((void**)&gx,    g_x);
    cudaGetSymbolAddress((void**)&gac,   g_ac);
    cudaGetSymbolAddress((void**)&gbd,   g_bd);
    cudaGetSymbolAddress((void**)&gbk,   g_bk);
    cudaGetSymbolAddress((void**)&gbr,   g_br);
    cudaGetSymbolAddress((void**)&gxnh,  g_xnh);
    cudaGetSymbolAddress((void**)&grth,  g_rth);
    cudaGetSymbolAddress((void**)&gqkvh, g_qkvh);
    cudaGetSymbolAddress((void**)&gqkvl, g_qkvl);
    cudaGetSymbolAddress((void**)&gkrh,  g_krh);
    cudaGetSymbolAddress((void**)&gkrl,  g_krl);
    cudaGetSymbolAddress((void**)&gavh,  g_avh);
    cudaGetSymbolAddress((void**)&gffh,  g_ffh);
    cudaGetSymbolAddress((void**)&gwth,  g_wth);
    cudaGetSymbolAddress((void**)&gwtl,  g_wtl);
    cudaGetSymbolAddress((void**)&gvth,  g_vth);

    float* attn_out = outp + ((size_t)out_size - ATT_ELEMS);

    cudaMemcpyAsync(gx, x_in, X_ELEMS * sizeof(float), cudaMemcpyDeviceToDevice, 0);
    split_rt_kernel<<<X_ELEMS / 1024, 256>>>(r_t, grth);

    transpose_all_kernel<<<dim3(3328, 4), dim3(32, 8)>>>(
        Wqkv, Wkr_t, Wout, W1, W2, gwth, gwtl);

    const dim3 tb(32, 8);
    for (int l = 0; l < 4; ++l) {
        const size_t wb = (size_t)l * WT_TOTAL;

        ln_half_kernel<<<MROWS, 128>>>(gx, ln1_g + l * NDIM, ln1_b + l * NDIM, gxnh);
        // qkv: 2-term (A = xn hi; B hi/lo), hi/lo output
        mma2_kernel<1,0,2><<<dim3(12, 64), 256, MMA2_SMEM>>>(
            gxnh, gxnh, gwth + wb + WQKVT, gwtl + wb + WQKVT,
            nullptr, gqkvh, gqkvl, nullptr, nullptr, MROWS, 1536, 512);
        // kr: 2-term, hi/lo output
        mma2_kernel<1,0,2><<<dim3(4, 64), 256, MMA2_SMEM>>>(
            grth, grth, gwth + wb + WKRT, gwtl + wb + WKRT,
            nullptr, gkrh, gkrl, nullptr, nullptr, MROWS, 512, 512);

        bias_terms_kernel<<<256, 256>>>(gqkvh, gqkvl, gkrh, gkrl, bias_pf, gbk, gbr);

        acbd2_kernel<<<dim3(8, 8, 128), 256, MMA2_SMEM>>>(
            gqkvh, gqkvl, gkrh, gkrl, gbk, gbr, gac, gbd);

        vt_kernel<<<dim3(32, 2, 64), tb>>>(gqkvh, gvth);

        fused_sav_kernel<<<dim3(16, 8), 512, SAV_SMEM>>>(
            gac, gbd, gvth, gavh, (l == 3) ? attn_out : nullptr);

        mma2_kernel<0,0,2><<<dim3(4, 64), 256, MMA2_SMEM>>>(
            gavh, gavh, gwth + wb + WOUTT, gwtl + wb + WOUTT,
            gx, nullptr, nullptr, bout + l * NDIM, gx, MROWS, 512, 512);

        ln_half_kernel<<<MROWS, 128>>>(gx, ln2_g + l * NDIM, ln2_b + l * NDIM, gxnh);
        mma2_kernel<2,1,2><<<dim3(16, 64), 256, MMA2_SMEM>>>(
            gxnh, gxnh, gwth + wb + W1T, gwtl + wb + W1T,
            nullptr, gffh, nullptr, b1 + l * NFF, nullptr, MROWS, 2048, 512);
        float* xdst = (l == 3) ? outp : gx;
        mma2_kernel<0,0,2><<<dim3(4, 64), 256, MMA2_SMEM>>>(
            gffh, gffh, gwth + wb + W2T, gwtl + wb + W2T,
            xdst, nullptr, nullptr, b2 + l * NDIM, gx, MROWS, 512, 2048);
    }
}

// round 11
// speedup vs baseline: 1.4532x; 1.1163x over previous
#include <cuda_runtime.h>
#include <cuda_fp16.h>
#include <math.h>
#include <stdint.h>

#define NSEQ   1024
#define NBATCH 8
#define NDIM   512
#define NHEADS 8
#define NDH    64
#define NHD    512
#define NFF    2048
#define MROWS  (NBATCH*NSEQ)
#define ATT_ELEMS ((size_t)NBATCH*NHEADS*NSEQ*NSEQ)
#define X_ELEMS   ((size_t)MROWS*NDIM)

// transposed weight offsets (elements, within one layer's block)
#define WQKVT 0
#define WKRT  786432
#define WOUTT 1048576
#define W1T   1310720
#define W2T   2359296
#define WT_TOTAL 3407872

// ---------------- scratch --------------------------------------------------
static __device__ float g_x [MROWS*NDIM];
static __device__ float g_ac[NBATCH*NHEADS*NSEQ*NSEQ];
static __device__ float g_bd[NBATCH*NHEADS*NSEQ*NSEQ];
static __device__ float g_bk[NBATCH*NHEADS*NSEQ];
static __device__ float g_br[NBATCH*NHEADS*NSEQ];
static __device__ __half g_xnh [MROWS*NDIM];
static __device__ __half g_rth [MROWS*NDIM];
static __device__ __half g_qkvh[MROWS*3*NHD], g_qkvl[MROWS*3*NHD];
static __device__ __half g_krh [MROWS*NHD],   g_krl [MROWS*NHD];
static __device__ __half g_avh [MROWS*NHD];
static __device__ __half g_ffh [MROWS*NFF];
static __device__ __half g_wth [4*WT_TOTAL],  g_wtl [4*WT_TOTAL];
static __device__ __half g_vth [NBATCH*NHEADS*NDH*NSEQ];

// ---------------- primitives ------------------------------------------------
__device__ __forceinline__ uint32_t smem_u32(const void* p) {
    uint32_t a;
    asm("{ .reg .u64 t; cvta.to.shared.u64 t, %1; cvt.u32.u64 %0, t; }"
        : "=r"(a) : "l"(p));
    return a;
}
__device__ __forceinline__ void cp16(uint32_t dst, const void* src) {
    asm volatile("cp.async.cg.shared.global [%0], [%1], 16;" :: "r"(dst), "l"(src));
}
#define CP_COMMIT() asm volatile("cp.async.commit_group;")
#define CP_WAIT(n)  asm volatile("cp.async.wait_group %0;" :: "n"(n))

__device__ __forceinline__ void mma_f16(float* d, const uint32_t* a, const uint32_t* b) {
    asm volatile(
        "mma.sync.aligned.m16n8k16.row.col.f32.f16.f16.f32 "
        "{%0,%1,%2,%3}, {%4,%5,%6,%7}, {%8,%9}, {%0,%1,%2,%3};"
        : "+f"(d[0]), "+f"(d[1]), "+f"(d[2]), "+f"(d[3])
        : "r"(a[0]), "r"(a[1]), "r"(a[2]), "r"(a[3]), "r"(b[0]), "r"(b[1]));
}
__device__ __forceinline__ void ldm_x4(uint32_t* r, uint32_t addr) {
    asm volatile("ldmatrix.sync.aligned.m8n8.x4.shared.b16 {%0,%1,%2,%3}, [%4];"
        : "=r"(r[0]), "=r"(r[1]), "=r"(r[2]), "=r"(r[3]) : "r"(addr));
}
__device__ __forceinline__ void ldm_x2(uint32_t* r, uint32_t addr) {
    asm volatile("ldmatrix.sync.aligned.m8n8.x2.shared.b16 {%0,%1}, [%2];"
        : "=r"(r[0]), "=r"(r[1]) : "r"(addr));
}
__device__ __forceinline__ float gelu_exact(float v) {
    return 0.5f * v * (1.0f + erff(v * 0.70710678118654752f));
}
__device__ __forceinline__ void split1(float v, __half& h, __half& l) {
    h = __float2half_rn(v);
    l = __float2half_rn(v - __half2float(h));
}

// ---------- merged weight transpose+split for ALL layers: one launch --------
__global__ __launch_bounds__(256) void transpose_all_kernel(
    const float* __restrict__ Wqkv, const float* __restrict__ Wkr,
    const float* __restrict__ Wout, const float* __restrict__ W1,
    const float* __restrict__ W2,
    __half* __restrict__ Wth, __half* __restrict__ Wtl)
{
    __shared__ float t[32][33];
    const int l = blockIdx.y;
    const int tt = blockIdx.x;
    const float* W; int K, N, off, tloc;
    if (tt < 768)       { W = Wqkv + (size_t)l * 786432;  K = 512;  N = 1536; off = WQKVT; tloc = tt; }
    else if (tt < 1024) { W = Wkr  + (size_t)l * 262144;  K = 512;  N = 512;  off = WKRT;  tloc = tt - 768; }
    else if (tt < 1280) { W = Wout + (size_t)l * 262144;  K = 512;  N = 512;  off = WOUTT; tloc = tt - 1024; }
    else if (tt < 2304) { W = W1   + (size_t)l * 1048576; K = 512;  N = 2048; off = W1T;   tloc = tt - 1280; }
    else                { W = W2   + (size_t)l * 1048576; K = 2048; N = 512;  off = W2T;   tloc = tt - 2304; }
    const int ntn = N >> 5;
    const int kt = tloc / ntn, nt = tloc % ntn;
    const int k0 = kt * 32, n0 = nt * 32;
    const int x = threadIdx.x, y = threadIdx.y;
    const size_t dst = (size_t)l * WT_TOTAL + off;
#pragma unroll
    for (int i = 0; i < 32; i += 8)
        t[y + i][x] = W[(size_t)(k0 + y + i) * N + n0 + x];
    __syncthreads();
#pragma unroll
    for (int i = 0; i < 32; i += 8) {
        float v = t[x][y + i];
        __half h, lo; split1(v, h, lo);
        Wth[dst + (size_t)(n0 + y + i) * K + k0 + x] = h;
        Wtl[dst + (size_t)(n0 + y + i) * K + k0 + x] = lo;
    }
}

// ---------------- r_t -> fp16 hi only ----------------------------------------
__global__ __launch_bounds__(256) void split_rt_kernel(
    const float* __restrict__ src, __half* __restrict__ dh)
{
    const size_t i = ((size_t)blockIdx.x * 256 + threadIdx.x) * 4;
    float4 v = *(const float4*)(src + i);
    __half2 a, b;
    a.x = __float2half_rn(v.x); a.y = __float2half_rn(v.y);
    b.x = __float2half_rn(v.z); b.y = __float2half_rn(v.w);
    *(__half2*)(dh + i) = a;
    *(__half2*)(dh + i + 2) = b;
}

// ---------------- LayerNorm -> fp16 hi only ----------------------------------
__global__ __launch_bounds__(128) void ln_half_kernel(
    const float* __restrict__ x, const float* __restrict__ g,
    const float* __restrict__ b, __half* __restrict__ yh)
{
    const int row = blockIdx.x;
    const int tid = threadIdx.x;
    const float* xr = x + (size_t)row * NDIM;

    float4 v = ((const float4*)xr)[tid];
    float s  = v.x + v.y + v.z + v.w;
    float sq = v.x*v.x + v.y*v.y + v.z*v.z + v.w*v.w;
#pragma unroll
    for (int o = 16; o > 0; o >>= 1) {
        s  += __shfl_xor_sync(0xffffffffu, s,  o);
        sq += __shfl_xor_sync(0xffffffffu, sq, o);
    }
    __shared__ float red[8];
    const int w = tid >> 5;
    if ((tid & 31) == 0) { red[w] = s; red[4 + w] = sq; }
    __syncthreads();
    const float st  = red[0] + red[1] + red[2] + red[3];
    const float sqt = red[4] + red[5] + red[6] + red[7];
    const float mu  = st * (1.0f / NDIM);
    const float var = sqt * (1.0f / NDIM) - mu * mu;
    const float inv = rsqrtf(var + 1e-5f);

    float4 gg = ((const float4*)g)[tid];
    float4 bb = ((const float4*)b)[tid];
    __half2 a, c;
    a.x = __float2half_rn((v.x - mu) * inv * gg.x + bb.x);
    a.y = __float2half_rn((v.y - mu) * inv * gg.y + bb.y);
    c.x = __float2half_rn((v.z - mu) * inv * gg.z + bb.z);
    c.y = __float2half_rn((v.w - mu) * inv * gg.w + bb.w);
    const size_t base = (size_t)row * NDIM + tid * 4;
    *(__half2*)(yh + base) = a;
    *(__half2*)(yh + base + 2) = c;
}

// ====== dense fp16 mma GEMM, cp.async double-buffered ========================
// NTERM=3: A hi/lo + B hi/lo (hh+hl+lh). NTERM=2: A hi + B hi/lo (hh+hl).
// NTERM=1: A hi + B hi (hh only).
// SPLIT: 0 = fp32 out (+bias,+res); 1 = half hi/lo out; 2 = half hi-only out.
#define LDS 40
#define ARR   (128*LDS)
#define STAGE (4*ARR)
#define MMA2_SMEM (2*STAGE*2)

template<int SPLIT, int ACT, int NTERM>
__global__ __launch_bounds__(256, 2) void mma2_kernel(
    const __half* __restrict__ Ah, const __half* __restrict__ Al,
    const __half* __restrict__ Bh, const __half* __restrict__ Bl,
    float* __restrict__ Cf, __half* __restrict__ Ch,
    __half* __restrict__ Cl,
    const float* __restrict__ bias, const float* __restrict__ res,
    int M, int N, int K)
{
    extern __shared__ char dsm[];
    const uint32_t sbase = smem_u32(dsm);
    const int tid = threadIdx.x, wid = tid >> 5, lane = tid & 31;
    const int wm = wid >> 2, wn = wid & 3;
    const int bm = blockIdx.y * 128, bn = blockIdx.x * 128;

    const int lrow = tid >> 2, lcc = (tid & 3) * 8;
    const int lrow2 = (tid + 256) >> 2, lcc2 = ((tid + 256) & 3) * 8;

#define MMA2_ISSUE(kt, s) do {                                                   \
        const uint32_t st_ = sbase + (uint32_t)(s) * (STAGE * 2);                \
        const int k0_ = (kt) * 32;                                               \
        cp16(st_ + (uint32_t)((lrow * LDS + lcc) * 2),                           \
             Ah + (size_t)(bm + lrow) * K + k0_ + lcc);                          \
        cp16(st_ + (uint32_t)((lrow2 * LDS + lcc2) * 2),                         \
             Ah + (size_t)(bm + lrow2) * K + k0_ + lcc2);                        \
        if (NTERM == 3) {                                                        \
            cp16(st_ + (uint32_t)(ARR * 2) + (uint32_t)((lrow * LDS + lcc) * 2), \
                 Al + (size_t)(bm + lrow) * K + k0_ + lcc);                      \
            cp16(st_ + (uint32_t)(ARR * 2) + (uint32_t)((lrow2 * LDS + lcc2) * 2),\
                 Al + (size_t)(bm + lrow2) * K + k0_ + lcc2);                    \
        }                                                                        \
        cp16(st_ + (uint32_t)(2 * ARR * 2) + (uint32_t)((lrow * LDS + lcc) * 2), \
             Bh + (size_t)(bn + lrow) * K + k0_ + lcc);                          \
        cp16(st_ + (uint32_t)(2 * ARR * 2) + (uint32_t)((lrow2 * LDS + lcc2) * 2),\
             Bh + (size_t)(bn + lrow2) * K + k0_ + lcc2);                        \
        if (NTERM >= 2) {                                                        \
            cp16(st_ + (uint32_t)(3 * ARR * 2) + (uint32_t)((lrow * LDS + lcc) * 2), \
                 Bl + (size_t)(bn + lrow) * K + k0_ + lcc);                      \
            cp16(st_ + (uint32_t)(3 * ARR * 2) + (uint32_t)((lrow2 * LDS + lcc2) * 2),\
                 Bl + (size_t)(bn + lrow2) * K + k0_ + lcc2);                    \
        }                                                                        \
    } while (0)

    const int l15 = lane & 15;
    const uint32_t aoff = (uint32_t)(((wm * 64 + l15) * LDS + ((lane >> 4) << 3)) * 2);
    const uint32_t boff = (uint32_t)(((wn * 32 + (l15 & 7)) * LDS + (((l15 >> 3) & 1) << 3)) * 2);

    float acc[4][4][4];
#pragma unroll
    for (int i = 0; i < 4; ++i)
#pragma unroll
        for (int j = 0; j < 4; ++j)
#pragma unroll
            for (int q = 0; q < 4; ++q) acc[i][j][q] = 0.0f;

    const int NKT = K >> 5;
    MMA2_ISSUE(0, 0);
    CP_COMMIT();

    for (int kt = 0; kt < NKT; ++kt) {
        if (kt + 1 < NKT) {
            MMA2_ISSUE(kt + 1, (kt + 1) & 1);
            CP_COMMIT();
            CP_WAIT(1);
        } else {
            CP_WAIT(0);
        }
        __syncthreads();

        const uint32_t st = sbase + (uint32_t)(kt & 1) * (STAGE * 2);
        const uint32_t aAh = st, aAl = st + ARR * 2;
        const uint32_t aBh = st + 2 * ARR * 2, aBl = st + 3 * ARR * 2;
#pragma unroll
        for (int kk = 0; kk < 32; kk += 16) {
            uint32_t bh[4][2], bl[4][2], a[4][4];
#pragma unroll
            for (int nt = 0; nt < 4; ++nt) {
                const uint32_t bo = boff + (uint32_t)((nt * 8 * LDS + kk) * 2);
                ldm_x2(bh[nt], aBh + bo);
                if (NTERM >= 2) ldm_x2(bl[nt], aBl + bo);
            }
#pragma unroll
            for (int mt = 0; mt < 4; ++mt)
                ldm_x4(a[mt], aAh + aoff + (uint32_t)((mt * 16 * LDS + kk) * 2));
#pragma unroll
            for (int mt = 0; mt < 4; ++mt)
#pragma unroll
                for (int nt = 0; nt < 4; ++nt) {
                    mma_f16(acc[mt][nt], a[mt], bh[nt]);
                    if (NTERM >= 2) mma_f16(acc[mt][nt], a[mt], bl[nt]);
                }
            if (NTERM == 3) {
#pragma unroll
                for (int mt = 0; mt < 4; ++mt)
                    ldm_x4(a[mt], aAl + aoff + (uint32_t)((mt * 16 * LDS + kk) * 2));
#pragma unroll
                for (int mt = 0; mt < 4; ++mt)
#pragma unroll
                    for (int nt = 0; nt < 4; ++nt)
                        mma_f16(acc[mt][nt], a[mt], bh[nt]);
            }
        }
        __syncthreads();
    }
#undef MMA2_ISSUE

    const int g = lane >> 2, t2 = (lane & 3) * 2;
#pragma unroll
    for (int mt = 0; mt < 4; ++mt) {
#pragma unroll
        for (int nt = 0; nt < 4; ++nt) {
            const int r0 = bm + wm * 64 + mt * 16 + g;
            const int r1 = r0 + 8;
            const int c  = bn + wn * 32 + nt * 8 + t2;
            float v0 = acc[mt][nt][0], v1 = acc[mt][nt][1];
            float v2 = acc[mt][nt][2], v3 = acc[mt][nt][3];
            if (bias) {
                const float b0 = bias[c], b1 = bias[c + 1];
                v0 += b0; v1 += b1; v2 += b0; v3 += b1;
            }
            if (ACT) {
                v0 = gelu_exact(v0); v1 = gelu_exact(v1);
                v2 = gelu_exact(v2); v3 = gelu_exact(v3);
            }
            if (SPLIT == 1) {
                __half h0, l0, h1, l1;
                split1(v0, h0, l0); split1(v1, h1, l1);
                __half2 hp; hp.x = h0; hp.y = h1;
                __half2 lp; lp.x = l0; lp.y = l1;
                *(__half2*)(Ch + (size_t)r0 * N + c) = hp;
                *(__half2*)(Cl + (size_t)r0 * N + c) = lp;
                split1(v2, h0, l0); split1(v3, h1, l1);
                hp.x = h0; hp.y = h1; lp.x = l0; lp.y = l1;
                *(__half2*)(Ch + (size_t)r1 * N + c) = hp;
                *(__half2*)(Cl + (size_t)r1 * N + c) = lp;
            } else if (SPLIT == 2) {
                __half2 hp;
                hp.x = __float2half_rn(v0); hp.y = __float2half_rn(v1);
                *(__half2*)(Ch + (size_t)r0 * N + c) = hp;
                hp.x = __float2half_rn(v2); hp.y = __float2half_rn(v3);
                *(__half2*)(Ch + (size_t)r1 * N + c) = hp;
            } else {
                if (res) {
                    const float2 q0 = *(const float2*)(res + (size_t)r0 * N + c);
                    const float2 q1 = *(const float2*)(res + (size_t)r1 * N + c);
                    v0 += q0.x; v1 += q0.y; v2 += q1.x; v3 += q1.y;
                }
                *(float2*)(Cf + (size_t)r0 * N + c) = make_float2(v0, v1);
                *(float2*)(Cf + (size_t)r1 * N + c) = make_float2(v2, v3);
            }
        }
    }
}

// ---------------- bias rank-1 terms ------------------------------------------
__global__ __launch_bounds__(256) void bias_terms_kernel(
    const __half* __restrict__ qkvh, const __half* __restrict__ qkvl,
    const __half* __restrict__ krh, const __half* __restrict__ krl,
    const float* __restrict__ bias_pf,
    float* __restrict__ bk, float* __restrict__ br)
{
    const int idx = blockIdx.x * 256 + threadIdx.x;
    const int bh = idx >> 10, j = idx & 1023;
    const int b = bh >> 3, h = bh & 7;
    const size_t kb = ((size_t)b * NSEQ + j) * 1536 + 512 + h * 64;
    const size_t rb = ((size_t)b * NSEQ + j) * 512 + h * 64;
    float sk = 0.0f, sr = 0.0f;
#pragma unroll 16
    for (int d = 0; d < 64; ++d) {
        const float bp = bias_pf[h * 64 + d];
        sk += bp * (__half2float(qkvh[kb + d]) + __half2float(qkvl[kb + d]));
        sr += bp * (__half2float(krh[rb + d]) + __half2float(krl[rb + d]));
    }
    bk[idx] = sk;
    br[idx] = sr;
}

// =========== acbd fp16 mma, 2-term (A=Q hi; B hi/lo) =========================
__global__ __launch_bounds__(256, 2) void acbd2_kernel(
    const __half* __restrict__ qkvh, const __half* __restrict__ qkvl,
    const __half* __restrict__ krh, const __half* __restrict__ krl,
    const float* __restrict__ bk, const float* __restrict__ br,
    float* __restrict__ AC, float* __restrict__ BD)
{
    extern __shared__ char dsm[];
    const uint32_t sbase = smem_u32(dsm);
    const int tid = threadIdx.x, wid = tid >> 5, lane = tid & 31;
    const int wm = wid >> 2, wn = wid & 3;
    const int z = blockIdx.z, bh_idx = z & 63, isBD = z >> 6;
    const int b = bh_idx >> 3, h = bh_idx & 7;
    const int i0 = blockIdx.y * 128, j0 = blockIdx.x * 128;

    const __half* Ah = qkvh + ((size_t)b * NSEQ + i0) * 1536 + h * 64;
    const __half* Bh = isBD ? (krh + ((size_t)b * NSEQ + j0) * 512 + h * 64)
                            : (qkvh + ((size_t)b * NSEQ + j0) * 1536 + 512 + h * 64);
    const __half* Blp = isBD ? (krl + ((size_t)b * NSEQ + j0) * 512 + h * 64)
                             : (qkvl + ((size_t)b * NSEQ + j0) * 1536 + 512 + h * 64);
    const int ldb = isBD ? 512 : 1536;
    float* Cbase = (isBD ? BD : AC) + (size_t)bh_idx * NSEQ * NSEQ;
    const float* bvec = (isBD ? br : bk) + (size_t)bh_idx * NSEQ;

    const int lrow = tid >> 2, lcc = (tid & 3) * 8;
    const int lrow2 = (tid + 256) >> 2, lcc2 = ((tid + 256) & 3) * 8;

#define ACBD_ISSUE(kt, s) do {                                                   \
        const uint32_t st_ = sbase + (uint32_t)(s) * (STAGE * 2);                \
        const int k0_ = (kt) * 32;                                               \
        cp16(st_ + (uint32_t)((lrow * LDS + lcc) * 2),                           \
             Ah + (size_t)lrow * 1536 + k0_ + lcc);                              \
        cp16(st_ + (uint32_t)((lrow2 * LDS + lcc2) * 2),                         \
             Ah + (size_t)lrow2 * 1536 + k0_ + lcc2);                            \
        cp16(st_ + (uint32_t)(2 * ARR * 2) + (uint32_t)((lrow * LDS + lcc) * 2), \
             Bh + (size_t)lrow * ldb + k0_ + lcc);                               \
        cp16(st_ + (uint32_t)(2 * ARR * 2) + (uint32_t)((lrow2 * LDS + lcc2) * 2),\
             Bh + (size_t)lrow2 * ldb + k0_ + lcc2);                             \
        cp16(st_ + (uint32_t)(3 * ARR * 2) + (uint32_t)((lrow * LDS + lcc) * 2), \
             Blp + (size_t)lrow * ldb + k0_ + lcc);                              \
        cp16(st_ + (uint32_t)(3 * ARR * 2) + (uint32_t)((lrow2 * LDS + lcc2) * 2),\
             Blp + (size_t)lrow2 * ldb + k0_ + lcc2);                            \
    } while (0)

    const int l15 = lane & 15;
    const uint32_t aoff = (uint32_t)(((wm * 64 + l15) * LDS + ((lane >> 4) << 3)) * 2);
    const uint32_t boff = (uint32_t)(((wn * 32 + (l15 & 7)) * LDS + (((l15 >> 3) & 1) << 3)) * 2);

    float acc[4][4][4];
#pragma unroll
    for (int i = 0; i < 4; ++i)
#pragma unroll
        for (int j = 0; j < 4; ++j)
#pragma unroll
            for (int q = 0; q < 4; ++q) acc[i][j][q] = 0.0f;

    ACBD_ISSUE(0, 0);
    CP_COMMIT();
#pragma unroll
    for (int kt = 0; kt < 2; ++kt) {
        if (kt == 0) {
            ACBD_ISSUE(1, 1);
            CP_COMMIT();
            CP_WAIT(1);
        } else {
            CP_WAIT(0);
        }
        __syncthreads();
        const uint32_t st = sbase + (uint32_t)(kt & 1) * (STAGE * 2);
        const uint32_t aAh = st;
        const uint32_t aBh = st + 2 * ARR * 2, aBl = st + 3 * ARR * 2;
#pragma unroll
        for (int kk = 0; kk < 32; kk += 16) {
            uint32_t bh[4][2], bl[4][2], a[4][4];
#pragma unroll
            for (int nt = 0; nt < 4; ++nt) {
                const uint32_t bo = boff + (uint32_t)((nt * 8 * LDS + kk) * 2);
                ldm_x2(bh[nt], aBh + bo);
                ldm_x2(bl[nt], aBl + bo);
            }
#pragma unroll
            for (int mt = 0; mt < 4; ++mt)
                ldm_x4(a[mt], aAh + aoff + (uint32_t)((mt * 16 * LDS + kk) * 2));
#pragma unroll
            for (int mt = 0; mt < 4; ++mt)
#pragma unroll
                for (int nt = 0; nt < 4; ++nt) {
                    mma_f16(acc[mt][nt], a[mt], bh[nt]);
                    mma_f16(acc[mt][nt], a[mt], bl[nt]);
                }
        }
        __syncthreads();
    }
#undef ACBD_ISSUE

    const int g = lane >> 2, t2 = (lane & 3) * 2;
#pragma unroll
    for (int mt = 0; mt < 4; ++mt) {
#pragma unroll
        for (int nt = 0; nt < 4; ++nt) {
            const int r0 = i0 + wm * 64 + mt * 16 + g;
            const int c  = j0 + wn * 32 + nt * 8 + t2;
            const float b0 = bvec[c], b1 = bvec[c + 1];
            *(float2*)(Cbase + (size_t)r0 * NSEQ + c) =
                make_float2(acc[mt][nt][0] + b0, acc[mt][nt][1] + b1);
            *(float2*)(Cbase + (size_t)(r0 + 8) * NSEQ + c) =
                make_float2(acc[mt][nt][2] + b0, acc[mt][nt][3] + b1);
        }
    }
}

// ---------------- V transpose (hi only) --------------------------------------
__global__ __launch_bounds__(256) void vt_kernel(
    const __half* __restrict__ qkvh, __half* __restrict__ vth)
{
    __shared__ __half th[32][33];
    const int bh = blockIdx.z, b = bh >> 3, h = bh & 7;
    const int j0 = blockIdx.x * 32, d0 = blockIdx.y * 32;
    const int x = threadIdx.x, y = threadIdx.y;
#pragma unroll
    for (int i = 0; i < 32; i += 8)
        th[y + i][x] = qkvh[((size_t)b * NSEQ + j0 + y + i) * 1536 + 1024 + h * 64 + d0 + x];
    __syncthreads();
#pragma unroll
    for (int i = 0; i < 32; i += 8)
        vth[((size_t)bh * 64 + d0 + y + i) * NSEQ + j0 + x] = th[x][y + i];
}

// ======= FUSED shift+scale+softmax(heads) + attn@V (fp16 1-term) =============
#define SAV_ATT_H 0
#define SAV_V_H   40960
#define SAV_SMEM  81920

__global__ __launch_bounds__(512, 1) void fused_sav_kernel(
    const float* __restrict__ AC, const float* __restrict__ BDp,
    const __half* __restrict__ vth,
    __half* __restrict__ outh, float* __restrict__ attnf)
{
    extern __shared__ char dsm[];
    const uint32_t sb = smem_u32(dsm);
    const int tid = threadIdx.x, wid = tid >> 5, lane = tid & 31;
    const int b = blockIdx.y;
    const int i0 = blockIdx.x * 64;
    const int bq = b * NHEADS;

    const int ibA = tid >> 4;
    const int jjA = (tid & 15) * 2;

    const int h = wid & 7, ihalf = wid >> 3;
    const int l15 = lane & 15;
    const uint32_t headOff = (uint32_t)(h * 64 * 40 * 2);
    const uint32_t aAH = sb + SAV_ATT_H + headOff;
    const uint32_t aVH = sb + SAV_V_H + headOff;
    const uint32_t aoff = (uint32_t)(((ihalf * 32 + l15) * 40 + ((lane >> 4) << 3)) * 2);
    const uint32_t boff = (uint32_t)(((l15 & 7) * 40 + (((l15 >> 3) & 1) << 3)) * 2);

    float acc[2][8][4];
#pragma unroll
    for (int i = 0; i < 2; ++i)
#pragma unroll
        for (int j = 0; j < 8; ++j)
#pragma unroll
            for (int q = 0; q < 4; ++q) acc[i][j][q] = 0.0f;

    for (int kt = 0; kt < 32; ++kt) {
        const int j0 = kt * 32;
#pragma unroll
        for (int k = 0; k < 4; ++k) {
            const int idx = tid + k * 512;
            const int hv = idx >> 8;
            const int r = idx & 255;
            const int d = r >> 2, seg = r & 3;
            const uint32_t so = (uint32_t)((hv * 64 + d) * 80 + seg * 16);
            const size_t gsrc = (((size_t)(bq + hv) * 64 + d) << 10) + j0 + seg * 8;
            cp16(sb + SAV_V_H + so, vth + gsrc);
        }
        CP_COMMIT();

#pragma unroll
        for (int it = 0; it < 2; ++it) {
            const int i = ibA + it * 32;
            const int gi = i0 + i;
            float p0[8], p1[8];
#pragma unroll
            for (int e = 0; e < 2; ++e) {
                const int gj = j0 + jjA + e;
                const int g = (gi + 1) * NSEQ + gj;
                const int si = g / (NSEQ + 1);
                const int sj = g % (NSEQ + 1) - 1;
                float v[8];
                float mx = -1e30f;
#pragma unroll
                for (int hh = 0; hh < 8; ++hh) {
                    const size_t base = (size_t)(bq + hh) * NSEQ;
                    float d = AC[(base + gi) * NSEQ + gj];
                    if (sj >= 0) d += BDp[(base + si) * NSEQ + sj];
                    d *= 0.125f;
                    v[hh] = d;
                    mx = fmaxf(mx, d);
                }
                float s = 0.0f;
#pragma unroll
                for (int hh = 0; hh < 8; ++hh) { v[hh] = __expf(v[hh] - mx); s += v[hh]; }
                const float inv = 1.0f / s;
                float* pp = e ? p1 : p0;
#pragma unroll
                for (int hh = 0; hh < 8; ++hh) pp[hh] = v[hh] * inv;
            }
#pragma unroll
            for (int hh = 0; hh < 8; ++hh) {
                __half2 hp;
                hp.x = __float2half_rn(p0[hh]);
                hp.y = __float2half_rn(p1[hh]);
                const uint32_t so = (uint32_t)(((hh * 64 + i) * 40 + jjA) * 2);
                *(__half2*)(dsm + SAV_ATT_H + so) = hp;
                if (attnf) {
                    *(float2*)(attnf + ((size_t)(bq + hh) * NSEQ + gi) * NSEQ + j0 + jjA) =
                        make_float2(p0[hh], p1[hh]);
                }
            }
        }
        CP_WAIT(0);
        __syncthreads();

#pragma unroll
        for (int kk = 0; kk < 32; kk += 16) {
            uint32_t bhf[8][2], ah[2][4];
#pragma unroll
            for (int nt = 0; nt < 8; ++nt)
                ldm_x2(bhf[nt], aVH + boff + (uint32_t)((nt * 8 * 40 + kk) * 2));
#pragma unroll
            for (int mt = 0; mt < 2; ++mt)
                ldm_x4(ah[mt], aAH + aoff + (uint32_t)((mt * 16 * 40 + kk) * 2));
#pragma unroll
            for (int mt = 0; mt < 2; ++mt)
#pragma unroll
                for (int nt = 0; nt < 8; ++nt)
                    mma_f16(acc[mt][nt], ah[mt], bhf[nt]);
        }
        __syncthreads();
    }

    const int g = lane >> 2, t2 = (lane & 3) * 2;
#pragma unroll
    for (int mt = 0; mt < 2; ++mt) {
#pragma unroll
        for (int nt = 0; nt < 8; ++nt) {
            const int r0 = i0 + ihalf * 32 + mt * 16 + g;
            const int c  = h * 64 + nt * 8 + t2;
            __half2 hp;
            hp.x = __float2half_rn(acc[mt][nt][0]);
            hp.y = __float2half_rn(acc[mt][nt][1]);
            *(__half2*)(outh + ((size_t)b * NSEQ + r0) * NHD + c) = hp;
            hp.x = __float2half_rn(acc[mt][nt][2]);
            hp.y = __float2half_rn(acc[mt][nt][3]);
            *(__half2*)(outh + ((size_t)b * NSEQ + r0 + 8) * NHD + c) = hp;
        }
    }
}

// ---------------- host orchestration ----------------------------------------
extern "C" void kernel_launch(void* const* d_in, const int* in_sizes, int n_in,
                              void* d_out, int out_size)
{
    (void)in_sizes; (void)n_in;
    const float* x_in    = (const float*)d_in[0];
    const float* r_t     = (const float*)d_in[1];
    const float* bias_pf = (const float*)d_in[3];
    const float* ln1_g   = (const float*)d_in[4];
    const float* ln1_b   = (const float*)d_in[5];
    const float* Wqkv    = (const float*)d_in[6];
    const float* Wkr_t   = (const float*)d_in[7];
    const float* Wout    = (const float*)d_in[9];
    const float* bout    = (const float*)d_in[10];
    const float* ln2_g   = (const float*)d_in[11];
    const float* ln2_b   = (const float*)d_in[12];
    const float* W1      = (const float*)d_in[13];
    const float* b1      = (const float*)d_in[14];
    const float* W2      = (const float*)d_in[15];
    const float* b2      = (const float*)d_in[16];
    float* outp = (float*)d_out;

    static int attr_done = 0;
    if (!attr_done) {
        cudaFuncSetAttribute(mma2_kernel<1,0,2>, cudaFuncAttributeMaxDynamicSharedMemorySize, MMA2_SMEM);
        cudaFuncSetAttribute(mma2_kernel<0,0,2>, cudaFuncAttributeMaxDynamicSharedMemorySize, MMA2_SMEM);
        cudaFuncSetAttribute(mma2_kernel<2,1,1>, cudaFuncAttributeMaxDynamicSharedMemorySize, MMA2_SMEM);
        cudaFuncSetAttribute(mma2_kernel<0,0,1>, cudaFuncAttributeMaxDynamicSharedMemorySize, MMA2_SMEM);
        cudaFuncSetAttribute(acbd2_kernel,       cudaFuncAttributeMaxDynamicSharedMemorySize, MMA2_SMEM);
        cudaFuncSetAttribute(fused_sav_kernel,   cudaFuncAttributeMaxDynamicSharedMemorySize, SAV_SMEM);
        attr_done = 1;
    }

    float *gx, *gac, *gbd, *gbk, *gbr;
    __half *gxnh, *grth, *gqkvh, *gqkvl, *gkrh, *gkrl;
    __half *gavh, *gffh, *gwth, *gwtl, *gvth;
    cudaGetSymbolAddress((void**)&gx,    g_x);
    cudaGetSymbolAddress((void**)&gac,   g_ac);
    cudaGetSymbolAddress((void**)&gbd,   g_bd);
    cudaGetSymbolAddress((void**)&gbk,   g_bk);
    cudaGetSymbolAddress((void**)&gbr,   g_br);
    cudaGetSymbolAddress((void**)&gxnh,  g_xnh);
    cudaGetSymbolAddress((void**)&grth,  g_rth);
    cudaGetSymbolAddress((void**)&gqkvh, g_qkvh);
    cudaGetSymbolAddress((void**)&gqkvl, g_qkvl);
    cudaGetSymbolAddress((void**)&gkrh,  g_krh);
    cudaGetSymbolAddress((void**)&gkrl,  g_krl);
    cudaGetSymbolAddress((void**)&gavh,  g_avh);
    cudaGetSymbolAddress((void**)&gffh,  g_ffh);
    cudaGetSymbolAddress((void**)&gwth,  g_wth);
    cudaGetSymbolAddress((void**)&gwtl,  g_wtl);
    cudaGetSymbolAddress((void**)&gvth,  g_vth);

    float* attn_out = outp + ((size_t)out_size - ATT_ELEMS);

    cudaMemcpyAsync(gx, x_in, X_ELEMS * sizeof(float), cudaMemcpyDeviceToDevice, 0);
    split_rt_kernel<<<X_ELEMS / 1024, 256>>>(r_t, grth);

    transpose_all_kernel<<<dim3(3328, 4), dim3(32, 8)>>>(
        Wqkv, Wkr_t, Wout, W1, W2, gwth, gwtl);

    const dim3 tb(32, 8);
    for (int l = 0; l < 4; ++l) {
        const size_t wb = (size_t)l * WT_TOTAL;

        ln_half_kernel<<<MROWS, 128>>>(gx, ln1_g + l * NDIM, ln1_b + l * NDIM, gxnh);
        // qkv: 2-term (A = xn hi; B hi/lo), hi/lo output
        mma2_kernel<1,0,2><<<dim3(12, 64), 256, MMA2_SMEM>>>(
            gxnh, gxnh, gwth + wb + WQKVT, gwtl + wb + WQKVT,
            nullptr, gqkvh, gqkvl, nullptr, nullptr, MROWS, 1536, 512);
        // kr: 2-term, hi/lo output
        mma2_kernel<1,0,2><<<dim3(4, 64), 256, MMA2_SMEM>>>(
            grth, grth, gwth + wb + WKRT, gwtl + wb + WKRT,
            nullptr, gkrh, gkrl, nullptr, nullptr, MROWS, 512, 512);

        bias_terms_kernel<<<256, 256>>>(gqkvh, gqkvl, gkrh, gkrl, bias_pf, gbk, gbr);

        acbd2_kernel<<<dim3(8, 8, 128), 256, MMA2_SMEM>>>(
            gqkvh, gqkvl, gkrh, gkrl, gbk, gbr, gac, gbd);

        vt_kernel<<<dim3(32, 2, 64), tb>>>(gqkvh, gvth);

        fused_sav_kernel<<<dim3(16, 8), 512, SAV_SMEM>>>(
            gac, gbd, gvth, gavh, (l == 3) ? attn_out : nullptr);

        // Wout: 2-term (safety margin on x path entry)
        mma2_kernel<0,0,2><<<dim3(4, 64), 256, MMA2_SMEM>>>(
            gavh, gavh, gwth + wb + WOUTT, gwtl + wb + WOUTT,
            gx, nullptr, nullptr, bout + l * NDIM, gx, MROWS, 512, 512);

        ln_half_kernel<<<MROWS, 128>>>(gx, ln2_g + l * NDIM, ln2_b + l * NDIM, gxnh);
        // W1: 1-term (hi x hi), gelu, half hi out
        mma2_kernel<2,1,1><<<dim3(16, 64), 256, MMA2_SMEM>>>(
            gxnh, gxnh, gwth + wb + W1T, gwth + wb + W1T,
            nullptr, gffh, nullptr, b1 + l * NFF, nullptr, MROWS, 2048, 512);
        float* xdst = (l == 3) ? outp : gx;
        // W2: 1-term (hi x hi), fp32 out + residual
        mma2_kernel<0,0,1><<<dim3(4, 64), 256, MMA2_SMEM>>>(
            gffh, gffh, gwth + wb + W2T, gwth + wb + W2T,
            xdst, nullptr, nullptr, b2 + l * NDIM, gx, MROWS, 512, 2048);
    }
}

// round 12
// speedup vs baseline: 1.6249x; 1.1181x over previous
#include <cuda_runtime.h>
#include <cuda_fp16.h>
#include <math.h>
#include <stdint.h>

#define NSEQ   1024
#define NBATCH 8
#define NDIM   512
#define NHEADS 8
#define NDH    64
#define NHD    512
#define NFF    2048
#define MROWS  (NBATCH*NSEQ)
#define ATT_ELEMS ((size_t)NBATCH*NHEADS*NSEQ*NSEQ)
#define X_ELEMS   ((size_t)MROWS*NDIM)

// transposed weight offsets (elements, within one layer's block)
#define WQKVT 0
#define WKRT  786432
#define WOUTT 1048576
#define W1T   1310720
#define W2T   2359296
#define WT_TOTAL 3407872

// ---------------- scratch --------------------------------------------------
static __device__ float g_x [MROWS*NDIM];
static __device__ float g_ac[NBATCH*NHEADS*NSEQ*NSEQ];
static __device__ float g_bd[NBATCH*NHEADS*NSEQ*NSEQ];
static __device__ float g_bk[NBATCH*NHEADS*NSEQ];
static __device__ float g_br[NBATCH*NHEADS*NSEQ];
static __device__ __half g_xnh [MROWS*NDIM];
static __device__ __half g_rth [MROWS*NDIM];
static __device__ __half g_qkvh[MROWS*3*NHD];
static __device__ __half g_krh [MROWS*NHD];
static __device__ __half g_avh [MROWS*NHD];
static __device__ __half g_ffh [MROWS*NFF];
static __device__ __half g_wth [4*WT_TOTAL],  g_wtl [4*WT_TOTAL];
static __device__ __half g_vth [NBATCH*NHEADS*NDH*NSEQ];

// ---------------- primitives ------------------------------------------------
__device__ __forceinline__ uint32_t smem_u32(const void* p) {
    uint32_t a;
    asm("{ .reg .u64 t; cvta.to.shared.u64 t, %1; cvt.u32.u64 %0, t; }"
        : "=r"(a) : "l"(p));
    return a;
}
__device__ __forceinline__ void cp16(uint32_t dst, const void* src) {
    asm volatile("cp.async.cg.shared.global [%0], [%1], 16;" :: "r"(dst), "l"(src));
}
#define CP_COMMIT() asm volatile("cp.async.commit_group;")
#define CP_WAIT(n)  asm volatile("cp.async.wait_group %0;" :: "n"(n))

__device__ __forceinline__ void mma_f16(float* d, const uint32_t* a, const uint32_t* b) {
    asm volatile(
        "mma.sync.aligned.m16n8k16.row.col.f32.f16.f16.f32 "
        "{%0,%1,%2,%3}, {%4,%5,%6,%7}, {%8,%9}, {%0,%1,%2,%3};"
        : "+f"(d[0]), "+f"(d[1]), "+f"(d[2]), "+f"(d[3])
        : "r"(a[0]), "r"(a[1]), "r"(a[2]), "r"(a[3]), "r"(b[0]), "r"(b[1]));
}
__device__ __forceinline__ void ldm_x4(uint32_t* r, uint32_t addr) {
    asm volatile("ldmatrix.sync.aligned.m8n8.x4.shared.b16 {%0,%1,%2,%3}, [%4];"
        : "=r"(r[0]), "=r"(r[1]), "=r"(r[2]), "=r"(r[3]) : "r"(addr));
}
__device__ __forceinline__ void ldm_x2(uint32_t* r, uint32_t addr) {
    asm volatile("ldmatrix.sync.aligned.m8n8.x2.shared.b16 {%0,%1}, [%2];"
        : "=r"(r[0]), "=r"(r[1]) : "r"(addr));
}
__device__ __forceinline__ float gelu_exact(float v) {
    return 0.5f * v * (1.0f + erff(v * 0.70710678118654752f));
}
__device__ __forceinline__ void split1(float v, __half& h, __half& l) {
    h = __float2half_rn(v);
    l = __float2half_rn(v - __half2float(h));
}

// ---------- merged weight transpose+split for ALL layers: one launch --------
__global__ __launch_bounds__(256) void transpose_all_kernel(
    const float* __restrict__ Wqkv, const float* __restrict__ Wkr,
    const float* __restrict__ Wout, const float* __restrict__ W1,
    const float* __restrict__ W2,
    __half* __restrict__ Wth, __half* __restrict__ Wtl)
{
    __shared__ float t[32][33];
    const int l = blockIdx.y;
    const int tt = blockIdx.x;
    const float* W; int K, N, off, tloc;
    if (tt < 768)       { W = Wqkv + (size_t)l * 786432;  K = 512;  N = 1536; off = WQKVT; tloc = tt; }
    else if (tt < 1024) { W = Wkr  + (size_t)l * 262144;  K = 512;  N = 512;  off = WKRT;  tloc = tt - 768; }
    else if (tt < 1280) { W = Wout + (size_t)l * 262144;  K = 512;  N = 512;  off = WOUTT; tloc = tt - 1024; }
    else if (tt < 2304) { W = W1   + (size_t)l * 1048576; K = 512;  N = 2048; off = W1T;   tloc = tt - 1280; }
    else                { W = W2   + (size_t)l * 1048576; K = 2048; N = 512;  off = W2T;   tloc = tt - 2304; }
    const int ntn = N >> 5;
    const int kt = tloc / ntn, nt = tloc % ntn;
    const int k0 = kt * 32, n0 = nt * 32;
    const int x = threadIdx.x, y = threadIdx.y;
    const size_t dst = (size_t)l * WT_TOTAL + off;
#pragma unroll
    for (int i = 0; i < 32; i += 8)
        t[y + i][x] = W[(size_t)(k0 + y + i) * N + n0 + x];
    __syncthreads();
#pragma unroll
    for (int i = 0; i < 32; i += 8) {
        float v = t[x][y + i];
        __half h, lo; split1(v, h, lo);
        Wth[dst + (size_t)(n0 + y + i) * K + k0 + x] = h;
        Wtl[dst + (size_t)(n0 + y + i) * K + k0 + x] = lo;
    }
}

// ---------------- r_t -> fp16 hi only ----------------------------------------
__global__ __launch_bounds__(256) void split_rt_kernel(
    const float* __restrict__ src, __half* __restrict__ dh)
{
    const size_t i = ((size_t)blockIdx.x * 256 + threadIdx.x) * 4;
    float4 v = *(const float4*)(src + i);
    __half2 a, b;
    a.x = __float2half_rn(v.x); a.y = __float2half_rn(v.y);
    b.x = __float2half_rn(v.z); b.y = __float2half_rn(v.w);
    *(__half2*)(dh + i) = a;
    *(__half2*)(dh + i + 2) = b;
}

// ---------------- LayerNorm -> fp16 hi only ----------------------------------
__global__ __launch_bounds__(128) void ln_half_kernel(
    const float* __restrict__ x, const float* __restrict__ g,
    const float* __restrict__ b, __half* __restrict__ yh)
{
    const int row = blockIdx.x;
    const int tid = threadIdx.x;
    const float* xr = x + (size_t)row * NDIM;

    float4 v = ((const float4*)xr)[tid];
    float s  = v.x + v.y + v.z + v.w;
    float sq = v.x*v.x + v.y*v.y + v.z*v.z + v.w*v.w;
#pragma unroll
    for (int o = 16; o > 0; o >>= 1) {
        s  += __shfl_xor_sync(0xffffffffu, s,  o);
        sq += __shfl_xor_sync(0xffffffffu, sq, o);
    }
    __shared__ float red[8];
    const int w = tid >> 5;
    if ((tid & 31) == 0) { red[w] = s; red[4 + w] = sq; }
    __syncthreads();
    const float st  = red[0] + red[1] + red[2] + red[3];
    const float sqt = red[4] + red[5] + red[6] + red[7];
    const float mu  = st * (1.0f / NDIM);
    const float var = sqt * (1.0f / NDIM) - mu * mu;
    const float inv = rsqrtf(var + 1e-5f);

    float4 gg = ((const float4*)g)[tid];
    float4 bb = ((const float4*)b)[tid];
    __half2 a, c;
    a.x = __float2half_rn((v.x - mu) * inv * gg.x + bb.x);
    a.y = __float2half_rn((v.y - mu) * inv * gg.y + bb.y);
    c.x = __float2half_rn((v.z - mu) * inv * gg.z + bb.z);
    c.y = __float2half_rn((v.w - mu) * inv * gg.w + bb.w);
    const size_t base = (size_t)row * NDIM + tid * 4;
    *(__half2*)(yh + base) = a;
    *(__half2*)(yh + base + 2) = c;
}

// ====== dense fp16 mma GEMM, cp.async double-buffered ========================
// NTERM=2: A hi + B hi/lo (hh+hl). NTERM=1: A hi + B hi (hh only).
// SPLIT: 0 = fp32 out (+bias,+res); 2 = half hi-only out.
#define LDS 40
#define ARR   (128*LDS)
#define STAGE (4*ARR)
#define MMA2_SMEM (2*STAGE*2)

template<int SPLIT, int ACT, int NTERM>
__global__ __launch_bounds__(256, 2) void mma2_kernel(
    const __half* __restrict__ Ah,
    const __half* __restrict__ Bh, const __half* __restrict__ Bl,
    float* __restrict__ Cf, __half* __restrict__ Ch,
    const float* __restrict__ bias, const float* __restrict__ res,
    int M, int N, int K)
{
    extern __shared__ char dsm[];
    const uint32_t sbase = smem_u32(dsm);
    const int tid = threadIdx.x, wid = tid >> 5, lane = tid & 31;
    const int wm = wid >> 2, wn = wid & 3;
    const int bm = blockIdx.y * 128, bn = blockIdx.x * 128;

    const int lrow = tid >> 2, lcc = (tid & 3) * 8;
    const int lrow2 = (tid + 256) >> 2, lcc2 = ((tid + 256) & 3) * 8;

#define MMA2_ISSUE(kt, s) do {                                                   \
        const uint32_t st_ = sbase + (uint32_t)(s) * (STAGE * 2);                \
        const int k0_ = (kt) * 32;                                               \
        cp16(st_ + (uint32_t)((lrow * LDS + lcc) * 2),                           \
             Ah + (size_t)(bm + lrow) * K + k0_ + lcc);                          \
        cp16(st_ + (uint32_t)((lrow2 * LDS + lcc2) * 2),                         \
             Ah + (size_t)(bm + lrow2) * K + k0_ + lcc2);                        \
        cp16(st_ + (uint32_t)(2 * ARR * 2) + (uint32_t)((lrow * LDS + lcc) * 2), \
             Bh + (size_t)(bn + lrow) * K + k0_ + lcc);                          \
        cp16(st_ + (uint32_t)(2 * ARR * 2) + (uint32_t)((lrow2 * LDS + lcc2) * 2),\
             Bh + (size_t)(bn + lrow2) * K + k0_ + lcc2);                        \
        if (NTERM >= 2) {                                                        \
            cp16(st_ + (uint32_t)(3 * ARR * 2) + (uint32_t)((lrow * LDS + lcc) * 2), \
                 Bl + (size_t)(bn + lrow) * K + k0_ + lcc);                      \
            cp16(st_ + (uint32_t)(3 * ARR * 2) + (uint32_t)((lrow2 * LDS + lcc2) * 2),\
                 Bl + (size_t)(bn + lrow2) * K + k0_ + lcc2);                    \
        }                                                                        \
    } while (0)

    const int l15 = lane & 15;
    const uint32_t aoff = (uint32_t)(((wm * 64 + l15) * LDS + ((lane >> 4) << 3)) * 2);
    const uint32_t boff = (uint32_t)(((wn * 32 + (l15 & 7)) * LDS + (((l15 >> 3) & 1) << 3)) * 2);

    float acc[4][4][4];
#pragma unroll
    for (int i = 0; i < 4; ++i)
#pragma unroll
        for (int j = 0; j < 4; ++j)
#pragma unroll
            for (int q = 0; q < 4; ++q) acc[i][j][q] = 0.0f;

    const int NKT = K >> 5;
    MMA2_ISSUE(0, 0);
    CP_COMMIT();

    for (int kt = 0; kt < NKT; ++kt) {
        if (kt + 1 < NKT) {
            MMA2_ISSUE(kt + 1, (kt + 1) & 1);
            CP_COMMIT();
            CP_WAIT(1);
        } else {
            CP_WAIT(0);
        }
        __syncthreads();

        const uint32_t st = sbase + (uint32_t)(kt & 1) * (STAGE * 2);
        const uint32_t aAh = st;
        const uint32_t aBh = st + 2 * ARR * 2, aBl = st + 3 * ARR * 2;
#pragma unroll
        for (int kk = 0; kk < 32; kk += 16) {
            uint32_t bh[4][2], bl[4][2], a[4][4];
#pragma unroll
            for (int nt = 0; nt < 4; ++nt) {
                const uint32_t bo = boff + (uint32_t)((nt * 8 * LDS + kk) * 2);
                ldm_x2(bh[nt], aBh + bo);
                if (NTERM >= 2) ldm_x2(bl[nt], aBl + bo);
            }
#pragma unroll
            for (int mt = 0; mt < 4; ++mt)
                ldm_x4(a[mt], aAh + aoff + (uint32_t)((mt * 16 * LDS + kk) * 2));
#pragma unroll
            for (int mt = 0; mt < 4; ++mt)
#pragma unroll
                for (int nt = 0; nt < 4; ++nt) {
                    mma_f16(acc[mt][nt], a[mt], bh[nt]);
                    if (NTERM >= 2) mma_f16(acc[mt][nt], a[mt], bl[nt]);
                }
        }
        __syncthreads();
    }
#undef MMA2_ISSUE

    const int g = lane >> 2, t2 = (lane & 3) * 2;
#pragma unroll
    for (int mt = 0; mt < 4; ++mt) {
#pragma unroll
        for (int nt = 0; nt < 4; ++nt) {
            const int r0 = bm + wm * 64 + mt * 16 + g;
            const int r1 = r0 + 8;
            const int c  = bn + wn * 32 + nt * 8 + t2;
            float v0 = acc[mt][nt][0], v1 = acc[mt][nt][1];
            float v2 = acc[mt][nt][2], v3 = acc[mt][nt][3];
            if (bias) {
                const float b0 = bias[c], b1 = bias[c + 1];
                v0 += b0; v1 += b1; v2 += b0; v3 += b1;
            }
            if (ACT) {
                v0 = gelu_exact(v0); v1 = gelu_exact(v1);
                v2 = gelu_exact(v2); v3 = gelu_exact(v3);
            }
            if (SPLIT == 2) {
                __half2 hp;
                hp.x = __float2half_rn(v0); hp.y = __float2half_rn(v1);
                *(__half2*)(Ch + (size_t)r0 * N + c) = hp;
                hp.x = __float2half_rn(v2); hp.y = __float2half_rn(v3);
                *(__half2*)(Ch + (size_t)r1 * N + c) = hp;
            } else {
                if (res) {
                    const float2 q0 = *(const float2*)(res + (size_t)r0 * N + c);
                    const float2 q1 = *(const float2*)(res + (size_t)r1 * N + c);
                    v0 += q0.x; v1 += q0.y; v2 += q1.x; v3 += q1.y;
                }
                *(float2*)(Cf + (size_t)r0 * N + c) = make_float2(v0, v1);
                *(float2*)(Cf + (size_t)r1 * N + c) = make_float2(v2, v3);
            }
        }
    }
}

// ---------------- bias rank-1 terms (hi-only inputs) -------------------------
__global__ __launch_bounds__(256) void bias_terms_kernel(
    const __half* __restrict__ qkvh, const __half* __restrict__ krh,
    const float* __restrict__ bias_pf,
    float* __restrict__ bk, float* __restrict__ br)
{
    const int idx = blockIdx.x * 256 + threadIdx.x;
    const int bh = idx >> 10, j = idx & 1023;
    const int b = bh >> 3, h = bh & 7;
    const size_t kb = ((size_t)b * NSEQ + j) * 1536 + 512 + h * 64;
    const size_t rb = ((size_t)b * NSEQ + j) * 512 + h * 64;
    float sk = 0.0f, sr = 0.0f;
#pragma unroll 16
    for (int d = 0; d < 64; ++d) {
        const float bp = bias_pf[h * 64 + d];
        sk += bp * __half2float(qkvh[kb + d]);
        sr += bp * __half2float(krh[rb + d]);
    }
    bk[idx] = sk;
    br[idx] = sr;
}

// =========== acbd fp16 mma, 1-term (A=Q hi; B=K/KR hi) =======================
#define ACBD_STAGE (2*ARR)
#define ACBD_SMEM  (2*ACBD_STAGE*2)   // 40960 bytes

__global__ __launch_bounds__(256, 2) void acbd1_kernel(
    const __half* __restrict__ qkvh, const __half* __restrict__ krh,
    const float* __restrict__ bk, const float* __restrict__ br,
    float* __restrict__ AC, float* __restrict__ BD)
{
    extern __shared__ char dsm[];
    const uint32_t sbase = smem_u32(dsm);
    const int tid = threadIdx.x, wid = tid >> 5, lane = tid & 31;
    const int wm = wid >> 2, wn = wid & 3;
    const int z = blockIdx.z, bh_idx = z & 63, isBD = z >> 6;
    const int b = bh_idx >> 3, h = bh_idx & 7;
    const int i0 = blockIdx.y * 128, j0 = blockIdx.x * 128;

    const __half* Ah = qkvh + ((size_t)b * NSEQ + i0) * 1536 + h * 64;
    const __half* Bh = isBD ? (krh + ((size_t)b * NSEQ + j0) * 512 + h * 64)
                            : (qkvh + ((size_t)b * NSEQ + j0) * 1536 + 512 + h * 64);
    const int ldb = isBD ? 512 : 1536;
    float* Cbase = (isBD ? BD : AC) + (size_t)bh_idx * NSEQ * NSEQ;
    const float* bvec = (isBD ? br : bk) + (size_t)bh_idx * NSEQ;

    const int lrow = tid >> 2, lcc = (tid & 3) * 8;
    const int lrow2 = (tid + 256) >> 2, lcc2 = ((tid + 256) & 3) * 8;

#define ACBD_ISSUE(kt, s) do {                                                   \
        const uint32_t st_ = sbase + (uint32_t)(s) * (ACBD_STAGE * 2);           \
        const int k0_ = (kt) * 32;                                               \
        cp16(st_ + (uint32_t)((lrow * LDS + lcc) * 2),                           \
             Ah + (size_t)lrow * 1536 + k0_ + lcc);                              \
        cp16(st_ + (uint32_t)((lrow2 * LDS + lcc2) * 2),                         \
             Ah + (size_t)lrow2 * 1536 + k0_ + lcc2);                            \
        cp16(st_ + (uint32_t)(ARR * 2) + (uint32_t)((lrow * LDS + lcc) * 2),     \
             Bh + (size_t)lrow * ldb + k0_ + lcc);                               \
        cp16(st_ + (uint32_t)(ARR * 2) + (uint32_t)((lrow2 * LDS + lcc2) * 2),   \
             Bh + (size_t)lrow2 * ldb + k0_ + lcc2);                             \
    } while (0)

    const int l15 = lane & 15;
    const uint32_t aoff = (uint32_t)(((wm * 64 + l15) * LDS + ((lane >> 4) << 3)) * 2);
    const uint32_t boff = (uint32_t)(((wn * 32 + (l15 & 7)) * LDS + (((l15 >> 3) & 1) << 3)) * 2);

    float acc[4][4][4];
#pragma unroll
    for (int i = 0; i < 4; ++i)
#pragma unroll
        for (int j = 0; j < 4; ++j)
#pragma unroll
            for (int q = 0; q < 4; ++q) acc[i][j][q] = 0.0f;

    ACBD_ISSUE(0, 0);
    CP_COMMIT();
#pragma unroll
    for (int kt = 0; kt < 2; ++kt) {
        if (kt == 0) {
            ACBD_ISSUE(1, 1);
            CP_COMMIT();
            CP_WAIT(1);
        } else {
            CP_WAIT(0);
        }
        __syncthreads();
        const uint32_t st = sbase + (uint32_t)(kt & 1) * (ACBD_STAGE * 2);
        const uint32_t aAh = st, aBh = st + ARR * 2;
#pragma unroll
        for (int kk = 0; kk < 32; kk += 16) {
            uint32_t bh[4][2], a[4][4];
#pragma unroll
            for (int nt = 0; nt < 4; ++nt)
                ldm_x2(bh[nt], aBh + boff + (uint32_t)((nt * 8 * LDS + kk) * 2));
#pragma unroll
            for (int mt = 0; mt < 4; ++mt)
                ldm_x4(a[mt], aAh + aoff + (uint32_t)((mt * 16 * LDS + kk) * 2));
#pragma unroll
            for (int mt = 0; mt < 4; ++mt)
#pragma unroll
                for (int nt = 0; nt < 4; ++nt)
                    mma_f16(acc[mt][nt], a[mt], bh[nt]);
        }
        __syncthreads();
    }
#undef ACBD_ISSUE

    const int g = lane >> 2, t2 = (lane & 3) * 2;
#pragma unroll
    for (int mt = 0; mt < 4; ++mt) {
#pragma unroll
        for (int nt = 0; nt < 4; ++nt) {
            const int r0 = i0 + wm * 64 + mt * 16 + g;
            const int c  = j0 + wn * 32 + nt * 8 + t2;
            const float b0 = bvec[c], b1 = bvec[c + 1];
            *(float2*)(Cbase + (size_t)r0 * NSEQ + c) =
                make_float2(acc[mt][nt][0] + b0, acc[mt][nt][1] + b1);
            *(float2*)(Cbase + (size_t)(r0 + 8) * NSEQ + c) =
                make_float2(acc[mt][nt][2] + b0, acc[mt][nt][3] + b1);
        }
    }
}

// ---------------- V transpose (hi only) --------------------------------------
__global__ __launch_bounds__(256) void vt_kernel(
    const __half* __restrict__ qkvh, __half* __restrict__ vth)
{
    __shared__ __half th[32][33];
    const int bh = blockIdx.z, b = bh >> 3, h = bh & 7;
    const int j0 = blockIdx.x * 32, d0 = blockIdx.y * 32;
    const int x = threadIdx.x, y = threadIdx.y;
#pragma unroll
    for (int i = 0; i < 32; i += 8)
        th[y + i][x] = qkvh[((size_t)b * NSEQ + j0 + y + i) * 1536 + 1024 + h * 64 + d0 + x];
    __syncthreads();
#pragma unroll
    for (int i = 0; i < 32; i += 8)
        vth[((size_t)bh * 64 + d0 + y + i) * NSEQ + j0 + x] = th[x][y + i];
}

// ======= FUSED shift+scale+softmax(heads) + attn@V (fp16 1-term) =============
#define SAV_ATT_H 0
#define SAV_V_H   40960
#define SAV_SMEM  81920

__global__ __launch_bounds__(512, 1) void fused_sav_kernel(
    const float* __restrict__ AC, const float* __restrict__ BDp,
    const __half* __restrict__ vth,
    __half* __restrict__ outh, float* __restrict__ attnf)
{
    extern __shared__ char dsm[];
    const uint32_t sb = smem_u32(dsm);
    const int tid = threadIdx.x, wid = tid >> 5, lane = tid & 31;
    const int b = blockIdx.y;
    const int i0 = blockIdx.x * 64;
    const int bq = b * NHEADS;

    const int ibA = tid >> 4;
    const int jjA = (tid & 15) * 2;

    const int h = wid & 7, ihalf = wid >> 3;
    const int l15 = lane & 15;
    const uint32_t headOff = (uint32_t)(h * 64 * 40 * 2);
    const uint32_t aAH = sb + SAV_ATT_H + headOff;
    const uint32_t aVH = sb + SAV_V_H + headOff;
    const uint32_t aoff = (uint32_t)(((ihalf * 32 + l15) * 40 + ((lane >> 4) << 3)) * 2);
    const uint32_t boff = (uint32_t)(((l15 & 7) * 40 + (((l15 >> 3) & 1) << 3)) * 2);

    float acc[2][8][4];
#pragma unroll
    for (int i = 0; i < 2; ++i)
#pragma unroll
        for (int j = 0; j < 8; ++j)
#pragma unroll
            for (int q = 0; q < 4; ++q) acc[i][j][q] = 0.0f;

    for (int kt = 0; kt < 32; ++kt) {
        const int j0 = kt * 32;
#pragma unroll
        for (int k = 0; k < 4; ++k) {
            const int idx = tid + k * 512;
            const int hv = idx >> 8;
            const int r = idx & 255;
            const int d = r >> 2, seg = r & 3;
            const uint32_t so = (uint32_t)((hv * 64 + d) * 80 + seg * 16);
            const size_t gsrc = (((size_t)(bq + hv) * 64 + d) << 10) + j0 + seg * 8;
            cp16(sb + SAV_V_H + so, vth + gsrc);
        }
        CP_COMMIT();

#pragma unroll
        for (int it = 0; it < 2; ++it) {
            const int i = ibA + it * 32;
            const int gi = i0 + i;
            float p0[8], p1[8];
#pragma unroll
            for (int e = 0; e < 2; ++e) {
                const int gj = j0 + jjA + e;
                const int g = (gi + 1) * NSEQ + gj;
                const int si = g / (NSEQ + 1);
                const int sj = g % (NSEQ + 1) - 1;
                float v[8];
                float mx = -1e30f;
#pragma unroll
                for (int hh = 0; hh < 8; ++hh) {
                    const size_t base = (size_t)(bq + hh) * NSEQ;
                    float d = AC[(base + gi) * NSEQ + gj];
                    if (sj >= 0) d += BDp[(base + si) * NSEQ + sj];
                    d *= 0.125f;
                    v[hh] = d;
                    mx = fmaxf(mx, d);
                }
                float s = 0.0f;
#pragma unroll
                for (int hh = 0; hh < 8; ++hh) { v[hh] = __expf(v[hh] - mx); s += v[hh]; }
                const float inv = 1.0f / s;
                float* pp = e ? p1 : p0;
#pragma unroll
                for (int hh = 0; hh < 8; ++hh) pp[hh] = v[hh] * inv;
            }
#pragma unroll
            for (int hh = 0; hh < 8; ++hh) {
                __half2 hp;
                hp.x = __float2half_rn(p0[hh]);
                hp.y = __float2half_rn(p1[hh]);
                const uint32_t so = (uint32_t)(((hh * 64 + i) * 40 + jjA) * 2);
                *(__half2*)(dsm + SAV_ATT_H + so) = hp;
                if (attnf) {
                    *(float2*)(attnf + ((size_t)(bq + hh) * NSEQ + gi) * NSEQ + j0 + jjA) =
                        make_float2(p0[hh], p1[hh]);
                }
            }
        }
        CP_WAIT(0);
        __syncthreads();

#pragma unroll
        for (int kk = 0; kk < 32; kk += 16) {
            uint32_t bhf[8][2], ah[2][4];
#pragma unroll
            for (int nt = 0; nt < 8; ++nt)
                ldm_x2(bhf[nt], aVH + boff + (uint32_t)((nt * 8 * 40 + kk) * 2));
#pragma unroll
            for (int mt = 0; mt < 2; ++mt)
                ldm_x4(ah[mt], aAH + aoff + (uint32_t)((mt * 16 * 40 + kk) * 2));
#pragma unroll
            for (int mt = 0; mt < 2; ++mt)
#pragma unroll
                for (int nt = 0; nt < 8; ++nt)
                    mma_f16(acc[mt][nt], ah[mt], bhf[nt]);
        }
        __syncthreads();
    }

    const int g = lane >> 2, t2 = (lane & 3) * 2;
#pragma unroll
    for (int mt = 0; mt < 2; ++mt) {
#pragma unroll
        for (int nt = 0; nt < 8; ++nt) {
            const int r0 = i0 + ihalf * 32 + mt * 16 + g;
            const int c  = h * 64 + nt * 8 + t2;
            __half2 hp;
            hp.x = __float2half_rn(acc[mt][nt][0]);
            hp.y = __float2half_rn(acc[mt][nt][1]);
            *(__half2*)(outh + ((size_t)b * NSEQ + r0) * NHD + c) = hp;
            hp.x = __float2half_rn(acc[mt][nt][2]);
            hp.y = __float2half_rn(acc[mt][nt][3]);
            *(__half2*)(outh + ((size_t)b * NSEQ + r0 + 8) * NHD + c) = hp;
        }
    }
}

// ---------------- host orchestration ----------------------------------------
extern "C" void kernel_launch(void* const* d_in, const int* in_sizes, int n_in,
                              void* d_out, int out_size)
{
    (void)in_sizes; (void)n_in;
    const float* x_in    = (const float*)d_in[0];
    const float* r_t     = (const float*)d_in[1];
    const float* bias_pf = (const float*)d_in[3];
    const float* ln1_g   = (const float*)d_in[4];
    const float* ln1_b   = (const float*)d_in[5];
    const float* Wqkv    = (const float*)d_in[6];
    const float* Wkr_t   = (const float*)d_in[7];
    const float* Wout    = (const float*)d_in[9];
    const float* bout    = (const float*)d_in[10];
    const float* ln2_g   = (const float*)d_in[11];
    const float* ln2_b   = (const float*)d_in[12];
    const float* W1      = (const float*)d_in[13];
    const float* b1      = (const float*)d_in[14];
    const float* W2      = (const float*)d_in[15];
    const float* b2      = (const float*)d_in[16];
    float* outp = (float*)d_out;

    static int attr_done = 0;
    if (!attr_done) {
        cudaFuncSetAttribute(mma2_kernel<2,0,2>, cudaFuncAttributeMaxDynamicSharedMemorySize, MMA2_SMEM);
        cudaFuncSetAttribute(mma2_kernel<0,0,2>, cudaFuncAttributeMaxDynamicSharedMemorySize, MMA2_SMEM);
        cudaFuncSetAttribute(mma2_kernel<2,1,1>, cudaFuncAttributeMaxDynamicSharedMemorySize, MMA2_SMEM);
        cudaFuncSetAttribute(mma2_kernel<0,0,1>, cudaFuncAttributeMaxDynamicSharedMemorySize, MMA2_SMEM);
        cudaFuncSetAttribute(acbd1_kernel,       cudaFuncAttributeMaxDynamicSharedMemorySize, ACBD_SMEM);
        cudaFuncSetAttribute(fused_sav_kernel,   cudaFuncAttributeMaxDynamicSharedMemorySize, SAV_SMEM);
        attr_done = 1;
    }

    float *gx, *gac, *gbd, *gbk, *gbr;
    __half *gxnh, *grth, *gqkvh, *gkrh, *gavh, *gffh, *gwth, *gwtl, *gvth;
    cudaGetSymbolAddress((void**)&gx,    g_x);
    cudaGetSymbolAddress((void**)&gac,   g_ac);
    cudaGetSymbolAddress((void**)&gbd,   g_bd);
    cudaGetSymbolAddress((void**)&gbk,   g_bk);
    cudaGetSymbolAddress((void**)&gbr,   g_br);
    cudaGetSymbolAddress((void**)&gxnh,  g_xnh);
    cudaGetSymbolAddress((void**)&grth,  g_rth);
    cudaGetSymbolAddress((void**)&gqkvh, g_qkvh);
    cudaGetSymbolAddress((void**)&gkrh,  g_krh);
    cudaGetSymbolAddress((void**)&gavh,  g_avh);
    cudaGetSymbolAddress((void**)&gffh,  g_ffh);
    cudaGetSymbolAddress((void**)&gwth,  g_wth);
    cudaGetSymbolAddress((void**)&gwtl,  g_wtl);
    cudaGetSymbolAddress((void**)&gvth,  g_vth);

    float* attn_out = outp + ((size_t)out_size - ATT_ELEMS);

    cudaMemcpyAsync(gx, x_in, X_ELEMS * sizeof(float), cudaMemcpyDeviceToDevice, 0);
    split_rt_kernel<<<X_ELEMS / 1024, 256>>>(r_t, grth);

    transpose_all_kernel<<<dim3(3328, 4), dim3(32, 8)>>>(
        Wqkv, Wkr_t, Wout, W1, W2, gwth, gwtl);

    const dim3 tb(32, 8);
    for (int l = 0; l < 4; ++l) {
        const size_t wb = (size_t)l * WT_TOTAL;

        ln_half_kernel<<<MROWS, 128>>>(gx, ln1_g + l * NDIM, ln1_b + l * NDIM, gxnh);
        // qkv: 2-term (A = xn hi; B hi/lo), hi-only output
        mma2_kernel<2,0,2><<<dim3(12, 64), 256, MMA2_SMEM>>>(
            gxnh, gwth + wb + WQKVT, gwtl + wb + WQKVT,
            nullptr, gqkvh, nullptr, nullptr, MROWS, 1536, 512);
        // kr: 2-term, hi-only output
        mma2_kernel<2,0,2><<<dim3(4, 64), 256, MMA2_SMEM>>>(
            grth, gwth + wb + WKRT, gwtl + wb + WKRT,
            nullptr, gkrh, nullptr, nullptr, MROWS, 512, 512);

        bias_terms_kernel<<<256, 256>>>(gqkvh, gkrh, bias_pf, gbk, gbr);

        // acbd: 1-term (Q hi x K/KR hi)
        acbd1_kernel<<<dim3(8, 8, 128), 256, ACBD_SMEM>>>(
            gqkvh, gkrh, gbk, gbr, gac, gbd);

        vt_kernel<<<dim3(32, 2, 64), tb>>>(gqkvh, gvth);

        fused_sav_kernel<<<dim3(16, 8), 512, SAV_SMEM>>>(
            gac, gbd, gvth, gavh, (l == 3) ? attn_out : nullptr);

        // Wout: 2-term, fp32 out + residual
        mma2_kernel<0,0,2><<<dim3(4, 64), 256, MMA2_SMEM>>>(
            gavh, gwth + wb + WOUTT, gwtl + wb + WOUTT,
            gx, nullptr, bout + l * NDIM, gx, MROWS, 512, 512);

        ln_half_kernel<<<MROWS, 128>>>(gx, ln2_g + l * NDIM, ln2_b + l * NDIM, gxnh);
        // W1: 1-term, gelu, half hi out
        mma2_kernel<2,1,1><<<dim3(16, 64), 256, MMA2_SMEM>>>(
            gxnh, gwth + wb + W1T, gwth + wb + W1T,
            nullptr, gffh, b1 + l * NFF, nullptr, MROWS, 2048, 512);
        float* xdst = (l == 3) ? outp : gx;
        // W2: 1-term, fp32 out + residual
        mma2_kernel<0,0,1><<<dim3(4, 64), 256, MMA2_SMEM>>>(
            gffh, gwth + wb + W2T, gwth + wb + W2T,
            xdst, nullptr, b2 + l * NDIM, gx, MROWS, 512, 2048);
    }
}

// round 13
// speedup vs baseline: 1.6341x; 1.0056x over previous
#include <cuda_runtime.h>
#include <cuda_fp16.h>
#include <math.h>
#include <stdint.h>

#define NSEQ   1024
#define NBATCH 8
#define NDIM   512
#define NHEADS 8
#define NDH    64
#define NHD    512
#define NFF    2048
#define MROWS  (NBATCH*NSEQ)
#define ATT_ELEMS ((size_t)NBATCH*NHEADS*NSEQ*NSEQ)
#define X_ELEMS   ((size_t)MROWS*NDIM)

// transposed weight offsets (elements, within one layer's block)
#define WQKVT 0
#define WKRT  786432
#define WOUTT 1048576
#define W1T   1310720
#define W2T   2359296
#define WT_TOTAL 3407872

// ---------------- scratch --------------------------------------------------
static __device__ float g_x [MROWS*NDIM];
static __device__ float g_ac[NBATCH*NHEADS*NSEQ*NSEQ];
static __device__ float g_bd[NBATCH*NHEADS*NSEQ*NSEQ];
static __device__ float g_bk[NBATCH*NHEADS*NSEQ];
static __device__ float g_br[NBATCH*NHEADS*NSEQ];
static __device__ __half g_xnh [MROWS*NDIM];
static __device__ __half g_rth [MROWS*NDIM];
static __device__ __half g_qkvh[MROWS*3*NHD];
static __device__ __half g_krh [MROWS*NHD];
static __device__ __half g_avh [MROWS*NHD];
static __device__ __half g_ffh [MROWS*NFF];
static __device__ __half g_wth [4*WT_TOTAL],  g_wtl [4*WT_TOTAL];
static __device__ __half g_vth [NBATCH*NHEADS*NDH*NSEQ];

// ---------------- primitives ------------------------------------------------
__device__ __forceinline__ uint32_t smem_u32(const void* p) {
    uint32_t a;
    asm("{ .reg .u64 t; cvta.to.shared.u64 t, %1; cvt.u32.u64 %0, t; }"
        : "=r"(a) : "l"(p));
    return a;
}
__device__ __forceinline__ void cp16(uint32_t dst, const void* src) {
    asm volatile("cp.async.cg.shared.global [%0], [%1], 16;" :: "r"(dst), "l"(src));
}
#define CP_COMMIT() asm volatile("cp.async.commit_group;")
#define CP_WAIT(n)  asm volatile("cp.async.wait_group %0;" :: "n"(n))

__device__ __forceinline__ void mma_f16(float* d, const uint32_t* a, const uint32_t* b) {
    asm volatile(
        "mma.sync.aligned.m16n8k16.row.col.f32.f16.f16.f32 "
        "{%0,%1,%2,%3}, {%4,%5,%6,%7}, {%8,%9}, {%0,%1,%2,%3};"
        : "+f"(d[0]), "+f"(d[1]), "+f"(d[2]), "+f"(d[3])
        : "r"(a[0]), "r"(a[1]), "r"(a[2]), "r"(a[3]), "r"(b[0]), "r"(b[1]));
}
__device__ __forceinline__ void ldm_x4(uint32_t* r, uint32_t addr) {
    asm volatile("ldmatrix.sync.aligned.m8n8.x4.shared.b16 {%0,%1,%2,%3}, [%4];"
        : "=r"(r[0]), "=r"(r[1]), "=r"(r[2]), "=r"(r[3]) : "r"(addr));
}
__device__ __forceinline__ void ldm_x2(uint32_t* r, uint32_t addr) {
    asm volatile("ldmatrix.sync.aligned.m8n8.x2.shared.b16 {%0,%1}, [%2];"
        : "=r"(r[0]), "=r"(r[1]) : "r"(addr));
}
__device__ __forceinline__ float gelu_exact(float v) {
    return 0.5f * v * (1.0f + erff(v * 0.70710678118654752f));
}
__device__ __forceinline__ void split1(float v, __half& h, __half& l) {
    h = __float2half_rn(v);
    l = __float2half_rn(v - __half2float(h));
}

// ---------- merged weight transpose+split for ALL layers: one launch --------
__global__ __launch_bounds__(256) void transpose_all_kernel(
    const float* __restrict__ Wqkv, const float* __restrict__ Wkr,
    const float* __restrict__ Wout, const float* __restrict__ W1,
    const float* __restrict__ W2,
    __half* __restrict__ Wth, __half* __restrict__ Wtl)
{
    __shared__ float t[32][33];
    const int l = blockIdx.y;
    const int tt = blockIdx.x;
    const float* W; int K, N, off, tloc;
    if (tt < 768)       { W = Wqkv + (size_t)l * 786432;  K = 512;  N = 1536; off = WQKVT; tloc = tt; }
    else if (tt < 1024) { W = Wkr  + (size_t)l * 262144;  K = 512;  N = 512;  off = WKRT;  tloc = tt - 768; }
    else if (tt < 1280) { W = Wout + (size_t)l * 262144;  K = 512;  N = 512;  off = WOUTT; tloc = tt - 1024; }
    else if (tt < 2304) { W = W1   + (size_t)l * 1048576; K = 512;  N = 2048; off = W1T;   tloc = tt - 1280; }
    else                { W = W2   + (size_t)l * 1048576; K = 2048; N = 512;  off = W2T;   tloc = tt - 2304; }
    const int ntn = N >> 5;
    const int kt = tloc / ntn, nt = tloc % ntn;
    const int k0 = kt * 32, n0 = nt * 32;
    const int x = threadIdx.x, y = threadIdx.y;
    const size_t dst = (size_t)l * WT_TOTAL + off;
#pragma unroll
    for (int i = 0; i < 32; i += 8)
        t[y + i][x] = W[(size_t)(k0 + y + i) * N + n0 + x];
    __syncthreads();
#pragma unroll
    for (int i = 0; i < 32; i += 8) {
        float v = t[x][y + i];
        __half h, lo; split1(v, h, lo);
        Wth[dst + (size_t)(n0 + y + i) * K + k0 + x] = h;
        Wtl[dst + (size_t)(n0 + y + i) * K + k0 + x] = lo;
    }
}

// ---------------- r_t -> fp16 hi only ----------------------------------------
__global__ __launch_bounds__(256) void split_rt_kernel(
    const float* __restrict__ src, __half* __restrict__ dh)
{
    const size_t i = ((size_t)blockIdx.x * 256 + threadIdx.x) * 4;
    float4 v = *(const float4*)(src + i);
    __half2 a, b;
    a.x = __float2half_rn(v.x); a.y = __float2half_rn(v.y);
    b.x = __float2half_rn(v.z); b.y = __float2half_rn(v.w);
    *(__half2*)(dh + i) = a;
    *(__half2*)(dh + i + 2) = b;
}

// ---------------- LayerNorm -> fp16 hi only ----------------------------------
__global__ __launch_bounds__(128) void ln_half_kernel(
    const float* __restrict__ x, const float* __restrict__ g,
    const float* __restrict__ b, __half* __restrict__ yh)
{
    const int row = blockIdx.x;
    const int tid = threadIdx.x;
    const float* xr = x + (size_t)row * NDIM;

    float4 v = ((const float4*)xr)[tid];
    float s  = v.x + v.y + v.z + v.w;
    float sq = v.x*v.x + v.y*v.y + v.z*v.z + v.w*v.w;
#pragma unroll
    for (int o = 16; o > 0; o >>= 1) {
        s  += __shfl_xor_sync(0xffffffffu, s,  o);
        sq += __shfl_xor_sync(0xffffffffu, sq, o);
    }
    __shared__ float red[8];
    const int w = tid >> 5;
    if ((tid & 31) == 0) { red[w] = s; red[4 + w] = sq; }
    __syncthreads();
    const float st  = red[0] + red[1] + red[2] + red[3];
    const float sqt = red[4] + red[5] + red[6] + red[7];
    const float mu  = st * (1.0f / NDIM);
    const float var = sqt * (1.0f / NDIM) - mu * mu;
    const float inv = rsqrtf(var + 1e-5f);

    float4 gg = ((const float4*)g)[tid];
    float4 bb = ((const float4*)b)[tid];
    __half2 a, c;
    a.x = __float2half_rn((v.x - mu) * inv * gg.x + bb.x);
    a.y = __float2half_rn((v.y - mu) * inv * gg.y + bb.y);
    c.x = __float2half_rn((v.z - mu) * inv * gg.z + bb.z);
    c.y = __float2half_rn((v.w - mu) * inv * gg.w + bb.w);
    const size_t base = (size_t)row * NDIM + tid * 4;
    *(__half2*)(yh + base) = a;
    *(__half2*)(yh + base + 2) = c;
}

// ====== dense fp16 mma GEMM, 3-stage cp.async pipeline =======================
// NTERM=2: A hi + B hi/lo (hh+hl). NTERM=1: A hi + B hi (hh only).
// SPLIT: 0 = fp32 out (+bias,+res); 2 = half hi-only out.
// Stage layout: [A | Bh | (Bl)] each 128x40 halves; 3 stages.
#define LDS 40
#define ARR   (128*LDS)
#define ARRB  (ARR*2)
#define MMA_SMEM2 (3*3*ARRB)   // 92160
#define MMA_SMEM1 (3*2*ARRB)   // 61440

template<int SPLIT, int ACT, int NTERM>
__global__ __launch_bounds__(256, 2) void mma2_kernel(
    const __half* __restrict__ Ah,
    const __half* __restrict__ Bh, const __half* __restrict__ Bl,
    float* __restrict__ Cf, __half* __restrict__ Ch,
    const float* __restrict__ bias, const float* __restrict__ res,
    int M, int N, int K)
{
    constexpr uint32_t STAGEB = (NTERM >= 2 ? 3u : 2u) * ARRB;
    extern __shared__ char dsm[];
    const uint32_t sbase = smem_u32(dsm);
    const int tid = threadIdx.x, wid = tid >> 5, lane = tid & 31;
    const int wm = wid >> 2, wn = wid & 3;
    const int bm = blockIdx.y * 128, bn = blockIdx.x * 128;

    const int lrow = tid >> 2, lcc = (tid & 3) * 8;
    const int lrow2 = (tid + 256) >> 2, lcc2 = ((tid + 256) & 3) * 8;

#define MMA2_ISSUE(kt, s) do {                                                   \
        const uint32_t st_ = sbase + (uint32_t)(s) * STAGEB;                     \
        const int k0_ = (kt) * 32;                                               \
        cp16(st_ + (uint32_t)((lrow * LDS + lcc) * 2),                           \
             Ah + (size_t)(bm + lrow) * K + k0_ + lcc);                          \
        cp16(st_ + (uint32_t)((lrow2 * LDS + lcc2) * 2),                         \
             Ah + (size_t)(bm + lrow2) * K + k0_ + lcc2);                        \
        cp16(st_ + (uint32_t)ARRB + (uint32_t)((lrow * LDS + lcc) * 2),          \
             Bh + (size_t)(bn + lrow) * K + k0_ + lcc);                          \
        cp16(st_ + (uint32_t)ARRB + (uint32_t)((lrow2 * LDS + lcc2) * 2),        \
             Bh + (size_t)(bn + lrow2) * K + k0_ + lcc2);                        \
        if (NTERM >= 2) {                                                        \
            cp16(st_ + (uint32_t)(2 * ARRB) + (uint32_t)((lrow * LDS + lcc) * 2),\
                 Bl + (size_t)(bn + lrow) * K + k0_ + lcc);                      \
            cp16(st_ + (uint32_t)(2 * ARRB) + (uint32_t)((lrow2 * LDS + lcc2) * 2),\
                 Bl + (size_t)(bn + lrow2) * K + k0_ + lcc2);                    \
        }                                                                        \
    } while (0)

    const int l15 = lane & 15;
    const uint32_t aoff = (uint32_t)(((wm * 64 + l15) * LDS + ((lane >> 4) << 3)) * 2);
    const uint32_t boff = (uint32_t)(((wn * 32 + (l15 & 7)) * LDS + (((l15 >> 3) & 1) << 3)) * 2);

    float acc[4][4][4];
#pragma unroll
    for (int i = 0; i < 4; ++i)
#pragma unroll
        for (int j = 0; j < 4; ++j)
#pragma unroll
            for (int q = 0; q < 4; ++q) acc[i][j][q] = 0.0f;

    const int NKT = K >> 5;
    MMA2_ISSUE(0, 0);
    CP_COMMIT();
    MMA2_ISSUE(1, 1);
    CP_COMMIT();

    for (int kt = 0; kt < NKT; ++kt) {
        if (kt + 1 < NKT) { CP_WAIT(1); } else { CP_WAIT(0); }
        __syncthreads();
        if (kt + 2 < NKT) {
            MMA2_ISSUE(kt + 2, (kt + 2) % 3);
            CP_COMMIT();
        }
        const uint32_t st = sbase + (uint32_t)(kt % 3) * STAGEB;
        const uint32_t aAh = st;
        const uint32_t aBh = st + ARRB, aBl = st + 2 * ARRB;
#pragma unroll
        for (int kk = 0; kk < 32; kk += 16) {
            uint32_t bh[4][2], bl[4][2], a[4][4];
#pragma unroll
            for (int nt = 0; nt < 4; ++nt) {
                const uint32_t bo = boff + (uint32_t)((nt * 8 * LDS + kk) * 2);
                ldm_x2(bh[nt], aBh + bo);
                if (NTERM >= 2) ldm_x2(bl[nt], aBl + bo);
            }
#pragma unroll
            for (int mt = 0; mt < 4; ++mt)
                ldm_x4(a[mt], aAh + aoff + (uint32_t)((mt * 16 * LDS + kk) * 2));
#pragma unroll
            for (int mt = 0; mt < 4; ++mt)
#pragma unroll
                for (int nt = 0; nt < 4; ++nt) {
                    mma_f16(acc[mt][nt], a[mt], bh[nt]);
                    if (NTERM >= 2) mma_f16(acc[mt][nt], a[mt], bl[nt]);
                }
        }
    }
#undef MMA2_ISSUE
    __syncthreads();

    const int g = lane >> 2, t2 = (lane & 3) * 2;
#pragma unroll
    for (int mt = 0; mt < 4; ++mt) {
#pragma unroll
        for (int nt = 0; nt < 4; ++nt) {
            const int r0 = bm + wm * 64 + mt * 16 + g;
            const int r1 = r0 + 8;
            const int c  = bn + wn * 32 + nt * 8 + t2;
            float v0 = acc[mt][nt][0], v1 = acc[mt][nt][1];
            float v2 = acc[mt][nt][2], v3 = acc[mt][nt][3];
            if (bias) {
                const float b0 = bias[c], b1 = bias[c + 1];
                v0 += b0; v1 += b1; v2 += b0; v3 += b1;
            }
            if (ACT) {
                v0 = gelu_exact(v0); v1 = gelu_exact(v1);
                v2 = gelu_exact(v2); v3 = gelu_exact(v3);
            }
            if (SPLIT == 2) {
                __half2 hp;
                hp.x = __float2half_rn(v0); hp.y = __float2half_rn(v1);
                *(__half2*)(Ch + (size_t)r0 * N + c) = hp;
                hp.x = __float2half_rn(v2); hp.y = __float2half_rn(v3);
                *(__half2*)(Ch + (size_t)r1 * N + c) = hp;
            } else {
                if (res) {
                    const float2 q0 = *(const float2*)(res + (size_t)r0 * N + c);
                    const float2 q1 = *(const float2*)(res + (size_t)r1 * N + c);
                    v0 += q0.x; v1 += q0.y; v2 += q1.x; v3 += q1.y;
                }
                *(float2*)(Cf + (size_t)r0 * N + c) = make_float2(v0, v1);
                *(float2*)(Cf + (size_t)r1 * N + c) = make_float2(v2, v3);
            }
        }
    }
}

// ---------------- bias rank-1 terms (hi-only inputs) -------------------------
__global__ __launch_bounds__(256) void bias_terms_kernel(
    const __half* __restrict__ qkvh, const __half* __restrict__ krh,
    const float* __restrict__ bias_pf,
    float* __restrict__ bk, float* __restrict__ br)
{
    const int idx = blockIdx.x * 256 + threadIdx.x;
    const int bh = idx >> 10, j = idx & 1023;
    const int b = bh >> 3, h = bh & 7;
    const size_t kb = ((size_t)b * NSEQ + j) * 1536 + 512 + h * 64;
    const size_t rb = ((size_t)b * NSEQ + j) * 512 + h * 64;
    float sk = 0.0f, sr = 0.0f;
#pragma unroll 16
    for (int d = 0; d < 64; ++d) {
        const float bp = bias_pf[h * 64 + d];
        sk += bp * __half2float(qkvh[kb + d]);
        sr += bp * __half2float(krh[rb + d]);
    }
    bk[idx] = sk;
    br[idx] = sr;
}

// =========== acbd fp16 mma, 1-term (A=Q hi; B=K/KR hi) =======================
#define ACBD_STAGE (2*ARR)
#define ACBD_SMEM  (2*ACBD_STAGE*2)   // 40960 bytes

__global__ __launch_bounds__(256, 2) void acbd1_kernel(
    const __half* __restrict__ qkvh, const __half* __restrict__ krh,
    const float* __restrict__ bk, const float* __restrict__ br,
    float* __restrict__ AC, float* __restrict__ BD)
{
    extern __shared__ char dsm[];
    const uint32_t sbase = smem_u32(dsm);
    const int tid = threadIdx.x, wid = tid >> 5, lane = tid & 31;
    const int wm = wid >> 2, wn = wid & 3;
    const int z = blockIdx.z, bh_idx = z & 63, isBD = z >> 6;
    const int b = bh_idx >> 3, h = bh_idx & 7;
    const int i0 = blockIdx.y * 128, j0 = blockIdx.x * 128;

    const __half* Ah = qkvh + ((size_t)b * NSEQ + i0) * 1536 + h * 64;
    const __half* Bh = isBD ? (krh + ((size_t)b * NSEQ + j0) * 512 + h * 64)
                            : (qkvh + ((size_t)b * NSEQ + j0) * 1536 + 512 + h * 64);
    const int ldb = isBD ? 512 : 1536;
    float* Cbase = (isBD ? BD : AC) + (size_t)bh_idx * NSEQ * NSEQ;
    const float* bvec = (isBD ? br : bk) + (size_t)bh_idx * NSEQ;

    const int lrow = tid >> 2, lcc = (tid & 3) * 8;
    const int lrow2 = (tid + 256) >> 2, lcc2 = ((tid + 256) & 3) * 8;

#define ACBD_ISSUE(kt, s) do {                                                   \
        const uint32_t st_ = sbase + (uint32_t)(s) * (ACBD_STAGE * 2);           \
        const int k0_ = (kt) * 32;                                               \
        cp16(st_ + (uint32_t)((lrow * LDS + lcc) * 2),                           \
             Ah + (size_t)lrow * 1536 + k0_ + lcc);                              \
        cp16(st_ + (uint32_t)((lrow2 * LDS + lcc2) * 2),                         \
             Ah + (size_t)lrow2 * 1536 + k0_ + lcc2);                            \
        cp16(st_ + (uint32_t)(ARR * 2) + (uint32_t)((lrow * LDS + lcc) * 2),     \
             Bh + (size_t)lrow * ldb + k0_ + lcc);                               \
        cp16(st_ + (uint32_t)(ARR * 2) + (uint32_t)((lrow2 * LDS + lcc2) * 2),   \
             Bh + (size_t)lrow2 * ldb + k0_ + lcc2);                             \
    } while (0)

    const int l15 = lane & 15;
    const uint32_t aoff = (uint32_t)(((wm * 64 + l15) * LDS + ((lane >> 4) << 3)) * 2);
    const uint32_t boff = (uint32_t)(((wn * 32 + (l15 & 7)) * LDS + (((l15 >> 3) & 1) << 3)) * 2);

    float acc[4][4][4];
#pragma unroll
    for (int i = 0; i < 4; ++i)
#pragma unroll
        for (int j = 0; j < 4; ++j)
#pragma unroll
            for (int q = 0; q < 4; ++q) acc[i][j][q] = 0.0f;

    ACBD_ISSUE(0, 0);
    CP_COMMIT();
#pragma unroll
    for (int kt = 0; kt < 2; ++kt) {
        if (kt == 0) {
            ACBD_ISSUE(1, 1);
            CP_COMMIT();
            CP_WAIT(1);
        } else {
            CP_WAIT(0);
        }
        __syncthreads();
        const uint32_t st = sbase + (uint32_t)(kt & 1) * (ACBD_STAGE * 2);
        const uint32_t aAh = st, aBh = st + ARR * 2;
#pragma unroll
        for (int kk = 0; kk < 32; kk += 16) {
            uint32_t bh[4][2], a[4][4];
#pragma unroll
            for (int nt = 0; nt < 4; ++nt)
                ldm_x2(bh[nt], aBh + boff + (uint32_t)((nt * 8 * LDS + kk) * 2));
#pragma unroll
            for (int mt = 0; mt < 4; ++mt)
                ldm_x4(a[mt], aAh + aoff + (uint32_t)((mt * 16 * LDS + kk) * 2));
#pragma unroll
            for (int mt = 0; mt < 4; ++mt)
#pragma unroll
                for (int nt = 0; nt < 4; ++nt)
                    mma_f16(acc[mt][nt], a[mt], bh[nt]);
        }
        __syncthreads();
    }
#undef ACBD_ISSUE

    const int g = lane >> 2, t2 = (lane & 3) * 2;
#pragma unroll
    for (int mt = 0; mt < 4; ++mt) {
#pragma unroll
        for (int nt = 0; nt < 4; ++nt) {
            const int r0 = i0 + wm * 64 + mt * 16 + g;
            const int c  = j0 + wn * 32 + nt * 8 + t2;
            const float b0 = bvec[c], b1 = bvec[c + 1];
            *(float2*)(Cbase + (size_t)r0 * NSEQ + c) =
                make_float2(acc[mt][nt][0] + b0, acc[mt][nt][1] + b1);
            *(float2*)(Cbase + (size_t)(r0 + 8) * NSEQ + c) =
                make_float2(acc[mt][nt][2] + b0, acc[mt][nt][3] + b1);
        }
    }
}

// ---------------- V transpose (hi only) --------------------------------------
__global__ __launch_bounds__(256) void vt_kernel(
    const __half* __restrict__ qkvh, __half* __restrict__ vth)
{
    __shared__ __half th[32][33];
    const int bh = blockIdx.z, b = bh >> 3, h = bh & 7;
    const int j0 = blockIdx.x * 32, d0 = blockIdx.y * 32;
    const int x = threadIdx.x, y = threadIdx.y;
#pragma unroll
    for (int i = 0; i < 32; i += 8)
        th[y + i][x] = qkvh[((size_t)b * NSEQ + j0 + y + i) * 1536 + 1024 + h * 64 + d0 + x];
    __syncthreads();
#pragma unroll
    for (int i = 0; i < 32; i += 8)
        vth[((size_t)bh * 64 + d0 + y + i) * NSEQ + j0 + x] = th[x][y + i];
}

// ======= FUSED shift+scale+softmax(heads) + attn@V (fp16 1-term) =============
#define SAV_ATT_H 0
#define SAV_V_H   40960
#define SAV_SMEM  81920

__global__ __launch_bounds__(512, 1) void fused_sav_kernel(
    const float* __restrict__ AC, const float* __restrict__ BDp,
    const __half* __restrict__ vth,
    __half* __restrict__ outh, float* __restrict__ attnf)
{
    extern __shared__ char dsm[];
    const uint32_t sb = smem_u32(dsm);
    const int tid = threadIdx.x, wid = tid >> 5, lane = tid & 31;
    const int b = blockIdx.y;
    const int i0 = blockIdx.x * 64;
    const int bq = b * NHEADS;

    const int ibA = tid >> 4;
    const int jjA = (tid & 15) * 2;

    const int h = wid & 7, ihalf = wid >> 3;
    const int l15 = lane & 15;
    const uint32_t headOff = (uint32_t)(h * 64 * 40 * 2);
    const uint32_t aAH = sb + SAV_ATT_H + headOff;
    const uint32_t aVH = sb + SAV_V_H + headOff;
    const uint32_t aoff = (uint32_t)(((ihalf * 32 + l15) * 40 + ((lane >> 4) << 3)) * 2);
    const uint32_t boff = (uint32_t)(((l15 & 7) * 40 + (((l15 >> 3) & 1) << 3)) * 2);

    float acc[2][8][4];
#pragma unroll
    for (int i = 0; i < 2; ++i)
#pragma unroll
        for (int j = 0; j < 8; ++j)
#pragma unroll
            for (int q = 0; q < 4; ++q) acc[i][j][q] = 0.0f;

    for (int kt = 0; kt < 32; ++kt) {
        const int j0 = kt * 32;
#pragma unroll
        for (int k = 0; k < 4; ++k) {
            const int idx = tid + k * 512;
            const int hv = idx >> 8;
            const int r = idx & 255;
            const int d = r >> 2, seg = r & 3;
            const uint32_t so = (uint32_t)((hv * 64 + d) * 80 + seg * 16);
            const size_t gsrc = (((size_t)(bq + hv) * 64 + d) << 10) + j0 + seg * 8;
            cp16(sb + SAV_V_H + so, vth + gsrc);
        }
        CP_COMMIT();

#pragma unroll
        for (int it = 0; it < 2; ++it) {
            const int i = ibA + it * 32;
            const int gi = i0 + i;
            float p0[8], p1[8];
#pragma unroll
            for (int e = 0; e < 2; ++e) {
                const int gj = j0 + jjA + e;
                const int g = (gi + 1) * NSEQ + gj;
                const int si = g / (NSEQ + 1);
                const int sj = g % (NSEQ + 1) - 1;
                float v[8];
                float mx = -1e30f;
#pragma unroll
                for (int hh = 0; hh < 8; ++hh) {
                    const size_t base = (size_t)(bq + hh) * NSEQ;
                    float d = AC[(base + gi) * NSEQ + gj];
                    if (sj >= 0) d += BDp[(base + si) * NSEQ + sj];
                    d *= 0.125f;
                    v[hh] = d;
                    mx = fmaxf(mx, d);
                }
                float s = 0.0f;
#pragma unroll
                for (int hh = 0; hh < 8; ++hh) { v[hh] = __expf(v[hh] - mx); s += v[hh]; }
                const float inv = 1.0f / s;
                float* pp = e ? p1 : p0;
#pragma unroll
                for (int hh = 0; hh < 8; ++hh) pp[hh] = v[hh] * inv;
            }
#pragma unroll
            for (int hh = 0; hh < 8; ++hh) {
                __half2 hp;
                hp.x = __float2half_rn(p0[hh]);
                hp.y = __float2half_rn(p1[hh]);
                const uint32_t so = (uint32_t)(((hh * 64 + i) * 40 + jjA) * 2);
                *(__half2*)(dsm + SAV_ATT_H + so) = hp;
                if (attnf) {
                    *(float2*)(attnf + ((size_t)(bq + hh) * NSEQ + gi) * NSEQ + j0 + jjA) =
                        make_float2(p0[hh], p1[hh]);
                }
            }
        }
        CP_WAIT(0);
        __syncthreads();

#pragma unroll
        for (int kk = 0; kk < 32; kk += 16) {
            uint32_t bhf[8][2], ah[2][4];
#pragma unroll
            for (int nt = 0; nt < 8; ++nt)
                ldm_x2(bhf[nt], aVH + boff + (uint32_t)((nt * 8 * 40 + kk) * 2));
#pragma unroll
            for (int mt = 0; mt < 2; ++mt)
                ldm_x4(ah[mt], aAH + aoff + (uint32_t)((mt * 16 * 40 + kk) * 2));
#pragma unroll
            for (int mt = 0; mt < 2; ++mt)
#pragma unroll
                for (int nt = 0; nt < 8; ++nt)
                    mma_f16(acc[mt][nt], ah[mt], bhf[nt]);
        }
        __syncthreads();
    }

    const int g = lane >> 2, t2 = (lane & 3) * 2;
#pragma unroll
    for (int mt = 0; mt < 2; ++mt) {
#pragma unroll
        for (int nt = 0; nt < 8; ++nt) {
            const int r0 = i0 + ihalf * 32 + mt * 16 + g;
            const int c  = h * 64 + nt * 8 + t2;
            __half2 hp;
            hp.x = __float2half_rn(acc[mt][nt][0]);
            hp.y = __float2half_rn(acc[mt][nt][1]);
            *(__half2*)(outh + ((size_t)b * NSEQ + r0) * NHD + c) = hp;
            hp.x = __float2half_rn(acc[mt][nt][2]);
            hp.y = __float2half_rn(acc[mt][nt][3]);
            *(__half2*)(outh + ((size_t)b * NSEQ + r0 + 8) * NHD + c) = hp;
        }
    }
}

// ---------------- host orchestration ----------------------------------------
extern "C" void kernel_launch(void* const* d_in, const int* in_sizes, int n_in,
                              void* d_out, int out_size)
{
    (void)in_sizes; (void)n_in;
    const float* x_in    = (const float*)d_in[0];
    const float* r_t     = (const float*)d_in[1];
    const float* bias_pf = (const float*)d_in[3];
    const float* ln1_g   = (const float*)d_in[4];
    const float* ln1_b   = (const float*)d_in[5];
    const float* Wqkv    = (const float*)d_in[6];
    const float* Wkr_t   = (const float*)d_in[7];
    const float* Wout    = (const float*)d_in[9];
    const float* bout    = (const float*)d_in[10];
    const float* ln2_g   = (const float*)d_in[11];
    const float* ln2_b   = (const float*)d_in[12];
    const float* W1      = (const float*)d_in[13];
    const float* b1      = (const float*)d_in[14];
    const float* W2      = (const float*)d_in[15];
    const float* b2      = (const float*)d_in[16];
    float* outp = (float*)d_out;

    static int attr_done = 0;
    if (!attr_done) {
        cudaFuncSetAttribute(mma2_kernel<2,0,2>, cudaFuncAttributeMaxDynamicSharedMemorySize, MMA_SMEM2);
        cudaFuncSetAttribute(mma2_kernel<0,0,2>, cudaFuncAttributeMaxDynamicSharedMemorySize, MMA_SMEM2);
        cudaFuncSetAttribute(mma2_kernel<2,1,1>, cudaFuncAttributeMaxDynamicSharedMemorySize, MMA_SMEM1);
        cudaFuncSetAttribute(mma2_kernel<0,0,1>, cudaFuncAttributeMaxDynamicSharedMemorySize, MMA_SMEM1);
        cudaFuncSetAttribute(acbd1_kernel,       cudaFuncAttributeMaxDynamicSharedMemorySize, ACBD_SMEM);
        cudaFuncSetAttribute(fused_sav_kernel,   cudaFuncAttributeMaxDynamicSharedMemorySize, SAV_SMEM);
        attr_done = 1;
    }

    float *gx, *gac, *gbd, *gbk, *gbr;
    __half *gxnh, *grth, *gqkvh, *gkrh, *gavh, *gffh, *gwth, *gwtl, *gvth;
    cudaGetSymbolAddress((void**)&gx,    g_x);
    cudaGetSymbolAddress((void**)&gac,   g_ac);
    cudaGetSymbolAddress((void**)&gbd,   g_bd);
    cudaGetSymbolAddress((void**)&gbk,   g_bk);
    cudaGetSymbolAddress((void**)&gbr,   g_br);
    cudaGetSymbolAddress((void**)&gxnh,  g_xnh);
    cudaGetSymbolAddress((void**)&grth,  g_rth);
    cudaGetSymbolAddress((void**)&gqkvh, g_qkvh);
    cudaGetSymbolAddress((void**)&gkrh,  g_krh);
    cudaGetSymbolAddress((void**)&gavh,  g_avh);
    cudaGetSymbolAddress((void**)&gffh,  g_ffh);
    cudaGetSymbolAddress((void**)&gwth,  g_wth);
    cudaGetSymbolAddress((void**)&gwtl,  g_wtl);
    cudaGetSymbolAddress((void**)&gvth,  g_vth);

    float* attn_out = outp + ((size_t)out_size - ATT_ELEMS);

    cudaMemcpyAsync(gx, x_in, X_ELEMS * sizeof(float), cudaMemcpyDeviceToDevice, 0);
    split_rt_kernel<<<X_ELEMS / 1024, 256>>>(r_t, grth);

    transpose_all_kernel<<<dim3(3328, 4), dim3(32, 8)>>>(
        Wqkv, Wkr_t, Wout, W1, W2, gwth, gwtl);

    const dim3 tb(32, 8);
    for (int l = 0; l < 4; ++l) {
        const size_t wb = (size_t)l * WT_TOTAL;

        ln_half_kernel<<<MROWS, 128>>>(gx, ln1_g + l * NDIM, ln1_b + l * NDIM, gxnh);
        // qkv: 2-term (A = xn hi; B hi/lo), hi-only output
        mma2_kernel<2,0,2><<<dim3(12, 64), 256, MMA_SMEM2>>>(
            gxnh, gwth + wb + WQKVT, gwtl + wb + WQKVT,
            nullptr, gqkvh, nullptr, nullptr, MROWS, 1536, 512);
        // kr: 2-term, hi-only output
        mma2_kernel<2,0,2><<<dim3(4, 64), 256, MMA_SMEM2>>>(
            grth, gwth + wb + WKRT, gwtl + wb + WKRT,
            nullptr, gkrh, nullptr, nullptr, MROWS, 512, 512);

        bias_terms_kernel<<<256, 256>>>(gqkvh, gkrh, bias_pf, gbk, gbr);

        // acbd: 1-term (Q hi x K/KR hi)
        acbd1_kernel<<<dim3(8, 8, 128), 256, ACBD_SMEM>>>(
            gqkvh, gkrh, gbk, gbr, gac, gbd);

        vt_kernel<<<dim3(32, 2, 64), tb>>>(gqkvh, gvth);

        fused_sav_kernel<<<dim3(16, 8), 512, SAV_SMEM>>>(
            gac, gbd, gvth, gavh, (l == 3) ? attn_out : nullptr);

        // Wout: 2-term, fp32 out + residual
        mma2_kernel<0,0,2><<<dim3(4, 64), 256, MMA_SMEM2>>>(
            gavh, gwth + wb + WOUTT, gwtl + wb + WOUTT,
            gx, nullptr, bout + l * NDIM, gx, MROWS, 512, 512);

        ln_half_kernel<<<MROWS, 128>>>(gx, ln2_g + l * NDIM, ln2_b + l * NDIM, gxnh);
        // W1: 1-term, gelu, half hi out
        mma2_kernel<2,1,1><<<dim3(16, 64), 256, MMA_SMEM1>>>(
            gxnh, gwth + wb + W1T, gwth + wb + W1T,
            nullptr, gffh, b1 + l * NFF, nullptr, MROWS, 2048, 512);
        float* xdst = (l == 3) ? outp : gx;
        // W2: 1-term, fp32 out + residual
        mma2_kernel<0,0,1><<<dim3(4, 64), 256, MMA_SMEM1>>>(
            gffh, gwth + wb + W2T, gwth + wb + W2T,
            xdst, nullptr, b2 + l * NDIM, gx, MROWS, 512, 2048);
    }
}

// round 14
// speedup vs baseline: 1.7197x; 1.0524x over previous
#include <cuda_runtime.h>
#include <cuda_fp16.h>
#include <math.h>
#include <stdint.h>

#define NSEQ   1024
#define NBATCH 8
#define NDIM   512
#define NHEADS 8
#define NDH    64
#define NHD    512
#define NFF    2048
#define MROWS  (NBATCH*NSEQ)
#define ATT_ELEMS ((size_t)NBATCH*NHEADS*NSEQ*NSEQ)
#define X_ELEMS   ((size_t)MROWS*NDIM)

// transposed weight offsets (elements, within one layer's block)
#define WQKVT 0
#define WKRT  786432
#define WOUTT 1048576
#define W1T   1310720
#define W2T   2359296
#define WT_TOTAL 3407872

// ---------------- scratch --------------------------------------------------
static __device__ float g_x [MROWS*NDIM];
static __device__ float g_bk[NBATCH*NHEADS*NSEQ];
static __device__ float g_br[NBATCH*NHEADS*NSEQ];
static __device__ __half g_ac[NBATCH*NHEADS*NSEQ*NSEQ];
static __device__ __half g_bd[NBATCH*NHEADS*NSEQ*NSEQ];
static __device__ __half g_xnh [MROWS*NDIM];
static __device__ __half g_rth [MROWS*NDIM];
static __device__ __half g_qkvh[MROWS*3*NHD];
static __device__ __half g_krh [MROWS*NHD];
static __device__ __half g_avh [MROWS*NHD];
static __device__ __half g_ffh [MROWS*NFF];
static __device__ __half g_wth [4*WT_TOTAL],  g_wtl [4*WT_TOTAL];
static __device__ __half g_vth [NBATCH*NHEADS*NDH*NSEQ];

// ---------------- primitives ------------------------------------------------
__device__ __forceinline__ uint32_t smem_u32(const void* p) {
    uint32_t a;
    asm("{ .reg .u64 t; cvta.to.shared.u64 t, %1; cvt.u32.u64 %0, t; }"
        : "=r"(a) : "l"(p));
    return a;
}
__device__ __forceinline__ void cp16(uint32_t dst, const void* src) {
    asm volatile("cp.async.cg.shared.global [%0], [%1], 16;" :: "r"(dst), "l"(src));
}
#define CP_COMMIT() asm volatile("cp.async.commit_group;")
#define CP_WAIT(n)  asm volatile("cp.async.wait_group %0;" :: "n"(n))

__device__ __forceinline__ void mma_f16(float* d, const uint32_t* a, const uint32_t* b) {
    asm volatile(
        "mma.sync.aligned.m16n8k16.row.col.f32.f16.f16.f32 "
        "{%0,%1,%2,%3}, {%4,%5,%6,%7}, {%8,%9}, {%0,%1,%2,%3};"
        : "+f"(d[0]), "+f"(d[1]), "+f"(d[2]), "+f"(d[3])
        : "r"(a[0]), "r"(a[1]), "r"(a[2]), "r"(a[3]), "r"(b[0]), "r"(b[1]));
}
__device__ __forceinline__ void ldm_x4(uint32_t* r, uint32_t addr) {
    asm volatile("ldmatrix.sync.aligned.m8n8.x4.shared.b16 {%0,%1,%2,%3}, [%4];"
        : "=r"(r[0]), "=r"(r[1]), "=r"(r[2]), "=r"(r[3]) : "r"(addr));
}
__device__ __forceinline__ void ldm_x2(uint32_t* r, uint32_t addr) {
    asm volatile("ldmatrix.sync.aligned.m8n8.x2.shared.b16 {%0,%1}, [%2];"
        : "=r"(r[0]), "=r"(r[1]) : "r"(addr));
}
__device__ __forceinline__ float gelu_exact(float v) {
    return 0.5f * v * (1.0f + erff(v * 0.70710678118654752f));
}
__device__ __forceinline__ void split1(float v, __half& h, __half& l) {
    h = __float2half_rn(v);
    l = __float2half_rn(v - __half2float(h));
}

// ---------- merged weight transpose+split for ALL layers: one launch --------
__global__ __launch_bounds__(256) void transpose_all_kernel(
    const float* __restrict__ Wqkv, const float* __restrict__ Wkr,
    const float* __restrict__ Wout, const float* __restrict__ W1,
    const float* __restrict__ W2,
    __half* __restrict__ Wth, __half* __restrict__ Wtl)
{
    __shared__ float t[32][33];
    const int l = blockIdx.y;
    const int tt = blockIdx.x;
    const float* W; int K, N, off, tloc;
    if (tt < 768)       { W = Wqkv + (size_t)l * 786432;  K = 512;  N = 1536; off = WQKVT; tloc = tt; }
    else if (tt < 1024) { W = Wkr  + (size_t)l * 262144;  K = 512;  N = 512;  off = WKRT;  tloc = tt - 768; }
    else if (tt < 1280) { W = Wout + (size_t)l * 262144;  K = 512;  N = 512;  off = WOUTT; tloc = tt - 1024; }
    else if (tt < 2304) { W = W1   + (size_t)l * 1048576; K = 512;  N = 2048; off = W1T;   tloc = tt - 1280; }
    else                { W = W2   + (size_t)l * 1048576; K = 2048; N = 512;  off = W2T;   tloc = tt - 2304; }
    const int ntn = N >> 5;
    const int kt = tloc / ntn, nt = tloc % ntn;
    const int k0 = kt * 32, n0 = nt * 32;
    const int x = threadIdx.x, y = threadIdx.y;
    const size_t dst = (size_t)l * WT_TOTAL + off;
#pragma unroll
    for (int i = 0; i < 32; i += 8)
        t[y + i][x] = W[(size_t)(k0 + y + i) * N + n0 + x];
    __syncthreads();
#pragma unroll
    for (int i = 0; i < 32; i += 8) {
        float v = t[x][y + i];
        __half h, lo; split1(v, h, lo);
        Wth[dst + (size_t)(n0 + y + i) * K + k0 + x] = h;
        Wtl[dst + (size_t)(n0 + y + i) * K + k0 + x] = lo;
    }
}

// ---------------- r_t -> fp16 hi only ----------------------------------------
__global__ __launch_bounds__(256) void split_rt_kernel(
    const float* __restrict__ src, __half* __restrict__ dh)
{
    const size_t i = ((size_t)blockIdx.x * 256 + threadIdx.x) * 4;
    float4 v = *(const float4*)(src + i);
    __half2 a, b;
    a.x = __float2half_rn(v.x); a.y = __float2half_rn(v.y);
    b.x = __float2half_rn(v.z); b.y = __float2half_rn(v.w);
    *(__half2*)(dh + i) = a;
    *(__half2*)(dh + i + 2) = b;
}

// ---------------- LayerNorm -> fp16 hi only ----------------------------------
__global__ __launch_bounds__(128) void ln_half_kernel(
    const float* __restrict__ x, const float* __restrict__ g,
    const float* __restrict__ b, __half* __restrict__ yh)
{
    const int row = blockIdx.x;
    const int tid = threadIdx.x;
    const float* xr = x + (size_t)row * NDIM;

    float4 v = ((const float4*)xr)[tid];
    float s  = v.x + v.y + v.z + v.w;
    float sq = v.x*v.x + v.y*v.y + v.z*v.z + v.w*v.w;
#pragma unroll
    for (int o = 16; o > 0; o >>= 1) {
        s  += __shfl_xor_sync(0xffffffffu, s,  o);
        sq += __shfl_xor_sync(0xffffffffu, sq, o);
    }
    __shared__ float red[8];
    const int w = tid >> 5;
    if ((tid & 31) == 0) { red[w] = s; red[4 + w] = sq; }
    __syncthreads();
    const float st  = red[0] + red[1] + red[2] + red[3];
    const float sqt = red[4] + red[5] + red[6] + red[7];
    const float mu  = st * (1.0f / NDIM);
    const float var = sqt * (1.0f / NDIM) - mu * mu;
    const float inv = rsqrtf(var + 1e-5f);

    float4 gg = ((const float4*)g)[tid];
    float4 bb = ((const float4*)b)[tid];
    __half2 a, c;
    a.x = __float2half_rn((v.x - mu) * inv * gg.x + bb.x);
    a.y = __float2half_rn((v.y - mu) * inv * gg.y + bb.y);
    c.x = __float2half_rn((v.z - mu) * inv * gg.z + bb.z);
    c.y = __float2half_rn((v.w - mu) * inv * gg.w + bb.w);
    const size_t base = (size_t)row * NDIM + tid * 4;
    *(__half2*)(yh + base) = a;
    *(__half2*)(yh + base + 2) = c;
}

// ====== dense fp16 mma GEMM, 3-stage cp.async pipeline =======================
#define LDS 40
#define ARR   (128*LDS)
#define ARRB  (ARR*2)
#define MMA_SMEM2 (3*3*ARRB)   // 92160
#define MMA_SMEM1 (3*2*ARRB)   // 61440

template<int SPLIT, int ACT, int NTERM>
__global__ __launch_bounds__(256, 2) void mma2_kernel(
    const __half* __restrict__ Ah,
    const __half* __restrict__ Bh, const __half* __restrict__ Bl,
    float* __restrict__ Cf, __half* __restrict__ Ch,
    const float* __restrict__ bias, const float* __restrict__ res,
    int M, int N, int K)
{
    constexpr uint32_t STAGEB = (NTERM >= 2 ? 3u : 2u) * ARRB;
    extern __shared__ char dsm[];
    const uint32_t sbase = smem_u32(dsm);
    const int tid = threadIdx.x, wid = tid >> 5, lane = tid & 31;
    const int wm = wid >> 2, wn = wid & 3;
    const int bm = blockIdx.y * 128, bn = blockIdx.x * 128;

    const int lrow = tid >> 2, lcc = (tid & 3) * 8;
    const int lrow2 = (tid + 256) >> 2, lcc2 = ((tid + 256) & 3) * 8;

#define MMA2_ISSUE(kt, s) do {                                                   \
        const uint32_t st_ = sbase + (uint32_t)(s) * STAGEB;                     \
        const int k0_ = (kt) * 32;                                               \
        cp16(st_ + (uint32_t)((lrow * LDS + lcc) * 2),                           \
             Ah + (size_t)(bm + lrow) * K + k0_ + lcc);                          \
        cp16(st_ + (uint32_t)((lrow2 * LDS + lcc2) * 2),                         \
             Ah + (size_t)(bm + lrow2) * K + k0_ + lcc2);                        \
        cp16(st_ + (uint32_t)ARRB + (uint32_t)((lrow * LDS + lcc) * 2),          \
             Bh + (size_t)(bn + lrow) * K + k0_ + lcc);                          \
        cp16(st_ + (uint32_t)ARRB + (uint32_t)((lrow2 * LDS + lcc2) * 2),        \
             Bh + (size_t)(bn + lrow2) * K + k0_ + lcc2);                        \
        if (NTERM >= 2) {                                                        \
            cp16(st_ + (uint32_t)(2 * ARRB) + (uint32_t)((lrow * LDS + lcc) * 2),\
                 Bl + (size_t)(bn + lrow) * K + k0_ + lcc);                      \
            cp16(st_ + (uint32_t)(2 * ARRB) + (uint32_t)((lrow2 * LDS + lcc2) * 2),\
                 Bl + (size_t)(bn + lrow2) * K + k0_ + lcc2);                    \
        }                                                                        \
    } while (0)

    const int l15 = lane & 15;
    const uint32_t aoff = (uint32_t)(((wm * 64 + l15) * LDS + ((lane >> 4) << 3)) * 2);
    const uint32_t boff = (uint32_t)(((wn * 32 + (l15 & 7)) * LDS + (((l15 >> 3) & 1) << 3)) * 2);

    float acc[4][4][4];
#pragma unroll
    for (int i = 0; i < 4; ++i)
#pragma unroll
        for (int j = 0; j < 4; ++j)
#pragma unroll
            for (int q = 0; q < 4; ++q) acc[i][j][q] = 0.0f;

    const int NKT = K >> 5;
    MMA2_ISSUE(0, 0);
    CP_COMMIT();
    MMA2_ISSUE(1, 1);
    CP_COMMIT();

    for (int kt = 0; kt < NKT; ++kt) {
        if (kt + 1 < NKT) { CP_WAIT(1); } else { CP_WAIT(0); }
        __syncthreads();
        if (kt + 2 < NKT) {
            MMA2_ISSUE(kt + 2, (kt + 2) % 3);
            CP_COMMIT();
        }
        const uint32_t st = sbase + (uint32_t)(kt % 3) * STAGEB;
        const uint32_t aAh = st;
        const uint32_t aBh = st + ARRB, aBl = st + 2 * ARRB;
#pragma unroll
        for (int kk = 0; kk < 32; kk += 16) {
            uint32_t bh[4][2], bl[4][2], a[4][4];
#pragma unroll
            for (int nt = 0; nt < 4; ++nt) {
                const uint32_t bo = boff + (uint32_t)((nt * 8 * LDS + kk) * 2);
                ldm_x2(bh[nt], aBh + bo);
                if (NTERM >= 2) ldm_x2(bl[nt], aBl + bo);
            }
#pragma unroll
            for (int mt = 0; mt < 4; ++mt)
                ldm_x4(a[mt], aAh + aoff + (uint32_t)((mt * 16 * LDS + kk) * 2));
#pragma unroll
            for (int mt = 0; mt < 4; ++mt)
#pragma unroll
                for (int nt = 0; nt < 4; ++nt) {
                    mma_f16(acc[mt][nt], a[mt], bh[nt]);
                    if (NTERM >= 2) mma_f16(acc[mt][nt], a[mt], bl[nt]);
                }
        }
    }
#undef MMA2_ISSUE
    __syncthreads();

    const int g = lane >> 2, t2 = (lane & 3) * 2;
#pragma unroll
    for (int mt = 0; mt < 4; ++mt) {
#pragma unroll
        for (int nt = 0; nt < 4; ++nt) {
            const int r0 = bm + wm * 64 + mt * 16 + g;
            const int r1 = r0 + 8;
            const int c  = bn + wn * 32 + nt * 8 + t2;
            float v0 = acc[mt][nt][0], v1 = acc[mt][nt][1];
            float v2 = acc[mt][nt][2], v3 = acc[mt][nt][3];
            if (bias) {
                const float b0 = bias[c], b1 = bias[c + 1];
                v0 += b0; v1 += b1; v2 += b0; v3 += b1;
            }
            if (ACT) {
                v0 = gelu_exact(v0); v1 = gelu_exact(v1);
                v2 = gelu_exact(v2); v3 = gelu_exact(v3);
            }
            if (SPLIT == 2) {
                __half2 hp;
                hp.x = __float2half_rn(v0); hp.y = __float2half_rn(v1);
                *(__half2*)(Ch + (size_t)r0 * N + c) = hp;
                hp.x = __float2half_rn(v2); hp.y = __float2half_rn(v3);
                *(__half2*)(Ch + (size_t)r1 * N + c) = hp;
            } else {
                if (res) {
                    const float2 q0 = *(const float2*)(res + (size_t)r0 * N + c);
                    const float2 q1 = *(const float2*)(res + (size_t)r1 * N + c);
                    v0 += q0.x; v1 += q0.y; v2 += q1.x; v3 += q1.y;
                }
                *(float2*)(Cf + (size_t)r0 * N + c) = make_float2(v0, v1);
                *(float2*)(Cf + (size_t)r1 * N + c) = make_float2(v2, v3);
            }
        }
    }
}

// ---------------- bias rank-1 terms (hi-only inputs) -------------------------
__global__ __launch_bounds__(256) void bias_terms_kernel(
    const __half* __restrict__ qkvh, const __half* __restrict__ krh,
    const float* __restrict__ bias_pf,
    float* __restrict__ bk, float* __restrict__ br)
{
    const int idx = blockIdx.x * 256 + threadIdx.x;
    const int bh = idx >> 10, j = idx & 1023;
    const int b = bh >> 3, h = bh & 7;
    const size_t kb = ((size_t)b * NSEQ + j) * 1536 + 512 + h * 64;
    const size_t rb = ((size_t)b * NSEQ + j) * 512 + h * 64;
    float sk = 0.0f, sr = 0.0f;
#pragma unroll 16
    for (int d = 0; d < 64; ++d) {
        const float bp = bias_pf[h * 64 + d];
        sk += bp * __half2float(qkvh[kb + d]);
        sr += bp * __half2float(krh[rb + d]);
    }
    bk[idx] = sk;
    br[idx] = sr;
}

// =========== acbd fp16 mma, 1-term; fp16 score output ========================
#define ACBD_STAGE (2*ARR)
#define ACBD_SMEM  (2*ACBD_STAGE*2)   // 40960 bytes

__global__ __launch_bounds__(256, 2) void acbd1_kernel(
    const __half* __restrict__ qkvh, const __half* __restrict__ krh,
    const float* __restrict__ bk, const float* __restrict__ br,
    __half* __restrict__ AC, __half* __restrict__ BD)
{
    extern __shared__ char dsm[];
    const uint32_t sbase = smem_u32(dsm);
    const int tid = threadIdx.x, wid = tid >> 5, lane = tid & 31;
    const int wm = wid >> 2, wn = wid & 3;
    const int z = blockIdx.z, bh_idx = z & 63, isBD = z >> 6;
    const int b = bh_idx >> 3, h = bh_idx & 7;
    const int i0 = blockIdx.y * 128, j0 = blockIdx.x * 128;

    const __half* Ah = qkvh + ((size_t)b * NSEQ + i0) * 1536 + h * 64;
    const __half* Bh = isBD ? (krh + ((size_t)b * NSEQ + j0) * 512 + h * 64)
                            : (qkvh + ((size_t)b * NSEQ + j0) * 1536 + 512 + h * 64);
    const int ldb = isBD ? 512 : 1536;
    __half* Cbase = (isBD ? BD : AC) + (size_t)bh_idx * NSEQ * NSEQ;
    const float* bvec = (isBD ? br : bk) + (size_t)bh_idx * NSEQ;

    const int lrow = tid >> 2, lcc = (tid & 3) * 8;
    const int lrow2 = (tid + 256) >> 2, lcc2 = ((tid + 256) & 3) * 8;

#define ACBD_ISSUE(kt, s) do {                                                   \
        const uint32_t st_ = sbase + (uint32_t)(s) * (ACBD_STAGE * 2);           \
        const int k0_ = (kt) * 32;                                               \
        cp16(st_ + (uint32_t)((lrow * LDS + lcc) * 2),                           \
             Ah + (size_t)lrow * 1536 + k0_ + lcc);                              \
        cp16(st_ + (uint32_t)((lrow2 * LDS + lcc2) * 2),                         \
             Ah + (size_t)lrow2 * 1536 + k0_ + lcc2);                            \
        cp16(st_ + (uint32_t)(ARR * 2) + (uint32_t)((lrow * LDS + lcc) * 2),     \
             Bh + (size_t)lrow * ldb + k0_ + lcc);                               \
        cp16(st_ + (uint32_t)(ARR * 2) + (uint32_t)((lrow2 * LDS + lcc2) * 2),   \
             Bh + (size_t)lrow2 * ldb + k0_ + lcc2);                             \
    } while (0)

    const int l15 = lane & 15;
    const uint32_t aoff = (uint32_t)(((wm * 64 + l15) * LDS + ((lane >> 4) << 3)) * 2);
    const uint32_t boff = (uint32_t)(((wn * 32 + (l15 & 7)) * LDS + (((l15 >> 3) & 1) << 3)) * 2);

    float acc[4][4][4];
#pragma unroll
    for (int i = 0; i < 4; ++i)
#pragma unroll
        for (int j = 0; j < 4; ++j)
#pragma unroll
            for (int q = 0; q < 4; ++q) acc[i][j][q] = 0.0f;

    ACBD_ISSUE(0, 0);
    CP_COMMIT();
#pragma unroll
    for (int kt = 0; kt < 2; ++kt) {
        if (kt == 0) {
            ACBD_ISSUE(1, 1);
            CP_COMMIT();
            CP_WAIT(1);
        } else {
            CP_WAIT(0);
        }
        __syncthreads();
        const uint32_t st = sbase + (uint32_t)(kt & 1) * (ACBD_STAGE * 2);
        const uint32_t aAh = st, aBh = st + ARR * 2;
#pragma unroll
        for (int kk = 0; kk < 32; kk += 16) {
            uint32_t bh[4][2], a[4][4];
#pragma unroll
            for (int nt = 0; nt < 4; ++nt)
                ldm_x2(bh[nt], aBh + boff + (uint32_t)((nt * 8 * LDS + kk) * 2));
#pragma unroll
            for (int mt = 0; mt < 4; ++mt)
                ldm_x4(a[mt], aAh + aoff + (uint32_t)((mt * 16 * LDS + kk) * 2));
#pragma unroll
            for (int mt = 0; mt < 4; ++mt)
#pragma unroll
                for (int nt = 0; nt < 4; ++nt)
                    mma_f16(acc[mt][nt], a[mt], bh[nt]);
        }
        __syncthreads();
    }
#undef ACBD_ISSUE

    const int g = lane >> 2, t2 = (lane & 3) * 2;
#pragma unroll
    for (int mt = 0; mt < 4; ++mt) {
#pragma unroll
        for (int nt = 0; nt < 4; ++nt) {
            const int r0 = i0 + wm * 64 + mt * 16 + g;
            const int c  = j0 + wn * 32 + nt * 8 + t2;
            const float b0 = bvec[c], b1 = bvec[c + 1];
            __half2 p;
            p.x = __float2half_rn(acc[mt][nt][0] + b0);
            p.y = __float2half_rn(acc[mt][nt][1] + b1);
            *(__half2*)(Cbase + (size_t)r0 * NSEQ + c) = p;
            p.x = __float2half_rn(acc[mt][nt][2] + b0);
            p.y = __float2half_rn(acc[mt][nt][3] + b1);
            *(__half2*)(Cbase + (size_t)(r0 + 8) * NSEQ + c) = p;
        }
    }
}

// ---------------- V transpose (hi only) --------------------------------------
__global__ __launch_bounds__(256) void vt_kernel(
    const __half* __restrict__ qkvh, __half* __restrict__ vth)
{
    __shared__ __half th[32][33];
    const int bh = blockIdx.z, b = bh >> 3, h = bh & 7;
    const int j0 = blockIdx.x * 32, d0 = blockIdx.y * 32;
    const int x = threadIdx.x, y = threadIdx.y;
#pragma unroll
    for (int i = 0; i < 32; i += 8)
        th[y + i][x] = qkvh[((size_t)b * NSEQ + j0 + y + i) * 1536 + 1024 + h * 64 + d0 + x];
    __syncthreads();
#pragma unroll
    for (int i = 0; i < 32; i += 8)
        vth[((size_t)bh * 64 + d0 + y + i) * NSEQ + j0 + x] = th[x][y + i];
}

// ======= FUSED shift+scale+softmax(heads) + attn@V (fp16 scores) =============
#define SAV_ATT_H 0
#define SAV_V_H   40960
#define SAV_SMEM  81920

__global__ __launch_bounds__(512, 1) void fused_sav_kernel(
    const __half* __restrict__ AC, const __half* __restrict__ BDp,
    const __half* __restrict__ vth,
    __half* __restrict__ outh, float* __restrict__ attnf)
{
    extern __shared__ char dsm[];
    const uint32_t sb = smem_u32(dsm);
    const int tid = threadIdx.x, wid = tid >> 5, lane = tid & 31;
    const int b = blockIdx.y;
    const int i0 = blockIdx.x * 64;
    const int bq = b * NHEADS;

    const int ibA = tid >> 4;
    const int jjA = (tid & 15) * 2;

    const int h = wid & 7, ihalf = wid >> 3;
    const int l15 = lane & 15;
    const uint32_t headOff = (uint32_t)(h * 64 * 40 * 2);
    const uint32_t aAH = sb + SAV_ATT_H + headOff;
    const uint32_t aVH = sb + SAV_V_H + headOff;
    const uint32_t aoff = (uint32_t)(((ihalf * 32 + l15) * 40 + ((lane >> 4) << 3)) * 2);
    const uint32_t boff = (uint32_t)(((l15 & 7) * 40 + (((l15 >> 3) & 1) << 3)) * 2);

    float acc[2][8][4];
#pragma unroll
    for (int i = 0; i < 2; ++i)
#pragma unroll
        for (int j = 0; j < 8; ++j)
#pragma unroll
            for (int q = 0; q < 4; ++q) acc[i][j][q] = 0.0f;

    for (int kt = 0; kt < 32; ++kt) {
        const int j0 = kt * 32;
#pragma unroll
        for (int k = 0; k < 4; ++k) {
            const int idx = tid + k * 512;
            const int hv = idx >> 8;
            const int r = idx & 255;
            const int d = r >> 2, seg = r & 3;
            const uint32_t so = (uint32_t)((hv * 64 + d) * 80 + seg * 16);
            const size_t gsrc = (((size_t)(bq + hv) * 64 + d) << 10) + j0 + seg * 8;
            cp16(sb + SAV_V_H + so, vth + gsrc);
        }
        CP_COMMIT();

#pragma unroll
        for (int it = 0; it < 2; ++it) {
            const int i = ibA + it * 32;
            const int gi = i0 + i;
            float p0[8], p1[8];
#pragma unroll
            for (int e = 0; e < 2; ++e) {
                const int gj = j0 + jjA + e;
                const int g = (gi + 1) * NSEQ + gj;
                const int si = g / (NSEQ + 1);
                const int sj = g % (NSEQ + 1) - 1;
                float v[8];
                float mx = -1e30f;
#pragma unroll
                for (int hh = 0; hh < 8; ++hh) {
                    const size_t base = (size_t)(bq + hh) * NSEQ;
                    float d = __half2float(AC[(base + gi) * NSEQ + gj]);
                    if (sj >= 0) d += __half2float(BDp[(base + si) * NSEQ + sj]);
                    d *= 0.125f;
                    v[hh] = d;
                    mx = fmaxf(mx, d);
                }
                float s = 0.0f;
#pragma unroll
                for (int hh = 0; hh < 8; ++hh) { v[hh] = __expf(v[hh] - mx); s += v[hh]; }
                const float inv = 1.0f / s;
                float* pp = e ? p1 : p0;
#pragma unroll
                for (int hh = 0; hh < 8; ++hh) pp[hh] = v[hh] * inv;
            }
#pragma unroll
            for (int hh = 0; hh < 8; ++hh) {
                __half2 hp;
                hp.x = __float2half_rn(p0[hh]);
                hp.y = __float2half_rn(p1[hh]);
                const uint32_t so = (uint32_t)(((hh * 64 + i) * 40 + jjA) * 2);
                *(__half2*)(dsm + SAV_ATT_H + so) = hp;
                if (attnf) {
                    *(float2*)(attnf + ((size_t)(bq + hh) * NSEQ + gi) * NSEQ + j0 + jjA) =
                        make_float2(p0[hh], p1[hh]);
                }
            }
        }
        CP_WAIT(0);
        __syncthreads();

#pragma unroll
        for (int kk = 0; kk < 32; kk += 16) {
            uint32_t bhf[8][2], ah[2][4];
#pragma unroll
            for (int nt = 0; nt < 8; ++nt)
                ldm_x2(bhf[nt], aVH + boff + (uint32_t)((nt * 8 * 40 + kk) * 2));
#pragma unroll
            for (int mt = 0; mt < 2; ++mt)
                ldm_x4(ah[mt], aAH + aoff + (uint32_t)((mt * 16 * 40 + kk) * 2));
#pragma unroll
            for (int mt = 0; mt < 2; ++mt)
#pragma unroll
                for (int nt = 0; nt < 8; ++nt)
                    mma_f16(acc[mt][nt], ah[mt], bhf[nt]);
        }
        __syncthreads();
    }

    const int g = lane >> 2, t2 = (lane & 3) * 2;
#pragma unroll
    for (int mt = 0; mt < 2; ++mt) {
#pragma unroll
        for (int nt = 0; nt < 8; ++nt) {
            const int r0 = i0 + ihalf * 32 + mt * 16 + g;
            const int c  = h * 64 + nt * 8 + t2;
            __half2 hp;
            hp.x = __float2half_rn(acc[mt][nt][0]);
            hp.y = __float2half_rn(acc[mt][nt][1]);
            *(__half2*)(outh + ((size_t)b * NSEQ + r0) * NHD + c) = hp;
            hp.x = __float2half_rn(acc[mt][nt][2]);
            hp.y = __float2half_rn(acc[mt][nt][3]);
            *(__half2*)(outh + ((size_t)b * NSEQ + r0 + 8) * NHD + c) = hp;
        }
    }
}

// ---------------- host orchestration ----------------------------------------
extern "C" void kernel_launch(void* const* d_in, const int* in_sizes, int n_in,
                              void* d_out, int out_size)
{
    (void)in_sizes; (void)n_in;
    const float* x_in    = (const float*)d_in[0];
    const float* r_t     = (const float*)d_in[1];
    const float* bias_pf = (const float*)d_in[3];
    const float* ln1_g   = (const float*)d_in[4];
    const float* ln1_b   = (const float*)d_in[5];
    const float* Wqkv    = (const float*)d_in[6];
    const float* Wkr_t   = (const float*)d_in[7];
    const float* Wout    = (const float*)d_in[9];
    const float* bout    = (const float*)d_in[10];
    const float* ln2_g   = (const float*)d_in[11];
    const float* ln2_b   = (const float*)d_in[12];
    const float* W1      = (const float*)d_in[13];
    const float* b1      = (const float*)d_in[14];
    const float* W2      = (const float*)d_in[15];
    const float* b2      = (const float*)d_in[16];
    float* outp = (float*)d_out;

    static int attr_done = 0;
    if (!attr_done) {
        cudaFuncSetAttribute(mma2_kernel<2,0,2>, cudaFuncAttributeMaxDynamicSharedMemorySize, MMA_SMEM2);
        cudaFuncSetAttribute(mma2_kernel<0,0,2>, cudaFuncAttributeMaxDynamicSharedMemorySize, MMA_SMEM2);
        cudaFuncSetAttribute(mma2_kernel<2,1,1>, cudaFuncAttributeMaxDynamicSharedMemorySize, MMA_SMEM1);
        cudaFuncSetAttribute(mma2_kernel<0,0,1>, cudaFuncAttributeMaxDynamicSharedMemorySize, MMA_SMEM1);
        cudaFuncSetAttribute(acbd1_kernel,       cudaFuncAttributeMaxDynamicSharedMemorySize, ACBD_SMEM);
        cudaFuncSetAttribute(fused_sav_kernel,   cudaFuncAttributeMaxDynamicSharedMemorySize, SAV_SMEM);
        attr_done = 1;
    }

    float *gx, *gbk, *gbr;
    __half *gac, *gbd;
    __half *gxnh, *grth, *gqkvh, *gkrh, *gavh, *gffh, *gwth, *gwtl, *gvth;
    cudaGetSymbolAddress((void**)&gx,    g_x);
    cudaGetSymbolAddress((void**)&gac,   g_ac);
    cudaGetSymbolAddress((void**)&gbd,   g_bd);
    cudaGetSymbolAddress((void**)&gbk,   g_bk);
    cudaGetSymbolAddress((void**)&gbr,   g_br);
    cudaGetSymbolAddress((void**)&gxnh,  g_xnh);
    cudaGetSymbolAddress((void**)&grth,  g_rth);
    cudaGetSymbolAddress((void**)&gqkvh, g_qkvh);
    cudaGetSymbolAddress((void**)&gkrh,  g_krh);
    cudaGetSymbolAddress((void**)&gavh,  g_avh);
    cudaGetSymbolAddress((void**)&gffh,  g_ffh);
    cudaGetSymbolAddress((void**)&gwth,  g_wth);
    cudaGetSymbolAddress((void**)&gwtl,  g_wtl);
    cudaGetSymbolAddress((void**)&gvth,  g_vth);

    float* attn_out = outp + ((size_t)out_size - ATT_ELEMS);

    cudaMemcpyAsync(gx, x_in, X_ELEMS * sizeof(float), cudaMemcpyDeviceToDevice, 0);
    split_rt_kernel<<<X_ELEMS / 1024, 256>>>(r_t, grth);

    transpose_all_kernel<<<dim3(3328, 4), dim3(32, 8)>>>(
        Wqkv, Wkr_t, Wout, W1, W2, gwth, gwtl);

    const dim3 tb(32, 8);
    for (int l = 0; l < 4; ++l) {
        const size_t wb = (size_t)l * WT_TOTAL;

        ln_half_kernel<<<MROWS, 128>>>(gx, ln1_g + l * NDIM, ln1_b + l * NDIM, gxnh);
        // qkv: 2-term (A = xn hi; B hi/lo), hi-only output
        mma2_kernel<2,0,2><<<dim3(12, 64), 256, MMA_SMEM2>>>(
            gxnh, gwth + wb + WQKVT, gwtl + wb + WQKVT,
            nullptr, gqkvh, nullptr, nullptr, MROWS, 1536, 512);
        // kr: 2-term, hi-only output
        mma2_kernel<2,0,2><<<dim3(4, 64), 256, MMA_SMEM2>>>(
            grth, gwth + wb + WKRT, gwtl + wb + WKRT,
            nullptr, gkrh, nullptr, nullptr, MROWS, 512, 512);

        bias_terms_kernel<<<256, 256>>>(gqkvh, gkrh, bias_pf, gbk, gbr);

        // acbd: 1-term, fp16 score output
        acbd1_kernel<<<dim3(8, 8, 128), 256, ACBD_SMEM>>>(
            gqkvh, gkrh, gbk, gbr, gac, gbd);

        vt_kernel<<<dim3(32, 2, 64), tb>>>(gqkvh, gvth);

        fused_sav_kernel<<<dim3(16, 8), 512, SAV_SMEM>>>(
            gac, gbd, gvth, gavh, (l == 3) ? attn_out : nullptr);

        // Wout: 2-term, fp32 out + residual
        mma2_kernel<0,0,2><<<dim3(4, 64), 256, MMA_SMEM2>>>(
            gavh, gwth + wb + WOUTT, gwtl + wb + WOUTT,
            gx, nullptr, bout + l * NDIM, gx, MROWS, 512, 512);

        ln_half_kernel<<<MROWS, 128>>>(gx, ln2_g + l * NDIM, ln2_b + l * NDIM, gxnh);
        // W1: 1-term, gelu, half hi out
        mma2_kernel<2,1,1><<<dim3(16, 64), 256, MMA_SMEM1>>>(
            gxnh, gwth + wb + W1T, gwth + wb + W1T,
            nullptr, gffh, b1 + l * NFF, nullptr, MROWS, 2048, 512);
        float* xdst = (l == 3) ? outp : gx;
        // W2: 1-term, fp32 out + residual
        mma2_kernel<0,0,1><<<dim3(4, 64), 256, MMA_SMEM1>>>(
            gffh, gwth + wb + W2T, gwth + wb + W2T,
            xdst, nullptr, b2 + l * NDIM, gx, MROWS, 512, 2048);
    }
}

// round 15
// speedup vs baseline: 1.8876x; 1.0977x over previous
#include <cuda_runtime.h>
#include <cuda_fp16.h>
#include <math.h>
#include <stdint.h>

#define NSEQ   1024
#define NBATCH 8
#define NDIM   512
#define NHEADS 8
#define NDH    64
#define NHD    512
#define NFF    2048
#define MROWS  (NBATCH*NSEQ)
#define ATT_ELEMS ((size_t)NBATCH*NHEADS*NSEQ*NSEQ)
#define X_ELEMS   ((size_t)MROWS*NDIM)

// transposed weight offsets (elements, within one layer's block)
#define WQKVT 0
#define WKRT  786432
#define WOUTT 1048576
#define W1T   1310720
#define W2T   2359296
#define WT_TOTAL 3407872

// ---------------- scratch --------------------------------------------------
static __device__ float g_x [MROWS*NDIM];
static __device__ float g_bk[NBATCH*NHEADS*NSEQ];
static __device__ float g_br[NBATCH*NHEADS*NSEQ];
static __device__ __half g_ac[NBATCH*NHEADS*NSEQ*NSEQ];
static __device__ __half g_bd[NBATCH*NHEADS*NSEQ*NSEQ];
static __device__ __half g_xnh [MROWS*NDIM];
static __device__ __half g_rth [MROWS*NDIM];
static __device__ __half g_qkvh[MROWS*3*NHD];
static __device__ __half g_krh [MROWS*NHD];
static __device__ __half g_avh [MROWS*NHD];
static __device__ __half g_ffh [MROWS*NFF];
static __device__ __half g_wth [4*WT_TOTAL];
static __device__ __half g_vth [NBATCH*NHEADS*NDH*NSEQ];

// ---------------- primitives ------------------------------------------------
__device__ __forceinline__ uint32_t smem_u32(const void* p) {
    uint32_t a;
    asm("{ .reg .u64 t; cvta.to.shared.u64 t, %1; cvt.u32.u64 %0, t; }"
        : "=r"(a) : "l"(p));
    return a;
}
__device__ __forceinline__ void cp16(uint32_t dst, const void* src) {
    asm volatile("cp.async.cg.shared.global [%0], [%1], 16;" :: "r"(dst), "l"(src));
}
#define CP_COMMIT() asm volatile("cp.async.commit_group;")
#define CP_WAIT(n)  asm volatile("cp.async.wait_group %0;" :: "n"(n))

__device__ __forceinline__ void mma_f16(float* d, const uint32_t* a, const uint32_t* b) {
    asm volatile(
        "mma.sync.aligned.m16n8k16.row.col.f32.f16.f16.f32 "
        "{%0,%1,%2,%3}, {%4,%5,%6,%7}, {%8,%9}, {%0,%1,%2,%3};"
        : "+f"(d[0]), "+f"(d[1]), "+f"(d[2]), "+f"(d[3])
        : "r"(a[0]), "r"(a[1]), "r"(a[2]), "r"(a[3]), "r"(b[0]), "r"(b[1]));
}
__device__ __forceinline__ void ldm_x4(uint32_t* r, uint32_t addr) {
    asm volatile("ldmatrix.sync.aligned.m8n8.x4.shared.b16 {%0,%1,%2,%3}, [%4];"
        : "=r"(r[0]), "=r"(r[1]), "=r"(r[2]), "=r"(r[3]) : "r"(addr));
}
__device__ __forceinline__ void ldm_x2(uint32_t* r, uint32_t addr) {
    asm volatile("ldmatrix.sync.aligned.m8n8.x2.shared.b16 {%0,%1}, [%2];"
        : "=r"(r[0]), "=r"(r[1]) : "r"(addr));
}
__device__ __forceinline__ float gelu_exact(float v) {
    return 0.5f * v * (1.0f + erff(v * 0.70710678118654752f));
}

// ---------- merged weight transpose (hi-only) for ALL layers -----------------
__global__ __launch_bounds__(256) void transpose_all_kernel(
    const float* __restrict__ Wqkv, const float* __restrict__ Wkr,
    const float* __restrict__ Wout, const float* __restrict__ W1,
    const float* __restrict__ W2,
    __half* __restrict__ Wth)
{
    __shared__ float t[32][33];
    const int l = blockIdx.y;
    const int tt = blockIdx.x;
    const float* W; int K, N, off, tloc;
    if (tt < 768)       { W = Wqkv + (size_t)l * 786432;  K = 512;  N = 1536; off = WQKVT; tloc = tt; }
    else if (tt < 1024) { W = Wkr  + (size_t)l * 262144;  K = 512;  N = 512;  off = WKRT;  tloc = tt - 768; }
    else if (tt < 1280) { W = Wout + (size_t)l * 262144;  K = 512;  N = 512;  off = WOUTT; tloc = tt - 1024; }
    else if (tt < 2304) { W = W1   + (size_t)l * 1048576; K = 512;  N = 2048; off = W1T;   tloc = tt - 1280; }
    else                { W = W2   + (size_t)l * 1048576; K = 2048; N = 512;  off = W2T;   tloc = tt - 2304; }
    const int ntn = N >> 5;
    const int kt = tloc / ntn, nt = tloc % ntn;
    const int k0 = kt * 32, n0 = nt * 32;
    const int x = threadIdx.x, y = threadIdx.y;
    const size_t dst = (size_t)l * WT_TOTAL + off;
#pragma unroll
    for (int i = 0; i < 32; i += 8)
        t[y + i][x] = W[(size_t)(k0 + y + i) * N + n0 + x];
    __syncthreads();
#pragma unroll
    for (int i = 0; i < 32; i += 8)
        Wth[dst + (size_t)(n0 + y + i) * K + k0 + x] = __float2half_rn(t[x][y + i]);
}

// ---------------- r_t -> fp16 ----------------------------------------
__global__ __launch_bounds__(256) void split_rt_kernel(
    const float* __restrict__ src, __half* __restrict__ dh)
{
    const size_t i = ((size_t)blockIdx.x * 256 + threadIdx.x) * 4;
    float4 v = *(const float4*)(src + i);
    __half2 a, b;
    a.x = __float2half_rn(v.x); a.y = __float2half_rn(v.y);
    b.x = __float2half_rn(v.z); b.y = __float2half_rn(v.w);
    *(__half2*)(dh + i) = a;
    *(__half2*)(dh + i + 2) = b;
}

// ---------------- LayerNorm -> fp16 ------------------------------------------
__global__ __launch_bounds__(128) void ln_half_kernel(
    const float* __restrict__ x, const float* __restrict__ g,
    const float* __restrict__ b, __half* __restrict__ yh)
{
    const int row = blockIdx.x;
    const int tid = threadIdx.x;
    const float* xr = x + (size_t)row * NDIM;

    float4 v = ((const float4*)xr)[tid];
    float s  = v.x + v.y + v.z + v.w;
    float sq = v.x*v.x + v.y*v.y + v.z*v.z + v.w*v.w;
#pragma unroll
    for (int o = 16; o > 0; o >>= 1) {
        s  += __shfl_xor_sync(0xffffffffu, s,  o);
        sq += __shfl_xor_sync(0xffffffffu, sq, o);
    }
    __shared__ float red[8];
    const int w = tid >> 5;
    if ((tid & 31) == 0) { red[w] = s; red[4 + w] = sq; }
    __syncthreads();
    const float st  = red[0] + red[1] + red[2] + red[3];
    const float sqt = red[4] + red[5] + red[6] + red[7];
    const float mu  = st * (1.0f / NDIM);
    const float var = sqt * (1.0f / NDIM) - mu * mu;
    const float inv = rsqrtf(var + 1e-5f);

    float4 gg = ((const float4*)g)[tid];
    float4 bb = ((const float4*)b)[tid];
    __half2 a, c;
    a.x = __float2half_rn((v.x - mu) * inv * gg.x + bb.x);
    a.y = __float2half_rn((v.y - mu) * inv * gg.y + bb.y);
    c.x = __float2half_rn((v.z - mu) * inv * gg.z + bb.z);
    c.y = __float2half_rn((v.w - mu) * inv * gg.w + bb.w);
    const size_t base = (size_t)row * NDIM + tid * 4;
    *(__half2*)(yh + base) = a;
    *(__half2*)(yh + base + 2) = c;
}

// ====== dense fp16 mma GEMM, 3-stage cp.async pipeline, 1-term ===============
// SPLIT: 0 = fp32 out (+bias,+res); 2 = half out.
#define LDS 40
#define ARR   (128*LDS)
#define ARRB  (ARR*2)
#define MMA_SMEM1 (3*2*ARRB)   // 61440

template<int SPLIT, int ACT>
__global__ __launch_bounds__(256, 2) void mma1_kernel(
    const __half* __restrict__ Ah, const __half* __restrict__ Bh,
    float* __restrict__ Cf, __half* __restrict__ Ch,
    const float* __restrict__ bias, const float* __restrict__ res,
    int M, int N, int K)
{
    constexpr uint32_t STAGEB = 2u * ARRB;
    extern __shared__ char dsm[];
    const uint32_t sbase = smem_u32(dsm);
    const int tid = threadIdx.x, wid = tid >> 5, lane = tid & 31;
    const int wm = wid >> 2, wn = wid & 3;
    const int bm = blockIdx.y * 128, bn = blockIdx.x * 128;

    const int lrow = tid >> 2, lcc = (tid & 3) * 8;
    const int lrow2 = (tid + 256) >> 2, lcc2 = ((tid + 256) & 3) * 8;

#define MMA1_ISSUE(kt, s) do {                                                   \
        const uint32_t st_ = sbase + (uint32_t)(s) * STAGEB;                     \
        const int k0_ = (kt) * 32;                                               \
        cp16(st_ + (uint32_t)((lrow * LDS + lcc) * 2),                           \
             Ah + (size_t)(bm + lrow) * K + k0_ + lcc);                          \
        cp16(st_ + (uint32_t)((lrow2 * LDS + lcc2) * 2),                         \
             Ah + (size_t)(bm + lrow2) * K + k0_ + lcc2);                        \
        cp16(st_ + (uint32_t)ARRB + (uint32_t)((lrow * LDS + lcc) * 2),          \
             Bh + (size_t)(bn + lrow) * K + k0_ + lcc);                          \
        cp16(st_ + (uint32_t)ARRB + (uint32_t)((lrow2 * LDS + lcc2) * 2),        \
             Bh + (size_t)(bn + lrow2) * K + k0_ + lcc2);                        \
    } while (0)

    const int l15 = lane & 15;
    const uint32_t aoff = (uint32_t)(((wm * 64 + l15) * LDS + ((lane >> 4) << 3)) * 2);
    const uint32_t boff = (uint32_t)(((wn * 32 + (l15 & 7)) * LDS + (((l15 >> 3) & 1) << 3)) * 2);

    float acc[4][4][4];
#pragma unroll
    for (int i = 0; i < 4; ++i)
#pragma unroll
        for (int j = 0; j < 4; ++j)
#pragma unroll
            for (int q = 0; q < 4; ++q) acc[i][j][q] = 0.0f;

    const int NKT = K >> 5;
    MMA1_ISSUE(0, 0);
    CP_COMMIT();
    MMA1_ISSUE(1, 1);
    CP_COMMIT();

    for (int kt = 0; kt < NKT; ++kt) {
        if (kt + 1 < NKT) { CP_WAIT(1); } else { CP_WAIT(0); }
        __syncthreads();
        if (kt + 2 < NKT) {
            MMA1_ISSUE(kt + 2, (kt + 2) % 3);
            CP_COMMIT();
        }
        const uint32_t st = sbase + (uint32_t)(kt % 3) * STAGEB;
        const uint32_t aAh = st, aBh = st + ARRB;
#pragma unroll
        for (int kk = 0; kk < 32; kk += 16) {
            uint32_t bh[4][2], a[4][4];
#pragma unroll
            for (int nt = 0; nt < 4; ++nt)
                ldm_x2(bh[nt], aBh + boff + (uint32_t)((nt * 8 * LDS + kk) * 2));
#pragma unroll
            for (int mt = 0; mt < 4; ++mt)
                ldm_x4(a[mt], aAh + aoff + (uint32_t)((mt * 16 * LDS + kk) * 2));
#pragma unroll
            for (int mt = 0; mt < 4; ++mt)
#pragma unroll
                for (int nt = 0; nt < 4; ++nt)
                    mma_f16(acc[mt][nt], a[mt], bh[nt]);
        }
    }
#undef MMA1_ISSUE
    __syncthreads();

    const int g = lane >> 2, t2 = (lane & 3) * 2;
#pragma unroll
    for (int mt = 0; mt < 4; ++mt) {
#pragma unroll
        for (int nt = 0; nt < 4; ++nt) {
            const int r0 = bm + wm * 64 + mt * 16 + g;
            const int r1 = r0 + 8;
            const int c  = bn + wn * 32 + nt * 8 + t2;
            float v0 = acc[mt][nt][0], v1 = acc[mt][nt][1];
            float v2 = acc[mt][nt][2], v3 = acc[mt][nt][3];
            if (bias) {
                const float b0 = bias[c], b1 = bias[c + 1];
                v0 += b0; v1 += b1; v2 += b0; v3 += b1;
            }
            if (ACT) {
                v0 = gelu_exact(v0); v1 = gelu_exact(v1);
                v2 = gelu_exact(v2); v3 = gelu_exact(v3);
            }
            if (SPLIT == 2) {
                __half2 hp;
                hp.x = __float2half_rn(v0); hp.y = __float2half_rn(v1);
                *(__half2*)(Ch + (size_t)r0 * N + c) = hp;
                hp.x = __float2half_rn(v2); hp.y = __float2half_rn(v3);
                *(__half2*)(Ch + (size_t)r1 * N + c) = hp;
            } else {
                if (res) {
                    const float2 q0 = *(const float2*)(res + (size_t)r0 * N + c);
                    const float2 q1 = *(const float2*)(res + (size_t)r1 * N + c);
                    v0 += q0.x; v1 += q0.y; v2 += q1.x; v3 += q1.y;
                }
                *(float2*)(Cf + (size_t)r0 * N + c) = make_float2(v0, v1);
                *(float2*)(Cf + (size_t)r1 * N + c) = make_float2(v2, v3);
            }
        }
    }
}

// ---------------- bias rank-1 terms (hi-only inputs) -------------------------
__global__ __launch_bounds__(256) void bias_terms_kernel(
    const __half* __restrict__ qkvh, const __half* __restrict__ krh,
    const float* __restrict__ bias_pf,
    float* __restrict__ bk, float* __restrict__ br)
{
    const int idx = blockIdx.x * 256 + threadIdx.x;
    const int bh = idx >> 10, j = idx & 1023;
    const int b = bh >> 3, h = bh & 7;
    const size_t kb = ((size_t)b * NSEQ + j) * 1536 + 512 + h * 64;
    const size_t rb = ((size_t)b * NSEQ + j) * 512 + h * 64;
    float sk = 0.0f, sr = 0.0f;
#pragma unroll 16
    for (int d = 0; d < 64; ++d) {
        const float bp = bias_pf[h * 64 + d];
        sk += bp * __half2float(qkvh[kb + d]);
        sr += bp * __half2float(krh[rb + d]);
    }
    bk[idx] = sk;
    br[idx] = sr;
}

// =========== acbd fp16 mma, 1-term; fp16 score output ========================
#define ACBD_STAGE (2*ARR)
#define ACBD_SMEM  (2*ACBD_STAGE*2)   // 40960 bytes

__global__ __launch_bounds__(256, 2) void acbd1_kernel(
    const __half* __restrict__ qkvh, const __half* __restrict__ krh,
    const float* __restrict__ bk, const float* __restrict__ br,
    __half* __restrict__ AC, __half* __restrict__ BD)
{
    extern __shared__ char dsm[];
    const uint32_t sbase = smem_u32(dsm);
    const int tid = threadIdx.x, wid = tid >> 5, lane = tid & 31;
    const int wm = wid >> 2, wn = wid & 3;
    const int z = blockIdx.z, bh_idx = z & 63, isBD = z >> 6;
    const int b = bh_idx >> 3, h = bh_idx & 7;
    const int i0 = blockIdx.y * 128, j0 = blockIdx.x * 128;

    const __half* Ah = qkvh + ((size_t)b * NSEQ + i0) * 1536 + h * 64;
    const __half* Bh = isBD ? (krh + ((size_t)b * NSEQ + j0) * 512 + h * 64)
                            : (qkvh + ((size_t)b * NSEQ + j0) * 1536 + 512 + h * 64);
    const int ldb = isBD ? 512 : 1536;
    __half* Cbase = (isBD ? BD : AC) + (size_t)bh_idx * NSEQ * NSEQ;
    const float* bvec = (isBD ? br : bk) + (size_t)bh_idx * NSEQ;

    const int lrow = tid >> 2, lcc = (tid & 3) * 8;
    const int lrow2 = (tid + 256) >> 2, lcc2 = ((tid + 256) & 3) * 8;

#define ACBD_ISSUE(kt, s) do {                                                   \
        const uint32_t st_ = sbase + (uint32_t)(s) * (ACBD_STAGE * 2);           \
        const int k0_ = (kt) * 32;                                               \
        cp16(st_ + (uint32_t)((lrow * LDS + lcc) * 2),                           \
             Ah + (size_t)lrow * 1536 + k0_ + lcc);                              \
        cp16(st_ + (uint32_t)((lrow2 * LDS + lcc2) * 2),                         \
             Ah + (size_t)lrow2 * 1536 + k0_ + lcc2);                            \
        cp16(st_ + (uint32_t)(ARR * 2) + (uint32_t)((lrow * LDS + lcc) * 2),     \
             Bh + (size_t)lrow * ldb + k0_ + lcc);                               \
        cp16(st_ + (uint32_t)(ARR * 2) + (uint32_t)((lrow2 * LDS + lcc2) * 2),   \
             Bh + (size_t)lrow2 * ldb + k0_ + lcc2);                             \
    } while (0)

    const int l15 = lane & 15;
    const uint32_t aoff = (uint32_t)(((wm * 64 + l15) * LDS + ((lane >> 4) << 3)) * 2);
    const uint32_t boff = (uint32_t)(((wn * 32 + (l15 & 7)) * LDS + (((l15 >> 3) & 1) << 3)) * 2);

    float acc[4][4][4];
#pragma unroll
    for (int i = 0; i < 4; ++i)
#pragma unroll
        for (int j = 0; j < 4; ++j)
#pragma unroll
            for (int q = 0; q < 4; ++q) acc[i][j][q] = 0.0f;

    ACBD_ISSUE(0, 0);
    CP_COMMIT();
#pragma unroll
    for (int kt = 0; kt < 2; ++kt) {
        if (kt == 0) {
            ACBD_ISSUE(1, 1);
            CP_COMMIT();
            CP_WAIT(1);
        } else {
            CP_WAIT(0);
        }
        __syncthreads();
        const uint32_t st = sbase + (uint32_t)(kt & 1) * (ACBD_STAGE * 2);
        const uint32_t aAh = st, aBh = st + ARR * 2;
#pragma unroll
        for (int kk = 0; kk < 32; kk += 16) {
            uint32_t bh[4][2], a[4][4];
#pragma unroll
            for (int nt = 0; nt < 4; ++nt)
                ldm_x2(bh[nt], aBh + boff + (uint32_t)((nt * 8 * LDS + kk) * 2));
#pragma unroll
            for (int mt = 0; mt < 4; ++mt)
                ldm_x4(a[mt], aAh + aoff + (uint32_t)((mt * 16 * LDS + kk) * 2));
#pragma unroll
            for (int mt = 0; mt < 4; ++mt)
#pragma unroll
                for (int nt = 0; nt < 4; ++nt)
                    mma_f16(acc[mt][nt], a[mt], bh[nt]);
        }
        __syncthreads();
    }
#undef ACBD_ISSUE

    const int g = lane >> 2, t2 = (lane & 3) * 2;
#pragma unroll
    for (int mt = 0; mt < 4; ++mt) {
#pragma unroll
        for (int nt = 0; nt < 4; ++nt) {
            const int r0 = i0 + wm * 64 + mt * 16 + g;
            const int c  = j0 + wn * 32 + nt * 8 + t2;
            const float b0 = bvec[c], b1 = bvec[c + 1];
            __half2 p;
            p.x = __float2half_rn(acc[mt][nt][0] + b0);
            p.y = __float2half_rn(acc[mt][nt][1] + b1);
            *(__half2*)(Cbase + (size_t)r0 * NSEQ + c) = p;
            p.x = __float2half_rn(acc[mt][nt][2] + b0);
            p.y = __float2half_rn(acc[mt][nt][3] + b1);
            *(__half2*)(Cbase + (size_t)(r0 + 8) * NSEQ + c) = p;
        }
    }
}

// ---------------- V transpose (hi only) --------------------------------------
__global__ __launch_bounds__(256) void vt_kernel(
    const __half* __restrict__ qkvh, __half* __restrict__ vth)
{
    __shared__ __half th[32][33];
    const int bh = blockIdx.z, b = bh >> 3, h = bh & 7;
    const int j0 = blockIdx.x * 32, d0 = blockIdx.y * 32;
    const int x = threadIdx.x, y = threadIdx.y;
#pragma unroll
    for (int i = 0; i < 32; i += 8)
        th[y + i][x] = qkvh[((size_t)b * NSEQ + j0 + y + i) * 1536 + 1024 + h * 64 + d0 + x];
    __syncthreads();
#pragma unroll
    for (int i = 0; i < 32; i += 8)
        vth[((size_t)bh * 64 + d0 + y + i) * NSEQ + j0 + x] = th[x][y + i];
}

// ======= FUSED shift+scale+softmax(heads) + attn@V (fp16 scores) =============
#define SAV_ATT_H 0
#define SAV_V_H   40960
#define SAV_SMEM  81920

__global__ __launch_bounds__(512, 1) void fused_sav_kernel(
    const __half* __restrict__ AC, const __half* __restrict__ BDp,
    const __half* __restrict__ vth,
    __half* __restrict__ outh, float* __restrict__ attnf)
{
    extern __shared__ char dsm[];
    const uint32_t sb = smem_u32(dsm);
    const int tid = threadIdx.x, wid = tid >> 5, lane = tid & 31;
    const int b = blockIdx.y;
    const int i0 = blockIdx.x * 64;
    const int bq = b * NHEADS;

    const int ibA = tid >> 4;
    const int jjA = (tid & 15) * 2;

    const int h = wid & 7, ihalf = wid >> 3;
    const int l15 = lane & 15;
    const uint32_t headOff = (uint32_t)(h * 64 * 40 * 2);
    const uint32_t aAH = sb + SAV_ATT_H + headOff;
    const uint32_t aVH = sb + SAV_V_H + headOff;
    const uint32_t aoff = (uint32_t)(((ihalf * 32 + l15) * 40 + ((lane >> 4) << 3)) * 2);
    const uint32_t boff = (uint32_t)(((l15 & 7) * 40 + (((l15 >> 3) & 1) << 3)) * 2);

    float acc[2][8][4];
#pragma unroll
    for (int i = 0; i < 2; ++i)
#pragma unroll
        for (int j = 0; j < 8; ++j)
#pragma unroll
            for (int q = 0; q < 4; ++q) acc[i][j][q] = 0.0f;

    for (int kt = 0; kt < 32; ++kt) {
        const int j0 = kt * 32;
#pragma unroll
        for (int k = 0; k < 4; ++k) {
            const int idx = tid + k * 512;
            const int hv = idx >> 8;
            const int r = idx & 255;
            const int d = r >> 2, seg = r & 3;
            const uint32_t so = (uint32_t)((hv * 64 + d) * 80 + seg * 16);
            const size_t gsrc = (((size_t)(bq + hv) * 64 + d) << 10) + j0 + seg * 8;
            cp16(sb + SAV_V_H + so, vth + gsrc);
        }
        CP_COMMIT();

#pragma unroll
        for (int it = 0; it < 2; ++it) {
            const int i = ibA + it * 32;
            const int gi = i0 + i;
            float p0[8], p1[8];
#pragma unroll
            for (int e = 0; e < 2; ++e) {
                const int gj = j0 + jjA + e;
                const int g = (gi + 1) * NSEQ + gj;
                const int si = g / (NSEQ + 1);
                const int sj = g % (NSEQ + 1) - 1;
                float v[8];
                float mx = -1e30f;
#pragma unroll
                for (int hh = 0; hh < 8; ++hh) {
                    const size_t base = (size_t)(bq + hh) * NSEQ;
                    float d = __half2float(AC[(base + gi) * NSEQ + gj]);
                    if (sj >= 0) d += __half2float(BDp[(base + si) * NSEQ + sj]);
                    d *= 0.125f;
                    v[hh] = d;
                    mx = fmaxf(mx, d);
                }
                float s = 0.0f;
#pragma unroll
                for (int hh = 0; hh < 8; ++hh) { v[hh] = __expf(v[hh] - mx); s += v[hh]; }
                const float inv = 1.0f / s;
                float* pp = e ? p1 : p0;
#pragma unroll
                for (int hh = 0; hh < 8; ++hh) pp[hh] = v[hh] * inv;
            }
#pragma unroll
            for (int hh = 0; hh < 8; ++hh) {
                __half2 hp;
                hp.x = __float2half_rn(p0[hh]);
                hp.y = __float2half_rn(p1[hh]);
                const uint32_t so = (uint32_t)(((hh * 64 + i) * 40 + jjA) * 2);
                *(__half2*)(dsm + SAV_ATT_H + so) = hp;
                if (attnf) {
                    *(float2*)(attnf + ((size_t)(bq + hh) * NSEQ + gi) * NSEQ + j0 + jjA) =
                        make_float2(p0[hh], p1[hh]);
                }
            }
        }
        CP_WAIT(0);
        __syncthreads();

#pragma unroll
        for (int kk = 0; kk < 32; kk += 16) {
            uint32_t bhf[8][2], ah[2][4];
#pragma unroll
            for (int nt = 0; nt < 8; ++nt)
                ldm_x2(bhf[nt], aVH + boff + (uint32_t)((nt * 8 * 40 + kk) * 2));
#pragma unroll
            for (int mt = 0; mt < 2; ++mt)
                ldm_x4(ah[mt], aAH + aoff + (uint32_t)((mt * 16 * 40 + kk) * 2));
#pragma unroll
            for (int mt = 0; mt < 2; ++mt)
#pragma unroll
                for (int nt = 0; nt < 8; ++nt)
                    mma_f16(acc[mt][nt], ah[mt], bhf[nt]);
        }
        __syncthreads();
    }

    const int g = lane >> 2, t2 = (lane & 3) * 2;
#pragma unroll
    for (int mt = 0; mt < 2; ++mt) {
#pragma unroll
        for (int nt = 0; nt < 8; ++nt) {
            const int r0 = i0 + ihalf * 32 + mt * 16 + g;
            const int c  = h * 64 + nt * 8 + t2;
            __half2 hp;
            hp.x = __float2half_rn(acc[mt][nt][0]);
            hp.y = __float2half_rn(acc[mt][nt][1]);
            *(__half2*)(outh + ((size_t)b * NSEQ + r0) * NHD + c) = hp;
            hp.x = __float2half_rn(acc[mt][nt][2]);
            hp.y = __float2half_rn(acc[mt][nt][3]);
            *(__half2*)(outh + ((size_t)b * NSEQ + r0 + 8) * NHD + c) = hp;
        }
    }
}

// ---------------- host orchestration ----------------------------------------
extern "C" void kernel_launch(void* const* d_in, const int* in_sizes, int n_in,
                              void* d_out, int out_size)
{
    (void)in_sizes; (void)n_in;
    const float* x_in    = (const float*)d_in[0];
    const float* r_t     = (const float*)d_in[1];
    const float* bias_pf = (const float*)d_in[3];
    const float* ln1_g   = (const float*)d_in[4];
    const float* ln1_b   = (const float*)d_in[5];
    const float* Wqkv    = (const float*)d_in[6];
    const float* Wkr_t   = (const float*)d_in[7];
    const float* Wout    = (const float*)d_in[9];
    const float* bout    = (const float*)d_in[10];
    const float* ln2_g   = (const float*)d_in[11];
    const float* ln2_b   = (const float*)d_in[12];
    const float* W1      = (const float*)d_in[13];
    const float* b1      = (const float*)d_in[14];
    const float* W2      = (const float*)d_in[15];
    const float* b2      = (const float*)d_in[16];
    float* outp = (float*)d_out;

    static int attr_done = 0;
    if (!attr_done) {
        cudaFuncSetAttribute(mma1_kernel<2,0>, cudaFuncAttributeMaxDynamicSharedMemorySize, MMA_SMEM1);
        cudaFuncSetAttribute(mma1_kernel<0,0>, cudaFuncAttributeMaxDynamicSharedMemorySize, MMA_SMEM1);
        cudaFuncSetAttribute(mma1_kernel<2,1>, cudaFuncAttributeMaxDynamicSharedMemorySize, MMA_SMEM1);
        cudaFuncSetAttribute(acbd1_kernel,     cudaFuncAttributeMaxDynamicSharedMemorySize, ACBD_SMEM);
        cudaFuncSetAttribute(fused_sav_kernel, cudaFuncAttributeMaxDynamicSharedMemorySize, SAV_SMEM);
        attr_done = 1;
    }

    float *gx, *gbk, *gbr;
    __half *gac, *gbd;
    __half *gxnh, *grth, *gqkvh, *gkrh, *gavh, *gffh, *gwth, *gvth;
    cudaGetSymbolAddress((void**)&gx,    g_x);
    cudaGetSymbolAddress((void**)&gac,   g_ac);
    cudaGetSymbolAddress((void**)&gbd,   g_bd);
    cudaGetSymbolAddress((void**)&gbk,   g_bk);
    cudaGetSymbolAddress((void**)&gbr,   g_br);
    cudaGetSymbolAddress((void**)&gxnh,  g_xnh);
    cudaGetSymbolAddress((void**)&grth,  g_rth);
    cudaGetSymbolAddress((void**)&gqkvh, g_qkvh);
    cudaGetSymbolAddress((void**)&gkrh,  g_krh);
    cudaGetSymbolAddress((void**)&gavh,  g_avh);
    cudaGetSymbolAddress((void**)&gffh,  g_ffh);
    cudaGetSymbolAddress((void**)&gwth,  g_wth);
    cudaGetSymbolAddress((void**)&gvth,  g_vth);

    float* attn_out = outp + ((size_t)out_size - ATT_ELEMS);

    cudaMemcpyAsync(gx, x_in, X_ELEMS * sizeof(float), cudaMemcpyDeviceToDevice, 0);
    split_rt_kernel<<<X_ELEMS / 1024, 256>>>(r_t, grth);

    transpose_all_kernel<<<dim3(3328, 4), dim3(32, 8)>>>(
        Wqkv, Wkr_t, Wout, W1, W2, gwth);

    const dim3 tb(32, 8);
    for (int l = 0; l < 4; ++l) {
        const size_t wb = (size_t)l * WT_TOTAL;

        ln_half_kernel<<<MROWS, 128>>>(gx, ln1_g + l * NDIM, ln1_b + l * NDIM, gxnh);
        // qkv: 1-term (hi x hi), half out
        mma1_kernel<2,0><<<dim3(12, 64), 256, MMA_SMEM1>>>(
            gxnh, gwth + wb + WQKVT, nullptr, gqkvh, nullptr, nullptr, MROWS, 1536, 512);
        // kr: 1-term, half out
        mma1_kernel<2,0><<<dim3(4, 64), 256, MMA_SMEM1>>>(
            grth, gwth + wb + WKRT, nullptr, gkrh, nullptr, nullptr, MROWS, 512, 512);

        bias_terms_kernel<<<256, 256>>>(gqkvh, gkrh, bias_pf, gbk, gbr);

        // acbd: 1-term, fp16 score output
        acbd1_kernel<<<dim3(8, 8, 128), 256, ACBD_SMEM>>>(
            gqkvh, gkrh, gbk, gbr, gac, gbd);

        vt_kernel<<<dim3(32, 2, 64), tb>>>(gqkvh, gvth);

        fused_sav_kernel<<<dim3(16, 8), 512, SAV_SMEM>>>(
            gac, gbd, gvth, gavh, (l == 3) ? attn_out : nullptr);

        // Wout: 1-term, fp32 out + residual
        mma1_kernel<0,0><<<dim3(4, 64), 256, MMA_SMEM1>>>(
            gavh, gwth + wb + WOUTT, gx, nullptr, bout + l * NDIM, gx, MROWS, 512, 512);

        ln_half_kernel<<<MROWS, 128>>>(gx, ln2_g + l * NDIM, ln2_b + l * NDIM, gxnh);
        // W1: 1-term, gelu, half out
        mma1_kernel<2,1><<<dim3(16, 64), 256, MMA_SMEM1>>>(
            gxnh, gwth + wb + W1T, nullptr, gffh, b1 + l * NFF, nullptr, MROWS, 2048, 512);
        float* xdst = (l == 3) ? outp : gx;
        // W2: 1-term, fp32 out + residual
        mma1_kernel<0,0><<<dim3(4, 64), 256, MMA_SMEM1>>>(
            gffh, gwth + wb + W2T, xdst, nullptr, b2 + l * NDIM, gx, MROWS, 512, 2048);
    }
}

// round 16
// speedup vs baseline: 1.8885x; 1.0005x over previous
#include <cuda_runtime.h>
#include <cuda_fp16.h>
#include <math.h>
#include <stdint.h>

#define NSEQ   1024
#define NBATCH 8
#define NDIM   512
#define NHEADS 8
#define NDH    64
#define NHD    512
#define NFF    2048
#define MROWS  (NBATCH*NSEQ)
#define ATT_ELEMS ((size_t)NBATCH*NHEADS*NSEQ*NSEQ)
#define X_ELEMS   ((size_t)MROWS*NDIM)

// transposed weight offsets (elements, within one layer's block)
#define WQKVT 0
#define WKRT  786432
#define WOUTT 1048576
#define W1T   1310720
#define W2T   2359296
#define WT_TOTAL 3407872

// ---------------- scratch --------------------------------------------------
static __device__ float g_x [MROWS*NDIM];
static __device__ float g_bk[NBATCH*NHEADS*NSEQ];
static __device__ float g_br[NBATCH*NHEADS*NSEQ];
static __device__ __half g_ac[NBATCH*NHEADS*NSEQ*NSEQ];
static __device__ __half g_bd[NBATCH*NHEADS*NSEQ*NSEQ];
static __device__ __half g_xnh [MROWS*NDIM];
static __device__ __half g_rth [MROWS*NDIM];
static __device__ __half g_qkvh[MROWS*3*NHD];
static __device__ __half g_krh [MROWS*NHD];
static __device__ __half g_avh [MROWS*NHD];
static __device__ __half g_ffh [MROWS*NFF];
static __device__ __half g_wth [4*WT_TOTAL];
static __device__ __half g_vth [NBATCH*NHEADS*NDH*NSEQ];

// ---------------- primitives ------------------------------------------------
__device__ __forceinline__ uint32_t smem_u32(const void* p) {
    uint32_t a;
    asm("{ .reg .u64 t; cvta.to.shared.u64 t, %1; cvt.u32.u64 %0, t; }"
        : "=r"(a) : "l"(p));
    return a;
}
__device__ __forceinline__ void cp16(uint32_t dst, const void* src) {
    asm volatile("cp.async.cg.shared.global [%0], [%1], 16;" :: "r"(dst), "l"(src));
}
#define CP_COMMIT() asm volatile("cp.async.commit_group;")
#define CP_WAIT(n)  asm volatile("cp.async.wait_group %0;" :: "n"(n))

__device__ __forceinline__ void mma_f16(float* d, const uint32_t* a, const uint32_t* b) {
    asm volatile(
        "mma.sync.aligned.m16n8k16.row.col.f32.f16.f16.f32 "
        "{%0,%1,%2,%3}, {%4,%5,%6,%7}, {%8,%9}, {%0,%1,%2,%3};"
        : "+f"(d[0]), "+f"(d[1]), "+f"(d[2]), "+f"(d[3])
        : "r"(a[0]), "r"(a[1]), "r"(a[2]), "r"(a[3]), "r"(b[0]), "r"(b[1]));
}
__device__ __forceinline__ void ldm_x4(uint32_t* r, uint32_t addr) {
    asm volatile("ldmatrix.sync.aligned.m8n8.x4.shared.b16 {%0,%1,%2,%3}, [%4];"
        : "=r"(r[0]), "=r"(r[1]), "=r"(r[2]), "=r"(r[3]) : "r"(addr));
}
__device__ __forceinline__ void ldm_x2(uint32_t* r, uint32_t addr) {
    asm volatile("ldmatrix.sync.aligned.m8n8.x2.shared.b16 {%0,%1}, [%2];"
        : "=r"(r[0]), "=r"(r[1]) : "r"(addr));
}
__device__ __forceinline__ float gelu_exact(float v) {
    return 0.5f * v * (1.0f + erff(v * 0.70710678118654752f));
}

// ---------- merged weight transpose (hi-only) for ALL layers -----------------
__global__ __launch_bounds__(256) void transpose_all_kernel(
    const float* __restrict__ Wqkv, const float* __restrict__ Wkr,
    const float* __restrict__ Wout, const float* __restrict__ W1,
    const float* __restrict__ W2,
    __half* __restrict__ Wth)
{
    __shared__ float t[32][33];
    const int l = blockIdx.y;
    const int tt = blockIdx.x;
    const float* W; int K, N, off, tloc;
    if (tt < 768)       { W = Wqkv + (size_t)l * 786432;  K = 512;  N = 1536; off = WQKVT; tloc = tt; }
    else if (tt < 1024) { W = Wkr  + (size_t)l * 262144;  K = 512;  N = 512;  off = WKRT;  tloc = tt - 768; }
    else if (tt < 1280) { W = Wout + (size_t)l * 262144;  K = 512;  N = 512;  off = WOUTT; tloc = tt - 1024; }
    else if (tt < 2304) { W = W1   + (size_t)l * 1048576; K = 512;  N = 2048; off = W1T;   tloc = tt - 1280; }
    else                { W = W2   + (size_t)l * 1048576; K = 2048; N = 512;  off = W2T;   tloc = tt - 2304; }
    const int ntn = N >> 5;
    const int kt = tloc / ntn, nt = tloc % ntn;
    const int k0 = kt * 32, n0 = nt * 32;
    const int x = threadIdx.x, y = threadIdx.y;
    const size_t dst = (size_t)l * WT_TOTAL + off;
#pragma unroll
    for (int i = 0; i < 32; i += 8)
        t[y + i][x] = W[(size_t)(k0 + y + i) * N + n0 + x];
    __syncthreads();
#pragma unroll
    for (int i = 0; i < 32; i += 8)
        Wth[dst + (size_t)(n0 + y + i) * K + k0 + x] = __float2half_rn(t[x][y + i]);
}

// ---------------- r_t -> fp16 ----------------------------------------
__global__ __launch_bounds__(256) void split_rt_kernel(
    const float* __restrict__ src, __half* __restrict__ dh)
{
    const size_t i = ((size_t)blockIdx.x * 256 + threadIdx.x) * 4;
    float4 v = *(const float4*)(src + i);
    __half2 a, b;
    a.x = __float2half_rn(v.x); a.y = __float2half_rn(v.y);
    b.x = __float2half_rn(v.z); b.y = __float2half_rn(v.w);
    *(__half2*)(dh + i) = a;
    *(__half2*)(dh + i + 2) = b;
}

// ---------------- LayerNorm -> fp16 ------------------------------------------
__global__ __launch_bounds__(128) void ln_half_kernel(
    const float* __restrict__ x, const float* __restrict__ g,
    const float* __restrict__ b, __half* __restrict__ yh)
{
    const int row = blockIdx.x;
    const int tid = threadIdx.x;
    const float* xr = x + (size_t)row * NDIM;

    float4 v = ((const float4*)xr)[tid];
    float s  = v.x + v.y + v.z + v.w;
    float sq = v.x*v.x + v.y*v.y + v.z*v.z + v.w*v.w;
#pragma unroll
    for (int o = 16; o > 0; o >>= 1) {
        s  += __shfl_xor_sync(0xffffffffu, s,  o);
        sq += __shfl_xor_sync(0xffffffffu, sq, o);
    }
    __shared__ float red[8];
    const int w = tid >> 5;
    if ((tid & 31) == 0) { red[w] = s; red[4 + w] = sq; }
    __syncthreads();
    const float st  = red[0] + red[1] + red[2] + red[3];
    const float sqt = red[4] + red[5] + red[6] + red[7];
    const float mu  = st * (1.0f / NDIM);
    const float var = sqt * (1.0f / NDIM) - mu * mu;
    const float inv = rsqrtf(var + 1e-5f);

    float4 gg = ((const float4*)g)[tid];
    float4 bb = ((const float4*)b)[tid];
    __half2 a, c;
    a.x = __float2half_rn((v.x - mu) * inv * gg.x + bb.x);
    a.y = __float2half_rn((v.y - mu) * inv * gg.y + bb.y);
    c.x = __float2half_rn((v.z - mu) * inv * gg.z + bb.z);
    c.y = __float2half_rn((v.w - mu) * inv * gg.w + bb.w);
    const size_t base = (size_t)row * NDIM + tid * 4;
    *(__half2*)(yh + base) = a;
    *(__half2*)(yh + base + 2) = c;
}

// ====== dense fp16 mma GEMM, 3-stage cp.async pipeline, 1-term ===============
#define LDS 40
#define ARR   (128*LDS)
#define ARRB  (ARR*2)
#define MMA_SMEM1 (3*2*ARRB)   // 61440

template<int SPLIT, int ACT>
__global__ __launch_bounds__(256, 2) void mma1_kernel(
    const __half* __restrict__ Ah, const __half* __restrict__ Bh,
    float* __restrict__ Cf, __half* __restrict__ Ch,
    const float* __restrict__ bias, const float* __restrict__ res,
    int M, int N, int K)
{
    constexpr uint32_t STAGEB = 2u * ARRB;
    extern __shared__ char dsm[];
    const uint32_t sbase = smem_u32(dsm);
    const int tid = threadIdx.x, wid = tid >> 5, lane = tid & 31;
    const int wm = wid >> 2, wn = wid & 3;
    const int bm = blockIdx.y * 128, bn = blockIdx.x * 128;

    const int lrow = tid >> 2, lcc = (tid & 3) * 8;
    const int lrow2 = (tid + 256) >> 2, lcc2 = ((tid + 256) & 3) * 8;

#define MMA1_ISSUE(kt, s) do {                                                   \
        const uint32_t st_ = sbase + (uint32_t)(s) * STAGEB;                     \
        const int k0_ = (kt) * 32;                                               \
        cp16(st_ + (uint32_t)((lrow * LDS + lcc) * 2),                           \
             Ah + (size_t)(bm + lrow) * K + k0_ + lcc);                          \
        cp16(st_ + (uint32_t)((lrow2 * LDS + lcc2) * 2),                         \
             Ah + (size_t)(bm + lrow2) * K + k0_ + lcc2);                        \
        cp16(st_ + (uint32_t)ARRB + (uint32_t)((lrow * LDS + lcc) * 2),          \
             Bh + (size_t)(bn + lrow) * K + k0_ + lcc);                          \
        cp16(st_ + (uint32_t)ARRB + (uint32_t)((lrow2 * LDS + lcc2) * 2),        \
             Bh + (size_t)(bn + lrow2) * K + k0_ + lcc2);                        \
    } while (0)

    const int l15 = lane & 15;
    const uint32_t aoff = (uint32_t)(((wm * 64 + l15) * LDS + ((lane >> 4) << 3)) * 2);
    const uint32_t boff = (uint32_t)(((wn * 32 + (l15 & 7)) * LDS + (((l15 >> 3) & 1) << 3)) * 2);

    float acc[4][4][4];
#pragma unroll
    for (int i = 0; i < 4; ++i)
#pragma unroll
        for (int j = 0; j < 4; ++j)
#pragma unroll
            for (int q = 0; q < 4; ++q) acc[i][j][q] = 0.0f;

    const int NKT = K >> 5;
    MMA1_ISSUE(0, 0);
    CP_COMMIT();
    MMA1_ISSUE(1, 1);
    CP_COMMIT();

    for (int kt = 0; kt < NKT; ++kt) {
        if (kt + 1 < NKT) { CP_WAIT(1); } else { CP_WAIT(0); }
        __syncthreads();
        if (kt + 2 < NKT) {
            MMA1_ISSUE(kt + 2, (kt + 2) % 3);
            CP_COMMIT();
        }
        const uint32_t st = sbase + (uint32_t)(kt % 3) * STAGEB;
        const uint32_t aAh = st, aBh = st + ARRB;
#pragma unroll
        for (int kk = 0; kk < 32; kk += 16) {
            uint32_t bh[4][2], a[4][4];
#pragma unroll
            for (int nt = 0; nt < 4; ++nt)
                ldm_x2(bh[nt], aBh + boff + (uint32_t)((nt * 8 * LDS + kk) * 2));
#pragma unroll
            for (int mt = 0; mt < 4; ++mt)
                ldm_x4(a[mt], aAh + aoff + (uint32_t)((mt * 16 * LDS + kk) * 2));
#pragma unroll
            for (int mt = 0; mt < 4; ++mt)
#pragma unroll
                for (int nt = 0; nt < 4; ++nt)
                    mma_f16(acc[mt][nt], a[mt], bh[nt]);
        }
    }
#undef MMA1_ISSUE
    __syncthreads();

    const int g = lane >> 2, t2 = (lane & 3) * 2;
#pragma unroll
    for (int mt = 0; mt < 4; ++mt) {
#pragma unroll
        for (int nt = 0; nt < 4; ++nt) {
            const int r0 = bm + wm * 64 + mt * 16 + g;
            const int r1 = r0 + 8;
            const int c  = bn + wn * 32 + nt * 8 + t2;
            float v0 = acc[mt][nt][0], v1 = acc[mt][nt][1];
            float v2 = acc[mt][nt][2], v3 = acc[mt][nt][3];
            if (bias) {
                const float b0 = bias[c], b1 = bias[c + 1];
                v0 += b0; v1 += b1; v2 += b0; v3 += b1;
            }
            if (ACT) {
                v0 = gelu_exact(v0); v1 = gelu_exact(v1);
                v2 = gelu_exact(v2); v3 = gelu_exact(v3);
            }
            if (SPLIT == 2) {
                __half2 hp;
                hp.x = __float2half_rn(v0); hp.y = __float2half_rn(v1);
                *(__half2*)(Ch + (size_t)r0 * N + c) = hp;
                hp.x = __float2half_rn(v2); hp.y = __float2half_rn(v3);
                *(__half2*)(Ch + (size_t)r1 * N + c) = hp;
            } else {
                if (res) {
                    const float2 q0 = *(const float2*)(res + (size_t)r0 * N + c);
                    const float2 q1 = *(const float2*)(res + (size_t)r1 * N + c);
                    v0 += q0.x; v1 += q0.y; v2 += q1.x; v3 += q1.y;
                }
                *(float2*)(Cf + (size_t)r0 * N + c) = make_float2(v0, v1);
                *(float2*)(Cf + (size_t)r1 * N + c) = make_float2(v2, v3);
            }
        }
    }
}

// ---------------- bias rank-1 terms (hi-only inputs) -------------------------
__global__ __launch_bounds__(256) void bias_terms_kernel(
    const __half* __restrict__ qkvh, const __half* __restrict__ krh,
    const float* __restrict__ bias_pf,
    float* __restrict__ bk, float* __restrict__ br)
{
    const int idx = blockIdx.x * 256 + threadIdx.x;
    const int bh = idx >> 10, j = idx & 1023;
    const int b = bh >> 3, h = bh & 7;
    const size_t kb = ((size_t)b * NSEQ + j) * 1536 + 512 + h * 64;
    const size_t rb = ((size_t)b * NSEQ + j) * 512 + h * 64;
    float sk = 0.0f, sr = 0.0f;
#pragma unroll 16
    for (int d = 0; d < 64; ++d) {
        const float bp = bias_pf[h * 64 + d];
        sk += bp * __half2float(qkvh[kb + d]);
        sr += bp * __half2float(krh[rb + d]);
    }
    bk[idx] = sk;
    br[idx] = sr;
}

// =========== acbd fp16 mma, 1-term; fp16 score output ========================
#define ACBD_STAGE (2*ARR)
#define ACBD_SMEM  (2*ACBD_STAGE*2)   // 40960 bytes

__global__ __launch_bounds__(256, 2) void acbd1_kernel(
    const __half* __restrict__ qkvh, const __half* __restrict__ krh,
    const float* __restrict__ bk, const float* __restrict__ br,
    __half* __restrict__ AC, __half* __restrict__ BD)
{
    extern __shared__ char dsm[];
    const uint32_t sbase = smem_u32(dsm);
    const int tid = threadIdx.x, wid = tid >> 5, lane = tid & 31;
    const int wm = wid >> 2, wn = wid & 3;
    const int z = blockIdx.z, bh_idx = z & 63, isBD = z >> 6;
    const int b = bh_idx >> 3, h = bh_idx & 7;
    const int i0 = blockIdx.y * 128, j0 = blockIdx.x * 128;

    const __half* Ah = qkvh + ((size_t)b * NSEQ + i0) * 1536 + h * 64;
    const __half* Bh = isBD ? (krh + ((size_t)b * NSEQ + j0) * 512 + h * 64)
                            : (qkvh + ((size_t)b * NSEQ + j0) * 1536 + 512 + h * 64);
    const int ldb = isBD ? 512 : 1536;
    __half* Cbase = (isBD ? BD : AC) + (size_t)bh_idx * NSEQ * NSEQ;
    const float* bvec = (isBD ? br : bk) + (size_t)bh_idx * NSEQ;

    const int lrow = tid >> 2, lcc = (tid & 3) * 8;
    const int lrow2 = (tid + 256) >> 2, lcc2 = ((tid + 256) & 3) * 8;

#define ACBD_ISSUE(kt, s) do {                                                   \
        const uint32_t st_ = sbase + (uint32_t)(s) * (ACBD_STAGE * 2);           \
        const int k0_ = (kt) * 32;                                               \
        cp16(st_ + (uint32_t)((lrow * LDS + lcc) * 2),                           \
             Ah + (size_t)lrow * 1536 + k0_ + lcc);                              \
        cp16(st_ + (uint32_t)((lrow2 * LDS + lcc2) * 2),                         \
             Ah + (size_t)lrow2 * 1536 + k0_ + lcc2);                            \
        cp16(st_ + (uint32_t)(ARR * 2) + (uint32_t)((lrow * LDS + lcc) * 2),     \
             Bh + (size_t)lrow * ldb + k0_ + lcc);                               \
        cp16(st_ + (uint32_t)(ARR * 2) + (uint32_t)((lrow2 * LDS + lcc2) * 2),   \
             Bh + (size_t)lrow2 * ldb + k0_ + lcc2);                             \
    } while (0)

    const int l15 = lane & 15;
    const uint32_t aoff = (uint32_t)(((wm * 64 + l15) * LDS + ((lane >> 4) << 3)) * 2);
    const uint32_t boff = (uint32_t)(((wn * 32 + (l15 & 7)) * LDS + (((l15 >> 3) & 1) << 3)) * 2);

    float acc[4][4][4];
#pragma unroll
    for (int i = 0; i < 4; ++i)
#pragma unroll
        for (int j = 0; j < 4; ++j)
#pragma unroll
            for (int q = 0; q < 4; ++q) acc[i][j][q] = 0.0f;

    ACBD_ISSUE(0, 0);
    CP_COMMIT();
#pragma unroll
    for (int kt = 0; kt < 2; ++kt) {
        if (kt == 0) {
            ACBD_ISSUE(1, 1);
            CP_COMMIT();
            CP_WAIT(1);
        } else {
            CP_WAIT(0);
        }
        __syncthreads();
        const uint32_t st = sbase + (uint32_t)(kt & 1) * (ACBD_STAGE * 2);
        const uint32_t aAh = st, aBh = st + ARR * 2;
#pragma unroll
        for (int kk = 0; kk < 32; kk += 16) {
            uint32_t bh[4][2], a[4][4];
#pragma unroll
            for (int nt = 0; nt < 4; ++nt)
                ldm_x2(bh[nt], aBh + boff + (uint32_t)((nt * 8 * LDS + kk) * 2));
#pragma unroll
            for (int mt = 0; mt < 4; ++mt)
                ldm_x4(a[mt], aAh + aoff + (uint32_t)((mt * 16 * LDS + kk) * 2));
#pragma unroll
            for (int mt = 0; mt < 4; ++mt)
#pragma unroll
                for (int nt = 0; nt < 4; ++nt)
                    mma_f16(acc[mt][nt], a[mt], bh[nt]);
        }
        __syncthreads();
    }
#undef ACBD_ISSUE

    const int g = lane >> 2, t2 = (lane & 3) * 2;
#pragma unroll
    for (int mt = 0; mt < 4; ++mt) {
#pragma unroll
        for (int nt = 0; nt < 4; ++nt) {
            const int r0 = i0 + wm * 64 + mt * 16 + g;
            const int c  = j0 + wn * 32 + nt * 8 + t2;
            const float b0 = bvec[c], b1 = bvec[c + 1];
            __half2 p;
            p.x = __float2half_rn(acc[mt][nt][0] + b0);
            p.y = __float2half_rn(acc[mt][nt][1] + b1);
            *(__half2*)(Cbase + (size_t)r0 * NSEQ + c) = p;
            p.x = __float2half_rn(acc[mt][nt][2] + b0);
            p.y = __float2half_rn(acc[mt][nt][3] + b1);
            *(__half2*)(Cbase + (size_t)(r0 + 8) * NSEQ + c) = p;
        }
    }
}

// ---------------- V transpose (hi only) --------------------------------------
__global__ __launch_bounds__(256) void vt_kernel(
    const __half* __restrict__ qkvh, __half* __restrict__ vth)
{
    __shared__ __half th[32][33];
    const int bh = blockIdx.z, b = bh >> 3, h = bh & 7;
    const int j0 = blockIdx.x * 32, d0 = blockIdx.y * 32;
    const int x = threadIdx.x, y = threadIdx.y;
#pragma unroll
    for (int i = 0; i < 32; i += 8)
        th[y + i][x] = qkvh[((size_t)b * NSEQ + j0 + y + i) * 1536 + 1024 + h * 64 + d0 + x];
    __syncthreads();
#pragma unroll
    for (int i = 0; i < 32; i += 8)
        vth[((size_t)bh * 64 + d0 + y + i) * NSEQ + j0 + x] = th[x][y + i];
}

// ======= FUSED softmax(heads)+attn@V, double-buffered, 1 barrier/iter ========
// Buffers: att[2] at 0 / 40960; V[2] at 81920 / 122880. Total 163840 B.
#define SAV_ATT(buf) ((uint32_t)(buf) * 40960u)
#define SAV_V(buf)   (81920u + (uint32_t)(buf) * 40960u)
#define SAV_SMEM  163840

__global__ __launch_bounds__(512, 1) void fused_sav_kernel(
    const __half* __restrict__ AC, const __half* __restrict__ BDp,
    const __half* __restrict__ vth,
    __half* __restrict__ outh, float* __restrict__ attnf)
{
    extern __shared__ char dsm[];
    const uint32_t sb = smem_u32(dsm);
    const int tid = threadIdx.x, wid = tid >> 5, lane = tid & 31;
    const int b = blockIdx.y;
    const int i0 = blockIdx.x * 64;
    const int bq = b * NHEADS;

    const int ibA = tid >> 4;
    const int jjA = (tid & 15) * 2;

    const int h = wid & 7, ihalf = wid >> 3;
    const int l15 = lane & 15;
    const uint32_t headOff = (uint32_t)(h * 64 * 40 * 2);
    const uint32_t aoff = (uint32_t)(((ihalf * 32 + l15) * 40 + ((lane >> 4) << 3)) * 2);
    const uint32_t boff = (uint32_t)(((l15 & 7) * 40 + (((l15 >> 3) & 1) << 3)) * 2);

    float acc[2][8][4];
#pragma unroll
    for (int i = 0; i < 2; ++i)
#pragma unroll
        for (int j = 0; j < 8; ++j)
#pragma unroll
            for (int q = 0; q < 4; ++q) acc[i][j][q] = 0.0f;

    // ---- V tile issue for j-tile ktv into V buffer `buf` ----
#define SAV_VISSUE(ktv, buf) do {                                                \
        const int j0_ = (ktv) * 32;                                              \
        _Pragma("unroll")                                                        \
        for (int k_ = 0; k_ < 4; ++k_) {                                         \
            const int idx_ = tid + k_ * 512;                                     \
            const int hv_ = idx_ >> 8;                                           \
            const int r_ = idx_ & 255;                                           \
            const int d_ = r_ >> 2, seg_ = r_ & 3;                               \
            const uint32_t so_ = (uint32_t)((hv_ * 64 + d_) * 80 + seg_ * 16);   \
            const size_t gsrc_ = (((size_t)(bq + hv_) * 64 + d_) << 10) + j0_ + seg_ * 8; \
            cp16(sb + SAV_V(buf) + so_, vth + gsrc_);                            \
        }                                                                        \
        CP_COMMIT();                                                             \
    } while (0)

    // ---- softmax for j-tile ktv into att buffer `buf` ----
#define SAV_SOFTMAX(ktv, buf) do {                                               \
        const int j0_ = (ktv) * 32;                                              \
        _Pragma("unroll")                                                        \
        for (int it_ = 0; it_ < 2; ++it_) {                                      \
            const int i_ = ibA + it_ * 32;                                       \
            const int gi_ = i0 + i_;                                             \
            float p0_[8], p1_[8];                                                \
            _Pragma("unroll")                                                    \
            for (int e_ = 0; e_ < 2; ++e_) {                                     \
                const int gj_ = j0_ + jjA + e_;                                  \
                const int g_ = (gi_ + 1) * NSEQ + gj_;                           \
                const int si_ = g_ / (NSEQ + 1);                                 \
                const int sj_ = g_ % (NSEQ + 1) - 1;                             \
                float v_[8];                                                     \
                float mx_ = -1e30f;                                              \
                _Pragma("unroll")                                                \
                for (int hh_ = 0; hh_ < 8; ++hh_) {                              \
                    const size_t base_ = (size_t)(bq + hh_) * NSEQ;              \
                    float d_ = __half2float(AC[(base_ + gi_) * NSEQ + gj_]);     \
                    if (sj_ >= 0) d_ += __half2float(BDp[(base_ + si_) * NSEQ + sj_]); \
                    d_ *= 0.125f;                                                \
                    v_[hh_] = d_;                                                \
                    mx_ = fmaxf(mx_, d_);                                        \
                }                                                                \
                float s_ = 0.0f;                                                 \
                _Pragma("unroll")                                                \
                for (int hh_ = 0; hh_ < 8; ++hh_) { v_[hh_] = __expf(v_[hh_] - mx_); s_ += v_[hh_]; } \
                const float inv_ = 1.0f / s_;                                    \
                float* pp_ = e_ ? p1_ : p0_;                                     \
                _Pragma("unroll")                                                \
                for (int hh_ = 0; hh_ < 8; ++hh_) pp_[hh_] = v_[hh_] * inv_;     \
            }                                                                    \
            _Pragma("unroll")                                                    \
            for (int hh_ = 0; hh_ < 8; ++hh_) {                                  \
                __half2 hp_;                                                     \
                hp_.x = __float2half_rn(p0_[hh_]);                               \
                hp_.y = __float2half_rn(p1_[hh_]);                               \
                const uint32_t so_ = (uint32_t)(((hh_ * 64 + i_) * 40 + jjA) * 2);\
                *(__half2*)(dsm + SAV_ATT(buf) + so_) = hp_;                     \
                if (attnf) {                                                     \
                    *(float2*)(attnf + ((size_t)(bq + hh_) * NSEQ + gi_) * NSEQ + j0_ + jjA) = \
                        make_float2(p0_[hh_], p1_[hh_]);                         \
                }                                                                \
            }                                                                    \
        }                                                                        \
    } while (0)

    // prologue: V(0) in flight while softmax(0) computes
    SAV_VISSUE(0, 0);
    SAV_SOFTMAX(0, 0);

    for (int kt = 0; kt < 32; ++kt) {
        const int buf = kt & 1;
        CP_WAIT(0);          // V(kt) complete (issued one iteration ago)
        __syncthreads();     // att[buf] + V[buf] visible to all warps
        if (kt + 1 < 32)
            SAV_VISSUE(kt + 1, buf ^ 1);   // safe: nobody reads V[buf^1] now

        const uint32_t aAH = sb + SAV_ATT(buf) + headOff;
        const uint32_t aVH = sb + SAV_V(buf) + headOff;
#pragma unroll
        for (int kk = 0; kk < 32; kk += 16) {
            uint32_t bhf[8][2], ah[2][4];
#pragma unroll
            for (int nt = 0; nt < 8; ++nt)
                ldm_x2(bhf[nt], aVH + boff + (uint32_t)((nt * 8 * 40 + kk) * 2));
#pragma unroll
            for (int mt = 0; mt < 2; ++mt)
                ldm_x4(ah[mt], aAH + aoff + (uint32_t)((mt * 16 * 40 + kk) * 2));
#pragma unroll
            for (int mt = 0; mt < 2; ++mt)
#pragma unroll
                for (int nt = 0; nt < 8; ++nt)
                    mma_f16(acc[mt][nt], ah[mt], bhf[nt]);
        }

        if (kt + 1 < 32)
            SAV_SOFTMAX(kt + 1, buf ^ 1);  // writes other att buffer; no barrier needed
    }
#undef SAV_VISSUE
#undef SAV_SOFTMAX

    const int g = lane >> 2, t2 = (lane & 3) * 2;
#pragma unroll
    for (int mt = 0; mt < 2; ++mt) {
#pragma unroll
        for (int nt = 0; nt < 8; ++nt) {
            const int r0 = i0 + ihalf * 32 + mt * 16 + g;
            const int c  = h * 64 + nt * 8 + t2;
            __half2 hp;
            hp.x = __float2half_rn(acc[mt][nt][0]);
            hp.y = __float2half_rn(acc[mt][nt][1]);
            *(__half2*)(outh + ((size_t)b * NSEQ + r0) * NHD + c) = hp;
            hp.x = __float2half_rn(acc[mt][nt][2]);
            hp.y = __float2half_rn(acc[mt][nt][3]);
            *(__half2*)(outh + ((size_t)b * NSEQ + r0 + 8) * NHD + c) = hp;
        }
    }
}

// ---------------- host orchestration ----------------------------------------
extern "C" void kernel_launch(void* const* d_in, const int* in_sizes, int n_in,
                              void* d_out, int out_size)
{
    (void)in_sizes; (void)n_in;
    const float* x_in    = (const float*)d_in[0];
    const float* r_t     = (const float*)d_in[1];
    const float* bias_pf = (const float*)d_in[3];
    const float* ln1_g   = (const float*)d_in[4];
    const float* ln1_b   = (const float*)d_in[5];
    const float* Wqkv    = (const float*)d_in[6];
    const float* Wkr_t   = (const float*)d_in[7];
    const float* Wout    = (const float*)d_in[9];
    const float* bout    = (const float*)d_in[10];
    const float* ln2_g   = (const float*)d_in[11];
    const float* ln2_b   = (const float*)d_in[12];
    const float* W1      = (const float*)d_in[13];
    const float* b1      = (const float*)d_in[14];
    const float* W2      = (const float*)d_in[15];
    const float* b2      = (const float*)d_in[16];
    float* outp = (float*)d_out;

    static int attr_done = 0;
    if (!attr_done) {
        cudaFuncSetAttribute(mma1_kernel<2,0>, cudaFuncAttributeMaxDynamicSharedMemorySize, MMA_SMEM1);
        cudaFuncSetAttribute(mma1_kernel<0,0>, cudaFuncAttributeMaxDynamicSharedMemorySize, MMA_SMEM1);
        cudaFuncSetAttribute(mma1_kernel<2,1>, cudaFuncAttributeMaxDynamicSharedMemorySize, MMA_SMEM1);
        cudaFuncSetAttribute(acbd1_kernel,     cudaFuncAttributeMaxDynamicSharedMemorySize, ACBD_SMEM);
        cudaFuncSetAttribute(fused_sav_kernel, cudaFuncAttributeMaxDynamicSharedMemorySize, SAV_SMEM);
        attr_done = 1;
    }

    float *gx, *gbk, *gbr;
    __half *gac, *gbd;
    __half *gxnh, *grth, *gqkvh, *gkrh, *gavh, *gffh, *gwth, *gvth;
    cudaGetSymbolAddress((void**)&gx,    g_x);
    cudaGetSymbolAddress((void**)&gac,   g_ac);
    cudaGetSymbolAddress((void**)&gbd,   g_bd);
    cudaGetSymbolAddress((void**)&gbk,   g_bk);
    cudaGetSymbolAddress((void**)&gbr,   g_br);
    cudaGetSymbolAddress((void**)&gxnh,  g_xnh);
    cudaGetSymbolAddress((void**)&grth,  g_rth);
    cudaGetSymbolAddress((void**)&gqkvh, g_qkvh);
    cudaGetSymbolAddress((void**)&gkrh,  g_krh);
    cudaGetSymbolAddress((void**)&gavh,  g_avh);
    cudaGetSymbolAddress((void**)&gffh,  g_ffh);
    cudaGetSymbolAddress((void**)&gwth,  g_wth);
    cudaGetSymbolAddress((void**)&gvth,  g_vth);

    float* attn_out = outp + ((size_t)out_size - ATT_ELEMS);

    cudaMemcpyAsync(gx, x_in, X_ELEMS * sizeof(float), cudaMemcpyDeviceToDevice, 0);
    split_rt_kernel<<<X_ELEMS / 1024, 256>>>(r_t, grth);

    transpose_all_kernel<<<dim3(3328, 4), dim3(32, 8)>>>(
        Wqkv, Wkr_t, Wout, W1, W2, gwth);

    const dim3 tb(32, 8);
    for (int l = 0; l < 4; ++l) {
        const size_t wb = (size_t)l * WT_TOTAL;

        ln_half_kernel<<<MROWS, 128>>>(gx, ln1_g + l * NDIM, ln1_b + l * NDIM, gxnh);
        mma1_kernel<2,0><<<dim3(12, 64), 256, MMA_SMEM1>>>(
            gxnh, gwth + wb + WQKVT, nullptr, gqkvh, nullptr, nullptr, MROWS, 1536, 512);
        mma1_kernel<2,0><<<dim3(4, 64), 256, MMA_SMEM1>>>(
            grth, gwth + wb + WKRT, nullptr, gkrh, nullptr, nullptr, MROWS, 512, 512);

        bias_terms_kernel<<<256, 256>>>(gqkvh, gkrh, bias_pf, gbk, gbr);

        acbd1_kernel<<<dim3(8, 8, 128), 256, ACBD_SMEM>>>(
            gqkvh, gkrh, gbk, gbr, gac, gbd);

        vt_kernel<<<dim3(32, 2, 64), tb>>>(gqkvh, gvth);

        fused_sav_kernel<<<dim3(16, 8), 512, SAV_SMEM>>>(
            gac, gbd, gvth, gavh, (l == 3) ? attn_out : nullptr);

        mma1_kernel<0,0><<<dim3(4, 64), 256, MMA_SMEM1>>>(
            gavh, gwth + wb + WOUTT, gx, nullptr, bout + l * NDIM, gx, MROWS, 512, 512);

        ln_half_kernel<<<MROWS, 128>>>(gx, ln2_g + l * NDIM, ln2_b + l * NDIM, gxnh);
        mma1_kernel<2,1><<<dim3(16, 64), 256, MMA_SMEM1>>>(
            gxnh, gwth + wb + W1T, nullptr, gffh, b1 + l * NFF, nullptr, MROWS, 2048, 512);
        float* xdst = (l == 3) ? outp : gx;
        mma1_kernel<0,0><<<dim3(4, 64), 256, MMA_SMEM1>>>(
            gffh, gwth + wb + W2T, xdst, nullptr, b2 + l * NDIM, gx, MROWS, 512, 2048);
    }
}